// round 1
// baseline (speedup 1.0000x reference)
#include <cuda_runtime.h>
#include <math.h>

// Problem dims (fixed by the dataset)
#define B_DIM 1024
#define T_DIM 128
#define L_DIM 16
#define H_DIM 512
#define D_DIM 64
#define G_DIM (4 * H_DIM)   // 2048

// ---------------------------------------------------------------------------
// Scratch (device globals — no allocation allowed in kernel_launch)
// ---------------------------------------------------------------------------
__device__ float g_x1[B_DIM * H_DIM];                     //   2 MB
__device__ float g_x2[B_DIM * H_DIM];                     //   2 MB
__device__ float g_conds[B_DIM * H_DIM];                  //   2 MB
__device__ float g_CW[B_DIM * G_DIM];                     //   8 MB  conds @ Wih^T
__device__ float g_ZW[(size_t)T_DIM * B_DIM * G_DIM];     //   1 GB  z @ Wih^T
__device__ float g_HW[B_DIM * G_DIM];                     //   8 MB  h @ Whh^T (per step)
__device__ float g_h[B_DIM * H_DIM];                      //   2 MB
__device__ float g_c[B_DIM * H_DIM];                      //   2 MB
__device__ float g_Hbuf[(size_t)T_DIM * B_DIM * H_DIM];   // 256 MB  all h_t
__device__ float g_y1[(size_t)T_DIM * B_DIM * H_DIM];     // 256 MB
__device__ float g_y2[(size_t)T_DIM * B_DIM * H_DIM];     // 256 MB

// ---------------------------------------------------------------------------
// Tiled SGEMM:  C[M,N] = act(A[M,K] @ W[N,K]^T + bias[N])
// All dims must be multiples of the block tile (true for every call site).
// ACT: 0 = none, 1 = relu.  PERM: remap row m = t*B+b -> out[(b*T+t)*D + n].
// ---------------------------------------------------------------------------
template<int BM, int BN, int BK, int TM, int TN, int ACT, bool PERM>
__global__ void gemm_kernel(const float* __restrict__ A,
                            const float* __restrict__ W,
                            const float* __restrict__ bias,
                            float* __restrict__ C,
                            int M, int N, int K)
{
    __shared__ float As[BK][BM];
    __shared__ float Ws[BK][BN];

    constexpr int NTHREADS = (BM / TM) * (BN / TN);
    const int tid = threadIdx.x;
    const int tx = tid % (BN / TN);
    const int ty = tid / (BN / TN);
    const int m0 = blockIdx.y * BM;
    const int n0 = blockIdx.x * BN;

    float acc[TM][TN];
#pragma unroll
    for (int i = 0; i < TM; i++)
#pragma unroll
        for (int j = 0; j < TN; j++) acc[i][j] = 0.f;

    for (int k0 = 0; k0 < K; k0 += BK) {
        // Load A tile (transposed into As[k][m]) with float4 global reads
#pragma unroll
        for (int i = tid * 4; i < BM * BK; i += NTHREADS * 4) {
            int m = i / BK, k = i % BK;
            float4 v = *(const float4*)(A + (long)(m0 + m) * K + (k0 + k));
            As[k + 0][m] = v.x; As[k + 1][m] = v.y;
            As[k + 2][m] = v.z; As[k + 3][m] = v.w;
        }
        // Load W tile (transposed into Ws[k][n])
#pragma unroll
        for (int i = tid * 4; i < BN * BK; i += NTHREADS * 4) {
            int n = i / BK, k = i % BK;
            float4 v = *(const float4*)(W + (long)(n0 + n) * K + (k0 + k));
            Ws[k + 0][n] = v.x; Ws[k + 1][n] = v.y;
            Ws[k + 2][n] = v.z; Ws[k + 3][n] = v.w;
        }
        __syncthreads();

#pragma unroll
        for (int k = 0; k < BK; k++) {
            float am[TM], wn[TN];
#pragma unroll
            for (int i = 0; i < TM; i++) am[i] = As[k][ty * TM + i];
#pragma unroll
            for (int j = 0; j < TN; j++) wn[j] = Ws[k][tx * TN + j];
#pragma unroll
            for (int i = 0; i < TM; i++)
#pragma unroll
                for (int j = 0; j < TN; j++)
                    acc[i][j] = fmaf(am[i], wn[j], acc[i][j]);
        }
        __syncthreads();
    }

    // Epilogue
#pragma unroll
    for (int i = 0; i < TM; i++) {
        int m = m0 + ty * TM + i;
#pragma unroll
        for (int j = 0; j < TN; j++) {
            int n = n0 + tx * TN + j;
            float v = acc[i][j];
            if (bias) v += bias[n];
            if (ACT == 1) v = fmaxf(v, 0.f);
            if (PERM) {
                int t = m / B_DIM;
                int b = m % B_DIM;
                C[((long)b * T_DIM + t) * D_DIM + n] = v;
            } else {
                C[(long)m * N + n] = v;
            }
        }
    }
}

// ---------------------------------------------------------------------------
// LSTM cell (elementwise): gates = ZW[t] + CW + HW + bih + bhh
// torch gate order: i, f, g, o at offsets 0, H, 2H, 3H
// ---------------------------------------------------------------------------
__global__ void lstm_cell_kernel(const float* __restrict__ ZWt,
                                 const float* __restrict__ CW,
                                 const float* __restrict__ HW,
                                 const float* __restrict__ bih,
                                 const float* __restrict__ bhh,
                                 float* __restrict__ h,
                                 float* __restrict__ c,
                                 float* __restrict__ hbuf)
{
    int idx = blockIdx.x * blockDim.x + threadIdx.x;  // [0, B*H)
    int b = idx / H_DIM;
    int j = idx % H_DIM;
    long base = (long)b * G_DIM;

    float gi = ZWt[base + 0 * H_DIM + j] + CW[base + 0 * H_DIM + j] + HW[base + 0 * H_DIM + j]
             + bih[0 * H_DIM + j] + bhh[0 * H_DIM + j];
    float gf = ZWt[base + 1 * H_DIM + j] + CW[base + 1 * H_DIM + j] + HW[base + 1 * H_DIM + j]
             + bih[1 * H_DIM + j] + bhh[1 * H_DIM + j];
    float gg = ZWt[base + 2 * H_DIM + j] + CW[base + 2 * H_DIM + j] + HW[base + 2 * H_DIM + j]
             + bih[2 * H_DIM + j] + bhh[2 * H_DIM + j];
    float go = ZWt[base + 3 * H_DIM + j] + CW[base + 3 * H_DIM + j] + HW[base + 3 * H_DIM + j]
             + bih[3 * H_DIM + j] + bhh[3 * H_DIM + j];

    float i_ = 1.f / (1.f + expf(-gi));
    float f_ = 1.f / (1.f + expf(-gf));
    float g_ = tanhf(gg);
    float o_ = 1.f / (1.f + expf(-go));

    float cn = f_ * c[idx] + i_ * g_;
    float hn = o_ * tanhf(cn);
    c[idx] = cn;
    h[idx] = hn;
    hbuf[idx] = hn;
}

__global__ void init_hc_kernel(float* __restrict__ h, float* __restrict__ c)
{
    int idx = blockIdx.x * blockDim.x + threadIdx.x;
    h[idx] = 0.f;
    c[idx] = 0.f;
}

// ---------------------------------------------------------------------------
// Launch
// ---------------------------------------------------------------------------
extern "C" void kernel_launch(void* const* d_in, const int* in_sizes, int n_in,
                              void* d_out, int out_size)
{
    const float* labels = (const float*)d_in[0];
    const float* z      = (const float*)d_in[1];
    const float* W1     = (const float*)d_in[2];
    const float* b1     = (const float*)d_in[3];
    const float* W2     = (const float*)d_in[4];
    const float* b2     = (const float*)d_in[5];
    const float* W3     = (const float*)d_in[6];
    const float* Wih    = (const float*)d_in[7];
    const float* Whh    = (const float*)d_in[8];
    const float* bih    = (const float*)d_in[9];
    const float* bhh    = (const float*)d_in[10];
    const float* P1     = (const float*)d_in[11];
    const float* pb1    = (const float*)d_in[12];
    const float* P2     = (const float*)d_in[13];
    const float* pb2    = (const float*)d_in[14];
    const float* P3     = (const float*)d_in[15];
    const float* pb3    = (const float*)d_in[16];
    float* out = (float*)d_out;

    float *x1, *x2, *conds, *CW, *ZW, *HW, *h, *c, *Hbuf, *y1, *y2;
    cudaGetSymbolAddress((void**)&x1,    g_x1);
    cudaGetSymbolAddress((void**)&x2,    g_x2);
    cudaGetSymbolAddress((void**)&conds, g_conds);
    cudaGetSymbolAddress((void**)&CW,    g_CW);
    cudaGetSymbolAddress((void**)&ZW,    g_ZW);
    cudaGetSymbolAddress((void**)&HW,    g_HW);
    cudaGetSymbolAddress((void**)&h,     g_h);
    cudaGetSymbolAddress((void**)&c,     g_c);
    cudaGetSymbolAddress((void**)&Hbuf,  g_Hbuf);
    cudaGetSymbolAddress((void**)&y1,    g_y1);
    cudaGetSymbolAddress((void**)&y2,    g_y2);

    // --- Label MLP: conds = relu(relu(labels@W1^T+b1)@W2^T+b2)@W3^T ---
    gemm_kernel<128,128,16,8,8,1,false><<<dim3(H_DIM/128, B_DIM/128), 256>>>(
        labels, W1, b1, x1, B_DIM, H_DIM, L_DIM);
    gemm_kernel<128,128,16,8,8,1,false><<<dim3(H_DIM/128, B_DIM/128), 256>>>(
        x1, W2, b2, x2, B_DIM, H_DIM, H_DIM);
    gemm_kernel<128,128,16,8,8,0,false><<<dim3(H_DIM/128, B_DIM/128), 256>>>(
        x2, W3, nullptr, conds, B_DIM, H_DIM, H_DIM);

    // --- Precompute input contributions (fully parallel) ---
    // CW = conds @ Wih^T          [B, 4H]
    gemm_kernel<128,128,16,8,8,0,false><<<dim3(G_DIM/128, B_DIM/128), 256>>>(
        conds, Wih, nullptr, CW, B_DIM, G_DIM, H_DIM);
    // ZW = z @ Wih^T              [T*B, 4H]  (one big GEMM)
    gemm_kernel<128,128,16,8,8,0,false><<<dim3(G_DIM/128, (T_DIM*B_DIM)/128), 256>>>(
        z, Wih, nullptr, ZW, T_DIM*B_DIM, G_DIM, H_DIM);

    // --- Recurrence (only truly sequential part) ---
    init_hc_kernel<<<(B_DIM*H_DIM)/256, 256>>>(h, c);
    for (int t = 0; t < T_DIM; t++) {
        gemm_kernel<128,128,16,8,8,0,false><<<dim3(G_DIM/128, B_DIM/128), 256>>>(
            h, Whh, nullptr, HW, B_DIM, G_DIM, H_DIM);
        lstm_cell_kernel<<<(B_DIM*H_DIM)/256, 256>>>(
            ZW + (long)t * B_DIM * G_DIM, CW, HW, bih, bhh,
            h, c, Hbuf + (long)t * B_DIM * H_DIM);
    }

    // --- Projection MLP, batched over all T*B rows (fully parallel) ---
    gemm_kernel<128,128,16,8,8,1,false><<<dim3(H_DIM/128, (T_DIM*B_DIM)/128), 256>>>(
        Hbuf, P1, pb1, y1, T_DIM*B_DIM, H_DIM, H_DIM);
    gemm_kernel<128,128,16,8,8,1,false><<<dim3(H_DIM/128, (T_DIM*B_DIM)/128), 256>>>(
        y1, P2, pb2, y2, T_DIM*B_DIM, H_DIM, H_DIM);
    // Final projection with [T,B,D] -> [B,T,D] permute fused into the epilogue
    gemm_kernel<64,64,16,4,4,0,true><<<dim3(D_DIM/64, (T_DIM*B_DIM)/64), 256>>>(
        y2, P3, pb3, out, T_DIM*B_DIM, D_DIM, H_DIM);
}

// round 2
// speedup vs baseline: 1.3807x; 1.3807x over previous
#include <cuda_runtime.h>
#include <math.h>

// Problem dims (fixed by the dataset)
#define B_DIM 1024
#define T_DIM 128
#define L_DIM 16
#define H_DIM 512
#define D_DIM 64
#define G_DIM (4 * H_DIM)   // 2048

// ---------------------------------------------------------------------------
// Scratch (device globals — no allocation allowed in kernel_launch)
// ---------------------------------------------------------------------------
__device__ float g_x1[B_DIM * H_DIM];
__device__ float g_x2[B_DIM * H_DIM];
__device__ float g_conds[B_DIM * H_DIM];
__device__ float g_CW[B_DIM * G_DIM];
__device__ float g_ZW[(size_t)T_DIM * B_DIM * G_DIM];     // 1 GB
__device__ float g_HW[B_DIM * G_DIM];
__device__ float g_h[B_DIM * H_DIM];
__device__ float g_c[B_DIM * H_DIM];
__device__ float g_Hbuf[(size_t)T_DIM * B_DIM * H_DIM];   // 256 MB
__device__ float g_y1[(size_t)T_DIM * B_DIM * H_DIM];
__device__ float g_y2[(size_t)T_DIM * B_DIM * H_DIM];

// ---------------------------------------------------------------------------
// Packed fp32x2 helpers (sm_103a dual-rate FFMA path — PTX only)
// ---------------------------------------------------------------------------
__device__ __forceinline__ void ffma2(unsigned long long& d,
                                      unsigned long long a,
                                      unsigned long long b) {
    asm("fma.rn.f32x2 %0, %1, %2, %0;" : "+l"(d) : "l"(a), "l"(b));
}
__device__ __forceinline__ unsigned long long pack2(float lo, float hi) {
    unsigned long long r;
    asm("mov.b64 %0, {%1, %2};" : "=l"(r) : "f"(lo), "f"(hi));
    return r;
}
__device__ __forceinline__ float2 unpack2(unsigned long long u) {
    float2 f;
    asm("mov.b64 {%0, %1}, %2;" : "=f"(f.x), "=f"(f.y) : "l"(u));
    return f;
}

// ---------------------------------------------------------------------------
// Packed tiled SGEMM:  C[M,N] = act(A[M,K] @ W[N,K]^T + bias[N])
// TM must be mult of 4, TN == 4. Accumulators packed over the M dimension
// (natural from contiguous As reads); W values duplicated into both halves.
// ACT: 0 = none, 1 = relu.  PERM: row m = t*B+b -> out[(b*T+t)*D + n].
// ---------------------------------------------------------------------------
template<int BM, int BN, int BK, int TM, int TN, int ACT, bool PERM>
__global__ void gemm2_kernel(const float* __restrict__ A,
                             const float* __restrict__ W,
                             const float* __restrict__ bias,
                             float* __restrict__ C,
                             int M, int N, int K)
{
    constexpr int AS_STRIDE = BM + 4;   // pad: keeps 16B alignment, kills
    constexpr int WS_STRIDE = BN + 4;   // cross-k same-bank store conflicts
    __shared__ float As[BK][AS_STRIDE];
    __shared__ float Ws[BK][WS_STRIDE];

    constexpr int NTH = (BM / TM) * (BN / TN);
    const int tid = threadIdx.x;
    const int tx = tid % (BN / TN);
    const int ty = tid / (BN / TN);
    const int m0 = blockIdx.y * BM;
    const int n0 = blockIdx.x * BN;

    unsigned long long acc2[TM / 2][TN];   // (row 2p, row 2p+1) packed
#pragma unroll
    for (int p = 0; p < TM / 2; p++)
#pragma unroll
        for (int j = 0; j < TN; j++) acc2[p][j] = 0ULL;

    for (int k0 = 0; k0 < K; k0 += BK) {
        // Load A tile, transposed into As[k][m]
#pragma unroll
        for (int i = tid * 4; i < BM * BK; i += NTH * 4) {
            int m = i / BK, k = i % BK;
            float4 v = *(const float4*)(A + (long)(m0 + m) * K + (k0 + k));
            As[k + 0][m] = v.x; As[k + 1][m] = v.y;
            As[k + 2][m] = v.z; As[k + 3][m] = v.w;
        }
        // Load W tile, transposed into Ws[k][n]
#pragma unroll
        for (int i = tid * 4; i < BN * BK; i += NTH * 4) {
            int n = i / BK, k = i % BK;
            float4 v = *(const float4*)(W + (long)(n0 + n) * K + (k0 + k));
            Ws[k + 0][n] = v.x; Ws[k + 1][n] = v.y;
            Ws[k + 2][n] = v.z; Ws[k + 3][n] = v.w;
        }
        __syncthreads();

#pragma unroll
        for (int k = 0; k < BK; k++) {
            // A fragment: TM contiguous floats -> TM/2 packed pairs (16B loads)
            unsigned long long am2[TM / 2];
            const ulonglong2* ap =
                reinterpret_cast<const ulonglong2*>(&As[k][ty * TM]);
#pragma unroll
            for (int q = 0; q < TM / 4; q++) {
                ulonglong2 t = ap[q];
                am2[2 * q + 0] = t.x;
                am2[2 * q + 1] = t.y;
            }
            // W fragment: 4 floats, each duplicated into both packed halves
            float4 w4 = *reinterpret_cast<const float4*>(&Ws[k][tx * TN]);
            unsigned long long wd[TN];
            wd[0] = pack2(w4.x, w4.x);
            wd[1] = pack2(w4.y, w4.y);
            wd[2] = pack2(w4.z, w4.z);
            wd[3] = pack2(w4.w, w4.w);
#pragma unroll
            for (int p = 0; p < TM / 2; p++)
#pragma unroll
                for (int j = 0; j < TN; j++)
                    ffma2(acc2[p][j], am2[p], wd[j]);
        }
        __syncthreads();
    }

    // Epilogue: one float4 store per output row
    float4 bv = make_float4(0.f, 0.f, 0.f, 0.f);
    if (bias)
        bv = *reinterpret_cast<const float4*>(bias + n0 + tx * TN);

#pragma unroll
    for (int p = 0; p < TM / 2; p++) {
        float2 v0 = unpack2(acc2[p][0]);
        float2 v1 = unpack2(acc2[p][1]);
        float2 v2 = unpack2(acc2[p][2]);
        float2 v3 = unpack2(acc2[p][3]);
        float4 rowA = make_float4(v0.x + bv.x, v1.x + bv.y, v2.x + bv.z, v3.x + bv.w);
        float4 rowB = make_float4(v0.y + bv.x, v1.y + bv.y, v2.y + bv.z, v3.y + bv.w);
        if (ACT == 1) {
            rowA.x = fmaxf(rowA.x, 0.f); rowA.y = fmaxf(rowA.y, 0.f);
            rowA.z = fmaxf(rowA.z, 0.f); rowA.w = fmaxf(rowA.w, 0.f);
            rowB.x = fmaxf(rowB.x, 0.f); rowB.y = fmaxf(rowB.y, 0.f);
            rowB.z = fmaxf(rowB.z, 0.f); rowB.w = fmaxf(rowB.w, 0.f);
        }
        int mA = m0 + ty * TM + 2 * p;
        int n  = n0 + tx * TN;
        if (PERM) {
            int tA = mA / B_DIM, bA = mA % B_DIM;
            int tB = (mA + 1) / B_DIM, bB = (mA + 1) % B_DIM;
            *reinterpret_cast<float4*>(C + ((long)bA * T_DIM + tA) * D_DIM + n) = rowA;
            *reinterpret_cast<float4*>(C + ((long)bB * T_DIM + tB) * D_DIM + n) = rowB;
        } else {
            *reinterpret_cast<float4*>(C + (long)mA * N + n) = rowA;
            *reinterpret_cast<float4*>(C + (long)(mA + 1) * N + n) = rowB;
        }
    }
}

// ---------------------------------------------------------------------------
// LSTM cell (elementwise)
// ---------------------------------------------------------------------------
__global__ void lstm_cell_kernel(const float* __restrict__ ZWt,
                                 const float* __restrict__ CW,
                                 const float* __restrict__ HW,
                                 const float* __restrict__ bih,
                                 const float* __restrict__ bhh,
                                 float* __restrict__ h,
                                 float* __restrict__ c,
                                 float* __restrict__ hbuf)
{
    int idx = blockIdx.x * blockDim.x + threadIdx.x;  // [0, B*H)
    int b = idx / H_DIM;
    int j = idx % H_DIM;
    long base = (long)b * G_DIM;

    float gi = ZWt[base + 0 * H_DIM + j] + CW[base + 0 * H_DIM + j] + HW[base + 0 * H_DIM + j]
             + bih[0 * H_DIM + j] + bhh[0 * H_DIM + j];
    float gf = ZWt[base + 1 * H_DIM + j] + CW[base + 1 * H_DIM + j] + HW[base + 1 * H_DIM + j]
             + bih[1 * H_DIM + j] + bhh[1 * H_DIM + j];
    float gg = ZWt[base + 2 * H_DIM + j] + CW[base + 2 * H_DIM + j] + HW[base + 2 * H_DIM + j]
             + bih[2 * H_DIM + j] + bhh[2 * H_DIM + j];
    float go = ZWt[base + 3 * H_DIM + j] + CW[base + 3 * H_DIM + j] + HW[base + 3 * H_DIM + j]
             + bih[3 * H_DIM + j] + bhh[3 * H_DIM + j];

    float i_ = 1.f / (1.f + expf(-gi));
    float f_ = 1.f / (1.f + expf(-gf));
    float g_ = tanhf(gg);
    float o_ = 1.f / (1.f + expf(-go));

    float cn = f_ * c[idx] + i_ * g_;
    float hn = o_ * tanhf(cn);
    c[idx] = cn;
    h[idx] = hn;
    hbuf[idx] = hn;
}

__global__ void init_hc_kernel(float* __restrict__ h, float* __restrict__ c)
{
    int idx = blockIdx.x * blockDim.x + threadIdx.x;
    h[idx] = 0.f;
    c[idx] = 0.f;
}

// ---------------------------------------------------------------------------
// Launch
// ---------------------------------------------------------------------------
extern "C" void kernel_launch(void* const* d_in, const int* in_sizes, int n_in,
                              void* d_out, int out_size)
{
    const float* labels = (const float*)d_in[0];
    const float* z      = (const float*)d_in[1];
    const float* W1     = (const float*)d_in[2];
    const float* b1     = (const float*)d_in[3];
    const float* W2     = (const float*)d_in[4];
    const float* b2     = (const float*)d_in[5];
    const float* W3     = (const float*)d_in[6];
    const float* Wih    = (const float*)d_in[7];
    const float* Whh    = (const float*)d_in[8];
    const float* bih    = (const float*)d_in[9];
    const float* bhh    = (const float*)d_in[10];
    const float* P1     = (const float*)d_in[11];
    const float* pb1    = (const float*)d_in[12];
    const float* P2     = (const float*)d_in[13];
    const float* pb2    = (const float*)d_in[14];
    const float* P3     = (const float*)d_in[15];
    const float* pb3    = (const float*)d_in[16];
    float* out = (float*)d_out;

    float *x1, *x2, *conds, *CW, *ZW, *HW, *h, *c, *Hbuf, *y1, *y2;
    cudaGetSymbolAddress((void**)&x1,    g_x1);
    cudaGetSymbolAddress((void**)&x2,    g_x2);
    cudaGetSymbolAddress((void**)&conds, g_conds);
    cudaGetSymbolAddress((void**)&CW,    g_CW);
    cudaGetSymbolAddress((void**)&ZW,    g_ZW);
    cudaGetSymbolAddress((void**)&HW,    g_HW);
    cudaGetSymbolAddress((void**)&h,     g_h);
    cudaGetSymbolAddress((void**)&c,     g_c);
    cudaGetSymbolAddress((void**)&Hbuf,  g_Hbuf);
    cudaGetSymbolAddress((void**)&y1,    g_y1);
    cudaGetSymbolAddress((void**)&y2,    g_y2);

    // Config: BM=128, BN=128, BK=16, TM=8, TN=4 -> 512 threads
    constexpr int THR_128 = (128 / 8) * (128 / 4);   // 512
    constexpr int THR_64  = (128 / 8) * (64 / 4);    // 256

    // --- Label MLP ---
    gemm2_kernel<128,128,16,8,4,1,false><<<dim3(H_DIM/128, B_DIM/128), THR_128>>>(
        labels, W1, b1, x1, B_DIM, H_DIM, L_DIM);
    gemm2_kernel<128,128,16,8,4,1,false><<<dim3(H_DIM/128, B_DIM/128), THR_128>>>(
        x1, W2, b2, x2, B_DIM, H_DIM, H_DIM);
    gemm2_kernel<128,128,16,8,4,0,false><<<dim3(H_DIM/128, B_DIM/128), THR_128>>>(
        x2, W3, nullptr, conds, B_DIM, H_DIM, H_DIM);

    // --- Precompute input contributions (fully parallel) ---
    gemm2_kernel<128,128,16,8,4,0,false><<<dim3(G_DIM/128, B_DIM/128), THR_128>>>(
        conds, Wih, nullptr, CW, B_DIM, G_DIM, H_DIM);
    gemm2_kernel<128,128,16,8,4,0,false><<<dim3(G_DIM/128, (T_DIM*B_DIM)/128), THR_128>>>(
        z, Wih, nullptr, ZW, T_DIM*B_DIM, G_DIM, H_DIM);

    // --- Recurrence (only truly sequential part) ---
    init_hc_kernel<<<(B_DIM*H_DIM)/256, 256>>>(h, c);
    for (int t = 0; t < T_DIM; t++) {
        gemm2_kernel<128,128,16,8,4,0,false><<<dim3(G_DIM/128, B_DIM/128), THR_128>>>(
            h, Whh, nullptr, HW, B_DIM, G_DIM, H_DIM);
        lstm_cell_kernel<<<(B_DIM*H_DIM)/256, 256>>>(
            ZW + (long)t * B_DIM * G_DIM, CW, HW, bih, bhh,
            h, c, Hbuf + (long)t * B_DIM * H_DIM);
    }

    // --- Projection MLP, batched over all T*B rows ---
    gemm2_kernel<128,128,16,8,4,1,false><<<dim3(H_DIM/128, (T_DIM*B_DIM)/128), THR_128>>>(
        Hbuf, P1, pb1, y1, T_DIM*B_DIM, H_DIM, H_DIM);
    gemm2_kernel<128,128,16,8,4,1,false><<<dim3(H_DIM/128, (T_DIM*B_DIM)/128), THR_128>>>(
        y1, P2, pb2, y2, T_DIM*B_DIM, H_DIM, H_DIM);
    gemm2_kernel<128,64,16,8,4,0,true><<<dim3(D_DIM/64, (T_DIM*B_DIM)/128), THR_64>>>(
        y2, P3, pb3, out, T_DIM*B_DIM, D_DIM, H_DIM);
}

// round 3
// speedup vs baseline: 1.8221x; 1.3197x over previous
#include <cuda_runtime.h>
#include <cuda_bf16.h>
#include <math.h>

// Problem dims (fixed by the dataset)
#define B_DIM 1024
#define T_DIM 128
#define L_DIM 16
#define H_DIM 512
#define D_DIM 64
#define G_DIM 2048          // 4*H

// ---------------------------------------------------------------------------
// Scratch (device globals — no allocation allowed in kernel_launch)
// Packed format: one u32 per fp32 element = (bf16_hi << 16) | bf16_lo
// ---------------------------------------------------------------------------
__device__ float    g_x1[B_DIM * H_DIM];
__device__ float    g_x2[B_DIM * H_DIM];
__device__ float    g_conds[B_DIM * H_DIM];
__device__ unsigned g_condsp[B_DIM * H_DIM];
__device__ float    g_bperm[G_DIM];
__device__ unsigned g_Wihp[G_DIM * H_DIM];                    // gate-permuted, packed
__device__ unsigned g_Whhp[G_DIM * H_DIM];
__device__ unsigned g_P1p[H_DIM * H_DIM];
__device__ unsigned g_P2p[H_DIM * H_DIM];
__device__ unsigned g_P3p[D_DIM * H_DIM];
__device__ float    g_CWB[B_DIM * G_DIM];                     // conds@Wih^T + biases (perm)
__device__ unsigned g_zp[(size_t)T_DIM * B_DIM * H_DIM];      // packed z
__device__ float    g_ZW[(size_t)T_DIM * B_DIM * G_DIM];      // 1 GB, z@Wih^T (perm cols)
__device__ unsigned g_h0p[B_DIM * H_DIM];
__device__ float    g_c[B_DIM * H_DIM];
__device__ unsigned g_Hp[(size_t)T_DIM * B_DIM * H_DIM];      // packed h_t
__device__ unsigned g_y1p[(size_t)T_DIM * B_DIM * H_DIM];
__device__ unsigned g_y2p[(size_t)T_DIM * B_DIM * H_DIM];

// ---------------------------------------------------------------------------
// bf16 hi/lo split packing
// ---------------------------------------------------------------------------
__device__ __forceinline__ unsigned packf(float x) {
    __nv_bfloat16 h = __float2bfloat16(x);
    float r = x - __bfloat162float(h);
    __nv_bfloat16 l = __float2bfloat16(r);
    return ((unsigned)__bfloat16_as_ushort(h) << 16) |
            (unsigned)__bfloat16_as_ushort(l);
}
__device__ __forceinline__ uint4 packf4(float4 v) {
    return make_uint4(packf(v.x), packf(v.y), packf(v.z), packf(v.w));
}

// mma.sync m16n8k16 row.col bf16 -> f32
__device__ __forceinline__ void mma16816(float& c0, float& c1, float& c2, float& c3,
                                         unsigned a0, unsigned a1, unsigned a2, unsigned a3,
                                         unsigned b0, unsigned b1) {
    asm volatile(
        "mma.sync.aligned.m16n8k16.row.col.f32.bf16.bf16.f32 "
        "{%0,%1,%2,%3}, {%4,%5,%6,%7}, {%8,%9}, {%0,%1,%2,%3};\n"
        : "+f"(c0), "+f"(c1), "+f"(c2), "+f"(c3)
        : "r"(a0), "r"(a1), "r"(a2), "r"(a3), "r"(b0), "r"(b1));
}

// ---------------------------------------------------------------------------
// Generic tensor-core GEMM (3xbf16):  C[M,N] = act(A[M,K] @ W[N,K]^T + bias)
// A, W packed u32. OUTMODE: 0 = fp32, 1 = packed u32, 2 = fp32 + [T,B]->[B,T] perm
// ---------------------------------------------------------------------------
template<int BM, int BN, int WM, int WN, int ACT, int OUTMODE>
__global__ void __launch_bounds__((BM / WM) * (BN / WN) * 32)
tgemm_kernel(const unsigned* __restrict__ A,
             const unsigned* __restrict__ W,
             const float* __restrict__ bias,
             void* __restrict__ Cout,
             int M, int N, int K)
{
    constexpr int BK = 32;
    constexpr int WARPS_N = BN / WN;
    constexpr int NTH = (BM / WM) * (BN / WN) * 32;
    constexpr int MI = WM / 16, NI = WN / 8;
    constexpr int AST = BK + 4;

    __shared__ unsigned As[BM * AST];
    __shared__ unsigned Ws[BN * AST];

    const int tid  = threadIdx.x;
    const int warp = tid >> 5, lane = tid & 31;
    const int g = lane >> 2, t = lane & 3;
    const int wm0 = (warp / WARPS_N) * WM;
    const int wn0 = (warp % WARPS_N) * WN;
    const int m0 = blockIdx.y * BM;
    const int n0 = blockIdx.x * BN;

    float acc[MI][NI][4];
#pragma unroll
    for (int mi = 0; mi < MI; mi++)
#pragma unroll
        for (int ni = 0; ni < NI; ni++)
#pragma unroll
            for (int q = 0; q < 4; q++) acc[mi][ni][q] = 0.f;

    for (int k0 = 0; k0 < K; k0 += BK) {
#pragma unroll
        for (int i = tid; i < BM * BK / 4; i += NTH) {
            int r = i >> 3, c = (i & 7) << 2;
            uint4 v = *(const uint4*)(A + (size_t)(m0 + r) * K + k0 + c);
            *(uint4*)&As[r * AST + c] = v;
        }
#pragma unroll
        for (int i = tid; i < BN * BK / 4; i += NTH) {
            int r = i >> 3, c = (i & 7) << 2;
            uint4 v = *(const uint4*)(W + (size_t)(n0 + r) * K + k0 + c);
            *(uint4*)&Ws[r * AST + c] = v;
        }
        __syncthreads();

#pragma unroll
        for (int kk = 0; kk < BK; kk += 16) {
            unsigned ah[MI][4], al[MI][4], bh[NI][2], bl[NI][2];
#pragma unroll
            for (int mi = 0; mi < MI; mi++) {
                const unsigned* p0 = &As[(wm0 + mi * 16 + g) * AST + kk + 2 * t];
                const unsigned* p1 = &As[(wm0 + mi * 16 + g + 8) * AST + kk + 2 * t];
                uint2 w0 = *(const uint2*)p0;
                uint2 w1 = *(const uint2*)p1;
                uint2 w2 = *(const uint2*)(p0 + 8);
                uint2 w3 = *(const uint2*)(p1 + 8);
                ah[mi][0] = __byte_perm(w0.x, w0.y, 0x7632); al[mi][0] = __byte_perm(w0.x, w0.y, 0x5410);
                ah[mi][1] = __byte_perm(w1.x, w1.y, 0x7632); al[mi][1] = __byte_perm(w1.x, w1.y, 0x5410);
                ah[mi][2] = __byte_perm(w2.x, w2.y, 0x7632); al[mi][2] = __byte_perm(w2.x, w2.y, 0x5410);
                ah[mi][3] = __byte_perm(w3.x, w3.y, 0x7632); al[mi][3] = __byte_perm(w3.x, w3.y, 0x5410);
            }
#pragma unroll
            for (int ni = 0; ni < NI; ni++) {
                const unsigned* p = &Ws[(wn0 + ni * 8 + g) * AST + kk + 2 * t];
                uint2 v0 = *(const uint2*)p;
                uint2 v1 = *(const uint2*)(p + 8);
                bh[ni][0] = __byte_perm(v0.x, v0.y, 0x7632); bl[ni][0] = __byte_perm(v0.x, v0.y, 0x5410);
                bh[ni][1] = __byte_perm(v1.x, v1.y, 0x7632); bl[ni][1] = __byte_perm(v1.x, v1.y, 0x5410);
            }
#pragma unroll
            for (int mi = 0; mi < MI; mi++)
#pragma unroll
                for (int ni = 0; ni < NI; ni++) {
                    mma16816(acc[mi][ni][0], acc[mi][ni][1], acc[mi][ni][2], acc[mi][ni][3],
                             ah[mi][0], ah[mi][1], ah[mi][2], ah[mi][3], bh[ni][0], bh[ni][1]);
                    mma16816(acc[mi][ni][0], acc[mi][ni][1], acc[mi][ni][2], acc[mi][ni][3],
                             ah[mi][0], ah[mi][1], ah[mi][2], ah[mi][3], bl[ni][0], bl[ni][1]);
                    mma16816(acc[mi][ni][0], acc[mi][ni][1], acc[mi][ni][2], acc[mi][ni][3],
                             al[mi][0], al[mi][1], al[mi][2], al[mi][3], bh[ni][0], bh[ni][1]);
                }
        }
        __syncthreads();
    }

    // Epilogue
    float2 bv[NI];
#pragma unroll
    for (int ni = 0; ni < NI; ni++) {
        if (bias) bv[ni] = *(const float2*)(bias + n0 + wn0 + ni * 8 + 2 * t);
        else      bv[ni] = make_float2(0.f, 0.f);
    }
#pragma unroll
    for (int mi = 0; mi < MI; mi++) {
        int row0 = m0 + wm0 + mi * 16 + g;
#pragma unroll
        for (int ni = 0; ni < NI; ni++) {
            int col = n0 + wn0 + ni * 8 + 2 * t;
            float v0 = acc[mi][ni][0] + bv[ni].x;
            float v1 = acc[mi][ni][1] + bv[ni].y;
            float v2 = acc[mi][ni][2] + bv[ni].x;
            float v3 = acc[mi][ni][3] + bv[ni].y;
            if (ACT == 1) {
                v0 = fmaxf(v0, 0.f); v1 = fmaxf(v1, 0.f);
                v2 = fmaxf(v2, 0.f); v3 = fmaxf(v3, 0.f);
            }
            if (OUTMODE == 0) {
                float* C = (float*)Cout;
                *(float2*)(C + (size_t)row0 * N + col)       = make_float2(v0, v1);
                *(float2*)(C + (size_t)(row0 + 8) * N + col) = make_float2(v2, v3);
            } else if (OUTMODE == 1) {
                unsigned* C = (unsigned*)Cout;
                *(uint2*)(C + (size_t)row0 * N + col)       = make_uint2(packf(v0), packf(v1));
                *(uint2*)(C + (size_t)(row0 + 8) * N + col) = make_uint2(packf(v2), packf(v3));
            } else {
                float* C = (float*)Cout;
                int tt0 = row0 / B_DIM, bb0 = row0 % B_DIM;
                int r1 = row0 + 8;
                int tt1 = r1 / B_DIM, bb1 = r1 % B_DIM;
                *(float2*)(C + ((size_t)bb0 * T_DIM + tt0) * D_DIM + col) = make_float2(v0, v1);
                *(float2*)(C + ((size_t)bb1 * T_DIM + tt1) * D_DIM + col) = make_float2(v2, v3);
            }
        }
    }
}

// ---------------------------------------------------------------------------
// Fused LSTM step: gates = h_prev @ Whh_perm^T  (3xbf16 tensor GEMM)
//                  + ZW_t + CWB, then cell, writing h packed + c.
// Gate-permuted layout: column n' = j*4 + gate (i,f,g,o).
// M=1024 (batch), N=2048 (perm gates), K=512.
// ---------------------------------------------------------------------------
__global__ void __launch_bounds__(256)
lstm_step_kernel(const unsigned* __restrict__ A,    // h_prev packed [1024x512]
                 const unsigned* __restrict__ W,    // Whh_perm packed [2048x512]
                 const float* __restrict__ ZWt,     // [1024x2048] (perm cols)
                 const float* __restrict__ CWB,     // [1024x2048] (perm cols, incl. biases)
                 float* __restrict__ c_state,       // [1024x512]
                 unsigned* __restrict__ hout)       // [1024x512] packed
{
    constexpr int BM = 128, BN = 128, BK = 32;
    constexpr int WM = 64, WN = 32;
    constexpr int WARPS_N = BN / WN;   // 4
    constexpr int NTH = 256;
    constexpr int MI = WM / 16, NI = WN / 8;   // 4, 4
    constexpr int AST = BK + 4;
    constexpr int K = H_DIM, N = G_DIM;

    __shared__ unsigned As[BM * AST];
    __shared__ unsigned Ws[BN * AST];

    const int tid  = threadIdx.x;
    const int warp = tid >> 5, lane = tid & 31;
    const int g = lane >> 2, t = lane & 3;
    const int wm0 = (warp / WARPS_N) * WM;
    const int wn0 = (warp % WARPS_N) * WN;
    const int m0 = blockIdx.y * BM;
    const int n0 = blockIdx.x * BN;

    float acc[MI][NI][4];
#pragma unroll
    for (int mi = 0; mi < MI; mi++)
#pragma unroll
        for (int ni = 0; ni < NI; ni++)
#pragma unroll
            for (int q = 0; q < 4; q++) acc[mi][ni][q] = 0.f;

    for (int k0 = 0; k0 < K; k0 += BK) {
#pragma unroll
        for (int i = tid; i < BM * BK / 4; i += NTH) {
            int r = i >> 3, c = (i & 7) << 2;
            uint4 v = *(const uint4*)(A + (size_t)(m0 + r) * K + k0 + c);
            *(uint4*)&As[r * AST + c] = v;
        }
#pragma unroll
        for (int i = tid; i < BN * BK / 4; i += NTH) {
            int r = i >> 3, c = (i & 7) << 2;
            uint4 v = *(const uint4*)(W + (size_t)(n0 + r) * K + k0 + c);
            *(uint4*)&Ws[r * AST + c] = v;
        }
        __syncthreads();

#pragma unroll
        for (int kk = 0; kk < BK; kk += 16) {
            unsigned ah[MI][4], al[MI][4], bh[NI][2], bl[NI][2];
#pragma unroll
            for (int mi = 0; mi < MI; mi++) {
                const unsigned* p0 = &As[(wm0 + mi * 16 + g) * AST + kk + 2 * t];
                const unsigned* p1 = &As[(wm0 + mi * 16 + g + 8) * AST + kk + 2 * t];
                uint2 w0 = *(const uint2*)p0;
                uint2 w1 = *(const uint2*)p1;
                uint2 w2 = *(const uint2*)(p0 + 8);
                uint2 w3 = *(const uint2*)(p1 + 8);
                ah[mi][0] = __byte_perm(w0.x, w0.y, 0x7632); al[mi][0] = __byte_perm(w0.x, w0.y, 0x5410);
                ah[mi][1] = __byte_perm(w1.x, w1.y, 0x7632); al[mi][1] = __byte_perm(w1.x, w1.y, 0x5410);
                ah[mi][2] = __byte_perm(w2.x, w2.y, 0x7632); al[mi][2] = __byte_perm(w2.x, w2.y, 0x5410);
                ah[mi][3] = __byte_perm(w3.x, w3.y, 0x7632); al[mi][3] = __byte_perm(w3.x, w3.y, 0x5410);
            }
#pragma unroll
            for (int ni = 0; ni < NI; ni++) {
                const unsigned* p = &Ws[(wn0 + ni * 8 + g) * AST + kk + 2 * t];
                uint2 v0 = *(const uint2*)p;
                uint2 v1 = *(const uint2*)(p + 8);
                bh[ni][0] = __byte_perm(v0.x, v0.y, 0x7632); bl[ni][0] = __byte_perm(v0.x, v0.y, 0x5410);
                bh[ni][1] = __byte_perm(v1.x, v1.y, 0x7632); bl[ni][1] = __byte_perm(v1.x, v1.y, 0x5410);
            }
#pragma unroll
            for (int mi = 0; mi < MI; mi++)
#pragma unroll
                for (int ni = 0; ni < NI; ni++) {
                    mma16816(acc[mi][ni][0], acc[mi][ni][1], acc[mi][ni][2], acc[mi][ni][3],
                             ah[mi][0], ah[mi][1], ah[mi][2], ah[mi][3], bh[ni][0], bh[ni][1]);
                    mma16816(acc[mi][ni][0], acc[mi][ni][1], acc[mi][ni][2], acc[mi][ni][3],
                             ah[mi][0], ah[mi][1], ah[mi][2], ah[mi][3], bl[ni][0], bl[ni][1]);
                    mma16816(acc[mi][ni][0], acc[mi][ni][1], acc[mi][ni][2], acc[mi][ni][3],
                             al[mi][0], al[mi][1], al[mi][2], al[mi][3], bh[ni][0], bh[ni][1]);
                }
        }
        __syncthreads();
    }

    // Cell epilogue. Lanes l and l^1 hold {i,f} and {g,o} for the same j;
    // exchange so even lane owns row r, odd lane owns row r+8.
    const bool hi_half = (t & 1);
#pragma unroll
    for (int mi = 0; mi < MI; mi++) {
        int row0 = m0 + wm0 + mi * 16 + g;
#pragma unroll
        for (int ni = 0; ni < NI; ni++) {
            int col = n0 + wn0 + ni * 8 + 2 * t;
            float c0 = acc[mi][ni][0], c1 = acc[mi][ni][1];
            float c2 = acc[mi][ni][2], c3 = acc[mi][ni][3];
            float sx = __shfl_xor_sync(0xffffffffu, hi_half ? c0 : c2, 1);
            float sy = __shfl_xor_sync(0xffffffffu, hi_half ? c1 : c3, 1);
            int row = hi_half ? row0 + 8 : row0;
            float gi, gf, gg, go;
            if (!hi_half) { gi = c0; gf = c1; gg = sx; go = sy; }
            else          { gi = sx; gf = sy; gg = c2; go = c3; }

            int base = col & ~3;
            float4 zw = *(const float4*)(ZWt + (size_t)row * G_DIM + base);
            float4 cw = *(const float4*)(CWB + (size_t)row * G_DIM + base);
            gi += zw.x + cw.x; gf += zw.y + cw.y;
            gg += zw.z + cw.z; go += zw.w + cw.w;

            float ig = 1.f / (1.f + expf(-gi));
            float fg = 1.f / (1.f + expf(-gf));
            float gt = tanhf(gg);
            float og = 1.f / (1.f + expf(-go));

            size_t cidx = (size_t)row * H_DIM + (col >> 2);
            float cn = fg * c_state[cidx] + ig * gt;
            c_state[cidx] = cn;
            hout[cidx] = packf(og * tanhf(cn));
        }
    }
}

// ---------------------------------------------------------------------------
// f32x2 SGEMM (kept for the tiny label MLP; from round 2)
// ---------------------------------------------------------------------------
__device__ __forceinline__ void ffma2(unsigned long long& d,
                                      unsigned long long a,
                                      unsigned long long b) {
    asm("fma.rn.f32x2 %0, %1, %2, %0;" : "+l"(d) : "l"(a), "l"(b));
}
__device__ __forceinline__ unsigned long long pack2(float lo, float hi) {
    unsigned long long r;
    asm("mov.b64 %0, {%1, %2};" : "=l"(r) : "f"(lo), "f"(hi));
    return r;
}
__device__ __forceinline__ float2 unpack2(unsigned long long u) {
    float2 f;
    asm("mov.b64 {%0, %1}, %2;" : "=f"(f.x), "=f"(f.y) : "l"(u));
    return f;
}

template<int BM, int BN, int BK, int TM, int TN, int ACT>
__global__ void gemm2_kernel(const float* __restrict__ A,
                             const float* __restrict__ W,
                             const float* __restrict__ bias,
                             float* __restrict__ C,
                             int M, int N, int K)
{
    constexpr int AS_STRIDE = BM + 4;
    constexpr int WS_STRIDE = BN + 4;
    __shared__ float As[BK][AS_STRIDE];
    __shared__ float Ws[BK][WS_STRIDE];

    constexpr int NTH = (BM / TM) * (BN / TN);
    const int tid = threadIdx.x;
    const int tx = tid % (BN / TN);
    const int ty = tid / (BN / TN);
    const int m0 = blockIdx.y * BM;
    const int n0 = blockIdx.x * BN;

    unsigned long long acc2[TM / 2][TN];
#pragma unroll
    for (int p = 0; p < TM / 2; p++)
#pragma unroll
        for (int j = 0; j < TN; j++) acc2[p][j] = 0ULL;

    for (int k0 = 0; k0 < K; k0 += BK) {
#pragma unroll
        for (int i = tid * 4; i < BM * BK; i += NTH * 4) {
            int m = i / BK, k = i % BK;
            float4 v = *(const float4*)(A + (long)(m0 + m) * K + (k0 + k));
            As[k + 0][m] = v.x; As[k + 1][m] = v.y;
            As[k + 2][m] = v.z; As[k + 3][m] = v.w;
        }
#pragma unroll
        for (int i = tid * 4; i < BN * BK; i += NTH * 4) {
            int n = i / BK, k = i % BK;
            float4 v = *(const float4*)(W + (long)(n0 + n) * K + (k0 + k));
            Ws[k + 0][n] = v.x; Ws[k + 1][n] = v.y;
            Ws[k + 2][n] = v.z; Ws[k + 3][n] = v.w;
        }
        __syncthreads();

#pragma unroll
        for (int k = 0; k < BK; k++) {
            unsigned long long am2[TM / 2];
            const ulonglong2* ap = reinterpret_cast<const ulonglong2*>(&As[k][ty * TM]);
#pragma unroll
            for (int q = 0; q < TM / 4; q++) {
                ulonglong2 tt = ap[q];
                am2[2 * q + 0] = tt.x;
                am2[2 * q + 1] = tt.y;
            }
            float4 w4 = *reinterpret_cast<const float4*>(&Ws[k][tx * TN]);
            unsigned long long wd[TN];
            wd[0] = pack2(w4.x, w4.x); wd[1] = pack2(w4.y, w4.y);
            wd[2] = pack2(w4.z, w4.z); wd[3] = pack2(w4.w, w4.w);
#pragma unroll
            for (int p = 0; p < TM / 2; p++)
#pragma unroll
                for (int j = 0; j < TN; j++) ffma2(acc2[p][j], am2[p], wd[j]);
        }
        __syncthreads();
    }

    float4 bv = make_float4(0.f, 0.f, 0.f, 0.f);
    if (bias) bv = *reinterpret_cast<const float4*>(bias + n0 + tx * TN);

#pragma unroll
    for (int p = 0; p < TM / 2; p++) {
        float2 v0 = unpack2(acc2[p][0]);
        float2 v1 = unpack2(acc2[p][1]);
        float2 v2 = unpack2(acc2[p][2]);
        float2 v3 = unpack2(acc2[p][3]);
        float4 rowA = make_float4(v0.x + bv.x, v1.x + bv.y, v2.x + bv.z, v3.x + bv.w);
        float4 rowB = make_float4(v0.y + bv.x, v1.y + bv.y, v2.y + bv.z, v3.y + bv.w);
        if (ACT == 1) {
            rowA.x = fmaxf(rowA.x, 0.f); rowA.y = fmaxf(rowA.y, 0.f);
            rowA.z = fmaxf(rowA.z, 0.f); rowA.w = fmaxf(rowA.w, 0.f);
            rowB.x = fmaxf(rowB.x, 0.f); rowB.y = fmaxf(rowB.y, 0.f);
            rowB.z = fmaxf(rowB.z, 0.f); rowB.w = fmaxf(rowB.w, 0.f);
        }
        int mA = m0 + ty * TM + 2 * p;
        int n  = n0 + tx * TN;
        *reinterpret_cast<float4*>(C + (long)mA * N + n) = rowA;
        *reinterpret_cast<float4*>(C + (long)(mA + 1) * N + n) = rowB;
    }
}

// ---------------------------------------------------------------------------
// Prep kernels
// ---------------------------------------------------------------------------
__global__ void pack_kernel(const float4* __restrict__ src,
                            uint4* __restrict__ dst, int n4)
{
    int i = blockIdx.x * blockDim.x + threadIdx.x;
    if (i < n4) dst[i] = packf4(src[i]);
}

// W [2048][512] -> perm rows n' = j*4 + gate, packed
__global__ void perm_pack_w_kernel(const float* __restrict__ src,
                                   unsigned* __restrict__ dst)
{
    int i = blockIdx.x * blockDim.x + threadIdx.x;   // over G_DIM * H_DIM/4
    int r = i / (H_DIM / 4);
    int c = i % (H_DIM / 4);
    int j = r >> 2, gg = r & 3;
    float4 v = ((const float4*)src)[(size_t)(gg * H_DIM + j) * (H_DIM / 4) + c];
    ((uint4*)dst)[(size_t)r * (H_DIM / 4) + c] = packf4(v);
}

__global__ void bias_perm_kernel(const float* __restrict__ bih,
                                 const float* __restrict__ bhh,
                                 float* __restrict__ bp)
{
    int i = blockIdx.x * blockDim.x + threadIdx.x;
    if (i < G_DIM) {
        int j = i >> 2, gg = i & 3;
        bp[i] = bih[gg * H_DIM + j] + bhh[gg * H_DIM + j];
    }
}

__global__ void zero_state_kernel(unsigned* __restrict__ h0,
                                  float* __restrict__ c)
{
    int i = blockIdx.x * blockDim.x + threadIdx.x;
    h0[i] = 0u;
    c[i] = 0.f;
}

// ---------------------------------------------------------------------------
// Launch
// ---------------------------------------------------------------------------
extern "C" void kernel_launch(void* const* d_in, const int* in_sizes, int n_in,
                              void* d_out, int out_size)
{
    const float* labels = (const float*)d_in[0];
    const float* z      = (const float*)d_in[1];
    const float* W1     = (const float*)d_in[2];
    const float* b1     = (const float*)d_in[3];
    const float* W2     = (const float*)d_in[4];
    const float* b2     = (const float*)d_in[5];
    const float* W3     = (const float*)d_in[6];
    const float* Wih    = (const float*)d_in[7];
    const float* Whh    = (const float*)d_in[8];
    const float* bih    = (const float*)d_in[9];
    const float* bhh    = (const float*)d_in[10];
    const float* P1     = (const float*)d_in[11];
    const float* pb1    = (const float*)d_in[12];
    const float* P2     = (const float*)d_in[13];
    const float* pb2    = (const float*)d_in[14];
    const float* P3     = (const float*)d_in[15];
    const float* pb3    = (const float*)d_in[16];
    float* out = (float*)d_out;

    float *x1, *x2, *conds, *bperm, *CWB, *ZW, *cst;
    unsigned *condsp, *Wihp, *Whhp, *P1p, *P2p, *P3p, *zp, *h0p, *Hp, *y1p, *y2p;
    cudaGetSymbolAddress((void**)&x1,     g_x1);
    cudaGetSymbolAddress((void**)&x2,     g_x2);
    cudaGetSymbolAddress((void**)&conds,  g_conds);
    cudaGetSymbolAddress((void**)&condsp, g_condsp);
    cudaGetSymbolAddress((void**)&bperm,  g_bperm);
    cudaGetSymbolAddress((void**)&Wihp,   g_Wihp);
    cudaGetSymbolAddress((void**)&Whhp,   g_Whhp);
    cudaGetSymbolAddress((void**)&P1p,    g_P1p);
    cudaGetSymbolAddress((void**)&P2p,    g_P2p);
    cudaGetSymbolAddress((void**)&P3p,    g_P3p);
    cudaGetSymbolAddress((void**)&CWB,    g_CWB);
    cudaGetSymbolAddress((void**)&zp,     g_zp);
    cudaGetSymbolAddress((void**)&ZW,     g_ZW);
    cudaGetSymbolAddress((void**)&h0p,    g_h0p);
    cudaGetSymbolAddress((void**)&cst,    g_c);
    cudaGetSymbolAddress((void**)&Hp,     g_Hp);
    cudaGetSymbolAddress((void**)&y1p,    g_y1p);
    cudaGetSymbolAddress((void**)&y2p,    g_y2p);

    const int TB = T_DIM * B_DIM;          // 131072
    const size_t BH = (size_t)B_DIM * H_DIM;

    // --- Weight / input prep ---
    pack_kernel<<<(H_DIM * H_DIM / 4) / 256, 256>>>((const float4*)P1, (uint4*)P1p, H_DIM * H_DIM / 4);
    pack_kernel<<<(H_DIM * H_DIM / 4) / 256, 256>>>((const float4*)P2, (uint4*)P2p, H_DIM * H_DIM / 4);
    pack_kernel<<<(D_DIM * H_DIM / 4) / 256, 256>>>((const float4*)P3, (uint4*)P3p, D_DIM * H_DIM / 4);
    perm_pack_w_kernel<<<(G_DIM * H_DIM / 4) / 256, 256>>>(Wih, Wihp);
    perm_pack_w_kernel<<<(G_DIM * H_DIM / 4) / 256, 256>>>(Whh, Whhp);
    bias_perm_kernel<<<G_DIM / 256, 256>>>(bih, bhh, bperm);
    pack_kernel<<<((size_t)TB * H_DIM / 4) / 256, 256>>>((const float4*)z, (uint4*)zp, TB * (H_DIM / 4));

    // --- Label MLP (tiny, f32x2 path) ---
    gemm2_kernel<128,128,16,8,4,1><<<dim3(H_DIM/128, B_DIM/128), 512>>>(
        labels, W1, b1, x1, B_DIM, H_DIM, L_DIM);
    gemm2_kernel<128,128,16,8,4,1><<<dim3(H_DIM/128, B_DIM/128), 512>>>(
        x1, W2, b2, x2, B_DIM, H_DIM, H_DIM);
    gemm2_kernel<128,128,16,8,4,0><<<dim3(H_DIM/128, B_DIM/128), 512>>>(
        x2, W3, nullptr, conds, B_DIM, H_DIM, H_DIM);
    pack_kernel<<<(B_DIM * H_DIM / 4) / 256, 256>>>((const float4*)conds, (uint4*)condsp, B_DIM * H_DIM / 4);

    // --- CWB = conds @ Wih_perm^T + (bih+bhh)_perm ---
    tgemm_kernel<128,128,64,32,0,0><<<dim3(G_DIM/128, B_DIM/128), 256>>>(
        condsp, Wihp, bperm, CWB, B_DIM, G_DIM, H_DIM);
    // --- ZW = z @ Wih_perm^T ---
    tgemm_kernel<128,128,64,32,0,0><<<dim3(G_DIM/128, TB/128), 256>>>(
        zp, Wihp, nullptr, ZW, TB, G_DIM, H_DIM);

    // --- Recurrence (fused gate GEMM + cell) ---
    zero_state_kernel<<<(B_DIM * H_DIM) / 256, 256>>>(h0p, cst);
    for (int t = 0; t < T_DIM; t++) {
        const unsigned* hin = (t == 0) ? h0p : (Hp + (size_t)(t - 1) * BH);
        lstm_step_kernel<<<dim3(G_DIM/128, B_DIM/128), 256>>>(
            hin, Whhp, ZW + (size_t)t * B_DIM * G_DIM, CWB,
            cst, Hp + (size_t)t * BH);
    }

    // --- Projection MLP over all T*B rows ---
    tgemm_kernel<128,128,64,32,1,1><<<dim3(H_DIM/128, TB/128), 256>>>(
        Hp, P1p, pb1, y1p, TB, H_DIM, H_DIM);
    tgemm_kernel<128,128,64,32,1,1><<<dim3(H_DIM/128, TB/128), 256>>>(
        y1p, P2p, pb2, y2p, TB, H_DIM, H_DIM);
    tgemm_kernel<128,64,32,32,0,2><<<dim3(D_DIM/64, TB/128), 256>>>(
        y2p, P3p, pb3, out, TB, D_DIM, H_DIM);
}

// round 4
// speedup vs baseline: 2.1516x; 1.1808x over previous
#include <cuda_runtime.h>
#include <cuda_bf16.h>
#include <math.h>

// Problem dims (fixed by the dataset)
#define B_DIM 1024
#define T_DIM 128
#define L_DIM 16
#define H_DIM 512
#define D_DIM 64
#define G_DIM 2048          // 4*H

// ---------------------------------------------------------------------------
// Scratch (device globals — no allocation allowed in kernel_launch)
// Packed format: one u32 per fp32 element = (bf16_hi << 16) | bf16_lo
// ---------------------------------------------------------------------------
__device__ float    g_x1[B_DIM * H_DIM];
__device__ float    g_x2[B_DIM * H_DIM];
__device__ float    g_conds[B_DIM * H_DIM];
__device__ unsigned g_condsp[B_DIM * H_DIM];
__device__ float    g_bperm[G_DIM];
__device__ unsigned g_Wihp[G_DIM * H_DIM];
__device__ unsigned g_Whhp[G_DIM * H_DIM];
__device__ unsigned g_P1p[H_DIM * H_DIM];
__device__ unsigned g_P2p[H_DIM * H_DIM];
__device__ unsigned g_P3p[D_DIM * H_DIM];
__device__ float    g_CWB[B_DIM * G_DIM];                 // conds@Wih^T + biases (perm)
__device__ unsigned g_zp[(size_t)T_DIM * B_DIM * H_DIM];
__device__ float    g_ZW[(size_t)T_DIM * B_DIM * G_DIM];  // 1 GB, z@Wih^T + CWB (perm cols)
__device__ unsigned g_h0p[B_DIM * H_DIM];
__device__ float    g_c[B_DIM * H_DIM];
__device__ unsigned g_Hp[(size_t)T_DIM * B_DIM * H_DIM];
__device__ unsigned g_y1p[(size_t)T_DIM * B_DIM * H_DIM];
__device__ unsigned g_y2p[(size_t)T_DIM * B_DIM * H_DIM];

// ---------------------------------------------------------------------------
// Helpers
// ---------------------------------------------------------------------------
__device__ __forceinline__ unsigned packf(float x) {
    __nv_bfloat16 h = __float2bfloat16(x);
    float r = x - __bfloat162float(h);
    __nv_bfloat16 l = __float2bfloat16(r);
    return ((unsigned)__bfloat16_as_ushort(h) << 16) |
            (unsigned)__bfloat16_as_ushort(l);
}
__device__ __forceinline__ uint4 packf4(float4 v) {
    return make_uint4(packf(v.x), packf(v.y), packf(v.z), packf(v.w));
}

__device__ __forceinline__ void mma16816(float& c0, float& c1, float& c2, float& c3,
                                         unsigned a0, unsigned a1, unsigned a2, unsigned a3,
                                         unsigned b0, unsigned b1) {
    asm volatile(
        "mma.sync.aligned.m16n8k16.row.col.f32.bf16.bf16.f32 "
        "{%0,%1,%2,%3}, {%4,%5,%6,%7}, {%8,%9}, {%0,%1,%2,%3};\n"
        : "+f"(c0), "+f"(c1), "+f"(c2), "+f"(c3)
        : "r"(a0), "r"(a1), "r"(a2), "r"(a3), "r"(b0), "r"(b1));
}

__device__ __forceinline__ void cp_async16(unsigned* sptr, const void* gptr) {
    unsigned sa = (unsigned)__cvta_generic_to_shared(sptr);
    asm volatile("cp.async.cg.shared.global [%0], [%1], 16;\n" :: "r"(sa), "l"(gptr));
}
__device__ __forceinline__ void cp_commit() {
    asm volatile("cp.async.commit_group;\n");
}
template<int N>
__device__ __forceinline__ void cp_wait() {
    asm volatile("cp.async.wait_group %0;\n" :: "n"(N));
}

// ---------------------------------------------------------------------------
// Pipelined tensor-core GEMM (3xbf16):  C[M,N] = act(A@W^T + bias [+ addvec])
// OUTMODE: 0 = fp32, 1 = packed u32, 2 = fp32 + [T,B]->[B,T] perm,
//          3 = fp32 + addvec[row % B_DIM][col]  (CWB fold for ZW)
// Dynamic smem: 2 stages x (BM+BN) x (BK+4) u32.
// ---------------------------------------------------------------------------
template<int BM, int BN, int WM, int WN, int ACT, int OUTMODE>
__global__ void __launch_bounds__((BM / WM) * (BN / WN) * 32)
tgemm_kernel(const unsigned* __restrict__ A,
             const unsigned* __restrict__ W,
             const float* __restrict__ bias,
             const float* __restrict__ addvec,
             void* __restrict__ Cout,
             int M, int N, int K)
{
    constexpr int BK = 32;
    constexpr int AST = BK + 4;
    constexpr int WARPS_N = BN / WN;
    constexpr int NTH = (BM / WM) * (BN / WN) * 32;
    constexpr int MI = WM / 16, NI = WN / 8;
    constexpr int STAGE = (BM + BN) * AST;

    extern __shared__ unsigned sm[];

    const int tid  = threadIdx.x;
    const int warp = tid >> 5, lane = tid & 31;
    const int g = lane >> 2, t = lane & 3;
    const int wm0 = (warp / WARPS_N) * WM;
    const int wn0 = (warp % WARPS_N) * WN;
    const int m0 = blockIdx.y * BM;
    const int n0 = blockIdx.x * BN;

    float acc[MI][NI][4];
#pragma unroll
    for (int mi = 0; mi < MI; mi++)
#pragma unroll
        for (int ni = 0; ni < NI; ni++)
#pragma unroll
            for (int q = 0; q < 4; q++) acc[mi][ni][q] = 0.f;

    auto load_tiles = [&](int k0, int s) {
        unsigned* As = sm + s * STAGE;
        unsigned* Ws = sm + s * STAGE + BM * AST;
#pragma unroll
        for (int i = tid; i < BM * BK / 4; i += NTH) {
            int r = i >> 3, c = (i & 7) << 2;
            cp_async16(&As[r * AST + c], A + (size_t)(m0 + r) * K + k0 + c);
        }
#pragma unroll
        for (int i = tid; i < BN * BK / 4; i += NTH) {
            int r = i >> 3, c = (i & 7) << 2;
            cp_async16(&Ws[r * AST + c], W + (size_t)(n0 + r) * K + k0 + c);
        }
        cp_commit();
    };

    const int KT = K / BK;
    load_tiles(0, 0);

    for (int kt = 0; kt < KT; kt++) {
        const int s = kt & 1;
        if (kt + 1 < KT) { load_tiles((kt + 1) * BK, s ^ 1); cp_wait<1>(); }
        else             { cp_wait<0>(); }
        __syncthreads();

        const unsigned* As = sm + s * STAGE;
        const unsigned* Ws = sm + s * STAGE + BM * AST;
#pragma unroll
        for (int kk = 0; kk < BK; kk += 16) {
            unsigned ah[MI][4], al[MI][4], bh[NI][2], bl[NI][2];
#pragma unroll
            for (int mi = 0; mi < MI; mi++) {
                const unsigned* p0 = &As[(wm0 + mi * 16 + g) * AST + kk + 2 * t];
                const unsigned* p1 = &As[(wm0 + mi * 16 + g + 8) * AST + kk + 2 * t];
                uint2 w0 = *(const uint2*)p0;
                uint2 w1 = *(const uint2*)p1;
                uint2 w2 = *(const uint2*)(p0 + 8);
                uint2 w3 = *(const uint2*)(p1 + 8);
                ah[mi][0] = __byte_perm(w0.x, w0.y, 0x7632); al[mi][0] = __byte_perm(w0.x, w0.y, 0x5410);
                ah[mi][1] = __byte_perm(w1.x, w1.y, 0x7632); al[mi][1] = __byte_perm(w1.x, w1.y, 0x5410);
                ah[mi][2] = __byte_perm(w2.x, w2.y, 0x7632); al[mi][2] = __byte_perm(w2.x, w2.y, 0x5410);
                ah[mi][3] = __byte_perm(w3.x, w3.y, 0x7632); al[mi][3] = __byte_perm(w3.x, w3.y, 0x5410);
            }
#pragma unroll
            for (int ni = 0; ni < NI; ni++) {
                const unsigned* p = &Ws[(wn0 + ni * 8 + g) * AST + kk + 2 * t];
                uint2 v0 = *(const uint2*)p;
                uint2 v1 = *(const uint2*)(p + 8);
                bh[ni][0] = __byte_perm(v0.x, v0.y, 0x7632); bl[ni][0] = __byte_perm(v0.x, v0.y, 0x5410);
                bh[ni][1] = __byte_perm(v1.x, v1.y, 0x7632); bl[ni][1] = __byte_perm(v1.x, v1.y, 0x5410);
            }
#pragma unroll
            for (int mi = 0; mi < MI; mi++)
#pragma unroll
                for (int ni = 0; ni < NI; ni++) {
                    mma16816(acc[mi][ni][0], acc[mi][ni][1], acc[mi][ni][2], acc[mi][ni][3],
                             ah[mi][0], ah[mi][1], ah[mi][2], ah[mi][3], bh[ni][0], bh[ni][1]);
                    mma16816(acc[mi][ni][0], acc[mi][ni][1], acc[mi][ni][2], acc[mi][ni][3],
                             ah[mi][0], ah[mi][1], ah[mi][2], ah[mi][3], bl[ni][0], bl[ni][1]);
                    mma16816(acc[mi][ni][0], acc[mi][ni][1], acc[mi][ni][2], acc[mi][ni][3],
                             al[mi][0], al[mi][1], al[mi][2], al[mi][3], bh[ni][0], bh[ni][1]);
                }
        }
        __syncthreads();
    }

    // Epilogue
    float2 bv[NI];
#pragma unroll
    for (int ni = 0; ni < NI; ni++) {
        if (bias) bv[ni] = *(const float2*)(bias + n0 + wn0 + ni * 8 + 2 * t);
        else      bv[ni] = make_float2(0.f, 0.f);
    }
#pragma unroll
    for (int mi = 0; mi < MI; mi++) {
        int row0 = m0 + wm0 + mi * 16 + g;
#pragma unroll
        for (int ni = 0; ni < NI; ni++) {
            int col = n0 + wn0 + ni * 8 + 2 * t;
            float v0 = acc[mi][ni][0] + bv[ni].x;
            float v1 = acc[mi][ni][1] + bv[ni].y;
            float v2 = acc[mi][ni][2] + bv[ni].x;
            float v3 = acc[mi][ni][3] + bv[ni].y;
            if (OUTMODE == 3) {
                float2 a0 = *(const float2*)(addvec + (size_t)(row0 & (B_DIM - 1)) * N + col);
                float2 a1 = *(const float2*)(addvec + (size_t)((row0 + 8) & (B_DIM - 1)) * N + col);
                v0 += a0.x; v1 += a0.y; v2 += a1.x; v3 += a1.y;
            }
            if (ACT == 1) {
                v0 = fmaxf(v0, 0.f); v1 = fmaxf(v1, 0.f);
                v2 = fmaxf(v2, 0.f); v3 = fmaxf(v3, 0.f);
            }
            if (OUTMODE == 0 || OUTMODE == 3) {
                float* C = (float*)Cout;
                *(float2*)(C + (size_t)row0 * N + col)       = make_float2(v0, v1);
                *(float2*)(C + (size_t)(row0 + 8) * N + col) = make_float2(v2, v3);
            } else if (OUTMODE == 1) {
                unsigned* C = (unsigned*)Cout;
                *(uint2*)(C + (size_t)row0 * N + col)       = make_uint2(packf(v0), packf(v1));
                *(uint2*)(C + (size_t)(row0 + 8) * N + col) = make_uint2(packf(v2), packf(v3));
            } else {
                float* C = (float*)Cout;
                int tt0 = row0 / B_DIM, bb0 = row0 % B_DIM;
                int r1 = row0 + 8;
                int tt1 = r1 / B_DIM, bb1 = r1 % B_DIM;
                *(float2*)(C + ((size_t)bb0 * T_DIM + tt0) * D_DIM + col) = make_float2(v0, v1);
                *(float2*)(C + ((size_t)bb1 * T_DIM + tt1) * D_DIM + col) = make_float2(v2, v3);
            }
        }
    }
}

// ---------------------------------------------------------------------------
// Fused LSTM step (pipelined): gates = h_prev @ Whh_perm^T + ZW_t (ZW already
// includes conds@Wih + biases). Gate-permuted cols: n' = j*4 + gate(i,f,g,o).
// ---------------------------------------------------------------------------
__global__ void __launch_bounds__(256)
lstm_step_kernel(const unsigned* __restrict__ A,    // h_prev packed [1024x512]
                 const unsigned* __restrict__ W,    // Whh_perm packed [2048x512]
                 const float* __restrict__ ZWt,     // [1024x2048] incl. CWB+biases
                 float* __restrict__ c_state,
                 unsigned* __restrict__ hout)
{
    constexpr int BM = 128, BN = 128, BK = 32;
    constexpr int WM = 64, WN = 32;
    constexpr int WARPS_N = BN / WN;
    constexpr int NTH = 256;
    constexpr int MI = WM / 16, NI = WN / 8;
    constexpr int AST = BK + 4;
    constexpr int STAGE = (BM + BN) * AST;
    constexpr int K = H_DIM;

    extern __shared__ unsigned sm[];

    const int tid  = threadIdx.x;
    const int warp = tid >> 5, lane = tid & 31;
    const int g = lane >> 2, t = lane & 3;
    const int wm0 = (warp / WARPS_N) * WM;
    const int wn0 = (warp % WARPS_N) * WN;
    const int m0 = blockIdx.y * BM;
    const int n0 = blockIdx.x * BN;

    float acc[MI][NI][4];
#pragma unroll
    for (int mi = 0; mi < MI; mi++)
#pragma unroll
        for (int ni = 0; ni < NI; ni++)
#pragma unroll
            for (int q = 0; q < 4; q++) acc[mi][ni][q] = 0.f;

    auto load_tiles = [&](int k0, int s) {
        unsigned* As = sm + s * STAGE;
        unsigned* Ws = sm + s * STAGE + BM * AST;
#pragma unroll
        for (int i = tid; i < BM * BK / 4; i += NTH) {
            int r = i >> 3, c = (i & 7) << 2;
            cp_async16(&As[r * AST + c], A + (size_t)(m0 + r) * K + k0 + c);
        }
#pragma unroll
        for (int i = tid; i < BN * BK / 4; i += NTH) {
            int r = i >> 3, c = (i & 7) << 2;
            cp_async16(&Ws[r * AST + c], W + (size_t)(n0 + r) * K + k0 + c);
        }
        cp_commit();
    };

    const int KT = K / BK;
    load_tiles(0, 0);

    for (int kt = 0; kt < KT; kt++) {
        const int s = kt & 1;
        if (kt + 1 < KT) { load_tiles((kt + 1) * BK, s ^ 1); cp_wait<1>(); }
        else             { cp_wait<0>(); }
        __syncthreads();

        const unsigned* As = sm + s * STAGE;
        const unsigned* Ws = sm + s * STAGE + BM * AST;
#pragma unroll
        for (int kk = 0; kk < BK; kk += 16) {
            unsigned ah[MI][4], al[MI][4], bh[NI][2], bl[NI][2];
#pragma unroll
            for (int mi = 0; mi < MI; mi++) {
                const unsigned* p0 = &As[(wm0 + mi * 16 + g) * AST + kk + 2 * t];
                const unsigned* p1 = &As[(wm0 + mi * 16 + g + 8) * AST + kk + 2 * t];
                uint2 w0 = *(const uint2*)p0;
                uint2 w1 = *(const uint2*)p1;
                uint2 w2 = *(const uint2*)(p0 + 8);
                uint2 w3 = *(const uint2*)(p1 + 8);
                ah[mi][0] = __byte_perm(w0.x, w0.y, 0x7632); al[mi][0] = __byte_perm(w0.x, w0.y, 0x5410);
                ah[mi][1] = __byte_perm(w1.x, w1.y, 0x7632); al[mi][1] = __byte_perm(w1.x, w1.y, 0x5410);
                ah[mi][2] = __byte_perm(w2.x, w2.y, 0x7632); al[mi][2] = __byte_perm(w2.x, w2.y, 0x5410);
                ah[mi][3] = __byte_perm(w3.x, w3.y, 0x7632); al[mi][3] = __byte_perm(w3.x, w3.y, 0x5410);
            }
#pragma unroll
            for (int ni = 0; ni < NI; ni++) {
                const unsigned* p = &Ws[(wn0 + ni * 8 + g) * AST + kk + 2 * t];
                uint2 v0 = *(const uint2*)p;
                uint2 v1 = *(const uint2*)(p + 8);
                bh[ni][0] = __byte_perm(v0.x, v0.y, 0x7632); bl[ni][0] = __byte_perm(v0.x, v0.y, 0x5410);
                bh[ni][1] = __byte_perm(v1.x, v1.y, 0x7632); bl[ni][1] = __byte_perm(v1.x, v1.y, 0x5410);
            }
#pragma unroll
            for (int mi = 0; mi < MI; mi++)
#pragma unroll
                for (int ni = 0; ni < NI; ni++) {
                    mma16816(acc[mi][ni][0], acc[mi][ni][1], acc[mi][ni][2], acc[mi][ni][3],
                             ah[mi][0], ah[mi][1], ah[mi][2], ah[mi][3], bh[ni][0], bh[ni][1]);
                    mma16816(acc[mi][ni][0], acc[mi][ni][1], acc[mi][ni][2], acc[mi][ni][3],
                             ah[mi][0], ah[mi][1], ah[mi][2], ah[mi][3], bl[ni][0], bl[ni][1]);
                    mma16816(acc[mi][ni][0], acc[mi][ni][1], acc[mi][ni][2], acc[mi][ni][3],
                             al[mi][0], al[mi][1], al[mi][2], al[mi][3], bh[ni][0], bh[ni][1]);
                }
        }
        __syncthreads();
    }

    // Cell epilogue (gate exchange via shfl, as validated in round 3)
    const bool hi_half = (t & 1);
#pragma unroll
    for (int mi = 0; mi < MI; mi++) {
        int row0 = m0 + wm0 + mi * 16 + g;
#pragma unroll
        for (int ni = 0; ni < NI; ni++) {
            int col = n0 + wn0 + ni * 8 + 2 * t;
            float c0 = acc[mi][ni][0], c1 = acc[mi][ni][1];
            float c2 = acc[mi][ni][2], c3 = acc[mi][ni][3];
            float sx = __shfl_xor_sync(0xffffffffu, hi_half ? c0 : c2, 1);
            float sy = __shfl_xor_sync(0xffffffffu, hi_half ? c1 : c3, 1);
            int row = hi_half ? row0 + 8 : row0;
            float gi, gf, gg, go;
            if (!hi_half) { gi = c0; gf = c1; gg = sx; go = sy; }
            else          { gi = sx; gf = sy; gg = c2; go = c3; }

            int base = col & ~3;
            float4 zw = *(const float4*)(ZWt + (size_t)row * G_DIM + base);
            gi += zw.x; gf += zw.y; gg += zw.z; go += zw.w;

            float ig = 1.f / (1.f + expf(-gi));
            float fg = 1.f / (1.f + expf(-gf));
            float gt = tanhf(gg);
            float og = 1.f / (1.f + expf(-go));

            size_t cidx = (size_t)row * H_DIM + (col >> 2);
            float cn = fg * c_state[cidx] + ig * gt;
            c_state[cidx] = cn;
            hout[cidx] = packf(og * tanhf(cn));
        }
    }
}

// ---------------------------------------------------------------------------
// f32x2 SGEMM (tiny label MLP)
// ---------------------------------------------------------------------------
__device__ __forceinline__ void ffma2(unsigned long long& d,
                                      unsigned long long a,
                                      unsigned long long b) {
    asm("fma.rn.f32x2 %0, %1, %2, %0;" : "+l"(d) : "l"(a), "l"(b));
}
__device__ __forceinline__ unsigned long long pack2(float lo, float hi) {
    unsigned long long r;
    asm("mov.b64 %0, {%1, %2};" : "=l"(r) : "f"(lo), "f"(hi));
    return r;
}
__device__ __forceinline__ float2 unpack2(unsigned long long u) {
    float2 f;
    asm("mov.b64 {%0, %1}, %2;" : "=f"(f.x), "=f"(f.y) : "l"(u));
    return f;
}

template<int BM, int BN, int BK, int TM, int TN, int ACT>
__global__ void gemm2_kernel(const float* __restrict__ A,
                             const float* __restrict__ W,
                             const float* __restrict__ bias,
                             float* __restrict__ C,
                             int M, int N, int K)
{
    constexpr int AS_STRIDE = BM + 4;
    constexpr int WS_STRIDE = BN + 4;
    __shared__ float As[BK][AS_STRIDE];
    __shared__ float Ws[BK][WS_STRIDE];

    constexpr int NTH = (BM / TM) * (BN / TN);
    const int tid = threadIdx.x;
    const int tx = tid % (BN / TN);
    const int ty = tid / (BN / TN);
    const int m0 = blockIdx.y * BM;
    const int n0 = blockIdx.x * BN;

    unsigned long long acc2[TM / 2][TN];
#pragma unroll
    for (int p = 0; p < TM / 2; p++)
#pragma unroll
        for (int j = 0; j < TN; j++) acc2[p][j] = 0ULL;

    for (int k0 = 0; k0 < K; k0 += BK) {
#pragma unroll
        for (int i = tid * 4; i < BM * BK; i += NTH * 4) {
            int m = i / BK, k = i % BK;
            float4 v = *(const float4*)(A + (long)(m0 + m) * K + (k0 + k));
            As[k + 0][m] = v.x; As[k + 1][m] = v.y;
            As[k + 2][m] = v.z; As[k + 3][m] = v.w;
        }
#pragma unroll
        for (int i = tid * 4; i < BN * BK; i += NTH * 4) {
            int n = i / BK, k = i % BK;
            float4 v = *(const float4*)(W + (long)(n0 + n) * K + (k0 + k));
            Ws[k + 0][n] = v.x; Ws[k + 1][n] = v.y;
            Ws[k + 2][n] = v.z; Ws[k + 3][n] = v.w;
        }
        __syncthreads();

#pragma unroll
        for (int k = 0; k < BK; k++) {
            unsigned long long am2[TM / 2];
            const ulonglong2* ap = reinterpret_cast<const ulonglong2*>(&As[k][ty * TM]);
#pragma unroll
            for (int q = 0; q < TM / 4; q++) {
                ulonglong2 tt = ap[q];
                am2[2 * q + 0] = tt.x;
                am2[2 * q + 1] = tt.y;
            }
            float4 w4 = *reinterpret_cast<const float4*>(&Ws[k][tx * TN]);
            unsigned long long wd[TN];
            wd[0] = pack2(w4.x, w4.x); wd[1] = pack2(w4.y, w4.y);
            wd[2] = pack2(w4.z, w4.z); wd[3] = pack2(w4.w, w4.w);
#pragma unroll
            for (int p = 0; p < TM / 2; p++)
#pragma unroll
                for (int j = 0; j < TN; j++) ffma2(acc2[p][j], am2[p], wd[j]);
        }
        __syncthreads();
    }

    float4 bv = make_float4(0.f, 0.f, 0.f, 0.f);
    if (bias) bv = *reinterpret_cast<const float4*>(bias + n0 + tx * TN);

#pragma unroll
    for (int p = 0; p < TM / 2; p++) {
        float2 v0 = unpack2(acc2[p][0]);
        float2 v1 = unpack2(acc2[p][1]);
        float2 v2 = unpack2(acc2[p][2]);
        float2 v3 = unpack2(acc2[p][3]);
        float4 rowA = make_float4(v0.x + bv.x, v1.x + bv.y, v2.x + bv.z, v3.x + bv.w);
        float4 rowB = make_float4(v0.y + bv.x, v1.y + bv.y, v2.y + bv.z, v3.y + bv.w);
        if (ACT == 1) {
            rowA.x = fmaxf(rowA.x, 0.f); rowA.y = fmaxf(rowA.y, 0.f);
            rowA.z = fmaxf(rowA.z, 0.f); rowA.w = fmaxf(rowA.w, 0.f);
            rowB.x = fmaxf(rowB.x, 0.f); rowB.y = fmaxf(rowB.y, 0.f);
            rowB.z = fmaxf(rowB.z, 0.f); rowB.w = fmaxf(rowB.w, 0.f);
        }
        int mA = m0 + ty * TM + 2 * p;
        int n  = n0 + tx * TN;
        *reinterpret_cast<float4*>(C + (long)mA * N + n) = rowA;
        *reinterpret_cast<float4*>(C + (long)(mA + 1) * N + n) = rowB;
    }
}

// ---------------------------------------------------------------------------
// Prep kernels
// ---------------------------------------------------------------------------
__global__ void pack_kernel(const float4* __restrict__ src,
                            uint4* __restrict__ dst, int n4)
{
    int i = blockIdx.x * blockDim.x + threadIdx.x;
    if (i < n4) dst[i] = packf4(src[i]);
}

__global__ void perm_pack_w_kernel(const float* __restrict__ src,
                                   unsigned* __restrict__ dst)
{
    int i = blockIdx.x * blockDim.x + threadIdx.x;
    int r = i / (H_DIM / 4);
    int c = i % (H_DIM / 4);
    int j = r >> 2, gg = r & 3;
    float4 v = ((const float4*)src)[(size_t)(gg * H_DIM + j) * (H_DIM / 4) + c];
    ((uint4*)dst)[(size_t)r * (H_DIM / 4) + c] = packf4(v);
}

__global__ void bias_perm_kernel(const float* __restrict__ bih,
                                 const float* __restrict__ bhh,
                                 float* __restrict__ bp)
{
    int i = blockIdx.x * blockDim.x + threadIdx.x;
    if (i < G_DIM) {
        int j = i >> 2, gg = i & 3;
        bp[i] = bih[gg * H_DIM + j] + bhh[gg * H_DIM + j];
    }
}

__global__ void zero_state_kernel(unsigned* __restrict__ h0,
                                  float* __restrict__ c)
{
    int i = blockIdx.x * blockDim.x + threadIdx.x;
    h0[i] = 0u;
    c[i] = 0.f;
}

// ---------------------------------------------------------------------------
// Launch
// ---------------------------------------------------------------------------
extern "C" void kernel_launch(void* const* d_in, const int* in_sizes, int n_in,
                              void* d_out, int out_size)
{
    const float* labels = (const float*)d_in[0];
    const float* z      = (const float*)d_in[1];
    const float* W1     = (const float*)d_in[2];
    const float* b1     = (const float*)d_in[3];
    const float* W2     = (const float*)d_in[4];
    const float* b2     = (const float*)d_in[5];
    const float* W3     = (const float*)d_in[6];
    const float* Wih    = (const float*)d_in[7];
    const float* Whh    = (const float*)d_in[8];
    const float* bih    = (const float*)d_in[9];
    const float* bhh    = (const float*)d_in[10];
    const float* P1     = (const float*)d_in[11];
    const float* pb1    = (const float*)d_in[12];
    const float* P2     = (const float*)d_in[13];
    const float* pb2    = (const float*)d_in[14];
    const float* P3     = (const float*)d_in[15];
    const float* pb3    = (const float*)d_in[16];
    float* out = (float*)d_out;

    float *x1, *x2, *conds, *bperm, *CWB, *ZW, *cst;
    unsigned *condsp, *Wihp, *Whhp, *P1p, *P2p, *P3p, *zp, *h0p, *Hp, *y1p, *y2p;
    cudaGetSymbolAddress((void**)&x1,     g_x1);
    cudaGetSymbolAddress((void**)&x2,     g_x2);
    cudaGetSymbolAddress((void**)&conds,  g_conds);
    cudaGetSymbolAddress((void**)&condsp, g_condsp);
    cudaGetSymbolAddress((void**)&bperm,  g_bperm);
    cudaGetSymbolAddress((void**)&Wihp,   g_Wihp);
    cudaGetSymbolAddress((void**)&Whhp,   g_Whhp);
    cudaGetSymbolAddress((void**)&P1p,    g_P1p);
    cudaGetSymbolAddress((void**)&P2p,    g_P2p);
    cudaGetSymbolAddress((void**)&P3p,    g_P3p);
    cudaGetSymbolAddress((void**)&CWB,    g_CWB);
    cudaGetSymbolAddress((void**)&zp,     g_zp);
    cudaGetSymbolAddress((void**)&ZW,     g_ZW);
    cudaGetSymbolAddress((void**)&h0p,    g_h0p);
    cudaGetSymbolAddress((void**)&cst,    g_c);
    cudaGetSymbolAddress((void**)&Hp,     g_Hp);
    cudaGetSymbolAddress((void**)&y1p,    g_y1p);
    cudaGetSymbolAddress((void**)&y2p,    g_y2p);

    const int TB = T_DIM * B_DIM;
    const size_t BH = (size_t)B_DIM * H_DIM;

    // Dynamic smem sizes (2-stage pipeline)
    constexpr int SMEM_128_128 = 2 * (128 + 128) * 36 * 4;  // 73728
    constexpr int SMEM_128_64  = 2 * (128 + 64) * 36 * 4;   // 55296
    cudaFuncSetAttribute(tgemm_kernel<128,128,64,32,0,0>,
                         cudaFuncAttributeMaxDynamicSharedMemorySize, SMEM_128_128);
    cudaFuncSetAttribute(tgemm_kernel<128,128,64,32,0,3>,
                         cudaFuncAttributeMaxDynamicSharedMemorySize, SMEM_128_128);
    cudaFuncSetAttribute(tgemm_kernel<128,128,64,32,1,1>,
                         cudaFuncAttributeMaxDynamicSharedMemorySize, SMEM_128_128);
    cudaFuncSetAttribute(tgemm_kernel<128,64,32,32,0,2>,
                         cudaFuncAttributeMaxDynamicSharedMemorySize, SMEM_128_64);
    cudaFuncSetAttribute(lstm_step_kernel,
                         cudaFuncAttributeMaxDynamicSharedMemorySize, SMEM_128_128);

    // --- Weight / input prep ---
    pack_kernel<<<(H_DIM * H_DIM / 4) / 256, 256>>>((const float4*)P1, (uint4*)P1p, H_DIM * H_DIM / 4);
    pack_kernel<<<(H_DIM * H_DIM / 4) / 256, 256>>>((const float4*)P2, (uint4*)P2p, H_DIM * H_DIM / 4);
    pack_kernel<<<(D_DIM * H_DIM / 4) / 256, 256>>>((const float4*)P3, (uint4*)P3p, D_DIM * H_DIM / 4);
    perm_pack_w_kernel<<<(G_DIM * H_DIM / 4) / 256, 256>>>(Wih, Wihp);
    perm_pack_w_kernel<<<(G_DIM * H_DIM / 4) / 256, 256>>>(Whh, Whhp);
    bias_perm_kernel<<<G_DIM / 256, 256>>>(bih, bhh, bperm);
    pack_kernel<<<((size_t)TB * H_DIM / 4) / 256, 256>>>((const float4*)z, (uint4*)zp, TB * (H_DIM / 4));

    // --- Label MLP (tiny, f32x2 path) ---
    gemm2_kernel<128,128,16,8,4,1><<<dim3(H_DIM/128, B_DIM/128), 512>>>(
        labels, W1, b1, x1, B_DIM, H_DIM, L_DIM);
    gemm2_kernel<128,128,16,8,4,1><<<dim3(H_DIM/128, B_DIM/128), 512>>>(
        x1, W2, b2, x2, B_DIM, H_DIM, H_DIM);
    gemm2_kernel<128,128,16,8,4,0><<<dim3(H_DIM/128, B_DIM/128), 512>>>(
        x2, W3, nullptr, conds, B_DIM, H_DIM, H_DIM);
    pack_kernel<<<(B_DIM * H_DIM / 4) / 256, 256>>>((const float4*)conds, (uint4*)condsp, B_DIM * H_DIM / 4);

    // --- CWB = conds @ Wih_perm^T + (bih+bhh)_perm ---
    tgemm_kernel<128,128,64,32,0,0><<<dim3(G_DIM/128, B_DIM/128), 256, SMEM_128_128>>>(
        condsp, Wihp, bperm, nullptr, CWB, B_DIM, G_DIM, H_DIM);
    // --- ZW = z @ Wih_perm^T + CWB[row % B]  (CWB folded in) ---
    tgemm_kernel<128,128,64,32,0,3><<<dim3(G_DIM/128, TB/128), 256, SMEM_128_128>>>(
        zp, Wihp, nullptr, CWB, ZW, TB, G_DIM, H_DIM);

    // --- Recurrence (fused gate GEMM + cell) ---
    zero_state_kernel<<<(B_DIM * H_DIM) / 256, 256>>>(h0p, cst);
    for (int t = 0; t < T_DIM; t++) {
        const unsigned* hin = (t == 0) ? h0p : (Hp + (size_t)(t - 1) * BH);
        lstm_step_kernel<<<dim3(G_DIM/128, B_DIM/128), 256, SMEM_128_128>>>(
            hin, Whhp, ZW + (size_t)t * B_DIM * G_DIM,
            cst, Hp + (size_t)t * BH);
    }

    // --- Projection MLP over all T*B rows ---
    tgemm_kernel<128,128,64,32,1,1><<<dim3(H_DIM/128, TB/128), 256, SMEM_128_128>>>(
        Hp, P1p, pb1, nullptr, y1p, TB, H_DIM, H_DIM);
    tgemm_kernel<128,128,64,32,1,1><<<dim3(H_DIM/128, TB/128), 256, SMEM_128_128>>>(
        y1p, P2p, pb2, nullptr, y2p, TB, H_DIM, H_DIM);
    tgemm_kernel<128,64,32,32,0,2><<<dim3(D_DIM/64, TB/128), 256, SMEM_128_64>>>(
        y2p, P3p, pb3, nullptr, out, TB, D_DIM, H_DIM);
}

// round 6
// speedup vs baseline: 2.3558x; 1.0949x over previous
#include <cuda_runtime.h>
#include <cuda_bf16.h>
#include <math.h>
#include <stdint.h>

// Problem dims (fixed by the dataset)
#define B_DIM 1024
#define T_DIM 128
#define L_DIM 16
#define H_DIM 512
#define D_DIM 64
#define G_DIM 2048          // 4*H
#define TB_DIM (T_DIM * B_DIM)

// ---------------------------------------------------------------------------
// Scratch (device globals). bf16 hi/lo pairs stored as separate ushort arrays.
// ---------------------------------------------------------------------------
__device__ float    g_x1[B_DIM * H_DIM];
__device__ float    g_x2[B_DIM * H_DIM];
__device__ float    g_conds[B_DIM * H_DIM];
__device__ float    g_bperm[G_DIM];
__device__ unsigned short g_conds_h[B_DIM * H_DIM];
__device__ unsigned short g_conds_l[B_DIM * H_DIM];
__device__ unsigned short g_Wih_h[G_DIM * H_DIM];
__device__ unsigned short g_Wih_l[G_DIM * H_DIM];
__device__ unsigned short g_Whh_h[G_DIM * H_DIM];
__device__ unsigned short g_Whh_l[G_DIM * H_DIM];
__device__ unsigned short g_P1_h[H_DIM * H_DIM];
__device__ unsigned short g_P1_l[H_DIM * H_DIM];
__device__ unsigned short g_P2_h[H_DIM * H_DIM];
__device__ unsigned short g_P2_l[H_DIM * H_DIM];
__device__ unsigned short g_P3_h[D_DIM * H_DIM];
__device__ unsigned short g_P3_l[D_DIM * H_DIM];
__device__ float    g_CWB[B_DIM * G_DIM];
__device__ unsigned short g_z_h[(size_t)TB_DIM * H_DIM];
__device__ unsigned short g_z_l[(size_t)TB_DIM * H_DIM];
__device__ float    g_ZW[(size_t)TB_DIM * G_DIM];          // 1 GB
__device__ unsigned short g_h0_h[B_DIM * H_DIM];
__device__ unsigned short g_h0_l[B_DIM * H_DIM];
__device__ float    g_c[B_DIM * H_DIM];
__device__ unsigned short g_H_h[(size_t)TB_DIM * H_DIM];
__device__ unsigned short g_H_l[(size_t)TB_DIM * H_DIM];
__device__ unsigned short g_y1_h[(size_t)TB_DIM * H_DIM];
__device__ unsigned short g_y1_l[(size_t)TB_DIM * H_DIM];
__device__ unsigned short g_y2_h[(size_t)TB_DIM * H_DIM];
__device__ unsigned short g_y2_l[(size_t)TB_DIM * H_DIM];

// ---------------------------------------------------------------------------
// Helpers
// ---------------------------------------------------------------------------
__device__ __forceinline__ unsigned packf(float x) {
    __nv_bfloat16 h = __float2bfloat16(x);
    float r = x - __bfloat162float(h);
    __nv_bfloat16 l = __float2bfloat16(r);
    return ((unsigned)__bfloat16_as_ushort(h) << 16) |
            (unsigned)__bfloat16_as_ushort(l);
}

__device__ __forceinline__ void mma16816(float& c0, float& c1, float& c2, float& c3,
                                         unsigned a0, unsigned a1, unsigned a2, unsigned a3,
                                         unsigned b0, unsigned b1) {
    asm volatile(
        "mma.sync.aligned.m16n8k16.row.col.f32.bf16.bf16.f32 "
        "{%0,%1,%2,%3}, {%4,%5,%6,%7}, {%8,%9}, {%0,%1,%2,%3};\n"
        : "+f"(c0), "+f"(c1), "+f"(c2), "+f"(c3)
        : "r"(a0), "r"(a1), "r"(a2), "r"(a3), "r"(b0), "r"(b1));
}

__device__ __forceinline__ void cp_async16(void* sptr, const void* gptr) {
    unsigned sa = (unsigned)__cvta_generic_to_shared(sptr);
    asm volatile("cp.async.cg.shared.global [%0], [%1], 16;\n" :: "r"(sa), "l"(gptr));
}
__device__ __forceinline__ void cp_commit() {
    asm volatile("cp.async.commit_group;\n");
}
template<int N>
__device__ __forceinline__ void cp_wait() {
    asm volatile("cp.async.wait_group %0;\n" :: "n"(N));
}

// ---------------------------------------------------------------------------
// HMMA 3xbf16 GEMM with separate hi/lo operands (no PRMT in the hot loop).
// D[M,N] = A[M,K] @ B[N,K]^T,  A = Ah + Al, B = Bh + Bl (bf16 hi/lo split);
// D = Ah*Bh + Ah*Bl + Al*Bh, fp32 accumulate.
// smem rows padded to STR = BK+8 ushorts (80B = 20 banks -> conflict-free).
// EPI: 0 = fp32 + bias            (CWB)
//      1 = fp32 + addvec[row % B] (ZW build, CWB fold)
//      2 = hi/lo out + bias (+relu if ACT)   (P1, P2)
//      3 = fp32 + bias, [T,B]->[B,T] perm    (P3)
//      4 = LSTM cell: + addvec(=ZW_t), c update, h hi/lo out
// ---------------------------------------------------------------------------
template<int BM, int BN, int WM, int WN, int EPI, int ACT>
__global__ void __launch_bounds__((BM / WM) * (BN / WN) * 32)
hgemm(const unsigned short* __restrict__ Ah, const unsigned short* __restrict__ Al,
      const unsigned short* __restrict__ Bh, const unsigned short* __restrict__ Bl,
      const float* __restrict__ bias,
      const float* __restrict__ addvec,
      float* __restrict__ outf,
      unsigned short* __restrict__ out_hi,
      unsigned short* __restrict__ out_lo,
      float* __restrict__ c_state,
      int M, int N, int K)
{
    constexpr int BK = 32;
    constexpr int STR = BK + 8;              // ushorts per smem row
    constexpr int ATI = BM * STR;            // ushorts per A tile
    constexpr int BTI = BN * STR;
    constexpr int STAGE = 2 * ATI + 2 * BTI; // Ah, Al, Bh, Bl
    constexpr int WARPS_N = BN / WN;
    constexpr int NTH = (BM / WM) * (BN / WN) * 32;
    constexpr int MI = WM / 16, NI = WN / 8;

    extern __shared__ unsigned short sm[];

    const int tid  = threadIdx.x;
    const int warp = tid >> 5, lane = tid & 31;
    const int g = lane >> 2, t = lane & 3;
    const int wm0 = (warp / WARPS_N) * WM;
    const int wn0 = (warp % WARPS_N) * WN;
    const int m0 = blockIdx.y * BM;
    const int n0 = blockIdx.x * BN;

    float acc[MI][NI][4];
#pragma unroll
    for (int mi = 0; mi < MI; mi++)
#pragma unroll
        for (int ni = 0; ni < NI; ni++)
#pragma unroll
            for (int q = 0; q < 4; q++) acc[mi][ni][q] = 0.f;

    auto load_stage = [&](int k0, int s) {
        unsigned short* st = sm + s * STAGE;
#pragma unroll
        for (int i = tid; i < BM * 4; i += NTH) {
            int r = i >> 2, c = i & 3;
            const size_t gs = (size_t)(m0 + r) * K + k0 + c * 8;
            cp_async16(st + r * STR + c * 8,       Ah + gs);
            cp_async16(st + ATI + r * STR + c * 8, Al + gs);
        }
#pragma unroll
        for (int i = tid; i < BN * 4; i += NTH) {
            int r = i >> 2, c = i & 3;
            const size_t gs = (size_t)(n0 + r) * K + k0 + c * 8;
            cp_async16(st + 2 * ATI + r * STR + c * 8,       Bh + gs);
            cp_async16(st + 2 * ATI + BTI + r * STR + c * 8, Bl + gs);
        }
        cp_commit();
    };

    const int KT = K / BK;
    load_stage(0, 0);

    for (int kt = 0; kt < KT; kt++) {
        const int s = kt & 1;
        if (kt + 1 < KT) { load_stage((kt + 1) * BK, s ^ 1); cp_wait<1>(); }
        else             { cp_wait<0>(); }
        __syncthreads();

        const unsigned short* Ash = sm + s * STAGE;
        const unsigned short* Asl = Ash + ATI;
        const unsigned short* Bsh = Ash + 2 * ATI;
        const unsigned short* Bsl = Bsh + BTI;

#pragma unroll
        for (int kk = 0; kk < BK; kk += 16) {
            unsigned ah[MI][4], al[MI][4], bh[NI][2], bl[NI][2];
#pragma unroll
            for (int mi = 0; mi < MI; mi++) {
                int r0 = (wm0 + mi * 16 + g) * STR + kk + 2 * t;
                int r1 = r0 + 8 * STR;
                ah[mi][0] = *(const unsigned*)&Ash[r0];
                ah[mi][1] = *(const unsigned*)&Ash[r1];
                ah[mi][2] = *(const unsigned*)&Ash[r0 + 8];
                ah[mi][3] = *(const unsigned*)&Ash[r1 + 8];
                al[mi][0] = *(const unsigned*)&Asl[r0];
                al[mi][1] = *(const unsigned*)&Asl[r1];
                al[mi][2] = *(const unsigned*)&Asl[r0 + 8];
                al[mi][3] = *(const unsigned*)&Asl[r1 + 8];
            }
#pragma unroll
            for (int ni = 0; ni < NI; ni++) {
                int q0 = (wn0 + ni * 8 + g) * STR + kk + 2 * t;
                bh[ni][0] = *(const unsigned*)&Bsh[q0];
                bh[ni][1] = *(const unsigned*)&Bsh[q0 + 8];
                bl[ni][0] = *(const unsigned*)&Bsl[q0];
                bl[ni][1] = *(const unsigned*)&Bsl[q0 + 8];
            }
#pragma unroll
            for (int mi = 0; mi < MI; mi++)
#pragma unroll
                for (int ni = 0; ni < NI; ni++) {
                    mma16816(acc[mi][ni][0], acc[mi][ni][1], acc[mi][ni][2], acc[mi][ni][3],
                             ah[mi][0], ah[mi][1], ah[mi][2], ah[mi][3], bh[ni][0], bh[ni][1]);
                    mma16816(acc[mi][ni][0], acc[mi][ni][1], acc[mi][ni][2], acc[mi][ni][3],
                             ah[mi][0], ah[mi][1], ah[mi][2], ah[mi][3], bl[ni][0], bl[ni][1]);
                    mma16816(acc[mi][ni][0], acc[mi][ni][1], acc[mi][ni][2], acc[mi][ni][3],
                             al[mi][0], al[mi][1], al[mi][2], al[mi][3], bh[ni][0], bh[ni][1]);
                }
        }
        __syncthreads();
    }

    // ---- Epilogues (layouts identical to validated round-4 code) ----
    if (EPI == 0 || EPI == 2 || EPI == 3) {
        float2 bv[NI];
#pragma unroll
        for (int ni = 0; ni < NI; ni++)
            bv[ni] = *(const float2*)(bias + n0 + wn0 + ni * 8 + 2 * t);

#pragma unroll
        for (int mi = 0; mi < MI; mi++) {
            int row0 = m0 + wm0 + mi * 16 + g;
#pragma unroll
            for (int ni = 0; ni < NI; ni++) {
                int col = n0 + wn0 + ni * 8 + 2 * t;
                float v0 = acc[mi][ni][0] + bv[ni].x;
                float v1 = acc[mi][ni][1] + bv[ni].y;
                float v2 = acc[mi][ni][2] + bv[ni].x;
                float v3 = acc[mi][ni][3] + bv[ni].y;
                if (ACT == 1) {
                    v0 = fmaxf(v0, 0.f); v1 = fmaxf(v1, 0.f);
                    v2 = fmaxf(v2, 0.f); v3 = fmaxf(v3, 0.f);
                }
                if (EPI == 0) {
                    *(float2*)(outf + (size_t)row0 * N + col)       = make_float2(v0, v1);
                    *(float2*)(outf + (size_t)(row0 + 8) * N + col) = make_float2(v2, v3);
                } else if (EPI == 2) {
                    unsigned p0 = packf(v0), p1 = packf(v1), p2 = packf(v2), p3 = packf(v3);
                    *(ushort2*)(out_hi + (size_t)row0 * N + col) =
                        make_ushort2(p0 >> 16, p1 >> 16);
                    *(ushort2*)(out_lo + (size_t)row0 * N + col) =
                        make_ushort2(p0 & 0xffff, p1 & 0xffff);
                    *(ushort2*)(out_hi + (size_t)(row0 + 8) * N + col) =
                        make_ushort2(p2 >> 16, p3 >> 16);
                    *(ushort2*)(out_lo + (size_t)(row0 + 8) * N + col) =
                        make_ushort2(p2 & 0xffff, p3 & 0xffff);
                } else {
                    int tt0 = row0 / B_DIM, bb0 = row0 % B_DIM;
                    int r1 = row0 + 8;
                    int tt1 = r1 / B_DIM, bb1 = r1 % B_DIM;
                    *(float2*)(outf + ((size_t)bb0 * T_DIM + tt0) * D_DIM + col) = make_float2(v0, v1);
                    *(float2*)(outf + ((size_t)bb1 * T_DIM + tt1) * D_DIM + col) = make_float2(v2, v3);
                }
            }
        }
    } else if (EPI == 1) {
#pragma unroll
        for (int mi = 0; mi < MI; mi++) {
            int row0 = m0 + wm0 + mi * 16 + g;
#pragma unroll
            for (int ni = 0; ni < NI; ni++) {
                int col = n0 + wn0 + ni * 8 + 2 * t;
                float2 a0 = *(const float2*)(addvec + (size_t)(row0 & (B_DIM - 1)) * N + col);
                float2 a1 = *(const float2*)(addvec + (size_t)((row0 + 8) & (B_DIM - 1)) * N + col);
                *(float2*)(outf + (size_t)row0 * N + col) =
                    make_float2(acc[mi][ni][0] + a0.x, acc[mi][ni][1] + a0.y);
                *(float2*)(outf + (size_t)(row0 + 8) * N + col) =
                    make_float2(acc[mi][ni][2] + a1.x, acc[mi][ni][3] + a1.y);
            }
        }
    } else {
        // EPI == 4: LSTM cell. Cols gate-permuted: n' = j*4 + {i,f,g,o}.
        // Lanes l and l^1 exchange so even lane owns row0, odd owns row0+8.
        const bool hi_half = (t & 1);
#pragma unroll
        for (int mi = 0; mi < MI; mi++) {
            int row0 = m0 + wm0 + mi * 16 + g;
#pragma unroll
            for (int ni = 0; ni < NI; ni++) {
                int col = n0 + wn0 + ni * 8 + 2 * t;
                float c0 = acc[mi][ni][0], c1 = acc[mi][ni][1];
                float c2 = acc[mi][ni][2], c3 = acc[mi][ni][3];
                float sx = __shfl_xor_sync(0xffffffffu, hi_half ? c0 : c2, 1);
                float sy = __shfl_xor_sync(0xffffffffu, hi_half ? c1 : c3, 1);
                int row = hi_half ? row0 + 8 : row0;
                float gi, gf, gg, go;
                if (!hi_half) { gi = c0; gf = c1; gg = sx; go = sy; }
                else          { gi = sx; gf = sy; gg = c2; go = c3; }

                int base = col & ~3;
                float4 zw = *(const float4*)(addvec + (size_t)row * G_DIM + base);
                gi += zw.x; gf += zw.y; gg += zw.z; go += zw.w;

                float ig = 1.f / (1.f + expf(-gi));
                float fg = 1.f / (1.f + expf(-gf));
                float gt = tanhf(gg);
                float og = 1.f / (1.f + expf(-go));

                size_t cidx = (size_t)row * H_DIM + (col >> 2);
                float cn = fg * c_state[cidx] + ig * gt;
                c_state[cidx] = cn;
                unsigned p = packf(og * tanhf(cn));
                out_hi[cidx] = (unsigned short)(p >> 16);
                out_lo[cidx] = (unsigned short)(p & 0xffffu);
            }
        }
    }
}

// ---------------------------------------------------------------------------
// f32x2 SGEMM (tiny label MLP; validated rounds 2-4)
// ---------------------------------------------------------------------------
__device__ __forceinline__ void ffma2(unsigned long long& d,
                                      unsigned long long a,
                                      unsigned long long b) {
    asm("fma.rn.f32x2 %0, %1, %2, %0;" : "+l"(d) : "l"(a), "l"(b));
}
__device__ __forceinline__ unsigned long long pack2(float lo, float hi) {
    unsigned long long r;
    asm("mov.b64 %0, {%1, %2};" : "=l"(r) : "f"(lo), "f"(hi));
    return r;
}
__device__ __forceinline__ float2 unpack2(unsigned long long u) {
    float2 f;
    asm("mov.b64 {%0, %1}, %2;" : "=f"(f.x), "=f"(f.y) : "l"(u));
    return f;
}

template<int BM, int BN, int BK, int TM, int TN, int ACT>
__global__ void gemm2_kernel(const float* __restrict__ A,
                             const float* __restrict__ W,
                             const float* __restrict__ bias,
                             float* __restrict__ C,
                             int M, int N, int K)
{
    constexpr int AS_STRIDE = BM + 4;
    constexpr int WS_STRIDE = BN + 4;
    __shared__ float As[BK][AS_STRIDE];
    __shared__ float Ws[BK][WS_STRIDE];

    constexpr int NTH = (BM / TM) * (BN / TN);
    const int tid = threadIdx.x;
    const int tx = tid % (BN / TN);
    const int ty = tid / (BN / TN);
    const int m0 = blockIdx.y * BM;
    const int n0 = blockIdx.x * BN;

    unsigned long long acc2[TM / 2][TN];
#pragma unroll
    for (int p = 0; p < TM / 2; p++)
#pragma unroll
        for (int j = 0; j < TN; j++) acc2[p][j] = 0ULL;

    for (int k0 = 0; k0 < K; k0 += BK) {
#pragma unroll
        for (int i = tid * 4; i < BM * BK; i += NTH * 4) {
            int m = i / BK, k = i % BK;
            float4 v = *(const float4*)(A + (long)(m0 + m) * K + (k0 + k));
            As[k + 0][m] = v.x; As[k + 1][m] = v.y;
            As[k + 2][m] = v.z; As[k + 3][m] = v.w;
        }
#pragma unroll
        for (int i = tid * 4; i < BN * BK; i += NTH * 4) {
            int n = i / BK, k = i % BK;
            float4 v = *(const float4*)(W + (long)(n0 + n) * K + (k0 + k));
            Ws[k + 0][n] = v.x; Ws[k + 1][n] = v.y;
            Ws[k + 2][n] = v.z; Ws[k + 3][n] = v.w;
        }
        __syncthreads();

#pragma unroll
        for (int k = 0; k < BK; k++) {
            unsigned long long am2[TM / 2];
            const ulonglong2* ap = reinterpret_cast<const ulonglong2*>(&As[k][ty * TM]);
#pragma unroll
            for (int q = 0; q < TM / 4; q++) {
                ulonglong2 tt = ap[q];
                am2[2 * q + 0] = tt.x;
                am2[2 * q + 1] = tt.y;
            }
            float4 w4 = *reinterpret_cast<const float4*>(&Ws[k][tx * TN]);
            unsigned long long wd[TN];
            wd[0] = pack2(w4.x, w4.x); wd[1] = pack2(w4.y, w4.y);
            wd[2] = pack2(w4.z, w4.z); wd[3] = pack2(w4.w, w4.w);
#pragma unroll
            for (int p = 0; p < TM / 2; p++)
#pragma unroll
                for (int j = 0; j < TN; j++) ffma2(acc2[p][j], am2[p], wd[j]);
        }
        __syncthreads();
    }

    float4 bv = make_float4(0.f, 0.f, 0.f, 0.f);
    if (bias) bv = *reinterpret_cast<const float4*>(bias + n0 + tx * TN);

#pragma unroll
    for (int p = 0; p < TM / 2; p++) {
        float2 v0 = unpack2(acc2[p][0]);
        float2 v1 = unpack2(acc2[p][1]);
        float2 v2 = unpack2(acc2[p][2]);
        float2 v3 = unpack2(acc2[p][3]);
        float4 rowA = make_float4(v0.x + bv.x, v1.x + bv.y, v2.x + bv.z, v3.x + bv.w);
        float4 rowB = make_float4(v0.y + bv.x, v1.y + bv.y, v2.y + bv.z, v3.y + bv.w);
        if (ACT == 1) {
            rowA.x = fmaxf(rowA.x, 0.f); rowA.y = fmaxf(rowA.y, 0.f);
            rowA.z = fmaxf(rowA.z, 0.f); rowA.w = fmaxf(rowA.w, 0.f);
            rowB.x = fmaxf(rowB.x, 0.f); rowB.y = fmaxf(rowB.y, 0.f);
            rowB.z = fmaxf(rowB.z, 0.f); rowB.w = fmaxf(rowB.w, 0.f);
        }
        int mA = m0 + ty * TM + 2 * p;
        int n  = n0 + tx * TN;
        *reinterpret_cast<float4*>(C + (long)mA * N + n) = rowA;
        *reinterpret_cast<float4*>(C + (long)(mA + 1) * N + n) = rowB;
    }
}

// ---------------------------------------------------------------------------
// Prep kernels
// ---------------------------------------------------------------------------
__global__ void split_kernel(const float4* __restrict__ src,
                             ushort4* __restrict__ hi,
                             ushort4* __restrict__ lo, int n4)
{
    int i = blockIdx.x * blockDim.x + threadIdx.x;
    if (i >= n4) return;
    float4 v = src[i];
    unsigned px = packf(v.x), py = packf(v.y), pz = packf(v.z), pw = packf(v.w);
    hi[i] = make_ushort4(px >> 16, py >> 16, pz >> 16, pw >> 16);
    lo[i] = make_ushort4(px & 0xffff, py & 0xffff, pz & 0xffff, pw & 0xffff);
}

// W [4H x H] -> gate-permuted rows n' = j*4 + g, split hi/lo
__global__ void perm_split_w_kernel(const float* __restrict__ src,
                                    ushort4* __restrict__ hi,
                                    ushort4* __restrict__ lo)
{
    int i = blockIdx.x * blockDim.x + threadIdx.x;
    int r = i / (H_DIM / 4);
    int c = i % (H_DIM / 4);
    int j = r >> 2, gg = r & 3;
    float4 v = ((const float4*)src)[(size_t)(gg * H_DIM + j) * (H_DIM / 4) + c];
    unsigned px = packf(v.x), py = packf(v.y), pz = packf(v.z), pw = packf(v.w);
    size_t o = (size_t)r * (H_DIM / 4) + c;
    hi[o] = make_ushort4(px >> 16, py >> 16, pz >> 16, pw >> 16);
    lo[o] = make_ushort4(px & 0xffff, py & 0xffff, pz & 0xffff, pw & 0xffff);
}

__global__ void bias_perm_kernel(const float* __restrict__ bih,
                                 const float* __restrict__ bhh,
                                 float* __restrict__ bp)
{
    int i = blockIdx.x * blockDim.x + threadIdx.x;
    if (i < G_DIM) {
        int j = i >> 2, gg = i & 3;
        bp[i] = bih[gg * H_DIM + j] + bhh[gg * H_DIM + j];
    }
}

__global__ void zero_state_kernel(unsigned short* __restrict__ h0h,
                                  unsigned short* __restrict__ h0l,
                                  float* __restrict__ c)
{
    int i = blockIdx.x * blockDim.x + threadIdx.x;
    h0h[i] = 0; h0l[i] = 0; c[i] = 0.f;
}

// ---------------------------------------------------------------------------
// Launch
// ---------------------------------------------------------------------------
extern "C" void kernel_launch(void* const* d_in, const int* in_sizes, int n_in,
                              void* d_out, int out_size)
{
    const float* labels = (const float*)d_in[0];
    const float* z      = (const float*)d_in[1];
    const float* W1     = (const float*)d_in[2];
    const float* b1     = (const float*)d_in[3];
    const float* W2     = (const float*)d_in[4];
    const float* b2     = (const float*)d_in[5];
    const float* W3     = (const float*)d_in[6];
    const float* Wih    = (const float*)d_in[7];
    const float* Whh    = (const float*)d_in[8];
    const float* bih    = (const float*)d_in[9];
    const float* bhh    = (const float*)d_in[10];
    const float* P1     = (const float*)d_in[11];
    const float* pb1    = (const float*)d_in[12];
    const float* P2     = (const float*)d_in[13];
    const float* pb2    = (const float*)d_in[14];
    const float* P3     = (const float*)d_in[15];
    const float* pb3    = (const float*)d_in[16];
    float* out = (float*)d_out;

    float *x1, *x2, *conds, *bperm, *CWB, *ZW, *cst;
    unsigned short *conds_h, *conds_l, *Wih_h, *Wih_l, *Whh_h, *Whh_l;
    unsigned short *P1_h, *P1_l, *P2_h, *P2_l, *P3_h, *P3_l;
    unsigned short *z_h, *z_l, *h0_h, *h0_l, *H_h, *H_l, *y1_h, *y1_l, *y2_h, *y2_l;
    cudaGetSymbolAddress((void**)&x1,     g_x1);
    cudaGetSymbolAddress((void**)&x2,     g_x2);
    cudaGetSymbolAddress((void**)&conds,  g_conds);
    cudaGetSymbolAddress((void**)&bperm,  g_bperm);
    cudaGetSymbolAddress((void**)&conds_h, g_conds_h);
    cudaGetSymbolAddress((void**)&conds_l, g_conds_l);
    cudaGetSymbolAddress((void**)&Wih_h,  g_Wih_h);
    cudaGetSymbolAddress((void**)&Wih_l,  g_Wih_l);
    cudaGetSymbolAddress((void**)&Whh_h,  g_Whh_h);
    cudaGetSymbolAddress((void**)&Whh_l,  g_Whh_l);
    cudaGetSymbolAddress((void**)&P1_h,   g_P1_h);
    cudaGetSymbolAddress((void**)&P1_l,   g_P1_l);
    cudaGetSymbolAddress((void**)&P2_h,   g_P2_h);
    cudaGetSymbolAddress((void**)&P2_l,   g_P2_l);
    cudaGetSymbolAddress((void**)&P3_h,   g_P3_h);
    cudaGetSymbolAddress((void**)&P3_l,   g_P3_l);
    cudaGetSymbolAddress((void**)&CWB,    g_CWB);
    cudaGetSymbolAddress((void**)&z_h,    g_z_h);
    cudaGetSymbolAddress((void**)&z_l,    g_z_l);
    cudaGetSymbolAddress((void**)&ZW,     g_ZW);
    cudaGetSymbolAddress((void**)&h0_h,   g_h0_h);
    cudaGetSymbolAddress((void**)&h0_l,   g_h0_l);
    cudaGetSymbolAddress((void**)&cst,    g_c);
    cudaGetSymbolAddress((void**)&H_h,    g_H_h);
    cudaGetSymbolAddress((void**)&H_l,    g_H_l);
    cudaGetSymbolAddress((void**)&y1_h,   g_y1_h);
    cudaGetSymbolAddress((void**)&y1_l,   g_y1_l);
    cudaGetSymbolAddress((void**)&y2_h,   g_y2_h);
    cudaGetSymbolAddress((void**)&y2_l,   g_y2_l);

    const int TB = TB_DIM;
    const size_t BH = (size_t)B_DIM * H_DIM;

    // Dynamic smem: 2 stages x (2 A-tiles + 2 B-tiles), STR=40 ushorts/row
    constexpr int SM128 = 2 * (2 * 128 * 40 + 2 * 128 * 40) * 2;  // 81920 B
    constexpr int SM64  = 2 * (2 * 128 * 40 + 2 * 64 * 40) * 2;   // 61440 B
    cudaFuncSetAttribute((const void*)hgemm<128,128,64,32,0,0>,
                         cudaFuncAttributeMaxDynamicSharedMemorySize, SM128);
    cudaFuncSetAttribute((const void*)hgemm<128,128,64,32,1,0>,
                         cudaFuncAttributeMaxDynamicSharedMemorySize, SM128);
    cudaFuncSetAttribute((const void*)hgemm<128,128,64,32,2,1>,
                         cudaFuncAttributeMaxDynamicSharedMemorySize, SM128);
    cudaFuncSetAttribute((const void*)hgemm<128,128,64,32,4,0>,
                         cudaFuncAttributeMaxDynamicSharedMemorySize, SM128);
    cudaFuncSetAttribute((const void*)hgemm<128,64,64,16,3,0>,
                         cudaFuncAttributeMaxDynamicSharedMemorySize, SM64);

    // --- Weight / input prep ---
    split_kernel<<<(H_DIM * H_DIM / 4) / 256, 256>>>((const float4*)P1, (ushort4*)P1_h, (ushort4*)P1_l, H_DIM * H_DIM / 4);
    split_kernel<<<(H_DIM * H_DIM / 4) / 256, 256>>>((const float4*)P2, (ushort4*)P2_h, (ushort4*)P2_l, H_DIM * H_DIM / 4);
    split_kernel<<<(D_DIM * H_DIM / 4) / 256, 256>>>((const float4*)P3, (ushort4*)P3_h, (ushort4*)P3_l, D_DIM * H_DIM / 4);
    perm_split_w_kernel<<<(G_DIM * H_DIM / 4) / 256, 256>>>(Wih, (ushort4*)Wih_h, (ushort4*)Wih_l);
    perm_split_w_kernel<<<(G_DIM * H_DIM / 4) / 256, 256>>>(Whh, (ushort4*)Whh_h, (ushort4*)Whh_l);
    bias_perm_kernel<<<G_DIM / 256, 256>>>(bih, bhh, bperm);
    split_kernel<<<(int)(((size_t)TB * H_DIM / 4) / 256), 256>>>((const float4*)z, (ushort4*)z_h, (ushort4*)z_l, TB * (H_DIM / 4));

    // --- Label MLP (tiny, f32x2 path) ---
    gemm2_kernel<128,128,16,8,4,1><<<dim3(H_DIM/128, B_DIM/128), 512>>>(
        labels, W1, b1, x1, B_DIM, H_DIM, L_DIM);
    gemm2_kernel<128,128,16,8,4,1><<<dim3(H_DIM/128, B_DIM/128), 512>>>(
        x1, W2, b2, x2, B_DIM, H_DIM, H_DIM);
    gemm2_kernel<128,128,16,8,4,0><<<dim3(H_DIM/128, B_DIM/128), 512>>>(
        x2, W3, nullptr, conds, B_DIM, H_DIM, H_DIM);
    split_kernel<<<(B_DIM * H_DIM / 4) / 256, 256>>>((const float4*)conds, (ushort4*)conds_h, (ushort4*)conds_l, B_DIM * H_DIM / 4);

    // --- CWB = conds @ Wih_perm^T + (bih+bhh)_perm ---
    hgemm<128,128,64,32,0,0><<<dim3(G_DIM/128, B_DIM/128), 256, SM128>>>(
        conds_h, conds_l, Wih_h, Wih_l, bperm, nullptr,
        CWB, nullptr, nullptr, nullptr, B_DIM, G_DIM, H_DIM);
    // --- ZW = z @ Wih_perm^T + CWB[row % B] ---
    hgemm<128,128,64,32,1,0><<<dim3(G_DIM/128, TB/128), 256, SM128>>>(
        z_h, z_l, Wih_h, Wih_l, nullptr, CWB,
        ZW, nullptr, nullptr, nullptr, TB, G_DIM, H_DIM);

    // --- Recurrence (fused gate GEMM + cell) ---
    zero_state_kernel<<<(B_DIM * H_DIM) / 256, 256>>>(h0_h, h0_l, cst);
    for (int t = 0; t < T_DIM; t++) {
        const unsigned short* ah = (t == 0) ? h0_h : (H_h + (size_t)(t - 1) * BH);
        const unsigned short* al = (t == 0) ? h0_l : (H_l + (size_t)(t - 1) * BH);
        hgemm<128,128,64,32,4,0><<<dim3(G_DIM/128, B_DIM/128), 256, SM128>>>(
            ah, al, Whh_h, Whh_l, nullptr, ZW + (size_t)t * B_DIM * G_DIM,
            nullptr, H_h + (size_t)t * BH, H_l + (size_t)t * BH, cst,
            B_DIM, G_DIM, H_DIM);
    }

    // --- Projection MLP over all T*B rows ---
    hgemm<128,128,64,32,2,1><<<dim3(H_DIM/128, TB/128), 256, SM128>>>(
        H_h, H_l, P1_h, P1_l, pb1, nullptr,
        nullptr, y1_h, y1_l, nullptr, TB, H_DIM, H_DIM);
    hgemm<128,128,64,32,2,1><<<dim3(H_DIM/128, TB/128), 256, SM128>>>(
        y1_h, y1_l, P2_h, P2_l, pb2, nullptr,
        nullptr, y2_h, y2_l, nullptr, TB, H_DIM, H_DIM);
    hgemm<128,64,64,16,3,0><<<dim3(D_DIM/64, TB/128), 256, SM64>>>(
        y2_h, y2_l, P3_h, P3_l, pb3, nullptr,
        out, nullptr, nullptr, nullptr, TB, D_DIM, H_DIM);
}

// round 7
// speedup vs baseline: 2.8484x; 1.2091x over previous
#include <cuda_runtime.h>
#include <cuda_bf16.h>
#include <math.h>
#include <stdint.h>

// Problem dims (fixed by the dataset)
#define B_DIM 1024
#define T_DIM 128
#define L_DIM 16
#define H_DIM 512
#define D_DIM 64
#define G_DIM 2048          // 4*H
#define TB_DIM (T_DIM * B_DIM)
#define GRID_P 128          // persistent recurrence grid (<= 148 SMs)

// ---------------------------------------------------------------------------
// Scratch (device globals). bf16 hi/lo pairs stored as separate ushort arrays.
// ---------------------------------------------------------------------------
__device__ float    g_x1[B_DIM * H_DIM];
__device__ float    g_x2[B_DIM * H_DIM];
__device__ float    g_bperm[G_DIM];
__device__ unsigned short g_conds_h[B_DIM * H_DIM];
__device__ unsigned short g_conds_l[B_DIM * H_DIM];
__device__ unsigned short g_Wih_h[G_DIM * H_DIM];
__device__ unsigned short g_Wih_l[G_DIM * H_DIM];
__device__ unsigned short g_Whh_h[G_DIM * H_DIM];
__device__ unsigned short g_Whh_l[G_DIM * H_DIM];
__device__ unsigned short g_P1_h[H_DIM * H_DIM];
__device__ unsigned short g_P1_l[H_DIM * H_DIM];
__device__ unsigned short g_P2_h[H_DIM * H_DIM];
__device__ unsigned short g_P2_l[H_DIM * H_DIM];
__device__ unsigned short g_P3_h[D_DIM * H_DIM];
__device__ unsigned short g_P3_l[D_DIM * H_DIM];
__device__ float    g_CWB[B_DIM * G_DIM];
__device__ unsigned short g_z_h[(size_t)TB_DIM * H_DIM];
__device__ unsigned short g_z_l[(size_t)TB_DIM * H_DIM];
__device__ float    g_ZW[(size_t)TB_DIM * G_DIM];          // 1 GB
__device__ unsigned short g_H_h[(size_t)TB_DIM * H_DIM];
__device__ unsigned short g_H_l[(size_t)TB_DIM * H_DIM];
__device__ unsigned short g_y1_h[(size_t)TB_DIM * H_DIM];
__device__ unsigned short g_y1_l[(size_t)TB_DIM * H_DIM];
__device__ unsigned short g_y2_h[(size_t)TB_DIM * H_DIM];
__device__ unsigned short g_y2_l[(size_t)TB_DIM * H_DIM];

// Persistent-kernel grid barrier (monotonic; self-reset at kernel end)
__device__ unsigned g_bar_ctr  = 0;
__device__ unsigned g_done_ctr = 0;

// ---------------------------------------------------------------------------
// Helpers
// ---------------------------------------------------------------------------
__device__ __forceinline__ unsigned packf(float x) {
    __nv_bfloat16 h = __float2bfloat16(x);
    float r = x - __bfloat162float(h);
    __nv_bfloat16 l = __float2bfloat16(r);
    return ((unsigned)__bfloat16_as_ushort(h) << 16) |
            (unsigned)__bfloat16_as_ushort(l);
}

__device__ __forceinline__ void mma16816(float& c0, float& c1, float& c2, float& c3,
                                         unsigned a0, unsigned a1, unsigned a2, unsigned a3,
                                         unsigned b0, unsigned b1) {
    asm volatile(
        "mma.sync.aligned.m16n8k16.row.col.f32.bf16.bf16.f32 "
        "{%0,%1,%2,%3}, {%4,%5,%6,%7}, {%8,%9}, {%0,%1,%2,%3};\n"
        : "+f"(c0), "+f"(c1), "+f"(c2), "+f"(c3)
        : "r"(a0), "r"(a1), "r"(a2), "r"(a3), "r"(b0), "r"(b1));
}

__device__ __forceinline__ void cp_async16(void* sptr, const void* gptr) {
    unsigned sa = (unsigned)__cvta_generic_to_shared(sptr);
    asm volatile("cp.async.cg.shared.global [%0], [%1], 16;\n" :: "r"(sa), "l"(gptr));
}
__device__ __forceinline__ void cp_commit() {
    asm volatile("cp.async.commit_group;\n");
}
template<int N>
__device__ __forceinline__ void cp_wait() {
    asm volatile("cp.async.wait_group %0;\n" :: "n"(N));
}

// ---------------------------------------------------------------------------
// HMMA 3xbf16 GEMM, separate hi/lo operands, BK=64 2-stage cp.async pipeline.
// D[M,N] = A@B^T with A=Ah+Al, B=Bh+Bl; D = Ah*Bh + Ah*Bl + Al*Bh (fp32 acc).
// smem rows STR=72 ushorts (144B): mma-lane banks (4*row + t) mod 32 distinct.
// EPI: 0 = fp32 + bias (CWB)
//      1 = fp32 + addvec[row % B] (ZW build, CWB fold)
//      2 = hi/lo out + bias (+relu if ACT)   (P1, P2)
//      3 = fp32 + bias, [T,B]->[B,T] perm    (P3)
// ---------------------------------------------------------------------------
template<int BM, int BN, int WM, int WN, int EPI, int ACT>
__global__ void __launch_bounds__((BM / WM) * (BN / WN) * 32)
hgemm(const unsigned short* __restrict__ Ah, const unsigned short* __restrict__ Al,
      const unsigned short* __restrict__ Bh, const unsigned short* __restrict__ Bl,
      const float* __restrict__ bias,
      const float* __restrict__ addvec,
      float* __restrict__ outf,
      unsigned short* __restrict__ out_hi,
      unsigned short* __restrict__ out_lo,
      int M, int N, int K)
{
    constexpr int BK = 64;
    constexpr int STR = BK + 8;
    constexpr int ATI = BM * STR;
    constexpr int BTI = BN * STR;
    constexpr int STAGE = 2 * ATI + 2 * BTI;
    constexpr int WARPS_N = BN / WN;
    constexpr int NTH = (BM / WM) * (BN / WN) * 32;
    constexpr int MI = WM / 16, NI = WN / 8;

    extern __shared__ unsigned short sm[];

    const int tid  = threadIdx.x;
    const int warp = tid >> 5, lane = tid & 31;
    const int g = lane >> 2, t = lane & 3;
    const int wm0 = (warp / WARPS_N) * WM;
    const int wn0 = (warp % WARPS_N) * WN;
    const int m0 = blockIdx.y * BM;
    const int n0 = blockIdx.x * BN;

    float acc[MI][NI][4];
#pragma unroll
    for (int mi = 0; mi < MI; mi++)
#pragma unroll
        for (int ni = 0; ni < NI; ni++)
#pragma unroll
            for (int q = 0; q < 4; q++) acc[mi][ni][q] = 0.f;

    auto load_stage = [&](int k0, int s) {
        unsigned short* st = sm + s * STAGE;
#pragma unroll
        for (int i = tid; i < BM * 8; i += NTH) {
            int r = i >> 3, c = i & 7;
            const size_t gs = (size_t)(m0 + r) * K + k0 + c * 8;
            cp_async16(st + r * STR + c * 8,       Ah + gs);
            cp_async16(st + ATI + r * STR + c * 8, Al + gs);
        }
#pragma unroll
        for (int i = tid; i < BN * 8; i += NTH) {
            int r = i >> 3, c = i & 7;
            const size_t gs = (size_t)(n0 + r) * K + k0 + c * 8;
            cp_async16(st + 2 * ATI + r * STR + c * 8,       Bh + gs);
            cp_async16(st + 2 * ATI + BTI + r * STR + c * 8, Bl + gs);
        }
        cp_commit();
    };

    const int KT = K / BK;
    load_stage(0, 0);

    for (int kt = 0; kt < KT; kt++) {
        const int s = kt & 1;
        if (kt + 1 < KT) { load_stage((kt + 1) * BK, s ^ 1); cp_wait<1>(); }
        else             { cp_wait<0>(); }
        __syncthreads();

        const unsigned short* Ash = sm + s * STAGE;
        const unsigned short* Asl = Ash + ATI;
        const unsigned short* Bsh = Ash + 2 * ATI;
        const unsigned short* Bsl = Bsh + BTI;

#pragma unroll
        for (int kk = 0; kk < BK; kk += 16) {
            unsigned ah[MI][4], al[MI][4], bh[NI][2], bl[NI][2];
#pragma unroll
            for (int mi = 0; mi < MI; mi++) {
                int r0 = (wm0 + mi * 16 + g) * STR + kk + 2 * t;
                int r1 = r0 + 8 * STR;
                ah[mi][0] = *(const unsigned*)&Ash[r0];
                ah[mi][1] = *(const unsigned*)&Ash[r1];
                ah[mi][2] = *(const unsigned*)&Ash[r0 + 8];
                ah[mi][3] = *(const unsigned*)&Ash[r1 + 8];
                al[mi][0] = *(const unsigned*)&Asl[r0];
                al[mi][1] = *(const unsigned*)&Asl[r1];
                al[mi][2] = *(const unsigned*)&Asl[r0 + 8];
                al[mi][3] = *(const unsigned*)&Asl[r1 + 8];
            }
#pragma unroll
            for (int ni = 0; ni < NI; ni++) {
                int q0 = (wn0 + ni * 8 + g) * STR + kk + 2 * t;
                bh[ni][0] = *(const unsigned*)&Bsh[q0];
                bh[ni][1] = *(const unsigned*)&Bsh[q0 + 8];
                bl[ni][0] = *(const unsigned*)&Bsl[q0];
                bl[ni][1] = *(const unsigned*)&Bsl[q0 + 8];
            }
#pragma unroll
            for (int mi = 0; mi < MI; mi++)
#pragma unroll
                for (int ni = 0; ni < NI; ni++) {
                    mma16816(acc[mi][ni][0], acc[mi][ni][1], acc[mi][ni][2], acc[mi][ni][3],
                             ah[mi][0], ah[mi][1], ah[mi][2], ah[mi][3], bh[ni][0], bh[ni][1]);
                    mma16816(acc[mi][ni][0], acc[mi][ni][1], acc[mi][ni][2], acc[mi][ni][3],
                             ah[mi][0], ah[mi][1], ah[mi][2], ah[mi][3], bl[ni][0], bl[ni][1]);
                    mma16816(acc[mi][ni][0], acc[mi][ni][1], acc[mi][ni][2], acc[mi][ni][3],
                             al[mi][0], al[mi][1], al[mi][2], al[mi][3], bh[ni][0], bh[ni][1]);
                }
        }
        __syncthreads();
    }

    // ---- Epilogues ----
    if (EPI == 0 || EPI == 2 || EPI == 3) {
        float2 bv[NI];
#pragma unroll
        for (int ni = 0; ni < NI; ni++)
            bv[ni] = *(const float2*)(bias + n0 + wn0 + ni * 8 + 2 * t);

#pragma unroll
        for (int mi = 0; mi < MI; mi++) {
            int row0 = m0 + wm0 + mi * 16 + g;
#pragma unroll
            for (int ni = 0; ni < NI; ni++) {
                int col = n0 + wn0 + ni * 8 + 2 * t;
                float v0 = acc[mi][ni][0] + bv[ni].x;
                float v1 = acc[mi][ni][1] + bv[ni].y;
                float v2 = acc[mi][ni][2] + bv[ni].x;
                float v3 = acc[mi][ni][3] + bv[ni].y;
                if (ACT == 1) {
                    v0 = fmaxf(v0, 0.f); v1 = fmaxf(v1, 0.f);
                    v2 = fmaxf(v2, 0.f); v3 = fmaxf(v3, 0.f);
                }
                if (EPI == 0) {
                    *(float2*)(outf + (size_t)row0 * N + col)       = make_float2(v0, v1);
                    *(float2*)(outf + (size_t)(row0 + 8) * N + col) = make_float2(v2, v3);
                } else if (EPI == 2) {
                    unsigned p0 = packf(v0), p1 = packf(v1), p2 = packf(v2), p3 = packf(v3);
                    *(ushort2*)(out_hi + (size_t)row0 * N + col) =
                        make_ushort2(p0 >> 16, p1 >> 16);
                    *(ushort2*)(out_lo + (size_t)row0 * N + col) =
                        make_ushort2(p0 & 0xffff, p1 & 0xffff);
                    *(ushort2*)(out_hi + (size_t)(row0 + 8) * N + col) =
                        make_ushort2(p2 >> 16, p3 >> 16);
                    *(ushort2*)(out_lo + (size_t)(row0 + 8) * N + col) =
                        make_ushort2(p2 & 0xffff, p3 & 0xffff);
                } else {
                    int tt0 = row0 / B_DIM, bb0 = row0 % B_DIM;
                    int r1 = row0 + 8;
                    int tt1 = r1 / B_DIM, bb1 = r1 % B_DIM;
                    *(float2*)(outf + ((size_t)bb0 * T_DIM + tt0) * D_DIM + col) = make_float2(v0, v1);
                    *(float2*)(outf + ((size_t)bb1 * T_DIM + tt1) * D_DIM + col) = make_float2(v2, v3);
                }
            }
        }
    } else {
        // EPI == 1
#pragma unroll
        for (int mi = 0; mi < MI; mi++) {
            int row0 = m0 + wm0 + mi * 16 + g;
#pragma unroll
            for (int ni = 0; ni < NI; ni++) {
                int col = n0 + wn0 + ni * 8 + 2 * t;
                float2 a0 = *(const float2*)(addvec + (size_t)(row0 & (B_DIM - 1)) * N + col);
                float2 a1 = *(const float2*)(addvec + (size_t)((row0 + 8) & (B_DIM - 1)) * N + col);
                *(float2*)(outf + (size_t)row0 * N + col) =
                    make_float2(acc[mi][ni][0] + a0.x, acc[mi][ni][1] + a0.y);
                *(float2*)(outf + (size_t)(row0 + 8) * N + col) =
                    make_float2(acc[mi][ni][2] + a1.x, acc[mi][ni][3] + a1.y);
            }
        }
    }
}

// ---------------------------------------------------------------------------
// Persistent LSTM recurrence: all T steps in one launch, grid = 128 CTAs
// (all co-resident: 1 CTA/SM by smem, 128 <= 148). c-state lives in registers.
// Step t: gates = H[t-1] @ Whh_perm^T (3xbf16) + ZW[t] (incl. conds/biases),
// then cell, writing H[t] hi/lo. Software grid barrier between steps.
// ---------------------------------------------------------------------------
__global__ void __launch_bounds__(256)
lstm_persistent(const unsigned short* __restrict__ Whh_h,
                const unsigned short* __restrict__ Whh_l,
                const float* __restrict__ ZW,        // [T][B][G] (perm cols)
                unsigned short* __restrict__ H_h,
                unsigned short* __restrict__ H_l)
{
    constexpr int BM = 128, BN = 128, BK = 64, WM = 64, WN = 32;
    constexpr int STR = BK + 8;
    constexpr int ATI = BM * STR, BTI = BN * STR;
    constexpr int STAGE = 2 * ATI + 2 * BTI;
    constexpr int WARPS_N = BN / WN;
    constexpr int NTH = 256;
    constexpr int MI = WM / 16, NI = WN / 8;
    constexpr int K = H_DIM, N = G_DIM;
    constexpr int KT = K / BK;

    extern __shared__ unsigned short sm[];

    const int tid  = threadIdx.x;
    const int warp = tid >> 5, lane = tid & 31;
    const int g = lane >> 2, t4 = lane & 3;
    const int wm0 = (warp / WARPS_N) * WM;
    const int wn0 = (warp % WARPS_N) * WN;
    const int bid = blockIdx.x;
    const int m0 = (bid >> 4) * BM;     // 8 m-tiles
    const int n0 = (bid & 15) * BN;     // 16 n-tiles

    const bool hi_half = (t4 & 1);

    float creg[MI][NI];
#pragma unroll
    for (int mi = 0; mi < MI; mi++)
#pragma unroll
        for (int ni = 0; ni < NI; ni++) creg[mi][ni] = 0.f;

    for (int t = 0; t < T_DIM; t++) {
        float acc[MI][NI][4];
#pragma unroll
        for (int mi = 0; mi < MI; mi++)
#pragma unroll
            for (int ni = 0; ni < NI; ni++)
#pragma unroll
                for (int q = 0; q < 4; q++) acc[mi][ni][q] = 0.f;

        if (t > 0) {
            const unsigned short* Ah = H_h + (size_t)(t - 1) * B_DIM * H_DIM;
            const unsigned short* Al = H_l + (size_t)(t - 1) * B_DIM * H_DIM;

            auto load_stage = [&](int k0, int s) {
                unsigned short* st = sm + s * STAGE;
#pragma unroll
                for (int i = tid; i < BM * 8; i += NTH) {
                    int r = i >> 3, c = i & 7;
                    const size_t gs = (size_t)(m0 + r) * K + k0 + c * 8;
                    cp_async16(st + r * STR + c * 8,       Ah + gs);
                    cp_async16(st + ATI + r * STR + c * 8, Al + gs);
                }
#pragma unroll
                for (int i = tid; i < BN * 8; i += NTH) {
                    int r = i >> 3, c = i & 7;
                    const size_t gs = (size_t)(n0 + r) * K + k0 + c * 8;
                    cp_async16(st + 2 * ATI + r * STR + c * 8,       Whh_h + gs);
                    cp_async16(st + 2 * ATI + BTI + r * STR + c * 8, Whh_l + gs);
                }
                cp_commit();
            };

            load_stage(0, 0);
            for (int kt = 0; kt < KT; kt++) {
                const int s = kt & 1;
                if (kt + 1 < KT) { load_stage((kt + 1) * BK, s ^ 1); cp_wait<1>(); }
                else             { cp_wait<0>(); }
                __syncthreads();

                const unsigned short* Ash = sm + s * STAGE;
                const unsigned short* Asl = Ash + ATI;
                const unsigned short* Bsh = Ash + 2 * ATI;
                const unsigned short* Bsl = Bsh + BTI;

#pragma unroll
                for (int kk = 0; kk < BK; kk += 16) {
                    unsigned ah[MI][4], al[MI][4], bh[NI][2], bl[NI][2];
#pragma unroll
                    for (int mi = 0; mi < MI; mi++) {
                        int r0 = (wm0 + mi * 16 + g) * STR + kk + 2 * t4;
                        int r1 = r0 + 8 * STR;
                        ah[mi][0] = *(const unsigned*)&Ash[r0];
                        ah[mi][1] = *(const unsigned*)&Ash[r1];
                        ah[mi][2] = *(const unsigned*)&Ash[r0 + 8];
                        ah[mi][3] = *(const unsigned*)&Ash[r1 + 8];
                        al[mi][0] = *(const unsigned*)&Asl[r0];
                        al[mi][1] = *(const unsigned*)&Asl[r1];
                        al[mi][2] = *(const unsigned*)&Asl[r0 + 8];
                        al[mi][3] = *(const unsigned*)&Asl[r1 + 8];
                    }
#pragma unroll
                    for (int ni = 0; ni < NI; ni++) {
                        int q0 = (wn0 + ni * 8 + g) * STR + kk + 2 * t4;
                        bh[ni][0] = *(const unsigned*)&Bsh[q0];
                        bh[ni][1] = *(const unsigned*)&Bsh[q0 + 8];
                        bl[ni][0] = *(const unsigned*)&Bsl[q0];
                        bl[ni][1] = *(const unsigned*)&Bsl[q0 + 8];
                    }
#pragma unroll
                    for (int mi = 0; mi < MI; mi++)
#pragma unroll
                        for (int ni = 0; ni < NI; ni++) {
                            mma16816(acc[mi][ni][0], acc[mi][ni][1], acc[mi][ni][2], acc[mi][ni][3],
                                     ah[mi][0], ah[mi][1], ah[mi][2], ah[mi][3], bh[ni][0], bh[ni][1]);
                            mma16816(acc[mi][ni][0], acc[mi][ni][1], acc[mi][ni][2], acc[mi][ni][3],
                                     ah[mi][0], ah[mi][1], ah[mi][2], ah[mi][3], bl[ni][0], bl[ni][1]);
                            mma16816(acc[mi][ni][0], acc[mi][ni][1], acc[mi][ni][2], acc[mi][ni][3],
                                     al[mi][0], al[mi][1], al[mi][2], al[mi][3], bh[ni][0], bh[ni][1]);
                        }
                }
                __syncthreads();
            }
        }

        // ---- Cell epilogue (c in registers) ----
        const float* zwb = ZW + (size_t)t * B_DIM * G_DIM;
        unsigned short* hh = H_h + (size_t)t * B_DIM * H_DIM;
        unsigned short* hl = H_l + (size_t)t * B_DIM * H_DIM;
#pragma unroll
        for (int mi = 0; mi < MI; mi++) {
            int row0 = m0 + wm0 + mi * 16 + g;
#pragma unroll
            for (int ni = 0; ni < NI; ni++) {
                int col = n0 + wn0 + ni * 8 + 2 * t4;
                float c0 = acc[mi][ni][0], c1 = acc[mi][ni][1];
                float c2 = acc[mi][ni][2], c3 = acc[mi][ni][3];
                float sx = __shfl_xor_sync(0xffffffffu, hi_half ? c0 : c2, 1);
                float sy = __shfl_xor_sync(0xffffffffu, hi_half ? c1 : c3, 1);
                int row = hi_half ? row0 + 8 : row0;
                float gi, gf, gg, go;
                if (!hi_half) { gi = c0; gf = c1; gg = sx; go = sy; }
                else          { gi = sx; gf = sy; gg = c2; go = c3; }

                int base = col & ~3;
                float4 zw = *(const float4*)(zwb + (size_t)row * G_DIM + base);
                gi += zw.x; gf += zw.y; gg += zw.z; go += zw.w;

                float ig = 1.f / (1.f + expf(-gi));
                float fg = 1.f / (1.f + expf(-gf));
                float gt = tanhf(gg);
                float og = 1.f / (1.f + expf(-go));

                float cn = fg * creg[mi][ni] + ig * gt;
                creg[mi][ni] = cn;
                unsigned p = packf(og * tanhf(cn));
                size_t hidx = (size_t)row * H_DIM + (col >> 2);
                hh[hidx] = (unsigned short)(p >> 16);
                hl[hidx] = (unsigned short)(p & 0xffffu);
            }
        }

        // ---- Grid barrier between steps ----
        if (t < T_DIM - 1) {
            __syncthreads();
            if (tid == 0) {
                __threadfence();
                atomicAdd(&g_bar_ctr, 1u);
                unsigned target = (unsigned)(t + 1) * GRID_P;
                while (atomicAdd(&g_bar_ctr, 0u) < target) { }
            }
            __syncthreads();
        }
    }

    // Deterministic counter reset for graph replay
    __syncthreads();
    if (tid == 0) {
        unsigned d = atomicAdd(&g_done_ctr, 1u);
        if (d == GRID_P - 1) {
            g_bar_ctr = 0;
            g_done_ctr = 0;
            __threadfence();
        }
    }
}

// ---------------------------------------------------------------------------
// f32x2 SGEMM (tiny label MLP). OUT: 0 = fp32, 1 = hi/lo split out.
// ---------------------------------------------------------------------------
__device__ __forceinline__ void ffma2(unsigned long long& d,
                                      unsigned long long a,
                                      unsigned long long b) {
    asm("fma.rn.f32x2 %0, %1, %2, %0;" : "+l"(d) : "l"(a), "l"(b));
}
__device__ __forceinline__ unsigned long long pack2(float lo, float hi) {
    unsigned long long r;
    asm("mov.b64 %0, {%1, %2};" : "=l"(r) : "f"(lo), "f"(hi));
    return r;
}
__device__ __forceinline__ float2 unpack2(unsigned long long u) {
    float2 f;
    asm("mov.b64 {%0, %1}, %2;" : "=f"(f.x), "=f"(f.y) : "l"(u));
    return f;
}

template<int BM, int BN, int BK, int TM, int TN, int ACT, int OUT>
__global__ void gemm2_kernel(const float* __restrict__ A,
                             const float* __restrict__ W,
                             const float* __restrict__ bias,
                             float* __restrict__ C,
                             unsigned short* __restrict__ uh,
                             unsigned short* __restrict__ ul,
                             int M, int N, int K)
{
    constexpr int AS_STRIDE = BM + 4;
    constexpr int WS_STRIDE = BN + 4;
    __shared__ float As[BK][AS_STRIDE];
    __shared__ float Ws[BK][WS_STRIDE];

    constexpr int NTH = (BM / TM) * (BN / TN);
    const int tid = threadIdx.x;
    const int tx = tid % (BN / TN);
    const int ty = tid / (BN / TN);
    const int m0 = blockIdx.y * BM;
    const int n0 = blockIdx.x * BN;

    unsigned long long acc2[TM / 2][TN];
#pragma unroll
    for (int p = 0; p < TM / 2; p++)
#pragma unroll
        for (int j = 0; j < TN; j++) acc2[p][j] = 0ULL;

    for (int k0 = 0; k0 < K; k0 += BK) {
#pragma unroll
        for (int i = tid * 4; i < BM * BK; i += NTH * 4) {
            int m = i / BK, k = i % BK;
            float4 v = *(const float4*)(A + (long)(m0 + m) * K + (k0 + k));
            As[k + 0][m] = v.x; As[k + 1][m] = v.y;
            As[k + 2][m] = v.z; As[k + 3][m] = v.w;
        }
#pragma unroll
        for (int i = tid * 4; i < BN * BK; i += NTH * 4) {
            int n = i / BK, k = i % BK;
            float4 v = *(const float4*)(W + (long)(n0 + n) * K + (k0 + k));
            Ws[k + 0][n] = v.x; Ws[k + 1][n] = v.y;
            Ws[k + 2][n] = v.z; Ws[k + 3][n] = v.w;
        }
        __syncthreads();

#pragma unroll
        for (int k = 0; k < BK; k++) {
            unsigned long long am2[TM / 2];
            const ulonglong2* ap = reinterpret_cast<const ulonglong2*>(&As[k][ty * TM]);
#pragma unroll
            for (int q = 0; q < TM / 4; q++) {
                ulonglong2 tt = ap[q];
                am2[2 * q + 0] = tt.x;
                am2[2 * q + 1] = tt.y;
            }
            float4 w4 = *reinterpret_cast<const float4*>(&Ws[k][tx * TN]);
            unsigned long long wd[TN];
            wd[0] = pack2(w4.x, w4.x); wd[1] = pack2(w4.y, w4.y);
            wd[2] = pack2(w4.z, w4.z); wd[3] = pack2(w4.w, w4.w);
#pragma unroll
            for (int p = 0; p < TM / 2; p++)
#pragma unroll
                for (int j = 0; j < TN; j++) ffma2(acc2[p][j], am2[p], wd[j]);
        }
        __syncthreads();
    }

    float4 bv = make_float4(0.f, 0.f, 0.f, 0.f);
    if (bias) bv = *reinterpret_cast<const float4*>(bias + n0 + tx * TN);

#pragma unroll
    for (int p = 0; p < TM / 2; p++) {
        float2 v0 = unpack2(acc2[p][0]);
        float2 v1 = unpack2(acc2[p][1]);
        float2 v2 = unpack2(acc2[p][2]);
        float2 v3 = unpack2(acc2[p][3]);
        float4 rowA = make_float4(v0.x + bv.x, v1.x + bv.y, v2.x + bv.z, v3.x + bv.w);
        float4 rowB = make_float4(v0.y + bv.x, v1.y + bv.y, v2.y + bv.z, v3.y + bv.w);
        if (ACT == 1) {
            rowA.x = fmaxf(rowA.x, 0.f); rowA.y = fmaxf(rowA.y, 0.f);
            rowA.z = fmaxf(rowA.z, 0.f); rowA.w = fmaxf(rowA.w, 0.f);
            rowB.x = fmaxf(rowB.x, 0.f); rowB.y = fmaxf(rowB.y, 0.f);
            rowB.z = fmaxf(rowB.z, 0.f); rowB.w = fmaxf(rowB.w, 0.f);
        }
        int mA = m0 + ty * TM + 2 * p;
        int n  = n0 + tx * TN;
        if (OUT == 0) {
            *reinterpret_cast<float4*>(C + (long)mA * N + n) = rowA;
            *reinterpret_cast<float4*>(C + (long)(mA + 1) * N + n) = rowB;
        } else {
            unsigned a0 = packf(rowA.x), a1 = packf(rowA.y), a2 = packf(rowA.z), a3 = packf(rowA.w);
            unsigned b0 = packf(rowB.x), b1 = packf(rowB.y), b2 = packf(rowB.z), b3 = packf(rowB.w);
            *(ushort4*)(uh + (size_t)mA * N + n) = make_ushort4(a0 >> 16, a1 >> 16, a2 >> 16, a3 >> 16);
            *(ushort4*)(ul + (size_t)mA * N + n) = make_ushort4(a0 & 0xffff, a1 & 0xffff, a2 & 0xffff, a3 & 0xffff);
            *(ushort4*)(uh + (size_t)(mA + 1) * N + n) = make_ushort4(b0 >> 16, b1 >> 16, b2 >> 16, b3 >> 16);
            *(ushort4*)(ul + (size_t)(mA + 1) * N + n) = make_ushort4(b0 & 0xffff, b1 & 0xffff, b2 & 0xffff, b3 & 0xffff);
        }
    }
}

// ---------------------------------------------------------------------------
// Prep kernels
// ---------------------------------------------------------------------------
__device__ __forceinline__ void split4(const float4* src, int i,
                                       ushort4* hi, ushort4* lo) {
    float4 v = src[i];
    unsigned px = packf(v.x), py = packf(v.y), pz = packf(v.z), pw = packf(v.w);
    hi[i] = make_ushort4(px >> 16, py >> 16, pz >> 16, pw >> 16);
    lo[i] = make_ushort4(px & 0xffff, py & 0xffff, pz & 0xffff, pw & 0xffff);
}

__device__ __forceinline__ void permsplit4(const float* src, int i,
                                           ushort4* hi, ushort4* lo) {
    int r = i / (H_DIM / 4);
    int c = i % (H_DIM / 4);
    int j = r >> 2, gg = r & 3;
    float4 v = ((const float4*)src)[(size_t)(gg * H_DIM + j) * (H_DIM / 4) + c];
    unsigned px = packf(v.x), py = packf(v.y), pz = packf(v.z), pw = packf(v.w);
    size_t o = (size_t)r * (H_DIM / 4) + c;
    hi[o] = make_ushort4(px >> 16, py >> 16, pz >> 16, pw >> 16);
    lo[o] = make_ushort4(px & 0xffff, py & 0xffff, pz & 0xffff, pw & 0xffff);
}

// One fused kernel: P1/P2/P3 splits, Wih/Whh gate-perm splits, bias perm.
__global__ void prep_weights(const float* __restrict__ P1, const float* __restrict__ P2,
                             const float* __restrict__ P3,
                             const float* __restrict__ Wih, const float* __restrict__ Whh,
                             const float* __restrict__ bih, const float* __restrict__ bhh,
                             ushort4* P1h, ushort4* P1l, ushort4* P2h, ushort4* P2l,
                             ushort4* P3h, ushort4* P3l,
                             ushort4* Wihh, ushort4* Wihl, ushort4* Whhh, ushort4* Whhl,
                             float* bp)
{
    const int S0 = H_DIM * H_DIM / 4;           // 65536
    const int S1 = S0 + H_DIM * H_DIM / 4;      // 131072
    const int S2 = S1 + D_DIM * H_DIM / 4;      // 139264
    const int S3 = S2 + G_DIM * H_DIM / 4;      // 401408
    const int S4 = S3 + G_DIM * H_DIM / 4;      // 663552
    int i = blockIdx.x * blockDim.x + threadIdx.x;
    if      (i < S0) split4((const float4*)P1, i, P1h, P1l);
    else if (i < S1) split4((const float4*)P2, i - S0, P2h, P2l);
    else if (i < S2) split4((const float4*)P3, i - S1, P3h, P3l);
    else if (i < S3) permsplit4(Wih, i - S2, Wihh, Wihl);
    else if (i < S4) permsplit4(Whh, i - S3, Whhh, Whhl);
    else if (i < S4 + G_DIM) {
        int k = i - S4;
        int j = k >> 2, gg = k & 3;
        bp[k] = bih[gg * H_DIM + j] + bhh[gg * H_DIM + j];
    }
}

__global__ void split_kernel(const float4* __restrict__ src,
                             ushort4* __restrict__ hi,
                             ushort4* __restrict__ lo, int n4)
{
    int i = blockIdx.x * blockDim.x + threadIdx.x;
    if (i < n4) split4(src, i, hi, lo);
}

// ---------------------------------------------------------------------------
// Launch
// ---------------------------------------------------------------------------
extern "C" void kernel_launch(void* const* d_in, const int* in_sizes, int n_in,
                              void* d_out, int out_size)
{
    const float* labels = (const float*)d_in[0];
    const float* z      = (const float*)d_in[1];
    const float* W1     = (const float*)d_in[2];
    const float* b1     = (const float*)d_in[3];
    const float* W2     = (const float*)d_in[4];
    const float* b2     = (const float*)d_in[5];
    const float* W3     = (const float*)d_in[6];
    const float* Wih    = (const float*)d_in[7];
    const float* Whh    = (const float*)d_in[8];
    const float* bih    = (const float*)d_in[9];
    const float* bhh    = (const float*)d_in[10];
    const float* P1     = (const float*)d_in[11];
    const float* pb1    = (const float*)d_in[12];
    const float* P2     = (const float*)d_in[13];
    const float* pb2    = (const float*)d_in[14];
    const float* P3     = (const float*)d_in[15];
    const float* pb3    = (const float*)d_in[16];
    float* out = (float*)d_out;

    float *x1, *x2, *bperm, *CWB, *ZW;
    unsigned short *conds_h, *conds_l, *Wih_h, *Wih_l, *Whh_h, *Whh_l;
    unsigned short *P1_h, *P1_l, *P2_h, *P2_l, *P3_h, *P3_l;
    unsigned short *z_h, *z_l, *H_h, *H_l, *y1_h, *y1_l, *y2_h, *y2_l;
    cudaGetSymbolAddress((void**)&x1,     g_x1);
    cudaGetSymbolAddress((void**)&x2,     g_x2);
    cudaGetSymbolAddress((void**)&bperm,  g_bperm);
    cudaGetSymbolAddress((void**)&conds_h, g_conds_h);
    cudaGetSymbolAddress((void**)&conds_l, g_conds_l);
    cudaGetSymbolAddress((void**)&Wih_h,  g_Wih_h);
    cudaGetSymbolAddress((void**)&Wih_l,  g_Wih_l);
    cudaGetSymbolAddress((void**)&Whh_h,  g_Whh_h);
    cudaGetSymbolAddress((void**)&Whh_l,  g_Whh_l);
    cudaGetSymbolAddress((void**)&P1_h,   g_P1_h);
    cudaGetSymbolAddress((void**)&P1_l,   g_P1_l);
    cudaGetSymbolAddress((void**)&P2_h,   g_P2_h);
    cudaGetSymbolAddress((void**)&P2_l,   g_P2_l);
    cudaGetSymbolAddress((void**)&P3_h,   g_P3_h);
    cudaGetSymbolAddress((void**)&P3_l,   g_P3_l);
    cudaGetSymbolAddress((void**)&CWB,    g_CWB);
    cudaGetSymbolAddress((void**)&z_h,    g_z_h);
    cudaGetSymbolAddress((void**)&z_l,    g_z_l);
    cudaGetSymbolAddress((void**)&ZW,     g_ZW);
    cudaGetSymbolAddress((void**)&H_h,    g_H_h);
    cudaGetSymbolAddress((void**)&H_l,    g_H_l);
    cudaGetSymbolAddress((void**)&y1_h,   g_y1_h);
    cudaGetSymbolAddress((void**)&y1_l,   g_y1_l);
    cudaGetSymbolAddress((void**)&y2_h,   g_y2_h);
    cudaGetSymbolAddress((void**)&y2_l,   g_y2_l);

    const int TB = TB_DIM;

    // Dynamic smem: 2 stages x (2 A + 2 B tiles), STR = 72 ushorts/row
    constexpr int SM128 = 2 * (2 * 128 * 72 + 2 * 128 * 72) * 2;  // 147456 B
    constexpr int SM64  = 2 * (2 * 128 * 72 + 2 * 64 * 72) * 2;   // 110592 B
    cudaFuncSetAttribute((const void*)hgemm<128,128,64,32,0,0>,
                         cudaFuncAttributeMaxDynamicSharedMemorySize, SM128);
    cudaFuncSetAttribute((const void*)hgemm<128,128,64,32,1,0>,
                         cudaFuncAttributeMaxDynamicSharedMemorySize, SM128);
    cudaFuncSetAttribute((const void*)hgemm<128,128,64,32,2,1>,
                         cudaFuncAttributeMaxDynamicSharedMemorySize, SM128);
    cudaFuncSetAttribute((const void*)hgemm<128,64,64,16,3,0>,
                         cudaFuncAttributeMaxDynamicSharedMemorySize, SM64);
    cudaFuncSetAttribute((const void*)lstm_persistent,
                         cudaFuncAttributeMaxDynamicSharedMemorySize, SM128);

    // [0] fused weight prep
    {
        const int total = 2 * (H_DIM * H_DIM / 4) + D_DIM * H_DIM / 4
                        + 2 * (G_DIM * H_DIM / 4) + G_DIM;
        prep_weights<<<(total + 255) / 256, 256>>>(
            P1, P2, P3, Wih, Whh, bih, bhh,
            (ushort4*)P1_h, (ushort4*)P1_l, (ushort4*)P2_h, (ushort4*)P2_l,
            (ushort4*)P3_h, (ushort4*)P3_l,
            (ushort4*)Wih_h, (ushort4*)Wih_l, (ushort4*)Whh_h, (ushort4*)Whh_l,
            bperm);
    }
    // [1] z split
    split_kernel<<<(int)(((size_t)TB * H_DIM / 4) / 256), 256>>>(
        (const float4*)z, (ushort4*)z_h, (ushort4*)z_l, TB * (H_DIM / 4));

    // [2..4] Label MLP (f32x2); last layer writes conds hi/lo directly
    gemm2_kernel<128,128,16,8,4,1,0><<<dim3(H_DIM/128, B_DIM/128), 512>>>(
        labels, W1, b1, x1, nullptr, nullptr, B_DIM, H_DIM, L_DIM);
    gemm2_kernel<128,128,16,8,4,1,0><<<dim3(H_DIM/128, B_DIM/128), 512>>>(
        x1, W2, b2, x2, nullptr, nullptr, B_DIM, H_DIM, H_DIM);
    gemm2_kernel<128,128,16,8,4,0,1><<<dim3(H_DIM/128, B_DIM/128), 512>>>(
        x2, W3, nullptr, nullptr, conds_h, conds_l, B_DIM, H_DIM, H_DIM);

    // [5] CWB = conds @ Wih_perm^T + (bih+bhh)_perm   <- ncu profiles this one
    hgemm<128,128,64,32,0,0><<<dim3(G_DIM/128, B_DIM/128), 256, SM128>>>(
        conds_h, conds_l, Wih_h, Wih_l, bperm, nullptr,
        CWB, nullptr, nullptr, B_DIM, G_DIM, H_DIM);
    // [6] ZW = z @ Wih_perm^T + CWB[row % B]
    hgemm<128,128,64,32,1,0><<<dim3(G_DIM/128, TB/128), 256, SM128>>>(
        z_h, z_l, Wih_h, Wih_l, nullptr, CWB,
        ZW, nullptr, nullptr, TB, G_DIM, H_DIM);

    // [7] Persistent recurrence (one launch for all 128 steps)
    lstm_persistent<<<GRID_P, 256, SM128>>>(Whh_h, Whh_l, ZW, H_h, H_l);

    // [8..10] Projection MLP over all T*B rows
    hgemm<128,128,64,32,2,1><<<dim3(H_DIM/128, TB/128), 256, SM128>>>(
        H_h, H_l, P1_h, P1_l, pb1, nullptr,
        nullptr, y1_h, y1_l, TB, H_DIM, H_DIM);
    hgemm<128,128,64,32,2,1><<<dim3(H_DIM/128, TB/128), 256, SM128>>>(
        y1_h, y1_l, P2_h, P2_l, pb2, nullptr,
        nullptr, y2_h, y2_l, TB, H_DIM, H_DIM);
    hgemm<128,64,64,16,3,0><<<dim3(D_DIM/64, TB/128), 256, SM64>>>(
        y2_h, y2_l, P3_h, P3_l, pb3, nullptr,
        out, nullptr, nullptr, TB, D_DIM, H_DIM);
}

// round 8
// speedup vs baseline: 2.9218x; 1.0257x over previous
#include <cuda_runtime.h>
#include <cuda_bf16.h>
#include <math.h>
#include <stdint.h>

// Problem dims (fixed by the dataset)
#define B_DIM 1024
#define T_DIM 128
#define L_DIM 16
#define H_DIM 512
#define D_DIM 64
#define G_DIM 2048          // 4*H
#define TB_DIM (T_DIM * B_DIM)
#define GRID_P 128          // persistent recurrence grid (<= 148 SMs)

// ---------------------------------------------------------------------------
// Scratch (device globals). bf16 hi/lo pairs stored as separate ushort arrays.
// ---------------------------------------------------------------------------
__device__ float    g_x1[B_DIM * H_DIM];
__device__ float    g_x2[B_DIM * H_DIM];
__device__ float    g_bperm[G_DIM];
__device__ unsigned short g_conds_h[B_DIM * H_DIM];
__device__ unsigned short g_conds_l[B_DIM * H_DIM];
__device__ unsigned short g_Wih_h[G_DIM * H_DIM];
__device__ unsigned short g_Wih_l[G_DIM * H_DIM];
__device__ unsigned short g_Whh_h[G_DIM * H_DIM];
__device__ unsigned short g_Whh_l[G_DIM * H_DIM];
__device__ unsigned short g_P1_h[H_DIM * H_DIM];
__device__ unsigned short g_P1_l[H_DIM * H_DIM];
__device__ unsigned short g_P2_h[H_DIM * H_DIM];
__device__ unsigned short g_P2_l[H_DIM * H_DIM];
__device__ unsigned short g_P3_h[D_DIM * H_DIM];
__device__ unsigned short g_P3_l[D_DIM * H_DIM];
__device__ float    g_CWB[B_DIM * G_DIM];
__device__ unsigned short g_z_h[(size_t)TB_DIM * H_DIM];
__device__ unsigned short g_z_l[(size_t)TB_DIM * H_DIM];
__device__ float    g_ZW[(size_t)TB_DIM * G_DIM];          // 1 GB
__device__ unsigned short g_H_h[(size_t)TB_DIM * H_DIM];
__device__ unsigned short g_H_l[(size_t)TB_DIM * H_DIM];
__device__ unsigned short g_y1_h[(size_t)TB_DIM * H_DIM];
__device__ unsigned short g_y1_l[(size_t)TB_DIM * H_DIM];
__device__ unsigned short g_y2_h[(size_t)TB_DIM * H_DIM];
__device__ unsigned short g_y2_l[(size_t)TB_DIM * H_DIM];

// Persistent-kernel grid barrier (monotonic; self-reset at kernel end)
__device__ unsigned g_bar_ctr  = 0;
__device__ unsigned g_done_ctr = 0;

// ---------------------------------------------------------------------------
// Helpers
// ---------------------------------------------------------------------------
__device__ __forceinline__ unsigned packf(float x) {
    __nv_bfloat16 h = __float2bfloat16(x);
    float r = x - __bfloat162float(h);
    __nv_bfloat16 l = __float2bfloat16(r);
    return ((unsigned)__bfloat16_as_ushort(h) << 16) |
            (unsigned)__bfloat16_as_ushort(l);
}

__device__ __forceinline__ void mma16816(float& c0, float& c1, float& c2, float& c3,
                                         unsigned a0, unsigned a1, unsigned a2, unsigned a3,
                                         unsigned b0, unsigned b1) {
    asm volatile(
        "mma.sync.aligned.m16n8k16.row.col.f32.bf16.bf16.f32 "
        "{%0,%1,%2,%3}, {%4,%5,%6,%7}, {%8,%9}, {%0,%1,%2,%3};\n"
        : "+f"(c0), "+f"(c1), "+f"(c2), "+f"(c3)
        : "r"(a0), "r"(a1), "r"(a2), "r"(a3), "r"(b0), "r"(b1));
}

__device__ __forceinline__ void ldsm4(unsigned& r0, unsigned& r1,
                                      unsigned& r2, unsigned& r3, uint32_t a) {
    asm volatile("ldmatrix.sync.aligned.m8n8.x4.shared.b16 {%0,%1,%2,%3}, [%4];"
                 : "=r"(r0), "=r"(r1), "=r"(r2), "=r"(r3) : "r"(a));
}

__device__ __forceinline__ void cp_async16(void* sptr, const void* gptr) {
    unsigned sa = (unsigned)__cvta_generic_to_shared(sptr);
    asm volatile("cp.async.cg.shared.global [%0], [%1], 16;\n" :: "r"(sa), "l"(gptr));
}
__device__ __forceinline__ void cp_commit() {
    asm volatile("cp.async.commit_group;\n");
}
template<int N>
__device__ __forceinline__ void cp_wait() {
    asm volatile("cp.async.wait_group %0;\n" :: "n"(N));
}

// ---------------------------------------------------------------------------
// HMMA 3xbf16 GEMM, hi/lo operands, BK=64 2-stage cp.async pipeline,
// ldmatrix fragment loads. D = Ah*Bh + Ah*Bl + Al*Bh (fp32 acc).
// smem rows STR=72 ushorts (144B): ldmatrix 8-row phases hit all 32 banks.
// EPI: 0 = fp32 + bias (CWB)
//      1 = fp32 + addvec[row % B] (ZW build, CWB fold)
//      2 = hi/lo out + bias (+relu if ACT)   (P1, P2)
//      3 = fp32 + bias, [T,B]->[B,T] perm    (P3)
// ---------------------------------------------------------------------------
template<int BM, int BN, int WM, int WN, int EPI, int ACT>
__global__ void __launch_bounds__((BM / WM) * (BN / WN) * 32)
hgemm(const unsigned short* __restrict__ Ah, const unsigned short* __restrict__ Al,
      const unsigned short* __restrict__ Bh, const unsigned short* __restrict__ Bl,
      const float* __restrict__ bias,
      const float* __restrict__ addvec,
      float* __restrict__ outf,
      unsigned short* __restrict__ out_hi,
      unsigned short* __restrict__ out_lo,
      int M, int N, int K)
{
    constexpr int BK = 64;
    constexpr int STR = BK + 8;
    constexpr int ATI = BM * STR;
    constexpr int BTI = BN * STR;
    constexpr int STAGE = 2 * ATI + 2 * BTI;
    constexpr int WARPS_N = BN / WN;
    constexpr int NTH = (BM / WM) * (BN / WN) * 32;
    constexpr int MI = WM / 16, NI = WN / 8;

    extern __shared__ unsigned short sm[];

    const int tid  = threadIdx.x;
    const int warp = tid >> 5, lane = tid & 31;
    const int g = lane >> 2, t = lane & 3;
    const int wm0 = (warp / WARPS_N) * WM;
    const int wn0 = (warp % WARPS_N) * WN;
    const int m0 = blockIdx.y * BM;
    const int n0 = blockIdx.x * BN;

    // ldmatrix per-lane address components (byte offsets)
    const uint32_t smb = (uint32_t)__cvta_generic_to_shared(sm);
    const int aRow = (lane & 7) + ((lane >> 3) & 1) * 8;   // row within 16-block
    const int aKh  = (lane >> 4) * 16;                     // k-half byte offset
    const int bRow = (lane & 7) + (lane >> 4) * 8;         // row within 16-block
    const int bKh  = ((lane >> 3) & 1) * 16;
    const uint32_t aBase = smb + (uint32_t)(wm0 + aRow) * STR * 2 + aKh;
    const uint32_t bBase = smb + (uint32_t)(2 * ATI + (wn0 + bRow) * STR) * 2 + bKh;

    float acc[MI][NI][4];
#pragma unroll
    for (int mi = 0; mi < MI; mi++)
#pragma unroll
        for (int ni = 0; ni < NI; ni++)
#pragma unroll
            for (int q = 0; q < 4; q++) acc[mi][ni][q] = 0.f;

    auto load_stage = [&](int k0, int s) {
        unsigned short* st = sm + s * STAGE;
#pragma unroll
        for (int i = tid; i < BM * 8; i += NTH) {
            int r = i >> 3, c = i & 7;
            const size_t gs = (size_t)(m0 + r) * K + k0 + c * 8;
            cp_async16(st + r * STR + c * 8,       Ah + gs);
            cp_async16(st + ATI + r * STR + c * 8, Al + gs);
        }
#pragma unroll
        for (int i = tid; i < BN * 8; i += NTH) {
            int r = i >> 3, c = i & 7;
            const size_t gs = (size_t)(n0 + r) * K + k0 + c * 8;
            cp_async16(st + 2 * ATI + r * STR + c * 8,       Bh + gs);
            cp_async16(st + 2 * ATI + BTI + r * STR + c * 8, Bl + gs);
        }
        cp_commit();
    };

    const int KT = K / BK;
    load_stage(0, 0);

    for (int kt = 0; kt < KT; kt++) {
        const int s = kt & 1;
        if (kt + 1 < KT) { load_stage((kt + 1) * BK, s ^ 1); cp_wait<1>(); }
        else             { cp_wait<0>(); }
        __syncthreads();

        const uint32_t stOff = (uint32_t)(s * STAGE) * 2;
        const uint32_t aH = aBase + stOff;
        const uint32_t aL = aH + (uint32_t)ATI * 2;
        const uint32_t bH = bBase + stOff;
        const uint32_t bL = bH + (uint32_t)BTI * 2;

#pragma unroll
        for (int kk = 0; kk < BK; kk += 16) {
            unsigned ah[MI][4], al[MI][4], bh[NI][2], bl[NI][2];
#pragma unroll
            for (int mi = 0; mi < MI; mi++) {
                ldsm4(ah[mi][0], ah[mi][1], ah[mi][2], ah[mi][3],
                      aH + (uint32_t)(mi * 16 * STR + kk) * 2);
                ldsm4(al[mi][0], al[mi][1], al[mi][2], al[mi][3],
                      aL + (uint32_t)(mi * 16 * STR + kk) * 2);
            }
#pragma unroll
            for (int p = 0; p < NI / 2; p++) {
                ldsm4(bh[2*p][0], bh[2*p][1], bh[2*p+1][0], bh[2*p+1][1],
                      bH + (uint32_t)(p * 16 * STR + kk) * 2);
                ldsm4(bl[2*p][0], bl[2*p][1], bl[2*p+1][0], bl[2*p+1][1],
                      bL + (uint32_t)(p * 16 * STR + kk) * 2);
            }
#pragma unroll
            for (int mi = 0; mi < MI; mi++)
#pragma unroll
                for (int ni = 0; ni < NI; ni++) {
                    mma16816(acc[mi][ni][0], acc[mi][ni][1], acc[mi][ni][2], acc[mi][ni][3],
                             ah[mi][0], ah[mi][1], ah[mi][2], ah[mi][3], bh[ni][0], bh[ni][1]);
                    mma16816(acc[mi][ni][0], acc[mi][ni][1], acc[mi][ni][2], acc[mi][ni][3],
                             ah[mi][0], ah[mi][1], ah[mi][2], ah[mi][3], bl[ni][0], bl[ni][1]);
                    mma16816(acc[mi][ni][0], acc[mi][ni][1], acc[mi][ni][2], acc[mi][ni][3],
                             al[mi][0], al[mi][1], al[mi][2], al[mi][3], bh[ni][0], bh[ni][1]);
                }
        }
        __syncthreads();
    }

    // ---- Epilogues ----
    if (EPI == 0 || EPI == 2 || EPI == 3) {
        float2 bv[NI];
#pragma unroll
        for (int ni = 0; ni < NI; ni++)
            bv[ni] = *(const float2*)(bias + n0 + wn0 + ni * 8 + 2 * t);

#pragma unroll
        for (int mi = 0; mi < MI; mi++) {
            int row0 = m0 + wm0 + mi * 16 + g;
#pragma unroll
            for (int ni = 0; ni < NI; ni++) {
                int col = n0 + wn0 + ni * 8 + 2 * t;
                float v0 = acc[mi][ni][0] + bv[ni].x;
                float v1 = acc[mi][ni][1] + bv[ni].y;
                float v2 = acc[mi][ni][2] + bv[ni].x;
                float v3 = acc[mi][ni][3] + bv[ni].y;
                if (ACT == 1) {
                    v0 = fmaxf(v0, 0.f); v1 = fmaxf(v1, 0.f);
                    v2 = fmaxf(v2, 0.f); v3 = fmaxf(v3, 0.f);
                }
                if (EPI == 0) {
                    *(float2*)(outf + (size_t)row0 * N + col)       = make_float2(v0, v1);
                    *(float2*)(outf + (size_t)(row0 + 8) * N + col) = make_float2(v2, v3);
                } else if (EPI == 2) {
                    unsigned p0 = packf(v0), p1 = packf(v1), p2 = packf(v2), p3 = packf(v3);
                    *(ushort2*)(out_hi + (size_t)row0 * N + col) =
                        make_ushort2(p0 >> 16, p1 >> 16);
                    *(ushort2*)(out_lo + (size_t)row0 * N + col) =
                        make_ushort2(p0 & 0xffff, p1 & 0xffff);
                    *(ushort2*)(out_hi + (size_t)(row0 + 8) * N + col) =
                        make_ushort2(p2 >> 16, p3 >> 16);
                    *(ushort2*)(out_lo + (size_t)(row0 + 8) * N + col) =
                        make_ushort2(p2 & 0xffff, p3 & 0xffff);
                } else {
                    int tt0 = row0 / B_DIM, bb0 = row0 % B_DIM;
                    int r1 = row0 + 8;
                    int tt1 = r1 / B_DIM, bb1 = r1 % B_DIM;
                    *(float2*)(outf + ((size_t)bb0 * T_DIM + tt0) * D_DIM + col) = make_float2(v0, v1);
                    *(float2*)(outf + ((size_t)bb1 * T_DIM + tt1) * D_DIM + col) = make_float2(v2, v3);
                }
            }
        }
    } else {
        // EPI == 1
#pragma unroll
        for (int mi = 0; mi < MI; mi++) {
            int row0 = m0 + wm0 + mi * 16 + g;
#pragma unroll
            for (int ni = 0; ni < NI; ni++) {
                int col = n0 + wn0 + ni * 8 + 2 * t;
                float2 a0 = *(const float2*)(addvec + (size_t)(row0 & (B_DIM - 1)) * N + col);
                float2 a1 = *(const float2*)(addvec + (size_t)((row0 + 8) & (B_DIM - 1)) * N + col);
                *(float2*)(outf + (size_t)row0 * N + col) =
                    make_float2(acc[mi][ni][0] + a0.x, acc[mi][ni][1] + a0.y);
                *(float2*)(outf + (size_t)(row0 + 8) * N + col) =
                    make_float2(acc[mi][ni][2] + a1.x, acc[mi][ni][3] + a1.y);
            }
        }
    }
}

// ---------------------------------------------------------------------------
// Persistent LSTM recurrence: all T steps in one launch, grid = 128 CTAs.
// c-state in registers; ldmatrix fragment loads; grid barrier between steps.
// ---------------------------------------------------------------------------
__global__ void __launch_bounds__(256)
lstm_persistent(const unsigned short* __restrict__ Whh_h,
                const unsigned short* __restrict__ Whh_l,
                const float* __restrict__ ZW,        // [T][B][G] (perm cols)
                unsigned short* __restrict__ H_h,
                unsigned short* __restrict__ H_l)
{
    constexpr int BM = 128, BN = 128, BK = 64, WM = 64, WN = 32;
    constexpr int STR = BK + 8;
    constexpr int ATI = BM * STR, BTI = BN * STR;
    constexpr int STAGE = 2 * ATI + 2 * BTI;
    constexpr int WARPS_N = BN / WN;
    constexpr int NTH = 256;
    constexpr int MI = WM / 16, NI = WN / 8;
    constexpr int K = H_DIM, N = G_DIM;
    constexpr int KT = K / BK;

    extern __shared__ unsigned short sm[];

    const int tid  = threadIdx.x;
    const int warp = tid >> 5, lane = tid & 31;
    const int g = lane >> 2, t4 = lane & 3;
    const int wm0 = (warp / WARPS_N) * WM;
    const int wn0 = (warp % WARPS_N) * WN;
    const int bid = blockIdx.x;
    const int m0 = (bid >> 4) * BM;
    const int n0 = (bid & 15) * BN;

    const uint32_t smb = (uint32_t)__cvta_generic_to_shared(sm);
    const int aRow = (lane & 7) + ((lane >> 3) & 1) * 8;
    const int aKh  = (lane >> 4) * 16;
    const int bRow = (lane & 7) + (lane >> 4) * 8;
    const int bKh  = ((lane >> 3) & 1) * 16;
    const uint32_t aBase = smb + (uint32_t)(wm0 + aRow) * STR * 2 + aKh;
    const uint32_t bBase = smb + (uint32_t)(2 * ATI + (wn0 + bRow) * STR) * 2 + bKh;

    const bool hi_half = (t4 & 1);

    float creg[MI][NI];
#pragma unroll
    for (int mi = 0; mi < MI; mi++)
#pragma unroll
        for (int ni = 0; ni < NI; ni++) creg[mi][ni] = 0.f;

    for (int t = 0; t < T_DIM; t++) {
        float acc[MI][NI][4];
#pragma unroll
        for (int mi = 0; mi < MI; mi++)
#pragma unroll
            for (int ni = 0; ni < NI; ni++)
#pragma unroll
                for (int q = 0; q < 4; q++) acc[mi][ni][q] = 0.f;

        if (t > 0) {
            const unsigned short* Ah = H_h + (size_t)(t - 1) * B_DIM * H_DIM;
            const unsigned short* Al = H_l + (size_t)(t - 1) * B_DIM * H_DIM;

            auto load_stage = [&](int k0, int s) {
                unsigned short* st = sm + s * STAGE;
#pragma unroll
                for (int i = tid; i < BM * 8; i += NTH) {
                    int r = i >> 3, c = i & 7;
                    const size_t gs = (size_t)(m0 + r) * K + k0 + c * 8;
                    cp_async16(st + r * STR + c * 8,       Ah + gs);
                    cp_async16(st + ATI + r * STR + c * 8, Al + gs);
                }
#pragma unroll
                for (int i = tid; i < BN * 8; i += NTH) {
                    int r = i >> 3, c = i & 7;
                    const size_t gs = (size_t)(n0 + r) * K + k0 + c * 8;
                    cp_async16(st + 2 * ATI + r * STR + c * 8,       Whh_h + gs);
                    cp_async16(st + 2 * ATI + BTI + r * STR + c * 8, Whh_l + gs);
                }
                cp_commit();
            };

            load_stage(0, 0);
            for (int kt = 0; kt < KT; kt++) {
                const int s = kt & 1;
                if (kt + 1 < KT) { load_stage((kt + 1) * BK, s ^ 1); cp_wait<1>(); }
                else             { cp_wait<0>(); }
                __syncthreads();

                const uint32_t stOff = (uint32_t)(s * STAGE) * 2;
                const uint32_t aH = aBase + stOff;
                const uint32_t aL = aH + (uint32_t)ATI * 2;
                const uint32_t bH = bBase + stOff;
                const uint32_t bL = bH + (uint32_t)BTI * 2;

#pragma unroll
                for (int kk = 0; kk < BK; kk += 16) {
                    unsigned ah[MI][4], al[MI][4], bh[NI][2], bl[NI][2];
#pragma unroll
                    for (int mi = 0; mi < MI; mi++) {
                        ldsm4(ah[mi][0], ah[mi][1], ah[mi][2], ah[mi][3],
                              aH + (uint32_t)(mi * 16 * STR + kk) * 2);
                        ldsm4(al[mi][0], al[mi][1], al[mi][2], al[mi][3],
                              aL + (uint32_t)(mi * 16 * STR + kk) * 2);
                    }
#pragma unroll
                    for (int p = 0; p < NI / 2; p++) {
                        ldsm4(bh[2*p][0], bh[2*p][1], bh[2*p+1][0], bh[2*p+1][1],
                              bH + (uint32_t)(p * 16 * STR + kk) * 2);
                        ldsm4(bl[2*p][0], bl[2*p][1], bl[2*p+1][0], bl[2*p+1][1],
                              bL + (uint32_t)(p * 16 * STR + kk) * 2);
                    }
#pragma unroll
                    for (int mi = 0; mi < MI; mi++)
#pragma unroll
                        for (int ni = 0; ni < NI; ni++) {
                            mma16816(acc[mi][ni][0], acc[mi][ni][1], acc[mi][ni][2], acc[mi][ni][3],
                                     ah[mi][0], ah[mi][1], ah[mi][2], ah[mi][3], bh[ni][0], bh[ni][1]);
                            mma16816(acc[mi][ni][0], acc[mi][ni][1], acc[mi][ni][2], acc[mi][ni][3],
                                     ah[mi][0], ah[mi][1], ah[mi][2], ah[mi][3], bl[ni][0], bl[ni][1]);
                            mma16816(acc[mi][ni][0], acc[mi][ni][1], acc[mi][ni][2], acc[mi][ni][3],
                                     al[mi][0], al[mi][1], al[mi][2], al[mi][3], bh[ni][0], bh[ni][1]);
                        }
                }
                __syncthreads();
            }
        }

        // ---- Cell epilogue (c in registers) ----
        const float* zwb = ZW + (size_t)t * B_DIM * G_DIM;
        unsigned short* hh = H_h + (size_t)t * B_DIM * H_DIM;
        unsigned short* hl = H_l + (size_t)t * B_DIM * H_DIM;
#pragma unroll
        for (int mi = 0; mi < MI; mi++) {
            int row0 = m0 + wm0 + mi * 16 + g;
#pragma unroll
            for (int ni = 0; ni < NI; ni++) {
                int col = n0 + wn0 + ni * 8 + 2 * t4;
                float c0 = acc[mi][ni][0], c1 = acc[mi][ni][1];
                float c2 = acc[mi][ni][2], c3 = acc[mi][ni][3];
                float sx = __shfl_xor_sync(0xffffffffu, hi_half ? c0 : c2, 1);
                float sy = __shfl_xor_sync(0xffffffffu, hi_half ? c1 : c3, 1);
                int row = hi_half ? row0 + 8 : row0;
                float gi, gf, gg, go;
                if (!hi_half) { gi = c0; gf = c1; gg = sx; go = sy; }
                else          { gi = sx; gf = sy; gg = c2; go = c3; }

                int base = col & ~3;
                float4 zw = *(const float4*)(zwb + (size_t)row * G_DIM + base);
                gi += zw.x; gf += zw.y; gg += zw.z; go += zw.w;

                float ig = 1.f / (1.f + expf(-gi));
                float fg = 1.f / (1.f + expf(-gf));
                float gt = tanhf(gg);
                float og = 1.f / (1.f + expf(-go));

                float cn = fg * creg[mi][ni] + ig * gt;
                creg[mi][ni] = cn;
                unsigned p = packf(og * tanhf(cn));
                size_t hidx = (size_t)row * H_DIM + (col >> 2);
                hh[hidx] = (unsigned short)(p >> 16);
                hl[hidx] = (unsigned short)(p & 0xffffu);
            }
        }

        // ---- Grid barrier between steps ----
        if (t < T_DIM - 1) {
            __syncthreads();
            if (tid == 0) {
                __threadfence();
                atomicAdd(&g_bar_ctr, 1u);
                unsigned target = (unsigned)(t + 1) * GRID_P;
                while (atomicAdd(&g_bar_ctr, 0u) < target) { }
            }
            __syncthreads();
        }
    }

    // Deterministic counter reset for graph replay
    __syncthreads();
    if (tid == 0) {
        unsigned d = atomicAdd(&g_done_ctr, 1u);
        if (d == GRID_P - 1) {
            g_bar_ctr = 0;
            g_done_ctr = 0;
            __threadfence();
        }
    }
}

// ---------------------------------------------------------------------------
// f32x2 SGEMM (label MLP), 64x64 tiles -> 128 CTAs. OUT: 0 fp32, 1 hi/lo.
// ---------------------------------------------------------------------------
__device__ __forceinline__ void ffma2(unsigned long long& d,
                                      unsigned long long a,
                                      unsigned long long b) {
    asm("fma.rn.f32x2 %0, %1, %2, %0;" : "+l"(d) : "l"(a), "l"(b));
}
__device__ __forceinline__ unsigned long long pack2(float lo, float hi) {
    unsigned long long r;
    asm("mov.b64 %0, {%1, %2};" : "=l"(r) : "f"(lo), "f"(hi));
    return r;
}
__device__ __forceinline__ float2 unpack2(unsigned long long u) {
    float2 f;
    asm("mov.b64 {%0, %1}, %2;" : "=f"(f.x), "=f"(f.y) : "l"(u));
    return f;
}

template<int BM, int BN, int BK, int TM, int TN, int ACT, int OUT>
__global__ void gemm2_kernel(const float* __restrict__ A,
                             const float* __restrict__ W,
                             const float* __restrict__ bias,
                             float* __restrict__ C,
                             unsigned short* __restrict__ uh,
                             unsigned short* __restrict__ ul,
                             int M, int N, int K)
{
    constexpr int AS_STRIDE = BM + 4;
    constexpr int WS_STRIDE = BN + 4;
    __shared__ float As[BK][AS_STRIDE];
    __shared__ float Ws[BK][WS_STRIDE];

    constexpr int NTH = (BM / TM) * (BN / TN);
    const int tid = threadIdx.x;
    const int tx = tid % (BN / TN);
    const int ty = tid / (BN / TN);
    const int m0 = blockIdx.y * BM;
    const int n0 = blockIdx.x * BN;

    unsigned long long acc2[TM / 2][TN];
#pragma unroll
    for (int p = 0; p < TM / 2; p++)
#pragma unroll
        for (int j = 0; j < TN; j++) acc2[p][j] = 0ULL;

    for (int k0 = 0; k0 < K; k0 += BK) {
#pragma unroll
        for (int i = tid * 4; i < BM * BK; i += NTH * 4) {
            int m = i / BK, k = i % BK;
            float4 v = *(const float4*)(A + (long)(m0 + m) * K + (k0 + k));
            As[k + 0][m] = v.x; As[k + 1][m] = v.y;
            As[k + 2][m] = v.z; As[k + 3][m] = v.w;
        }
#pragma unroll
        for (int i = tid * 4; i < BN * BK; i += NTH * 4) {
            int n = i / BK, k = i % BK;
            float4 v = *(const float4*)(W + (long)(n0 + n) * K + (k0 + k));
            Ws[k + 0][n] = v.x; Ws[k + 1][n] = v.y;
            Ws[k + 2][n] = v.z; Ws[k + 3][n] = v.w;
        }
        __syncthreads();

#pragma unroll
        for (int k = 0; k < BK; k++) {
            unsigned long long am2[TM / 2];
            const ulonglong2* ap = reinterpret_cast<const ulonglong2*>(&As[k][ty * TM]);
#pragma unroll
            for (int q = 0; q < TM / 4; q++) {
                ulonglong2 tt = ap[q];
                am2[2 * q + 0] = tt.x;
                am2[2 * q + 1] = tt.y;
            }
            float4 w4 = *reinterpret_cast<const float4*>(&Ws[k][tx * TN]);
            unsigned long long wd[TN];
            wd[0] = pack2(w4.x, w4.x); wd[1] = pack2(w4.y, w4.y);
            wd[2] = pack2(w4.z, w4.z); wd[3] = pack2(w4.w, w4.w);
#pragma unroll
            for (int p = 0; p < TM / 2; p++)
#pragma unroll
                for (int j = 0; j < TN; j++) ffma2(acc2[p][j], am2[p], wd[j]);
        }
        __syncthreads();
    }

    float4 bv = make_float4(0.f, 0.f, 0.f, 0.f);
    if (bias) bv = *reinterpret_cast<const float4*>(bias + n0 + tx * TN);

#pragma unroll
    for (int p = 0; p < TM / 2; p++) {
        float2 v0 = unpack2(acc2[p][0]);
        float2 v1 = unpack2(acc2[p][1]);
        float2 v2 = unpack2(acc2[p][2]);
        float2 v3 = unpack2(acc2[p][3]);
        float4 rowA = make_float4(v0.x + bv.x, v1.x + bv.y, v2.x + bv.z, v3.x + bv.w);
        float4 rowB = make_float4(v0.y + bv.x, v1.y + bv.y, v2.y + bv.z, v3.y + bv.w);
        if (ACT == 1) {
            rowA.x = fmaxf(rowA.x, 0.f); rowA.y = fmaxf(rowA.y, 0.f);
            rowA.z = fmaxf(rowA.z, 0.f); rowA.w = fmaxf(rowA.w, 0.f);
            rowB.x = fmaxf(rowB.x, 0.f); rowB.y = fmaxf(rowB.y, 0.f);
            rowB.z = fmaxf(rowB.z, 0.f); rowB.w = fmaxf(rowB.w, 0.f);
        }
        int mA = m0 + ty * TM + 2 * p;
        int n  = n0 + tx * TN;
        if (OUT == 0) {
            *reinterpret_cast<float4*>(C + (long)mA * N + n) = rowA;
            *reinterpret_cast<float4*>(C + (long)(mA + 1) * N + n) = rowB;
        } else {
            unsigned a0 = packf(rowA.x), a1 = packf(rowA.y), a2 = packf(rowA.z), a3 = packf(rowA.w);
            unsigned b0 = packf(rowB.x), b1 = packf(rowB.y), b2 = packf(rowB.z), b3 = packf(rowB.w);
            *(ushort4*)(uh + (size_t)mA * N + n) = make_ushort4(a0 >> 16, a1 >> 16, a2 >> 16, a3 >> 16);
            *(ushort4*)(ul + (size_t)mA * N + n) = make_ushort4(a0 & 0xffff, a1 & 0xffff, a2 & 0xffff, a3 & 0xffff);
            *(ushort4*)(uh + (size_t)(mA + 1) * N + n) = make_ushort4(b0 >> 16, b1 >> 16, b2 >> 16, b3 >> 16);
            *(ushort4*)(ul + (size_t)(mA + 1) * N + n) = make_ushort4(b0 & 0xffff, b1 & 0xffff, b2 & 0xffff, b3 & 0xffff);
        }
    }
}

// ---------------------------------------------------------------------------
// Prep kernels
// ---------------------------------------------------------------------------
__device__ __forceinline__ void split4(const float4* src, int i,
                                       ushort4* hi, ushort4* lo) {
    float4 v = src[i];
    unsigned px = packf(v.x), py = packf(v.y), pz = packf(v.z), pw = packf(v.w);
    hi[i] = make_ushort4(px >> 16, py >> 16, pz >> 16, pw >> 16);
    lo[i] = make_ushort4(px & 0xffff, py & 0xffff, pz & 0xffff, pw & 0xffff);
}

__device__ __forceinline__ void permsplit4(const float* src, int i,
                                           ushort4* hi, ushort4* lo) {
    int r = i / (H_DIM / 4);
    int c = i % (H_DIM / 4);
    int j = r >> 2, gg = r & 3;
    float4 v = ((const float4*)src)[(size_t)(gg * H_DIM + j) * (H_DIM / 4) + c];
    unsigned px = packf(v.x), py = packf(v.y), pz = packf(v.z), pw = packf(v.w);
    size_t o = (size_t)r * (H_DIM / 4) + c;
    hi[o] = make_ushort4(px >> 16, py >> 16, pz >> 16, pw >> 16);
    lo[o] = make_ushort4(px & 0xffff, py & 0xffff, pz & 0xffff, pw & 0xffff);
}

__global__ void prep_weights(const float* __restrict__ P1, const float* __restrict__ P2,
                             const float* __restrict__ P3,
                             const float* __restrict__ Wih, const float* __restrict__ Whh,
                             const float* __restrict__ bih, const float* __restrict__ bhh,
                             ushort4* P1h, ushort4* P1l, ushort4* P2h, ushort4* P2l,
                             ushort4* P3h, ushort4* P3l,
                             ushort4* Wihh, ushort4* Wihl, ushort4* Whhh, ushort4* Whhl,
                             float* bp)
{
    const int S0 = H_DIM * H_DIM / 4;
    const int S1 = S0 + H_DIM * H_DIM / 4;
    const int S2 = S1 + D_DIM * H_DIM / 4;
    const int S3 = S2 + G_DIM * H_DIM / 4;
    const int S4 = S3 + G_DIM * H_DIM / 4;
    int i = blockIdx.x * blockDim.x + threadIdx.x;
    if      (i < S0) split4((const float4*)P1, i, P1h, P1l);
    else if (i < S1) split4((const float4*)P2, i - S0, P2h, P2l);
    else if (i < S2) split4((const float4*)P3, i - S1, P3h, P3l);
    else if (i < S3) permsplit4(Wih, i - S2, Wihh, Wihl);
    else if (i < S4) permsplit4(Whh, i - S3, Whhh, Whhl);
    else if (i < S4 + G_DIM) {
        int k = i - S4;
        int j = k >> 2, gg = k & 3;
        bp[k] = bih[gg * H_DIM + j] + bhh[gg * H_DIM + j];
    }
}

__global__ void split_kernel(const float4* __restrict__ src,
                             ushort4* __restrict__ hi,
                             ushort4* __restrict__ lo, int n4)
{
    int i = blockIdx.x * blockDim.x + threadIdx.x;
    if (i < n4) split4(src, i, hi, lo);
}

// ---------------------------------------------------------------------------
// Launch
// ---------------------------------------------------------------------------
extern "C" void kernel_launch(void* const* d_in, const int* in_sizes, int n_in,
                              void* d_out, int out_size)
{
    const float* labels = (const float*)d_in[0];
    const float* z      = (const float*)d_in[1];
    const float* W1     = (const float*)d_in[2];
    const float* b1     = (const float*)d_in[3];
    const float* W2     = (const float*)d_in[4];
    const float* b2     = (const float*)d_in[5];
    const float* W3     = (const float*)d_in[6];
    const float* Wih    = (const float*)d_in[7];
    const float* Whh    = (const float*)d_in[8];
    const float* bih    = (const float*)d_in[9];
    const float* bhh    = (const float*)d_in[10];
    const float* P1     = (const float*)d_in[11];
    const float* pb1    = (const float*)d_in[12];
    const float* P2     = (const float*)d_in[13];
    const float* pb2    = (const float*)d_in[14];
    const float* P3     = (const float*)d_in[15];
    const float* pb3    = (const float*)d_in[16];
    float* out = (float*)d_out;

    float *x1, *x2, *bperm, *CWB, *ZW;
    unsigned short *conds_h, *conds_l, *Wih_h, *Wih_l, *Whh_h, *Whh_l;
    unsigned short *P1_h, *P1_l, *P2_h, *P2_l, *P3_h, *P3_l;
    unsigned short *z_h, *z_l, *H_h, *H_l, *y1_h, *y1_l, *y2_h, *y2_l;
    cudaGetSymbolAddress((void**)&x1,     g_x1);
    cudaGetSymbolAddress((void**)&x2,     g_x2);
    cudaGetSymbolAddress((void**)&bperm,  g_bperm);
    cudaGetSymbolAddress((void**)&conds_h, g_conds_h);
    cudaGetSymbolAddress((void**)&conds_l, g_conds_l);
    cudaGetSymbolAddress((void**)&Wih_h,  g_Wih_h);
    cudaGetSymbolAddress((void**)&Wih_l,  g_Wih_l);
    cudaGetSymbolAddress((void**)&Whh_h,  g_Whh_h);
    cudaGetSymbolAddress((void**)&Whh_l,  g_Whh_l);
    cudaGetSymbolAddress((void**)&P1_h,   g_P1_h);
    cudaGetSymbolAddress((void**)&P1_l,   g_P1_l);
    cudaGetSymbolAddress((void**)&P2_h,   g_P2_h);
    cudaGetSymbolAddress((void**)&P2_l,   g_P2_l);
    cudaGetSymbolAddress((void**)&P3_h,   g_P3_h);
    cudaGetSymbolAddress((void**)&P3_l,   g_P3_l);
    cudaGetSymbolAddress((void**)&CWB,    g_CWB);
    cudaGetSymbolAddress((void**)&z_h,    g_z_h);
    cudaGetSymbolAddress((void**)&z_l,    g_z_l);
    cudaGetSymbolAddress((void**)&ZW,     g_ZW);
    cudaGetSymbolAddress((void**)&H_h,    g_H_h);
    cudaGetSymbolAddress((void**)&H_l,    g_H_l);
    cudaGetSymbolAddress((void**)&y1_h,   g_y1_h);
    cudaGetSymbolAddress((void**)&y1_l,   g_y1_l);
    cudaGetSymbolAddress((void**)&y2_h,   g_y2_h);
    cudaGetSymbolAddress((void**)&y2_l,   g_y2_l);

    const int TB = TB_DIM;

    constexpr int SM128 = 2 * (2 * 128 * 72 + 2 * 128 * 72) * 2;  // 147456 B
    constexpr int SM64  = 2 * (2 * 128 * 72 + 2 * 64 * 72) * 2;   // 110592 B
    cudaFuncSetAttribute((const void*)hgemm<128,128,64,32,0,0>,
                         cudaFuncAttributeMaxDynamicSharedMemorySize, SM128);
    cudaFuncSetAttribute((const void*)hgemm<128,128,64,32,1,0>,
                         cudaFuncAttributeMaxDynamicSharedMemorySize, SM128);
    cudaFuncSetAttribute((const void*)hgemm<128,128,64,32,2,1>,
                         cudaFuncAttributeMaxDynamicSharedMemorySize, SM128);
    cudaFuncSetAttribute((const void*)hgemm<128,64,64,16,3,0>,
                         cudaFuncAttributeMaxDynamicSharedMemorySize, SM64);
    cudaFuncSetAttribute((const void*)lstm_persistent,
                         cudaFuncAttributeMaxDynamicSharedMemorySize, SM128);

    // [0] fused weight prep
    {
        const int total = 2 * (H_DIM * H_DIM / 4) + D_DIM * H_DIM / 4
                        + 2 * (G_DIM * H_DIM / 4) + G_DIM;
        prep_weights<<<(total + 255) / 256, 256>>>(
            P1, P2, P3, Wih, Whh, bih, bhh,
            (ushort4*)P1_h, (ushort4*)P1_l, (ushort4*)P2_h, (ushort4*)P2_l,
            (ushort4*)P3_h, (ushort4*)P3_l,
            (ushort4*)Wih_h, (ushort4*)Wih_l, (ushort4*)Whh_h, (ushort4*)Whh_l,
            bperm);
    }
    // [1] z split
    split_kernel<<<(int)(((size_t)TB * H_DIM / 4) / 256), 256>>>(
        (const float4*)z, (ushort4*)z_h, (ushort4*)z_l, TB * (H_DIM / 4));

    // [2..4] Label MLP (f32x2, 64x64 tiles -> 128 CTAs each)
    gemm2_kernel<64,64,16,4,4,1,0><<<dim3(H_DIM/64, B_DIM/64), 256>>>(
        labels, W1, b1, x1, nullptr, nullptr, B_DIM, H_DIM, L_DIM);
    gemm2_kernel<64,64,16,4,4,1,0><<<dim3(H_DIM/64, B_DIM/64), 256>>>(
        x1, W2, b2, x2, nullptr, nullptr, B_DIM, H_DIM, H_DIM);
    gemm2_kernel<64,64,16,4,4,0,1><<<dim3(H_DIM/64, B_DIM/64), 256>>>(
        x2, W3, nullptr, nullptr, conds_h, conds_l, B_DIM, H_DIM, H_DIM);

    // [5] CWB = conds @ Wih_perm^T + (bih+bhh)_perm
    hgemm<128,128,64,32,0,0><<<dim3(G_DIM/128, B_DIM/128), 256, SM128>>>(
        conds_h, conds_l, Wih_h, Wih_l, bperm, nullptr,
        CWB, nullptr, nullptr, B_DIM, G_DIM, H_DIM);
    // [6] ZW = z @ Wih_perm^T + CWB[row % B]
    hgemm<128,128,64,32,1,0><<<dim3(G_DIM/128, TB/128), 256, SM128>>>(
        z_h, z_l, Wih_h, Wih_l, nullptr, CWB,
        ZW, nullptr, nullptr, TB, G_DIM, H_DIM);

    // [7] Persistent recurrence (one launch for all 128 steps)
    lstm_persistent<<<GRID_P, 256, SM128>>>(Whh_h, Whh_l, ZW, H_h, H_l);

    // [8..10] Projection MLP over all T*B rows
    hgemm<128,128,64,32,2,1><<<dim3(H_DIM/128, TB/128), 256, SM128>>>(
        H_h, H_l, P1_h, P1_l, pb1, nullptr,
        nullptr, y1_h, y1_l, TB, H_DIM, H_DIM);
    hgemm<128,128,64,32,2,1><<<dim3(H_DIM/128, TB/128), 256, SM128>>>(
        y1_h, y1_l, P2_h, P2_l, pb2, nullptr,
        nullptr, y2_h, y2_l, TB, H_DIM, H_DIM);
    hgemm<128,64,64,16,3,0><<<dim3(D_DIM/64, TB/128), 256, SM64>>>(
        y2_h, y2_l, P3_h, P3_l, pb3, nullptr,
        out, nullptr, nullptr, TB, D_DIM, H_DIM);
}

// round 9
// speedup vs baseline: 2.9450x; 1.0080x over previous
#include <cuda_runtime.h>
#include <cuda_bf16.h>
#include <math.h>
#include <stdint.h>

// Problem dims (fixed by the dataset)
#define B_DIM 1024
#define T_DIM 128
#define L_DIM 16
#define H_DIM 512
#define D_DIM 64
#define G_DIM 2048          // 4*H
#define TB_DIM (T_DIM * B_DIM)
#define GRID_P 256          // persistent recurrence grid (2 CTAs/SM, <=296 capacity)

// ---------------------------------------------------------------------------
// Scratch (device globals). bf16 hi/lo pairs stored as separate ushort arrays.
// ---------------------------------------------------------------------------
__device__ float    g_x1[B_DIM * H_DIM];
__device__ float    g_x2[B_DIM * H_DIM];
__device__ float    g_bperm[G_DIM];
__device__ unsigned short g_conds_h[B_DIM * H_DIM];
__device__ unsigned short g_conds_l[B_DIM * H_DIM];
__device__ unsigned short g_Wih_h[G_DIM * H_DIM];
__device__ unsigned short g_Wih_l[G_DIM * H_DIM];
__device__ unsigned short g_Whh_h[G_DIM * H_DIM];
__device__ unsigned short g_Whh_l[G_DIM * H_DIM];
__device__ unsigned short g_P1_h[H_DIM * H_DIM];
__device__ unsigned short g_P1_l[H_DIM * H_DIM];
__device__ unsigned short g_P2_h[H_DIM * H_DIM];
__device__ unsigned short g_P2_l[H_DIM * H_DIM];
__device__ unsigned short g_P3_h[D_DIM * H_DIM];
__device__ unsigned short g_P3_l[D_DIM * H_DIM];
__device__ float    g_CWB[B_DIM * G_DIM];
__device__ unsigned short g_z_h[(size_t)TB_DIM * H_DIM];
__device__ unsigned short g_z_l[(size_t)TB_DIM * H_DIM];
__device__ float    g_ZW[(size_t)TB_DIM * G_DIM];          // 1 GB
__device__ unsigned short g_H_h[(size_t)TB_DIM * H_DIM];
__device__ unsigned short g_H_l[(size_t)TB_DIM * H_DIM];
__device__ unsigned short g_y1_h[(size_t)TB_DIM * H_DIM];
__device__ unsigned short g_y1_l[(size_t)TB_DIM * H_DIM];
__device__ unsigned short g_y2_h[(size_t)TB_DIM * H_DIM];
__device__ unsigned short g_y2_l[(size_t)TB_DIM * H_DIM];

// Persistent-kernel grid barrier (monotonic; self-reset at kernel end)
__device__ unsigned g_bar_ctr  = 0;
__device__ unsigned g_done_ctr = 0;

// ---------------------------------------------------------------------------
// Helpers
// ---------------------------------------------------------------------------
__device__ __forceinline__ unsigned packf(float x) {
    __nv_bfloat16 h = __float2bfloat16(x);
    float r = x - __bfloat162float(h);
    __nv_bfloat16 l = __float2bfloat16(r);
    return ((unsigned)__bfloat16_as_ushort(h) << 16) |
            (unsigned)__bfloat16_as_ushort(l);
}

__device__ __forceinline__ void mma16816(float& c0, float& c1, float& c2, float& c3,
                                         unsigned a0, unsigned a1, unsigned a2, unsigned a3,
                                         unsigned b0, unsigned b1) {
    asm volatile(
        "mma.sync.aligned.m16n8k16.row.col.f32.bf16.bf16.f32 "
        "{%0,%1,%2,%3}, {%4,%5,%6,%7}, {%8,%9}, {%0,%1,%2,%3};\n"
        : "+f"(c0), "+f"(c1), "+f"(c2), "+f"(c3)
        : "r"(a0), "r"(a1), "r"(a2), "r"(a3), "r"(b0), "r"(b1));
}

__device__ __forceinline__ void ldsm4(unsigned& r0, unsigned& r1,
                                      unsigned& r2, unsigned& r3, uint32_t a) {
    asm volatile("ldmatrix.sync.aligned.m8n8.x4.shared.b16 {%0,%1,%2,%3}, [%4];"
                 : "=r"(r0), "=r"(r1), "=r"(r2), "=r"(r3) : "r"(a));
}

__device__ __forceinline__ void cp_async16(void* sptr, const void* gptr) {
    unsigned sa = (unsigned)__cvta_generic_to_shared(sptr);
    asm volatile("cp.async.cg.shared.global [%0], [%1], 16;\n" :: "r"(sa), "l"(gptr));
}
__device__ __forceinline__ void cp_commit() {
    asm volatile("cp.async.commit_group;\n");
}
template<int N>
__device__ __forceinline__ void cp_wait() {
    asm volatile("cp.async.wait_group %0;\n" :: "n"(N));
}

// ---------------------------------------------------------------------------
// HMMA 3xbf16 GEMM, hi/lo operands, BK=32 2-stage cp.async (82KB -> 2 CTAs/SM),
// ldmatrix fragments. D = Ah*Bh + Ah*Bl + Al*Bh (fp32 acc).
// smem rows STR=40 ushorts (80B): ldmatrix 8-row phases bank 20r mod 32 - clean.
// EPI: 0 = fp32 + bias (CWB)
//      1 = fp32 + addvec[row % B] (ZW build, CWB fold)
//      2 = hi/lo out + bias (+relu if ACT)   (P1, P2)
//      3 = fp32 + bias, [T,B]->[B,T] perm    (P3)
// ---------------------------------------------------------------------------
template<int BM, int BN, int WM, int WN, int EPI, int ACT>
__global__ void __launch_bounds__((BM / WM) * (BN / WN) * 32, 2)
hgemm(const unsigned short* __restrict__ Ah, const unsigned short* __restrict__ Al,
      const unsigned short* __restrict__ Bh, const unsigned short* __restrict__ Bl,
      const float* __restrict__ bias,
      const float* __restrict__ addvec,
      float* __restrict__ outf,
      unsigned short* __restrict__ out_hi,
      unsigned short* __restrict__ out_lo,
      int M, int N, int K)
{
    constexpr int BK = 32;
    constexpr int STR = BK + 8;              // 40 ushorts (80 B)
    constexpr int ATI = BM * STR;
    constexpr int BTI = BN * STR;
    constexpr int STAGE = 2 * ATI + 2 * BTI;
    constexpr int WARPS_N = BN / WN;
    constexpr int NTH = (BM / WM) * (BN / WN) * 32;
    constexpr int MI = WM / 16, NI = WN / 8;

    extern __shared__ unsigned short sm[];

    const int tid  = threadIdx.x;
    const int warp = tid >> 5, lane = tid & 31;
    const int g = lane >> 2, t = lane & 3;
    const int wm0 = (warp / WARPS_N) * WM;
    const int wn0 = (warp % WARPS_N) * WN;
    const int m0 = blockIdx.y * BM;
    const int n0 = blockIdx.x * BN;

    const uint32_t smb = (uint32_t)__cvta_generic_to_shared(sm);
    const int aRow = (lane & 7) + ((lane >> 3) & 1) * 8;
    const int aKh  = (lane >> 4) * 16;                 // byte offset (8 cols b16)
    const int bRow = (lane & 7) + (lane >> 4) * 8;
    const int bKh  = ((lane >> 3) & 1) * 16;
    const uint32_t aBase = smb + (uint32_t)(wm0 + aRow) * STR * 2 + aKh;
    const uint32_t bBase = smb + (uint32_t)(2 * ATI + (wn0 + bRow) * STR) * 2 + bKh;

    float acc[MI][NI][4];
#pragma unroll
    for (int mi = 0; mi < MI; mi++)
#pragma unroll
        for (int ni = 0; ni < NI; ni++)
#pragma unroll
            for (int q = 0; q < 4; q++) acc[mi][ni][q] = 0.f;

    auto load_stage = [&](int k0, int s) {
        unsigned short* st = sm + s * STAGE;
#pragma unroll
        for (int i = tid; i < BM * 4; i += NTH) {
            int r = i >> 2, c = i & 3;
            const size_t gs = (size_t)(m0 + r) * K + k0 + c * 8;
            cp_async16(st + r * STR + c * 8,       Ah + gs);
            cp_async16(st + ATI + r * STR + c * 8, Al + gs);
        }
#pragma unroll
        for (int i = tid; i < BN * 4; i += NTH) {
            int r = i >> 2, c = i & 3;
            const size_t gs = (size_t)(n0 + r) * K + k0 + c * 8;
            cp_async16(st + 2 * ATI + r * STR + c * 8,       Bh + gs);
            cp_async16(st + 2 * ATI + BTI + r * STR + c * 8, Bl + gs);
        }
        cp_commit();
    };

    const int KT = K / BK;
    load_stage(0, 0);

    for (int kt = 0; kt < KT; kt++) {
        const int s = kt & 1;
        if (kt + 1 < KT) { load_stage((kt + 1) * BK, s ^ 1); cp_wait<1>(); }
        else             { cp_wait<0>(); }
        __syncthreads();

        const uint32_t stOff = (uint32_t)(s * STAGE) * 2;
        const uint32_t aH = aBase + stOff;
        const uint32_t aL = aH + (uint32_t)ATI * 2;
        const uint32_t bH = bBase + stOff;
        const uint32_t bL = bH + (uint32_t)BTI * 2;

#pragma unroll
        for (int kk = 0; kk < BK; kk += 16) {
            unsigned ah[MI][4], al[MI][4], bh[NI][2], bl[NI][2];
#pragma unroll
            for (int mi = 0; mi < MI; mi++) {
                ldsm4(ah[mi][0], ah[mi][1], ah[mi][2], ah[mi][3],
                      aH + (uint32_t)(mi * 16 * STR + kk) * 2);
                ldsm4(al[mi][0], al[mi][1], al[mi][2], al[mi][3],
                      aL + (uint32_t)(mi * 16 * STR + kk) * 2);
            }
#pragma unroll
            for (int p = 0; p < NI / 2; p++) {
                ldsm4(bh[2*p][0], bh[2*p][1], bh[2*p+1][0], bh[2*p+1][1],
                      bH + (uint32_t)(p * 16 * STR + kk) * 2);
                ldsm4(bl[2*p][0], bl[2*p][1], bl[2*p+1][0], bl[2*p+1][1],
                      bL + (uint32_t)(p * 16 * STR + kk) * 2);
            }
#pragma unroll
            for (int mi = 0; mi < MI; mi++)
#pragma unroll
                for (int ni = 0; ni < NI; ni++) {
                    mma16816(acc[mi][ni][0], acc[mi][ni][1], acc[mi][ni][2], acc[mi][ni][3],
                             ah[mi][0], ah[mi][1], ah[mi][2], ah[mi][3], bh[ni][0], bh[ni][1]);
                    mma16816(acc[mi][ni][0], acc[mi][ni][1], acc[mi][ni][2], acc[mi][ni][3],
                             ah[mi][0], ah[mi][1], ah[mi][2], ah[mi][3], bl[ni][0], bl[ni][1]);
                    mma16816(acc[mi][ni][0], acc[mi][ni][1], acc[mi][ni][2], acc[mi][ni][3],
                             al[mi][0], al[mi][1], al[mi][2], al[mi][3], bh[ni][0], bh[ni][1]);
                }
        }
        __syncthreads();
    }

    // ---- Epilogues ----
    if (EPI == 0 || EPI == 2 || EPI == 3) {
        float2 bv[NI];
#pragma unroll
        for (int ni = 0; ni < NI; ni++)
            bv[ni] = *(const float2*)(bias + n0 + wn0 + ni * 8 + 2 * t);

#pragma unroll
        for (int mi = 0; mi < MI; mi++) {
            int row0 = m0 + wm0 + mi * 16 + g;
#pragma unroll
            for (int ni = 0; ni < NI; ni++) {
                int col = n0 + wn0 + ni * 8 + 2 * t;
                float v0 = acc[mi][ni][0] + bv[ni].x;
                float v1 = acc[mi][ni][1] + bv[ni].y;
                float v2 = acc[mi][ni][2] + bv[ni].x;
                float v3 = acc[mi][ni][3] + bv[ni].y;
                if (ACT == 1) {
                    v0 = fmaxf(v0, 0.f); v1 = fmaxf(v1, 0.f);
                    v2 = fmaxf(v2, 0.f); v3 = fmaxf(v3, 0.f);
                }
                if (EPI == 0) {
                    *(float2*)(outf + (size_t)row0 * N + col)       = make_float2(v0, v1);
                    *(float2*)(outf + (size_t)(row0 + 8) * N + col) = make_float2(v2, v3);
                } else if (EPI == 2) {
                    unsigned p0 = packf(v0), p1 = packf(v1), p2 = packf(v2), p3 = packf(v3);
                    *(ushort2*)(out_hi + (size_t)row0 * N + col) =
                        make_ushort2(p0 >> 16, p1 >> 16);
                    *(ushort2*)(out_lo + (size_t)row0 * N + col) =
                        make_ushort2(p0 & 0xffff, p1 & 0xffff);
                    *(ushort2*)(out_hi + (size_t)(row0 + 8) * N + col) =
                        make_ushort2(p2 >> 16, p3 >> 16);
                    *(ushort2*)(out_lo + (size_t)(row0 + 8) * N + col) =
                        make_ushort2(p2 & 0xffff, p3 & 0xffff);
                } else {
                    int tt0 = row0 / B_DIM, bb0 = row0 % B_DIM;
                    int r1 = row0 + 8;
                    int tt1 = r1 / B_DIM, bb1 = r1 % B_DIM;
                    *(float2*)(outf + ((size_t)bb0 * T_DIM + tt0) * D_DIM + col) = make_float2(v0, v1);
                    *(float2*)(outf + ((size_t)bb1 * T_DIM + tt1) * D_DIM + col) = make_float2(v2, v3);
                }
            }
        }
    } else {
        // EPI == 1
#pragma unroll
        for (int mi = 0; mi < MI; mi++) {
            int row0 = m0 + wm0 + mi * 16 + g;
#pragma unroll
            for (int ni = 0; ni < NI; ni++) {
                int col = n0 + wn0 + ni * 8 + 2 * t;
                float2 a0 = *(const float2*)(addvec + (size_t)(row0 & (B_DIM - 1)) * N + col);
                float2 a1 = *(const float2*)(addvec + (size_t)((row0 + 8) & (B_DIM - 1)) * N + col);
                *(float2*)(outf + (size_t)row0 * N + col) =
                    make_float2(acc[mi][ni][0] + a0.x, acc[mi][ni][1] + a0.y);
                *(float2*)(outf + (size_t)(row0 + 8) * N + col) =
                    make_float2(acc[mi][ni][2] + a1.x, acc[mi][ni][3] + a1.y);
            }
        }
    }
}

// ---------------------------------------------------------------------------
// Persistent LSTM recurrence: 256 CTAs (2/SM), tile 64x128, BK=32 pipeline.
// c-state in registers; ldmatrix fragments; grid barrier between steps.
// All 256 CTAs co-resident: smem 61,440 B/CTA + launch_bounds(256,2).
// ---------------------------------------------------------------------------
__global__ void __launch_bounds__(256, 2)
lstm_persistent(const unsigned short* __restrict__ Whh_h,
                const unsigned short* __restrict__ Whh_l,
                const float* __restrict__ ZW,        // [T][B][G] (perm cols)
                unsigned short* __restrict__ H_h,
                unsigned short* __restrict__ H_l)
{
    constexpr int BM = 64, BN = 128, BK = 32, WM = 32, WN = 32;
    constexpr int STR = BK + 8;
    constexpr int ATI = BM * STR, BTI = BN * STR;
    constexpr int STAGE = 2 * ATI + 2 * BTI;
    constexpr int WARPS_N = BN / WN;      // 4
    constexpr int NTH = 256;
    constexpr int MI = WM / 16, NI = WN / 8;   // 2, 4
    constexpr int K = H_DIM, N = G_DIM;
    constexpr int KT = K / BK;            // 16

    extern __shared__ unsigned short sm[];

    const int tid  = threadIdx.x;
    const int warp = tid >> 5, lane = tid & 31;
    const int g = lane >> 2, t4 = lane & 3;
    const int wm0 = (warp / WARPS_N) * WM;
    const int wn0 = (warp % WARPS_N) * WN;
    const int bid = blockIdx.x;
    const int m0 = (bid >> 4) * BM;       // 16 m-tiles
    const int n0 = (bid & 15) * BN;       // 16 n-tiles

    const uint32_t smb = (uint32_t)__cvta_generic_to_shared(sm);
    const int aRow = (lane & 7) + ((lane >> 3) & 1) * 8;
    const int aKh  = (lane >> 4) * 16;
    const int bRow = (lane & 7) + (lane >> 4) * 8;
    const int bKh  = ((lane >> 3) & 1) * 16;
    const uint32_t aBase = smb + (uint32_t)(wm0 + aRow) * STR * 2 + aKh;
    const uint32_t bBase = smb + (uint32_t)(2 * ATI + (wn0 + bRow) * STR) * 2 + bKh;

    const bool hi_half = (t4 & 1);

    float creg[MI][NI];
#pragma unroll
    for (int mi = 0; mi < MI; mi++)
#pragma unroll
        for (int ni = 0; ni < NI; ni++) creg[mi][ni] = 0.f;

    for (int t = 0; t < T_DIM; t++) {
        float acc[MI][NI][4];
#pragma unroll
        for (int mi = 0; mi < MI; mi++)
#pragma unroll
            for (int ni = 0; ni < NI; ni++)
#pragma unroll
                for (int q = 0; q < 4; q++) acc[mi][ni][q] = 0.f;

        if (t > 0) {
            const unsigned short* Ah = H_h + (size_t)(t - 1) * B_DIM * H_DIM;
            const unsigned short* Al = H_l + (size_t)(t - 1) * B_DIM * H_DIM;

            auto load_stage = [&](int k0, int s) {
                unsigned short* st = sm + s * STAGE;
#pragma unroll
                for (int i = tid; i < BM * 4; i += NTH) {
                    int r = i >> 2, c = i & 3;
                    const size_t gs = (size_t)(m0 + r) * K + k0 + c * 8;
                    cp_async16(st + r * STR + c * 8,       Ah + gs);
                    cp_async16(st + ATI + r * STR + c * 8, Al + gs);
                }
#pragma unroll
                for (int i = tid; i < BN * 4; i += NTH) {
                    int r = i >> 2, c = i & 3;
                    const size_t gs = (size_t)(n0 + r) * K + k0 + c * 8;
                    cp_async16(st + 2 * ATI + r * STR + c * 8,       Whh_h + gs);
                    cp_async16(st + 2 * ATI + BTI + r * STR + c * 8, Whh_l + gs);
                }
                cp_commit();
            };

            load_stage(0, 0);
            for (int kt = 0; kt < KT; kt++) {
                const int s = kt & 1;
                if (kt + 1 < KT) { load_stage((kt + 1) * BK, s ^ 1); cp_wait<1>(); }
                else             { cp_wait<0>(); }
                __syncthreads();

                const uint32_t stOff = (uint32_t)(s * STAGE) * 2;
                const uint32_t aH = aBase + stOff;
                const uint32_t aL = aH + (uint32_t)ATI * 2;
                const uint32_t bH = bBase + stOff;
                const uint32_t bL = bH + (uint32_t)BTI * 2;

#pragma unroll
                for (int kk = 0; kk < BK; kk += 16) {
                    unsigned ah[MI][4], al[MI][4], bh[NI][2], bl[NI][2];
#pragma unroll
                    for (int mi = 0; mi < MI; mi++) {
                        ldsm4(ah[mi][0], ah[mi][1], ah[mi][2], ah[mi][3],
                              aH + (uint32_t)(mi * 16 * STR + kk) * 2);
                        ldsm4(al[mi][0], al[mi][1], al[mi][2], al[mi][3],
                              aL + (uint32_t)(mi * 16 * STR + kk) * 2);
                    }
#pragma unroll
                    for (int p = 0; p < NI / 2; p++) {
                        ldsm4(bh[2*p][0], bh[2*p][1], bh[2*p+1][0], bh[2*p+1][1],
                              bH + (uint32_t)(p * 16 * STR + kk) * 2);
                        ldsm4(bl[2*p][0], bl[2*p][1], bl[2*p+1][0], bl[2*p+1][1],
                              bL + (uint32_t)(p * 16 * STR + kk) * 2);
                    }
#pragma unroll
                    for (int mi = 0; mi < MI; mi++)
#pragma unroll
                        for (int ni = 0; ni < NI; ni++) {
                            mma16816(acc[mi][ni][0], acc[mi][ni][1], acc[mi][ni][2], acc[mi][ni][3],
                                     ah[mi][0], ah[mi][1], ah[mi][2], ah[mi][3], bh[ni][0], bh[ni][1]);
                            mma16816(acc[mi][ni][0], acc[mi][ni][1], acc[mi][ni][2], acc[mi][ni][3],
                                     ah[mi][0], ah[mi][1], ah[mi][2], ah[mi][3], bl[ni][0], bl[ni][1]);
                            mma16816(acc[mi][ni][0], acc[mi][ni][1], acc[mi][ni][2], acc[mi][ni][3],
                                     al[mi][0], al[mi][1], al[mi][2], al[mi][3], bh[ni][0], bh[ni][1]);
                        }
                }
                __syncthreads();
            }
        }

        // ---- Cell epilogue (c in registers) ----
        const float* zwb = ZW + (size_t)t * B_DIM * G_DIM;
        unsigned short* hh = H_h + (size_t)t * B_DIM * H_DIM;
        unsigned short* hl = H_l + (size_t)t * B_DIM * H_DIM;
#pragma unroll
        for (int mi = 0; mi < MI; mi++) {
            int row0 = m0 + wm0 + mi * 16 + g;
#pragma unroll
            for (int ni = 0; ni < NI; ni++) {
                int col = n0 + wn0 + ni * 8 + 2 * t4;
                float c0 = acc[mi][ni][0], c1 = acc[mi][ni][1];
                float c2 = acc[mi][ni][2], c3 = acc[mi][ni][3];
                float sx = __shfl_xor_sync(0xffffffffu, hi_half ? c0 : c2, 1);
                float sy = __shfl_xor_sync(0xffffffffu, hi_half ? c1 : c3, 1);
                int row = hi_half ? row0 + 8 : row0;
                float gi, gf, gg, go;
                if (!hi_half) { gi = c0; gf = c1; gg = sx; go = sy; }
                else          { gi = sx; gf = sy; gg = c2; go = c3; }

                int base = col & ~3;
                float4 zw = *(const float4*)(zwb + (size_t)row * G_DIM + base);
                gi += zw.x; gf += zw.y; gg += zw.z; go += zw.w;

                float ig = 1.f / (1.f + expf(-gi));
                float fg = 1.f / (1.f + expf(-gf));
                float gt = tanhf(gg);
                float og = 1.f / (1.f + expf(-go));

                float cn = fg * creg[mi][ni] + ig * gt;
                creg[mi][ni] = cn;
                unsigned p = packf(og * tanhf(cn));
                size_t hidx = (size_t)row * H_DIM + (col >> 2);
                hh[hidx] = (unsigned short)(p >> 16);
                hl[hidx] = (unsigned short)(p & 0xffffu);
            }
        }

        // ---- Grid barrier between steps ----
        if (t < T_DIM - 1) {
            __syncthreads();
            if (tid == 0) {
                __threadfence();
                atomicAdd(&g_bar_ctr, 1u);
                unsigned target = (unsigned)(t + 1) * GRID_P;
                while (atomicAdd(&g_bar_ctr, 0u) < target) { }
            }
            __syncthreads();
        }
    }

    // Deterministic counter reset for graph replay
    __syncthreads();
    if (tid == 0) {
        unsigned d = atomicAdd(&g_done_ctr, 1u);
        if (d == GRID_P - 1) {
            g_bar_ctr = 0;
            g_done_ctr = 0;
            __threadfence();
        }
    }
}

// ---------------------------------------------------------------------------
// f32x2 SGEMM (label MLP), 64x64 tiles. OUT: 0 fp32, 1 hi/lo.
// ---------------------------------------------------------------------------
__device__ __forceinline__ void ffma2(unsigned long long& d,
                                      unsigned long long a,
                                      unsigned long long b) {
    asm("fma.rn.f32x2 %0, %1, %2, %0;" : "+l"(d) : "l"(a), "l"(b));
}
__device__ __forceinline__ unsigned long long pack2(float lo, float hi) {
    unsigned long long r;
    asm("mov.b64 %0, {%1, %2};" : "=l"(r) : "f"(lo), "f"(hi));
    return r;
}
__device__ __forceinline__ float2 unpack2(unsigned long long u) {
    float2 f;
    asm("mov.b64 {%0, %1}, %2;" : "=f"(f.x), "=f"(f.y) : "l"(u));
    return f;
}

template<int BM, int BN, int BK, int TM, int TN, int ACT, int OUT>
__global__ void gemm2_kernel(const float* __restrict__ A,
                             const float* __restrict__ W,
                             const float* __restrict__ bias,
                             float* __restrict__ C,
                             unsigned short* __restrict__ uh,
                             unsigned short* __restrict__ ul,
                             int M, int N, int K)
{
    constexpr int AS_STRIDE = BM + 4;
    constexpr int WS_STRIDE = BN + 4;
    __shared__ float As[BK][AS_STRIDE];
    __shared__ float Ws[BK][WS_STRIDE];

    constexpr int NTH = (BM / TM) * (BN / TN);
    const int tid = threadIdx.x;
    const int tx = tid % (BN / TN);
    const int ty = tid / (BN / TN);
    const int m0 = blockIdx.y * BM;
    const int n0 = blockIdx.x * BN;

    unsigned long long acc2[TM / 2][TN];
#pragma unroll
    for (int p = 0; p < TM / 2; p++)
#pragma unroll
        for (int j = 0; j < TN; j++) acc2[p][j] = 0ULL;

    for (int k0 = 0; k0 < K; k0 += BK) {
#pragma unroll
        for (int i = tid * 4; i < BM * BK; i += NTH * 4) {
            int m = i / BK, k = i % BK;
            float4 v = *(const float4*)(A + (long)(m0 + m) * K + (k0 + k));
            As[k + 0][m] = v.x; As[k + 1][m] = v.y;
            As[k + 2][m] = v.z; As[k + 3][m] = v.w;
        }
#pragma unroll
        for (int i = tid * 4; i < BN * BK; i += NTH * 4) {
            int n = i / BK, k = i % BK;
            float4 v = *(const float4*)(W + (long)(n0 + n) * K + (k0 + k));
            Ws[k + 0][n] = v.x; Ws[k + 1][n] = v.y;
            Ws[k + 2][n] = v.z; Ws[k + 3][n] = v.w;
        }
        __syncthreads();

#pragma unroll
        for (int k = 0; k < BK; k++) {
            unsigned long long am2[TM / 2];
            const ulonglong2* ap = reinterpret_cast<const ulonglong2*>(&As[k][ty * TM]);
#pragma unroll
            for (int q = 0; q < TM / 4; q++) {
                ulonglong2 tt = ap[q];
                am2[2 * q + 0] = tt.x;
                am2[2 * q + 1] = tt.y;
            }
            float4 w4 = *reinterpret_cast<const float4*>(&Ws[k][tx * TN]);
            unsigned long long wd[TN];
            wd[0] = pack2(w4.x, w4.x); wd[1] = pack2(w4.y, w4.y);
            wd[2] = pack2(w4.z, w4.z); wd[3] = pack2(w4.w, w4.w);
#pragma unroll
            for (int p = 0; p < TM / 2; p++)
#pragma unroll
                for (int j = 0; j < TN; j++) ffma2(acc2[p][j], am2[p], wd[j]);
        }
        __syncthreads();
    }

    float4 bv = make_float4(0.f, 0.f, 0.f, 0.f);
    if (bias) bv = *reinterpret_cast<const float4*>(bias + n0 + tx * TN);

#pragma unroll
    for (int p = 0; p < TM / 2; p++) {
        float2 v0 = unpack2(acc2[p][0]);
        float2 v1 = unpack2(acc2[p][1]);
        float2 v2 = unpack2(acc2[p][2]);
        float2 v3 = unpack2(acc2[p][3]);
        float4 rowA = make_float4(v0.x + bv.x, v1.x + bv.y, v2.x + bv.z, v3.x + bv.w);
        float4 rowB = make_float4(v0.y + bv.x, v1.y + bv.y, v2.y + bv.z, v3.y + bv.w);
        if (ACT == 1) {
            rowA.x = fmaxf(rowA.x, 0.f); rowA.y = fmaxf(rowA.y, 0.f);
            rowA.z = fmaxf(rowA.z, 0.f); rowA.w = fmaxf(rowA.w, 0.f);
            rowB.x = fmaxf(rowB.x, 0.f); rowB.y = fmaxf(rowB.y, 0.f);
            rowB.z = fmaxf(rowB.z, 0.f); rowB.w = fmaxf(rowB.w, 0.f);
        }
        int mA = m0 + ty * TM + 2 * p;
        int n  = n0 + tx * TN;
        if (OUT == 0) {
            *reinterpret_cast<float4*>(C + (long)mA * N + n) = rowA;
            *reinterpret_cast<float4*>(C + (long)(mA + 1) * N + n) = rowB;
        } else {
            unsigned a0 = packf(rowA.x), a1 = packf(rowA.y), a2 = packf(rowA.z), a3 = packf(rowA.w);
            unsigned b0 = packf(rowB.x), b1 = packf(rowB.y), b2 = packf(rowB.z), b3 = packf(rowB.w);
            *(ushort4*)(uh + (size_t)mA * N + n) = make_ushort4(a0 >> 16, a1 >> 16, a2 >> 16, a3 >> 16);
            *(ushort4*)(ul + (size_t)mA * N + n) = make_ushort4(a0 & 0xffff, a1 & 0xffff, a2 & 0xffff, a3 & 0xffff);
            *(ushort4*)(uh + (size_t)(mA + 1) * N + n) = make_ushort4(b0 >> 16, b1 >> 16, b2 >> 16, b3 >> 16);
            *(ushort4*)(ul + (size_t)(mA + 1) * N + n) = make_ushort4(b0 & 0xffff, b1 & 0xffff, b2 & 0xffff, b3 & 0xffff);
        }
    }
}

// ---------------------------------------------------------------------------
// Prep kernels
// ---------------------------------------------------------------------------
__device__ __forceinline__ void split4(const float4* src, int i,
                                       ushort4* hi, ushort4* lo) {
    float4 v = src[i];
    unsigned px = packf(v.x), py = packf(v.y), pz = packf(v.z), pw = packf(v.w);
    hi[i] = make_ushort4(px >> 16, py >> 16, pz >> 16, pw >> 16);
    lo[i] = make_ushort4(px & 0xffff, py & 0xffff, pz & 0xffff, pw & 0xffff);
}

__device__ __forceinline__ void permsplit4(const float* src, int i,
                                           ushort4* hi, ushort4* lo) {
    int r = i / (H_DIM / 4);
    int c = i % (H_DIM / 4);
    int j = r >> 2, gg = r & 3;
    float4 v = ((const float4*)src)[(size_t)(gg * H_DIM + j) * (H_DIM / 4) + c];
    unsigned px = packf(v.x), py = packf(v.y), pz = packf(v.z), pw = packf(v.w);
    size_t o = (size_t)r * (H_DIM / 4) + c;
    hi[o] = make_ushort4(px >> 16, py >> 16, pz >> 16, pw >> 16);
    lo[o] = make_ushort4(px & 0xffff, py & 0xffff, pz & 0xffff, pw & 0xffff);
}

__global__ void prep_weights(const float* __restrict__ P1, const float* __restrict__ P2,
                             const float* __restrict__ P3,
                             const float* __restrict__ Wih, const float* __restrict__ Whh,
                             const float* __restrict__ bih, const float* __restrict__ bhh,
                             ushort4* P1h, ushort4* P1l, ushort4* P2h, ushort4* P2l,
                             ushort4* P3h, ushort4* P3l,
                             ushort4* Wihh, ushort4* Wihl, ushort4* Whhh, ushort4* Whhl,
                             float* bp)
{
    const int S0 = H_DIM * H_DIM / 4;
    const int S1 = S0 + H_DIM * H_DIM / 4;
    const int S2 = S1 + D_DIM * H_DIM / 4;
    const int S3 = S2 + G_DIM * H_DIM / 4;
    const int S4 = S3 + G_DIM * H_DIM / 4;
    int i = blockIdx.x * blockDim.x + threadIdx.x;
    if      (i < S0) split4((const float4*)P1, i, P1h, P1l);
    else if (i < S1) split4((const float4*)P2, i - S0, P2h, P2l);
    else if (i < S2) split4((const float4*)P3, i - S1, P3h, P3l);
    else if (i < S3) permsplit4(Wih, i - S2, Wihh, Wihl);
    else if (i < S4) permsplit4(Whh, i - S3, Whhh, Whhl);
    else if (i < S4 + G_DIM) {
        int k = i - S4;
        int j = k >> 2, gg = k & 3;
        bp[k] = bih[gg * H_DIM + j] + bhh[gg * H_DIM + j];
    }
}

__global__ void split_kernel(const float4* __restrict__ src,
                             ushort4* __restrict__ hi,
                             ushort4* __restrict__ lo, int n4)
{
    int i = blockIdx.x * blockDim.x + threadIdx.x;
    if (i < n4) split4(src, i, hi, lo);
}

// ---------------------------------------------------------------------------
// Launch
// ---------------------------------------------------------------------------
extern "C" void kernel_launch(void* const* d_in, const int* in_sizes, int n_in,
                              void* d_out, int out_size)
{
    const float* labels = (const float*)d_in[0];
    const float* z      = (const float*)d_in[1];
    const float* W1     = (const float*)d_in[2];
    const float* b1     = (const float*)d_in[3];
    const float* W2     = (const float*)d_in[4];
    const float* b2     = (const float*)d_in[5];
    const float* W3     = (const float*)d_in[6];
    const float* Wih    = (const float*)d_in[7];
    const float* Whh    = (const float*)d_in[8];
    const float* bih    = (const float*)d_in[9];
    const float* bhh    = (const float*)d_in[10];
    const float* P1     = (const float*)d_in[11];
    const float* pb1    = (const float*)d_in[12];
    const float* P2     = (const float*)d_in[13];
    const float* pb2    = (const float*)d_in[14];
    const float* P3     = (const float*)d_in[15];
    const float* pb3    = (const float*)d_in[16];
    float* out = (float*)d_out;

    float *x1, *x2, *bperm, *CWB, *ZW;
    unsigned short *conds_h, *conds_l, *Wih_h, *Wih_l, *Whh_h, *Whh_l;
    unsigned short *P1_h, *P1_l, *P2_h, *P2_l, *P3_h, *P3_l;
    unsigned short *z_h, *z_l, *H_h, *H_l, *y1_h, *y1_l, *y2_h, *y2_l;
    cudaGetSymbolAddress((void**)&x1,     g_x1);
    cudaGetSymbolAddress((void**)&x2,     g_x2);
    cudaGetSymbolAddress((void**)&bperm,  g_bperm);
    cudaGetSymbolAddress((void**)&conds_h, g_conds_h);
    cudaGetSymbolAddress((void**)&conds_l, g_conds_l);
    cudaGetSymbolAddress((void**)&Wih_h,  g_Wih_h);
    cudaGetSymbolAddress((void**)&Wih_l,  g_Wih_l);
    cudaGetSymbolAddress((void**)&Whh_h,  g_Whh_h);
    cudaGetSymbolAddress((void**)&Whh_l,  g_Whh_l);
    cudaGetSymbolAddress((void**)&P1_h,   g_P1_h);
    cudaGetSymbolAddress((void**)&P1_l,   g_P1_l);
    cudaGetSymbolAddress((void**)&P2_h,   g_P2_h);
    cudaGetSymbolAddress((void**)&P2_l,   g_P2_l);
    cudaGetSymbolAddress((void**)&P3_h,   g_P3_h);
    cudaGetSymbolAddress((void**)&P3_l,   g_P3_l);
    cudaGetSymbolAddress((void**)&CWB,    g_CWB);
    cudaGetSymbolAddress((void**)&z_h,    g_z_h);
    cudaGetSymbolAddress((void**)&z_l,    g_z_l);
    cudaGetSymbolAddress((void**)&ZW,     g_ZW);
    cudaGetSymbolAddress((void**)&H_h,    g_H_h);
    cudaGetSymbolAddress((void**)&H_l,    g_H_l);
    cudaGetSymbolAddress((void**)&y1_h,   g_y1_h);
    cudaGetSymbolAddress((void**)&y1_l,   g_y1_l);
    cudaGetSymbolAddress((void**)&y2_h,   g_y2_h);
    cudaGetSymbolAddress((void**)&y2_l,   g_y2_l);

    const int TB = TB_DIM;

    // Dynamic smem (BK=32, STR=40): 2 stages x (2A + 2B) tiles
    constexpr int SM128 = 2 * (2 * 128 * 40 + 2 * 128 * 40) * 2;  // 81920 B
    constexpr int SM64B = 2 * (2 * 128 * 40 + 2 * 64 * 40) * 2;   // 61440 B (BM128,BN64)
    constexpr int SMP   = 2 * (2 * 64 * 40 + 2 * 128 * 40) * 2;   // 61440 B (persistent)
    cudaFuncSetAttribute((const void*)hgemm<128,128,64,32,0,0>,
                         cudaFuncAttributeMaxDynamicSharedMemorySize, SM128);
    cudaFuncSetAttribute((const void*)hgemm<128,128,64,32,1,0>,
                         cudaFuncAttributeMaxDynamicSharedMemorySize, SM128);
    cudaFuncSetAttribute((const void*)hgemm<128,128,64,32,2,1>,
                         cudaFuncAttributeMaxDynamicSharedMemorySize, SM128);
    cudaFuncSetAttribute((const void*)hgemm<128,64,64,16,3,0>,
                         cudaFuncAttributeMaxDynamicSharedMemorySize, SM64B);
    cudaFuncSetAttribute((const void*)lstm_persistent,
                         cudaFuncAttributeMaxDynamicSharedMemorySize, SMP);

    // [0] fused weight prep
    {
        const int total = 2 * (H_DIM * H_DIM / 4) + D_DIM * H_DIM / 4
                        + 2 * (G_DIM * H_DIM / 4) + G_DIM;
        prep_weights<<<(total + 255) / 256, 256>>>(
            P1, P2, P3, Wih, Whh, bih, bhh,
            (ushort4*)P1_h, (ushort4*)P1_l, (ushort4*)P2_h, (ushort4*)P2_l,
            (ushort4*)P3_h, (ushort4*)P3_l,
            (ushort4*)Wih_h, (ushort4*)Wih_l, (ushort4*)Whh_h, (ushort4*)Whh_l,
            bperm);
    }
    // [1] z split
    split_kernel<<<(int)(((size_t)TB * H_DIM / 4) / 256), 256>>>(
        (const float4*)z, (ushort4*)z_h, (ushort4*)z_l, TB * (H_DIM / 4));

    // [2..4] Label MLP (f32x2, 64x64 tiles)
    gemm2_kernel<64,64,16,4,4,1,0><<<dim3(H_DIM/64, B_DIM/64), 256>>>(
        labels, W1, b1, x1, nullptr, nullptr, B_DIM, H_DIM, L_DIM);
    gemm2_kernel<64,64,16,4,4,1,0><<<dim3(H_DIM/64, B_DIM/64), 256>>>(
        x1, W2, b2, x2, nullptr, nullptr, B_DIM, H_DIM, H_DIM);
    gemm2_kernel<64,64,16,4,4,0,1><<<dim3(H_DIM/64, B_DIM/64), 256>>>(
        x2, W3, nullptr, nullptr, conds_h, conds_l, B_DIM, H_DIM, H_DIM);

    // [5] CWB = conds @ Wih_perm^T + (bih+bhh)_perm   <- ncu profiles this one
    hgemm<128,128,64,32,0,0><<<dim3(G_DIM/128, B_DIM/128), 256, SM128>>>(
        conds_h, conds_l, Wih_h, Wih_l, bperm, nullptr,
        CWB, nullptr, nullptr, B_DIM, G_DIM, H_DIM);
    // [6] ZW = z @ Wih_perm^T + CWB[row % B]
    hgemm<128,128,64,32,1,0><<<dim3(G_DIM/128, TB/128), 256, SM128>>>(
        z_h, z_l, Wih_h, Wih_l, nullptr, CWB,
        ZW, nullptr, nullptr, TB, G_DIM, H_DIM);

    // [7] Persistent recurrence (one launch, 256 CTAs @ 2/SM)
    lstm_persistent<<<GRID_P, 256, SMP>>>(Whh_h, Whh_l, ZW, H_h, H_l);

    // [8..10] Projection MLP over all T*B rows
    hgemm<128,128,64,32,2,1><<<dim3(H_DIM/128, TB/128), 256, SM128>>>(
        H_h, H_l, P1_h, P1_l, pb1, nullptr,
        nullptr, y1_h, y1_l, TB, H_DIM, H_DIM);
    hgemm<128,128,64,32,2,1><<<dim3(H_DIM/128, TB/128), 256, SM128>>>(
        y1_h, y1_l, P2_h, P2_l, pb2, nullptr,
        nullptr, y2_h, y2_l, TB, H_DIM, H_DIM);
    hgemm<128,64,64,16,3,0><<<dim3(D_DIM/64, TB/128), 256, SM64B>>>(
        y2_h, y2_l, P3_h, P3_l, pb3, nullptr,
        out, nullptr, nullptr, TB, D_DIM, H_DIM);
}

// round 10
// speedup vs baseline: 4.0112x; 1.3620x over previous
#include <cuda_runtime.h>
#include <cuda_fp16.h>
#include <math.h>
#include <stdint.h>

// Problem dims (fixed by the dataset)
#define B_DIM 1024
#define T_DIM 128
#define L_DIM 16
#define H_DIM 512
#define D_DIM 64
#define G_DIM 2048          // 4*H
#define TB_DIM (T_DIM * B_DIM)
#define GRID_P 256          // persistent recurrence grid (2 CTAs/SM)

// ---------------------------------------------------------------------------
// Scratch. Activations: single fp16 (ushort). Weights: fp16 hi/lo pairs.
// ---------------------------------------------------------------------------
__device__ float    g_x1[B_DIM * H_DIM];
__device__ float    g_x2[B_DIM * H_DIM];
__device__ float    g_bperm[G_DIM];
__device__ unsigned short g_conds_h[B_DIM * H_DIM];
__device__ unsigned short g_Wih_h[G_DIM * H_DIM];
__device__ unsigned short g_Wih_l[G_DIM * H_DIM];
__device__ unsigned short g_Whh_h[G_DIM * H_DIM];
__device__ unsigned short g_Whh_l[G_DIM * H_DIM];
__device__ unsigned short g_P1_h[H_DIM * H_DIM];
__device__ unsigned short g_P1_l[H_DIM * H_DIM];
__device__ unsigned short g_P2_h[H_DIM * H_DIM];
__device__ unsigned short g_P2_l[H_DIM * H_DIM];
__device__ unsigned short g_P3_h[D_DIM * H_DIM];
__device__ unsigned short g_P3_l[D_DIM * H_DIM];
__device__ float    g_CWB[B_DIM * G_DIM];
__device__ unsigned short g_z_h[(size_t)TB_DIM * H_DIM];   // 128 MB
__device__ float    g_ZW[(size_t)TB_DIM * G_DIM];          // 1 GB
__device__ unsigned short g_H_h[(size_t)TB_DIM * H_DIM];
__device__ unsigned short g_y1_h[(size_t)TB_DIM * H_DIM];
__device__ unsigned short g_y2_h[(size_t)TB_DIM * H_DIM];

// Persistent-kernel grid barrier (monotonic; self-reset at kernel end)
__device__ unsigned g_bar_ctr  = 0;
__device__ unsigned g_done_ctr = 0;

// ---------------------------------------------------------------------------
// Helpers
// ---------------------------------------------------------------------------
__device__ __forceinline__ unsigned short h_of(float x) {
    return __half_as_ushort(__float2half_rn(x));
}
__device__ __forceinline__ void hsplit(float x, unsigned short& hi, unsigned short& lo) {
    __half h = __float2half_rn(x);
    float r = x - __half2float(h);
    __half l = __float2half_rn(r);
    hi = __half_as_ushort(h);
    lo = __half_as_ushort(l);
}

// mma m16n8k16 row.col fp16 -> f32
__device__ __forceinline__ void mma16816(float& c0, float& c1, float& c2, float& c3,
                                         unsigned a0, unsigned a1, unsigned a2, unsigned a3,
                                         unsigned b0, unsigned b1) {
    asm volatile(
        "mma.sync.aligned.m16n8k16.row.col.f32.f16.f16.f32 "
        "{%0,%1,%2,%3}, {%4,%5,%6,%7}, {%8,%9}, {%0,%1,%2,%3};\n"
        : "+f"(c0), "+f"(c1), "+f"(c2), "+f"(c3)
        : "r"(a0), "r"(a1), "r"(a2), "r"(a3), "r"(b0), "r"(b1));
}

__device__ __forceinline__ void ldsm4(unsigned& r0, unsigned& r1,
                                      unsigned& r2, unsigned& r3, uint32_t a) {
    asm volatile("ldmatrix.sync.aligned.m8n8.x4.shared.b16 {%0,%1,%2,%3}, [%4];"
                 : "=r"(r0), "=r"(r1), "=r"(r2), "=r"(r3) : "r"(a));
}

__device__ __forceinline__ void cp_async16(void* sptr, const void* gptr) {
    unsigned sa = (unsigned)__cvta_generic_to_shared(sptr);
    asm volatile("cp.async.cg.shared.global [%0], [%1], 16;\n" :: "r"(sa), "l"(gptr));
}
__device__ __forceinline__ void cp_commit() {
    asm volatile("cp.async.commit_group;\n");
}
template<int N>
__device__ __forceinline__ void cp_wait() {
    asm volatile("cp.async.wait_group %0;\n" :: "n"(N));
}

// ---------------------------------------------------------------------------
// fp16 2-term GEMM: D[M,N] = A@B^T, A single fp16, B = Bh + Bl (fp16 pair).
// D = A*Bh + A*Bl (2 MMAs). BK=32 2-stage cp.async, ldmatrix fragments.
// smem rows STR=40 ushorts (80 B), conflict-free ldmatrix phases.
// EPI: 0 = fp32 + bias (CWB)
//      1 = fp32 + addvec[row % B] (ZW build, CWB fold)
//      2 = fp16 out + bias (+relu if ACT)    (P1, P2)
//      3 = fp32 + bias, [T,B]->[B,T] perm    (P3)
// ---------------------------------------------------------------------------
template<int BM, int BN, int WM, int WN, int EPI, int ACT>
__global__ void __launch_bounds__((BM / WM) * (BN / WN) * 32, 2)
hgemm(const unsigned short* __restrict__ A,
      const unsigned short* __restrict__ Bh, const unsigned short* __restrict__ Bl,
      const float* __restrict__ bias,
      const float* __restrict__ addvec,
      float* __restrict__ outf,
      unsigned short* __restrict__ outh,
      int M, int N, int K)
{
    constexpr int BK = 32;
    constexpr int STR = BK + 8;              // 40 ushorts
    constexpr int ATI = BM * STR;
    constexpr int BTI = BN * STR;
    constexpr int STAGE = ATI + 2 * BTI;
    constexpr int WARPS_N = BN / WN;
    constexpr int NTH = (BM / WM) * (BN / WN) * 32;
    constexpr int MI = WM / 16, NI = WN / 8;

    extern __shared__ unsigned short sm[];

    const int tid  = threadIdx.x;
    const int warp = tid >> 5, lane = tid & 31;
    const int g = lane >> 2, t = lane & 3;
    const int wm0 = (warp / WARPS_N) * WM;
    const int wn0 = (warp % WARPS_N) * WN;
    const int m0 = blockIdx.y * BM;
    const int n0 = blockIdx.x * BN;

    const uint32_t smb = (uint32_t)__cvta_generic_to_shared(sm);
    const int aRow = (lane & 7) + ((lane >> 3) & 1) * 8;
    const int aKh  = (lane >> 4) * 16;
    const int bRow = (lane & 7) + (lane >> 4) * 8;
    const int bKh  = ((lane >> 3) & 1) * 16;
    const uint32_t aBase = smb + (uint32_t)(wm0 + aRow) * STR * 2 + aKh;
    const uint32_t bBase = smb + (uint32_t)(ATI + (wn0 + bRow) * STR) * 2 + bKh;

    float acc[MI][NI][4];
#pragma unroll
    for (int mi = 0; mi < MI; mi++)
#pragma unroll
        for (int ni = 0; ni < NI; ni++)
#pragma unroll
            for (int q = 0; q < 4; q++) acc[mi][ni][q] = 0.f;

    auto load_stage = [&](int k0, int s) {
        unsigned short* st = sm + s * STAGE;
#pragma unroll
        for (int i = tid; i < BM * 4; i += NTH) {
            int r = i >> 2, c = i & 3;
            cp_async16(st + r * STR + c * 8, A + (size_t)(m0 + r) * K + k0 + c * 8);
        }
#pragma unroll
        for (int i = tid; i < BN * 4; i += NTH) {
            int r = i >> 2, c = i & 3;
            const size_t gs = (size_t)(n0 + r) * K + k0 + c * 8;
            cp_async16(st + ATI + r * STR + c * 8,       Bh + gs);
            cp_async16(st + ATI + BTI + r * STR + c * 8, Bl + gs);
        }
        cp_commit();
    };

    const int KT = K / BK;
    load_stage(0, 0);

    for (int kt = 0; kt < KT; kt++) {
        const int s = kt & 1;
        if (kt + 1 < KT) { load_stage((kt + 1) * BK, s ^ 1); cp_wait<1>(); }
        else             { cp_wait<0>(); }
        __syncthreads();

        const uint32_t stOff = (uint32_t)(s * STAGE) * 2;
        const uint32_t aA = aBase + stOff;
        const uint32_t bH = bBase + stOff;
        const uint32_t bL = bH + (uint32_t)BTI * 2;

#pragma unroll
        for (int kk = 0; kk < BK; kk += 16) {
            unsigned ah[MI][4], bh[NI][2], bl[NI][2];
#pragma unroll
            for (int mi = 0; mi < MI; mi++)
                ldsm4(ah[mi][0], ah[mi][1], ah[mi][2], ah[mi][3],
                      aA + (uint32_t)(mi * 16 * STR + kk) * 2);
#pragma unroll
            for (int p = 0; p < NI / 2; p++) {
                ldsm4(bh[2*p][0], bh[2*p][1], bh[2*p+1][0], bh[2*p+1][1],
                      bH + (uint32_t)(p * 16 * STR + kk) * 2);
                ldsm4(bl[2*p][0], bl[2*p][1], bl[2*p+1][0], bl[2*p+1][1],
                      bL + (uint32_t)(p * 16 * STR + kk) * 2);
            }
#pragma unroll
            for (int mi = 0; mi < MI; mi++)
#pragma unroll
                for (int ni = 0; ni < NI; ni++) {
                    mma16816(acc[mi][ni][0], acc[mi][ni][1], acc[mi][ni][2], acc[mi][ni][3],
                             ah[mi][0], ah[mi][1], ah[mi][2], ah[mi][3], bh[ni][0], bh[ni][1]);
                    mma16816(acc[mi][ni][0], acc[mi][ni][1], acc[mi][ni][2], acc[mi][ni][3],
                             ah[mi][0], ah[mi][1], ah[mi][2], ah[mi][3], bl[ni][0], bl[ni][1]);
                }
        }
        __syncthreads();
    }

    // ---- Epilogues ----
    if (EPI == 0 || EPI == 2 || EPI == 3) {
        float2 bv[NI];
#pragma unroll
        for (int ni = 0; ni < NI; ni++)
            bv[ni] = *(const float2*)(bias + n0 + wn0 + ni * 8 + 2 * t);

#pragma unroll
        for (int mi = 0; mi < MI; mi++) {
            int row0 = m0 + wm0 + mi * 16 + g;
#pragma unroll
            for (int ni = 0; ni < NI; ni++) {
                int col = n0 + wn0 + ni * 8 + 2 * t;
                float v0 = acc[mi][ni][0] + bv[ni].x;
                float v1 = acc[mi][ni][1] + bv[ni].y;
                float v2 = acc[mi][ni][2] + bv[ni].x;
                float v3 = acc[mi][ni][3] + bv[ni].y;
                if (ACT == 1) {
                    v0 = fmaxf(v0, 0.f); v1 = fmaxf(v1, 0.f);
                    v2 = fmaxf(v2, 0.f); v3 = fmaxf(v3, 0.f);
                }
                if (EPI == 0) {
                    *(float2*)(outf + (size_t)row0 * N + col)       = make_float2(v0, v1);
                    *(float2*)(outf + (size_t)(row0 + 8) * N + col) = make_float2(v2, v3);
                } else if (EPI == 2) {
                    *(ushort2*)(outh + (size_t)row0 * N + col) =
                        make_ushort2(h_of(v0), h_of(v1));
                    *(ushort2*)(outh + (size_t)(row0 + 8) * N + col) =
                        make_ushort2(h_of(v2), h_of(v3));
                } else {
                    int tt0 = row0 / B_DIM, bb0 = row0 % B_DIM;
                    int r1 = row0 + 8;
                    int tt1 = r1 / B_DIM, bb1 = r1 % B_DIM;
                    *(float2*)(outf + ((size_t)bb0 * T_DIM + tt0) * D_DIM + col) = make_float2(v0, v1);
                    *(float2*)(outf + ((size_t)bb1 * T_DIM + tt1) * D_DIM + col) = make_float2(v2, v3);
                }
            }
        }
    } else {
        // EPI == 1
#pragma unroll
        for (int mi = 0; mi < MI; mi++) {
            int row0 = m0 + wm0 + mi * 16 + g;
#pragma unroll
            for (int ni = 0; ni < NI; ni++) {
                int col = n0 + wn0 + ni * 8 + 2 * t;
                float2 a0 = *(const float2*)(addvec + (size_t)(row0 & (B_DIM - 1)) * N + col);
                float2 a1 = *(const float2*)(addvec + (size_t)((row0 + 8) & (B_DIM - 1)) * N + col);
                *(float2*)(outf + (size_t)row0 * N + col) =
                    make_float2(acc[mi][ni][0] + a0.x, acc[mi][ni][1] + a0.y);
                *(float2*)(outf + (size_t)(row0 + 8) * N + col) =
                    make_float2(acc[mi][ni][2] + a1.x, acc[mi][ni][3] + a1.y);
            }
        }
    }
}

// ---------------------------------------------------------------------------
// Persistent LSTM recurrence: 256 CTAs (2/SM), tile 64x128, BK=32, fp16 2-term.
// A = H (single fp16), B = Whh hi/lo. c-state in registers; grid barrier.
// ---------------------------------------------------------------------------
__global__ void __launch_bounds__(256, 2)
lstm_persistent(const unsigned short* __restrict__ Whh_h,
                const unsigned short* __restrict__ Whh_l,
                const float* __restrict__ ZW,        // [T][B][G] (perm cols)
                unsigned short* __restrict__ H_h)
{
    constexpr int BM = 64, BN = 128, BK = 32, WM = 32, WN = 32;
    constexpr int STR = BK + 8;
    constexpr int ATI = BM * STR, BTI = BN * STR;
    constexpr int STAGE = ATI + 2 * BTI;
    constexpr int WARPS_N = BN / WN;
    constexpr int NTH = 256;
    constexpr int MI = WM / 16, NI = WN / 8;   // 2, 4
    constexpr int K = H_DIM, N = G_DIM;
    constexpr int KT = K / BK;

    extern __shared__ unsigned short sm[];

    const int tid  = threadIdx.x;
    const int warp = tid >> 5, lane = tid & 31;
    const int g = lane >> 2, t4 = lane & 3;
    const int wm0 = (warp / WARPS_N) * WM;
    const int wn0 = (warp % WARPS_N) * WN;
    const int bid = blockIdx.x;
    const int m0 = (bid >> 4) * BM;
    const int n0 = (bid & 15) * BN;

    const uint32_t smb = (uint32_t)__cvta_generic_to_shared(sm);
    const int aRow = (lane & 7) + ((lane >> 3) & 1) * 8;
    const int aKh  = (lane >> 4) * 16;
    const int bRow = (lane & 7) + (lane >> 4) * 8;
    const int bKh  = ((lane >> 3) & 1) * 16;
    const uint32_t aBase = smb + (uint32_t)(wm0 + aRow) * STR * 2 + aKh;
    const uint32_t bBase = smb + (uint32_t)(ATI + (wn0 + bRow) * STR) * 2 + bKh;

    const bool hi_half = (t4 & 1);

    float creg[MI][NI];
#pragma unroll
    for (int mi = 0; mi < MI; mi++)
#pragma unroll
        for (int ni = 0; ni < NI; ni++) creg[mi][ni] = 0.f;

    for (int t = 0; t < T_DIM; t++) {
        float acc[MI][NI][4];
#pragma unroll
        for (int mi = 0; mi < MI; mi++)
#pragma unroll
            for (int ni = 0; ni < NI; ni++)
#pragma unroll
                for (int q = 0; q < 4; q++) acc[mi][ni][q] = 0.f;

        if (t > 0) {
            const unsigned short* Ah = H_h + (size_t)(t - 1) * B_DIM * H_DIM;

            auto load_stage = [&](int k0, int s) {
                unsigned short* st = sm + s * STAGE;
#pragma unroll
                for (int i = tid; i < BM * 4; i += NTH) {
                    int r = i >> 2, c = i & 3;
                    cp_async16(st + r * STR + c * 8, Ah + (size_t)(m0 + r) * K + k0 + c * 8);
                }
#pragma unroll
                for (int i = tid; i < BN * 4; i += NTH) {
                    int r = i >> 2, c = i & 3;
                    const size_t gs = (size_t)(n0 + r) * K + k0 + c * 8;
                    cp_async16(st + ATI + r * STR + c * 8,       Whh_h + gs);
                    cp_async16(st + ATI + BTI + r * STR + c * 8, Whh_l + gs);
                }
                cp_commit();
            };

            load_stage(0, 0);
            for (int kt = 0; kt < KT; kt++) {
                const int s = kt & 1;
                if (kt + 1 < KT) { load_stage((kt + 1) * BK, s ^ 1); cp_wait<1>(); }
                else             { cp_wait<0>(); }
                __syncthreads();

                const uint32_t stOff = (uint32_t)(s * STAGE) * 2;
                const uint32_t aA = aBase + stOff;
                const uint32_t bH = bBase + stOff;
                const uint32_t bL = bH + (uint32_t)BTI * 2;

#pragma unroll
                for (int kk = 0; kk < BK; kk += 16) {
                    unsigned ah[MI][4], bh[NI][2], bl[NI][2];
#pragma unroll
                    for (int mi = 0; mi < MI; mi++)
                        ldsm4(ah[mi][0], ah[mi][1], ah[mi][2], ah[mi][3],
                              aA + (uint32_t)(mi * 16 * STR + kk) * 2);
#pragma unroll
                    for (int p = 0; p < NI / 2; p++) {
                        ldsm4(bh[2*p][0], bh[2*p][1], bh[2*p+1][0], bh[2*p+1][1],
                              bH + (uint32_t)(p * 16 * STR + kk) * 2);
                        ldsm4(bl[2*p][0], bl[2*p][1], bl[2*p+1][0], bl[2*p+1][1],
                              bL + (uint32_t)(p * 16 * STR + kk) * 2);
                    }
#pragma unroll
                    for (int mi = 0; mi < MI; mi++)
#pragma unroll
                        for (int ni = 0; ni < NI; ni++) {
                            mma16816(acc[mi][ni][0], acc[mi][ni][1], acc[mi][ni][2], acc[mi][ni][3],
                                     ah[mi][0], ah[mi][1], ah[mi][2], ah[mi][3], bh[ni][0], bh[ni][1]);
                            mma16816(acc[mi][ni][0], acc[mi][ni][1], acc[mi][ni][2], acc[mi][ni][3],
                                     ah[mi][0], ah[mi][1], ah[mi][2], ah[mi][3], bl[ni][0], bl[ni][1]);
                        }
                }
                __syncthreads();
            }
        }

        // ---- Cell epilogue (c in registers) ----
        const float* zwb = ZW + (size_t)t * B_DIM * G_DIM;
        unsigned short* hh = H_h + (size_t)t * B_DIM * H_DIM;
#pragma unroll
        for (int mi = 0; mi < MI; mi++) {
            int row0 = m0 + wm0 + mi * 16 + g;
#pragma unroll
            for (int ni = 0; ni < NI; ni++) {
                int col = n0 + wn0 + ni * 8 + 2 * t4;
                float c0 = acc[mi][ni][0], c1 = acc[mi][ni][1];
                float c2 = acc[mi][ni][2], c3 = acc[mi][ni][3];
                float sx = __shfl_xor_sync(0xffffffffu, hi_half ? c0 : c2, 1);
                float sy = __shfl_xor_sync(0xffffffffu, hi_half ? c1 : c3, 1);
                int row = hi_half ? row0 + 8 : row0;
                float gi, gf, gg, go;
                if (!hi_half) { gi = c0; gf = c1; gg = sx; go = sy; }
                else          { gi = sx; gf = sy; gg = c2; go = c3; }

                int base = col & ~3;
                float4 zw = *(const float4*)(zwb + (size_t)row * G_DIM + base);
                gi += zw.x; gf += zw.y; gg += zw.z; go += zw.w;

                float ig = 1.f / (1.f + expf(-gi));
                float fg = 1.f / (1.f + expf(-gf));
                float gt = tanhf(gg);
                float og = 1.f / (1.f + expf(-go));

                float cn = fg * creg[mi][ni] + ig * gt;
                creg[mi][ni] = cn;
                hh[(size_t)row * H_DIM + (col >> 2)] = h_of(og * tanhf(cn));
            }
        }

        // ---- Grid barrier between steps ----
        if (t < T_DIM - 1) {
            __syncthreads();
            if (tid == 0) {
                __threadfence();
                atomicAdd(&g_bar_ctr, 1u);
                unsigned target = (unsigned)(t + 1) * GRID_P;
                while (atomicAdd(&g_bar_ctr, 0u) < target) { }
            }
            __syncthreads();
        }
    }

    // Deterministic counter reset for graph replay
    __syncthreads();
    if (tid == 0) {
        unsigned d = atomicAdd(&g_done_ctr, 1u);
        if (d == GRID_P - 1) {
            g_bar_ctr = 0;
            g_done_ctr = 0;
            __threadfence();
        }
    }
}

// ---------------------------------------------------------------------------
// f32x2 SGEMM (label MLP), 64x64 tiles. OUT: 0 fp32, 1 single fp16.
// ---------------------------------------------------------------------------
__device__ __forceinline__ void ffma2(unsigned long long& d,
                                      unsigned long long a,
                                      unsigned long long b) {
    asm("fma.rn.f32x2 %0, %1, %2, %0;" : "+l"(d) : "l"(a), "l"(b));
}
__device__ __forceinline__ unsigned long long pack2(float lo, float hi) {
    unsigned long long r;
    asm("mov.b64 %0, {%1, %2};" : "=l"(r) : "f"(lo), "f"(hi));
    return r;
}
__device__ __forceinline__ float2 unpack2(unsigned long long u) {
    float2 f;
    asm("mov.b64 {%0, %1}, %2;" : "=f"(f.x), "=f"(f.y) : "l"(u));
    return f;
}

template<int BM, int BN, int BK, int TM, int TN, int ACT, int OUT>
__global__ void gemm2_kernel(const float* __restrict__ A,
                             const float* __restrict__ W,
                             const float* __restrict__ bias,
                             float* __restrict__ C,
                             unsigned short* __restrict__ uh,
                             int M, int N, int K)
{
    constexpr int AS_STRIDE = BM + 4;
    constexpr int WS_STRIDE = BN + 4;
    __shared__ float As[BK][AS_STRIDE];
    __shared__ float Ws[BK][WS_STRIDE];

    constexpr int NTH = (BM / TM) * (BN / TN);
    const int tid = threadIdx.x;
    const int tx = tid % (BN / TN);
    const int ty = tid / (BN / TN);
    const int m0 = blockIdx.y * BM;
    const int n0 = blockIdx.x * BN;

    unsigned long long acc2[TM / 2][TN];
#pragma unroll
    for (int p = 0; p < TM / 2; p++)
#pragma unroll
        for (int j = 0; j < TN; j++) acc2[p][j] = 0ULL;

    for (int k0 = 0; k0 < K; k0 += BK) {
#pragma unroll
        for (int i = tid * 4; i < BM * BK; i += NTH * 4) {
            int m = i / BK, k = i % BK;
            float4 v = *(const float4*)(A + (long)(m0 + m) * K + (k0 + k));
            As[k + 0][m] = v.x; As[k + 1][m] = v.y;
            As[k + 2][m] = v.z; As[k + 3][m] = v.w;
        }
#pragma unroll
        for (int i = tid * 4; i < BN * BK; i += NTH * 4) {
            int n = i / BK, k = i % BK;
            float4 v = *(const float4*)(W + (long)(n0 + n) * K + (k0 + k));
            Ws[k + 0][n] = v.x; Ws[k + 1][n] = v.y;
            Ws[k + 2][n] = v.z; Ws[k + 3][n] = v.w;
        }
        __syncthreads();

#pragma unroll
        for (int k = 0; k < BK; k++) {
            unsigned long long am2[TM / 2];
            const ulonglong2* ap = reinterpret_cast<const ulonglong2*>(&As[k][ty * TM]);
#pragma unroll
            for (int q = 0; q < TM / 4; q++) {
                ulonglong2 tt = ap[q];
                am2[2 * q + 0] = tt.x;
                am2[2 * q + 1] = tt.y;
            }
            float4 w4 = *reinterpret_cast<const float4*>(&Ws[k][tx * TN]);
            unsigned long long wd[TN];
            wd[0] = pack2(w4.x, w4.x); wd[1] = pack2(w4.y, w4.y);
            wd[2] = pack2(w4.z, w4.z); wd[3] = pack2(w4.w, w4.w);
#pragma unroll
            for (int p = 0; p < TM / 2; p++)
#pragma unroll
                for (int j = 0; j < TN; j++) ffma2(acc2[p][j], am2[p], wd[j]);
        }
        __syncthreads();
    }

    float4 bv = make_float4(0.f, 0.f, 0.f, 0.f);
    if (bias) bv = *reinterpret_cast<const float4*>(bias + n0 + tx * TN);

#pragma unroll
    for (int p = 0; p < TM / 2; p++) {
        float2 v0 = unpack2(acc2[p][0]);
        float2 v1 = unpack2(acc2[p][1]);
        float2 v2 = unpack2(acc2[p][2]);
        float2 v3 = unpack2(acc2[p][3]);
        float4 rowA = make_float4(v0.x + bv.x, v1.x + bv.y, v2.x + bv.z, v3.x + bv.w);
        float4 rowB = make_float4(v0.y + bv.x, v1.y + bv.y, v2.y + bv.z, v3.y + bv.w);
        if (ACT == 1) {
            rowA.x = fmaxf(rowA.x, 0.f); rowA.y = fmaxf(rowA.y, 0.f);
            rowA.z = fmaxf(rowA.z, 0.f); rowA.w = fmaxf(rowA.w, 0.f);
            rowB.x = fmaxf(rowB.x, 0.f); rowB.y = fmaxf(rowB.y, 0.f);
            rowB.z = fmaxf(rowB.z, 0.f); rowB.w = fmaxf(rowB.w, 0.f);
        }
        int mA = m0 + ty * TM + 2 * p;
        int n  = n0 + tx * TN;
        if (OUT == 0) {
            *reinterpret_cast<float4*>(C + (long)mA * N + n) = rowA;
            *reinterpret_cast<float4*>(C + (long)(mA + 1) * N + n) = rowB;
        } else {
            *(ushort4*)(uh + (size_t)mA * N + n) =
                make_ushort4(h_of(rowA.x), h_of(rowA.y), h_of(rowA.z), h_of(rowA.w));
            *(ushort4*)(uh + (size_t)(mA + 1) * N + n) =
                make_ushort4(h_of(rowB.x), h_of(rowB.y), h_of(rowB.z), h_of(rowB.w));
        }
    }
}

// ---------------------------------------------------------------------------
// Prep kernels
// ---------------------------------------------------------------------------
__device__ __forceinline__ void split4w(const float4* src, int i,
                                        ushort4* hi, ushort4* lo) {
    float4 v = src[i];
    ushort4 h, l;
    hsplit(v.x, h.x, l.x); hsplit(v.y, h.y, l.y);
    hsplit(v.z, h.z, l.z); hsplit(v.w, h.w, l.w);
    hi[i] = h; lo[i] = l;
}

__device__ __forceinline__ void permsplit4w(const float* src, int i,
                                            ushort4* hi, ushort4* lo) {
    int r = i / (H_DIM / 4);
    int c = i % (H_DIM / 4);
    int j = r >> 2, gg = r & 3;
    float4 v = ((const float4*)src)[(size_t)(gg * H_DIM + j) * (H_DIM / 4) + c];
    ushort4 h, l;
    hsplit(v.x, h.x, l.x); hsplit(v.y, h.y, l.y);
    hsplit(v.z, h.z, l.z); hsplit(v.w, h.w, l.w);
    size_t o = (size_t)r * (H_DIM / 4) + c;
    hi[o] = h; lo[o] = l;
}

__global__ void prep_weights(const float* __restrict__ P1, const float* __restrict__ P2,
                             const float* __restrict__ P3,
                             const float* __restrict__ Wih, const float* __restrict__ Whh,
                             const float* __restrict__ bih, const float* __restrict__ bhh,
                             ushort4* P1h, ushort4* P1l, ushort4* P2h, ushort4* P2l,
                             ushort4* P3h, ushort4* P3l,
                             ushort4* Wihh, ushort4* Wihl, ushort4* Whhh, ushort4* Whhl,
                             float* bp)
{
    const int S0 = H_DIM * H_DIM / 4;
    const int S1 = S0 + H_DIM * H_DIM / 4;
    const int S2 = S1 + D_DIM * H_DIM / 4;
    const int S3 = S2 + G_DIM * H_DIM / 4;
    const int S4 = S3 + G_DIM * H_DIM / 4;
    int i = blockIdx.x * blockDim.x + threadIdx.x;
    if      (i < S0) split4w((const float4*)P1, i, P1h, P1l);
    else if (i < S1) split4w((const float4*)P2, i - S0, P2h, P2l);
    else if (i < S2) split4w((const float4*)P3, i - S1, P3h, P3l);
    else if (i < S3) permsplit4w(Wih, i - S2, Wihh, Wihl);
    else if (i < S4) permsplit4w(Whh, i - S3, Whhh, Whhl);
    else if (i < S4 + G_DIM) {
        int k = i - S4;
        int j = k >> 2, gg = k & 3;
        bp[k] = bih[gg * H_DIM + j] + bhh[gg * H_DIM + j];
    }
}

// z -> single fp16
__global__ void cvt_half_kernel(const float4* __restrict__ src,
                                ushort4* __restrict__ dst, int n4)
{
    int i = blockIdx.x * blockDim.x + threadIdx.x;
    if (i >= n4) return;
    float4 v = src[i];
    dst[i] = make_ushort4(h_of(v.x), h_of(v.y), h_of(v.z), h_of(v.w));
}

// ---------------------------------------------------------------------------
// Launch
// ---------------------------------------------------------------------------
extern "C" void kernel_launch(void* const* d_in, const int* in_sizes, int n_in,
                              void* d_out, int out_size)
{
    const float* labels = (const float*)d_in[0];
    const float* z      = (const float*)d_in[1];
    const float* W1     = (const float*)d_in[2];
    const float* b1     = (const float*)d_in[3];
    const float* W2     = (const float*)d_in[4];
    const float* b2     = (const float*)d_in[5];
    const float* W3     = (const float*)d_in[6];
    const float* Wih    = (const float*)d_in[7];
    const float* Whh    = (const float*)d_in[8];
    const float* bih    = (const float*)d_in[9];
    const float* bhh    = (const float*)d_in[10];
    const float* P1     = (const float*)d_in[11];
    const float* pb1    = (const float*)d_in[12];
    const float* P2     = (const float*)d_in[13];
    const float* pb2    = (const float*)d_in[14];
    const float* P3     = (const float*)d_in[15];
    const float* pb3    = (const float*)d_in[16];
    float* out = (float*)d_out;

    float *x1, *x2, *bperm, *CWB, *ZW;
    unsigned short *conds_h, *Wih_h, *Wih_l, *Whh_h, *Whh_l;
    unsigned short *P1_h, *P1_l, *P2_h, *P2_l, *P3_h, *P3_l;
    unsigned short *z_h, *H_h, *y1_h, *y2_h;
    cudaGetSymbolAddress((void**)&x1,     g_x1);
    cudaGetSymbolAddress((void**)&x2,     g_x2);
    cudaGetSymbolAddress((void**)&bperm,  g_bperm);
    cudaGetSymbolAddress((void**)&conds_h, g_conds_h);
    cudaGetSymbolAddress((void**)&Wih_h,  g_Wih_h);
    cudaGetSymbolAddress((void**)&Wih_l,  g_Wih_l);
    cudaGetSymbolAddress((void**)&Whh_h,  g_Whh_h);
    cudaGetSymbolAddress((void**)&Whh_l,  g_Whh_l);
    cudaGetSymbolAddress((void**)&P1_h,   g_P1_h);
    cudaGetSymbolAddress((void**)&P1_l,   g_P1_l);
    cudaGetSymbolAddress((void**)&P2_h,   g_P2_h);
    cudaGetSymbolAddress((void**)&P2_l,   g_P2_l);
    cudaGetSymbolAddress((void**)&P3_h,   g_P3_h);
    cudaGetSymbolAddress((void**)&P3_l,   g_P3_l);
    cudaGetSymbolAddress((void**)&CWB,    g_CWB);
    cudaGetSymbolAddress((void**)&z_h,    g_z_h);
    cudaGetSymbolAddress((void**)&ZW,     g_ZW);
    cudaGetSymbolAddress((void**)&H_h,    g_H_h);
    cudaGetSymbolAddress((void**)&y1_h,   g_y1_h);
    cudaGetSymbolAddress((void**)&y2_h,   g_y2_h);

    const int TB = TB_DIM;

    // Dynamic smem (BK=32, STR=40): 2 stages x (A + 2B tiles)
    constexpr int SM128 = 2 * (128 * 40 + 2 * 128 * 40) * 2;  // 61440 B
    constexpr int SM64B = 2 * (128 * 40 + 2 * 64 * 40) * 2;   // 40960 B (BN=64)
    constexpr int SMP   = 2 * (64 * 40 + 2 * 128 * 40) * 2;   // 51200 B (persistent)
    cudaFuncSetAttribute((const void*)hgemm<128,128,64,32,0,0>,
                         cudaFuncAttributeMaxDynamicSharedMemorySize, SM128);
    cudaFuncSetAttribute((const void*)hgemm<128,128,64,32,1,0>,
                         cudaFuncAttributeMaxDynamicSharedMemorySize, SM128);
    cudaFuncSetAttribute((const void*)hgemm<128,128,64,32,2,1>,
                         cudaFuncAttributeMaxDynamicSharedMemorySize, SM128);
    cudaFuncSetAttribute((const void*)hgemm<128,64,64,16,3,0>,
                         cudaFuncAttributeMaxDynamicSharedMemorySize, SM64B);
    cudaFuncSetAttribute((const void*)lstm_persistent,
                         cudaFuncAttributeMaxDynamicSharedMemorySize, SMP);

    // [0] fused weight prep
    {
        const int total = 2 * (H_DIM * H_DIM / 4) + D_DIM * H_DIM / 4
                        + 2 * (G_DIM * H_DIM / 4) + G_DIM;
        prep_weights<<<(total + 255) / 256, 256>>>(
            P1, P2, P3, Wih, Whh, bih, bhh,
            (ushort4*)P1_h, (ushort4*)P1_l, (ushort4*)P2_h, (ushort4*)P2_l,
            (ushort4*)P3_h, (ushort4*)P3_l,
            (ushort4*)Wih_h, (ushort4*)Wih_l, (ushort4*)Whh_h, (ushort4*)Whh_l,
            bperm);
    }
    // [1] z -> fp16
    cvt_half_kernel<<<(int)(((size_t)TB * H_DIM / 4) / 256), 256>>>(
        (const float4*)z, (ushort4*)z_h, TB * (H_DIM / 4));

    // [2..4] Label MLP (f32x2, 64x64 tiles); last layer writes conds fp16
    gemm2_kernel<64,64,16,4,4,1,0><<<dim3(H_DIM/64, B_DIM/64), 256>>>(
        labels, W1, b1, x1, nullptr, B_DIM, H_DIM, L_DIM);
    gemm2_kernel<64,64,16,4,4,1,0><<<dim3(H_DIM/64, B_DIM/64), 256>>>(
        x1, W2, b2, x2, nullptr, B_DIM, H_DIM, H_DIM);
    gemm2_kernel<64,64,16,4,4,0,1><<<dim3(H_DIM/64, B_DIM/64), 256>>>(
        x2, W3, nullptr, nullptr, conds_h, B_DIM, H_DIM, H_DIM);

    // [5] CWB = conds @ Wih_perm^T + (bih+bhh)_perm
    hgemm<128,128,64,32,0,0><<<dim3(G_DIM/128, B_DIM/128), 256, SM128>>>(
        conds_h, Wih_h, Wih_l, bperm, nullptr,
        CWB, nullptr, B_DIM, G_DIM, H_DIM);
    // [6] ZW = z @ Wih_perm^T + CWB[row % B]
    hgemm<128,128,64,32,1,0><<<dim3(G_DIM/128, TB/128), 256, SM128>>>(
        z_h, Wih_h, Wih_l, nullptr, CWB,
        ZW, nullptr, TB, G_DIM, H_DIM);

    // [7] Persistent recurrence (one launch, 256 CTAs @ 2/SM)
    lstm_persistent<<<GRID_P, 256, SMP>>>(Whh_h, Whh_l, ZW, H_h);

    // [8..10] Projection MLP over all T*B rows
    hgemm<128,128,64,32,2,1><<<dim3(H_DIM/128, TB/128), 256, SM128>>>(
        H_h, P1_h, P1_l, pb1, nullptr,
        nullptr, y1_h, TB, H_DIM, H_DIM);
    hgemm<128,128,64,32,2,1><<<dim3(H_DIM/128, TB/128), 256, SM128>>>(
        y1_h, P2_h, P2_l, pb2, nullptr,
        nullptr, y2_h, TB, H_DIM, H_DIM);
    hgemm<128,64,64,16,3,0><<<dim3(D_DIM/64, TB/128), 256, SM64B>>>(
        y2_h, P3_h, P3_l, pb3, nullptr,
        out, nullptr, TB, D_DIM, H_DIM);
}

// round 11
// speedup vs baseline: 4.3999x; 1.0969x over previous
#include <cuda_runtime.h>
#include <cuda_fp16.h>
#include <math.h>
#include <stdint.h>

// Problem dims (fixed by the dataset)
#define B_DIM 1024
#define T_DIM 128
#define L_DIM 16
#define H_DIM 512
#define D_DIM 64
#define G_DIM 2048          // 4*H
#define TB_DIM (T_DIM * B_DIM)
#define GRID_P 256          // persistent recurrence grid (2 CTAs/SM)

// ---------------------------------------------------------------------------
// Scratch. Activations: single fp16 (ushort). Weights: fp16 hi/lo pairs.
// ---------------------------------------------------------------------------
__device__ float    g_x1[B_DIM * H_DIM];
__device__ float    g_x2[B_DIM * H_DIM];
__device__ float    g_bperm[G_DIM];
__device__ unsigned short g_conds_h[B_DIM * H_DIM];
__device__ unsigned short g_Wih_h[G_DIM * H_DIM];
__device__ unsigned short g_Wih_l[G_DIM * H_DIM];
__device__ unsigned short g_Whh_h[G_DIM * H_DIM];
__device__ unsigned short g_Whh_l[G_DIM * H_DIM];
__device__ unsigned short g_P1_h[H_DIM * H_DIM];
__device__ unsigned short g_P1_l[H_DIM * H_DIM];
__device__ unsigned short g_P2_h[H_DIM * H_DIM];
__device__ unsigned short g_P2_l[H_DIM * H_DIM];
__device__ unsigned short g_P3_h[D_DIM * H_DIM];
__device__ unsigned short g_P3_l[D_DIM * H_DIM];
__device__ float    g_CWB[B_DIM * G_DIM];
__device__ unsigned short g_z_h[(size_t)TB_DIM * H_DIM];   // 128 MB
__device__ float    g_ZW[(size_t)TB_DIM * G_DIM];          // 1 GB
__device__ unsigned short g_H_h[(size_t)TB_DIM * H_DIM];
__device__ unsigned short g_y1_h[(size_t)TB_DIM * H_DIM];
__device__ unsigned short g_y2_h[(size_t)TB_DIM * H_DIM];

// Persistent-kernel grid barrier (monotonic; self-reset at kernel end)
__device__ unsigned g_bar_ctr  = 0;
__device__ unsigned g_done_ctr = 0;

// ---------------------------------------------------------------------------
// Helpers
// ---------------------------------------------------------------------------
__device__ __forceinline__ unsigned short h_of(float x) {
    return __half_as_ushort(__float2half_rn(x));
}
__device__ __forceinline__ void hsplit(float x, unsigned short& hi, unsigned short& lo) {
    __half h = __float2half_rn(x);
    float r = x - __half2float(h);
    __half l = __float2half_rn(r);
    hi = __half_as_ushort(h);
    lo = __half_as_ushort(l);
}

// mma m16n8k16 row.col fp16 -> f32
__device__ __forceinline__ void mma16816(float& c0, float& c1, float& c2, float& c3,
                                         unsigned a0, unsigned a1, unsigned a2, unsigned a3,
                                         unsigned b0, unsigned b1) {
    asm volatile(
        "mma.sync.aligned.m16n8k16.row.col.f32.f16.f16.f32 "
        "{%0,%1,%2,%3}, {%4,%5,%6,%7}, {%8,%9}, {%0,%1,%2,%3};\n"
        : "+f"(c0), "+f"(c1), "+f"(c2), "+f"(c3)
        : "r"(a0), "r"(a1), "r"(a2), "r"(a3), "r"(b0), "r"(b1));
}

__device__ __forceinline__ void ldsm4(unsigned& r0, unsigned& r1,
                                      unsigned& r2, unsigned& r3, uint32_t a) {
    asm volatile("ldmatrix.sync.aligned.m8n8.x4.shared.b16 {%0,%1,%2,%3}, [%4];"
                 : "=r"(r0), "=r"(r1), "=r"(r2), "=r"(r3) : "r"(a));
}

__device__ __forceinline__ void cp_async16(void* sptr, const void* gptr) {
    unsigned sa = (unsigned)__cvta_generic_to_shared(sptr);
    asm volatile("cp.async.cg.shared.global [%0], [%1], 16;\n" :: "r"(sa), "l"(gptr));
}
__device__ __forceinline__ void cp_commit() {
    asm volatile("cp.async.commit_group;\n");
}
template<int N>
__device__ __forceinline__ void cp_wait() {
    asm volatile("cp.async.wait_group %0;\n" :: "n"(N));
}

// ---------------------------------------------------------------------------
// fp16 GEMM: D[M,N] = A@B^T, A single fp16, B = Bh (+ Bl if TERMS==2).
// BK=32 2-stage cp.async, ldmatrix fragments, STR=40 ushorts (conflict-free).
// EPI: 0 = fp32 + bias (CWB)
//      1 = fp32 + addvec[row % B] (ZW build, CWB fold)
//      2 = fp16 out + bias (+relu if ACT)    (P1, P2)
//      3 = fp32 + bias, [T,B]->[B,T] perm    (P3)
// ---------------------------------------------------------------------------
template<int BM, int BN, int WM, int WN, int EPI, int ACT, int TERMS>
__global__ void __launch_bounds__((BM / WM) * (BN / WN) * 32, 2)
hgemm(const unsigned short* __restrict__ A,
      const unsigned short* __restrict__ Bh, const unsigned short* __restrict__ Bl,
      const float* __restrict__ bias,
      const float* __restrict__ addvec,
      float* __restrict__ outf,
      unsigned short* __restrict__ outh,
      int M, int N, int K)
{
    constexpr int BK = 32;
    constexpr int STR = BK + 8;              // 40 ushorts
    constexpr int ATI = BM * STR;
    constexpr int BTI = BN * STR;
    constexpr int STAGE = ATI + TERMS * BTI;
    constexpr int WARPS_N = BN / WN;
    constexpr int NTH = (BM / WM) * (BN / WN) * 32;
    constexpr int MI = WM / 16, NI = WN / 8;

    extern __shared__ unsigned short sm[];

    const int tid  = threadIdx.x;
    const int warp = tid >> 5, lane = tid & 31;
    const int g = lane >> 2, t = lane & 3;
    const int wm0 = (warp / WARPS_N) * WM;
    const int wn0 = (warp % WARPS_N) * WN;
    const int m0 = blockIdx.y * BM;
    const int n0 = blockIdx.x * BN;

    const uint32_t smb = (uint32_t)__cvta_generic_to_shared(sm);
    const int aRow = (lane & 7) + ((lane >> 3) & 1) * 8;
    const int aKh  = (lane >> 4) * 16;
    const int bRow = (lane & 7) + (lane >> 4) * 8;
    const int bKh  = ((lane >> 3) & 1) * 16;
    const uint32_t aBase = smb + (uint32_t)(wm0 + aRow) * STR * 2 + aKh;
    const uint32_t bBase = smb + (uint32_t)(ATI + (wn0 + bRow) * STR) * 2 + bKh;

    float acc[MI][NI][4];
#pragma unroll
    for (int mi = 0; mi < MI; mi++)
#pragma unroll
        for (int ni = 0; ni < NI; ni++)
#pragma unroll
            for (int q = 0; q < 4; q++) acc[mi][ni][q] = 0.f;

    auto load_stage = [&](int k0, int s) {
        unsigned short* st = sm + s * STAGE;
#pragma unroll
        for (int i = tid; i < BM * 4; i += NTH) {
            int r = i >> 2, c = i & 3;
            cp_async16(st + r * STR + c * 8, A + (size_t)(m0 + r) * K + k0 + c * 8);
        }
#pragma unroll
        for (int i = tid; i < BN * 4; i += NTH) {
            int r = i >> 2, c = i & 3;
            const size_t gs = (size_t)(n0 + r) * K + k0 + c * 8;
            cp_async16(st + ATI + r * STR + c * 8, Bh + gs);
            if (TERMS == 2)
                cp_async16(st + ATI + BTI + r * STR + c * 8, Bl + gs);
        }
        cp_commit();
    };

    const int KT = K / BK;
    load_stage(0, 0);

    for (int kt = 0; kt < KT; kt++) {
        const int s = kt & 1;
        if (kt + 1 < KT) { load_stage((kt + 1) * BK, s ^ 1); cp_wait<1>(); }
        else             { cp_wait<0>(); }
        __syncthreads();

        const uint32_t stOff = (uint32_t)(s * STAGE) * 2;
        const uint32_t aA = aBase + stOff;
        const uint32_t bH = bBase + stOff;
        const uint32_t bL = bH + (uint32_t)BTI * 2;

#pragma unroll
        for (int kk = 0; kk < BK; kk += 16) {
            unsigned ah[MI][4], bh[NI][2], bl[NI][2];
#pragma unroll
            for (int mi = 0; mi < MI; mi++)
                ldsm4(ah[mi][0], ah[mi][1], ah[mi][2], ah[mi][3],
                      aA + (uint32_t)(mi * 16 * STR + kk) * 2);
#pragma unroll
            for (int p = 0; p < NI / 2; p++) {
                ldsm4(bh[2*p][0], bh[2*p][1], bh[2*p+1][0], bh[2*p+1][1],
                      bH + (uint32_t)(p * 16 * STR + kk) * 2);
                if (TERMS == 2)
                    ldsm4(bl[2*p][0], bl[2*p][1], bl[2*p+1][0], bl[2*p+1][1],
                          bL + (uint32_t)(p * 16 * STR + kk) * 2);
            }
#pragma unroll
            for (int mi = 0; mi < MI; mi++)
#pragma unroll
                for (int ni = 0; ni < NI; ni++) {
                    mma16816(acc[mi][ni][0], acc[mi][ni][1], acc[mi][ni][2], acc[mi][ni][3],
                             ah[mi][0], ah[mi][1], ah[mi][2], ah[mi][3], bh[ni][0], bh[ni][1]);
                    if (TERMS == 2)
                        mma16816(acc[mi][ni][0], acc[mi][ni][1], acc[mi][ni][2], acc[mi][ni][3],
                                 ah[mi][0], ah[mi][1], ah[mi][2], ah[mi][3], bl[ni][0], bl[ni][1]);
                }
        }
        __syncthreads();
    }

    // ---- Epilogues ----
    if (EPI == 0 || EPI == 2 || EPI == 3) {
        float2 bv[NI];
#pragma unroll
        for (int ni = 0; ni < NI; ni++)
            bv[ni] = *(const float2*)(bias + n0 + wn0 + ni * 8 + 2 * t);

#pragma unroll
        for (int mi = 0; mi < MI; mi++) {
            int row0 = m0 + wm0 + mi * 16 + g;
#pragma unroll
            for (int ni = 0; ni < NI; ni++) {
                int col = n0 + wn0 + ni * 8 + 2 * t;
                float v0 = acc[mi][ni][0] + bv[ni].x;
                float v1 = acc[mi][ni][1] + bv[ni].y;
                float v2 = acc[mi][ni][2] + bv[ni].x;
                float v3 = acc[mi][ni][3] + bv[ni].y;
                if (ACT == 1) {
                    v0 = fmaxf(v0, 0.f); v1 = fmaxf(v1, 0.f);
                    v2 = fmaxf(v2, 0.f); v3 = fmaxf(v3, 0.f);
                }
                if (EPI == 0) {
                    *(float2*)(outf + (size_t)row0 * N + col)       = make_float2(v0, v1);
                    *(float2*)(outf + (size_t)(row0 + 8) * N + col) = make_float2(v2, v3);
                } else if (EPI == 2) {
                    *(ushort2*)(outh + (size_t)row0 * N + col) =
                        make_ushort2(h_of(v0), h_of(v1));
                    *(ushort2*)(outh + (size_t)(row0 + 8) * N + col) =
                        make_ushort2(h_of(v2), h_of(v3));
                } else {
                    int tt0 = row0 / B_DIM, bb0 = row0 % B_DIM;
                    int r1 = row0 + 8;
                    int tt1 = r1 / B_DIM, bb1 = r1 % B_DIM;
                    *(float2*)(outf + ((size_t)bb0 * T_DIM + tt0) * D_DIM + col) = make_float2(v0, v1);
                    *(float2*)(outf + ((size_t)bb1 * T_DIM + tt1) * D_DIM + col) = make_float2(v2, v3);
                }
            }
        }
    } else {
        // EPI == 1
#pragma unroll
        for (int mi = 0; mi < MI; mi++) {
            int row0 = m0 + wm0 + mi * 16 + g;
#pragma unroll
            for (int ni = 0; ni < NI; ni++) {
                int col = n0 + wn0 + ni * 8 + 2 * t;
                float2 a0 = *(const float2*)(addvec + (size_t)(row0 & (B_DIM - 1)) * N + col);
                float2 a1 = *(const float2*)(addvec + (size_t)((row0 + 8) & (B_DIM - 1)) * N + col);
                *(float2*)(outf + (size_t)row0 * N + col) =
                    make_float2(acc[mi][ni][0] + a0.x, acc[mi][ni][1] + a0.y);
                *(float2*)(outf + (size_t)(row0 + 8) * N + col) =
                    make_float2(acc[mi][ni][2] + a1.x, acc[mi][ni][3] + a1.y);
            }
        }
    }
}

// ---------------------------------------------------------------------------
// Persistent LSTM recurrence: 256 CTAs (2/SM), tile 64x128, BK=32, fp16 2-term.
// A = H (single fp16), B = Whh hi/lo. c-state in registers; grid barrier.
// ---------------------------------------------------------------------------
__global__ void __launch_bounds__(256, 2)
lstm_persistent(const unsigned short* __restrict__ Whh_h,
                const unsigned short* __restrict__ Whh_l,
                const float* __restrict__ ZW,        // [T][B][G] (perm cols)
                unsigned short* __restrict__ H_h)
{
    constexpr int BM = 64, BN = 128, BK = 32, WM = 32, WN = 32;
    constexpr int STR = BK + 8;
    constexpr int ATI = BM * STR, BTI = BN * STR;
    constexpr int STAGE = ATI + 2 * BTI;
    constexpr int WARPS_N = BN / WN;
    constexpr int NTH = 256;
    constexpr int MI = WM / 16, NI = WN / 8;   // 2, 4
    constexpr int K = H_DIM, N = G_DIM;
    constexpr int KT = K / BK;

    extern __shared__ unsigned short sm[];

    const int tid  = threadIdx.x;
    const int warp = tid >> 5, lane = tid & 31;
    const int g = lane >> 2, t4 = lane & 3;
    const int wm0 = (warp / WARPS_N) * WM;
    const int wn0 = (warp % WARPS_N) * WN;
    const int bid = blockIdx.x;
    const int m0 = (bid >> 4) * BM;
    const int n0 = (bid & 15) * BN;

    const uint32_t smb = (uint32_t)__cvta_generic_to_shared(sm);
    const int aRow = (lane & 7) + ((lane >> 3) & 1) * 8;
    const int aKh  = (lane >> 4) * 16;
    const int bRow = (lane & 7) + (lane >> 4) * 8;
    const int bKh  = ((lane >> 3) & 1) * 16;
    const uint32_t aBase = smb + (uint32_t)(wm0 + aRow) * STR * 2 + aKh;
    const uint32_t bBase = smb + (uint32_t)(ATI + (wn0 + bRow) * STR) * 2 + bKh;

    const bool hi_half = (t4 & 1);

    float creg[MI][NI];
#pragma unroll
    for (int mi = 0; mi < MI; mi++)
#pragma unroll
        for (int ni = 0; ni < NI; ni++) creg[mi][ni] = 0.f;

    for (int t = 0; t < T_DIM; t++) {
        float acc[MI][NI][4];
#pragma unroll
        for (int mi = 0; mi < MI; mi++)
#pragma unroll
            for (int ni = 0; ni < NI; ni++)
#pragma unroll
                for (int q = 0; q < 4; q++) acc[mi][ni][q] = 0.f;

        if (t > 0) {
            const unsigned short* Ah = H_h + (size_t)(t - 1) * B_DIM * H_DIM;

            auto load_stage = [&](int k0, int s) {
                unsigned short* st = sm + s * STAGE;
#pragma unroll
                for (int i = tid; i < BM * 4; i += NTH) {
                    int r = i >> 2, c = i & 3;
                    cp_async16(st + r * STR + c * 8, Ah + (size_t)(m0 + r) * K + k0 + c * 8);
                }
#pragma unroll
                for (int i = tid; i < BN * 4; i += NTH) {
                    int r = i >> 2, c = i & 3;
                    const size_t gs = (size_t)(n0 + r) * K + k0 + c * 8;
                    cp_async16(st + ATI + r * STR + c * 8,       Whh_h + gs);
                    cp_async16(st + ATI + BTI + r * STR + c * 8, Whh_l + gs);
                }
                cp_commit();
            };

            load_stage(0, 0);
            for (int kt = 0; kt < KT; kt++) {
                const int s = kt & 1;
                if (kt + 1 < KT) { load_stage((kt + 1) * BK, s ^ 1); cp_wait<1>(); }
                else             { cp_wait<0>(); }
                __syncthreads();

                const uint32_t stOff = (uint32_t)(s * STAGE) * 2;
                const uint32_t aA = aBase + stOff;
                const uint32_t bH = bBase + stOff;
                const uint32_t bL = bH + (uint32_t)BTI * 2;

#pragma unroll
                for (int kk = 0; kk < BK; kk += 16) {
                    unsigned ah[MI][4], bh[NI][2], bl[NI][2];
#pragma unroll
                    for (int mi = 0; mi < MI; mi++)
                        ldsm4(ah[mi][0], ah[mi][1], ah[mi][2], ah[mi][3],
                              aA + (uint32_t)(mi * 16 * STR + kk) * 2);
#pragma unroll
                    for (int p = 0; p < NI / 2; p++) {
                        ldsm4(bh[2*p][0], bh[2*p][1], bh[2*p+1][0], bh[2*p+1][1],
                              bH + (uint32_t)(p * 16 * STR + kk) * 2);
                        ldsm4(bl[2*p][0], bl[2*p][1], bl[2*p+1][0], bl[2*p+1][1],
                              bL + (uint32_t)(p * 16 * STR + kk) * 2);
                    }
#pragma unroll
                    for (int mi = 0; mi < MI; mi++)
#pragma unroll
                        for (int ni = 0; ni < NI; ni++) {
                            mma16816(acc[mi][ni][0], acc[mi][ni][1], acc[mi][ni][2], acc[mi][ni][3],
                                     ah[mi][0], ah[mi][1], ah[mi][2], ah[mi][3], bh[ni][0], bh[ni][1]);
                            mma16816(acc[mi][ni][0], acc[mi][ni][1], acc[mi][ni][2], acc[mi][ni][3],
                                     ah[mi][0], ah[mi][1], ah[mi][2], ah[mi][3], bl[ni][0], bl[ni][1]);
                        }
                }
                __syncthreads();
            }
        }

        // ---- Cell epilogue (c in registers) ----
        const float* zwb = ZW + (size_t)t * B_DIM * G_DIM;
        unsigned short* hh = H_h + (size_t)t * B_DIM * H_DIM;
#pragma unroll
        for (int mi = 0; mi < MI; mi++) {
            int row0 = m0 + wm0 + mi * 16 + g;
#pragma unroll
            for (int ni = 0; ni < NI; ni++) {
                int col = n0 + wn0 + ni * 8 + 2 * t4;
                float c0 = acc[mi][ni][0], c1 = acc[mi][ni][1];
                float c2 = acc[mi][ni][2], c3 = acc[mi][ni][3];
                float sx = __shfl_xor_sync(0xffffffffu, hi_half ? c0 : c2, 1);
                float sy = __shfl_xor_sync(0xffffffffu, hi_half ? c1 : c3, 1);
                int row = hi_half ? row0 + 8 : row0;
                float gi, gf, gg, go;
                if (!hi_half) { gi = c0; gf = c1; gg = sx; go = sy; }
                else          { gi = sx; gf = sy; gg = c2; go = c3; }

                int base = col & ~3;
                float4 zw = *(const float4*)(zwb + (size_t)row * G_DIM + base);
                gi += zw.x; gf += zw.y; gg += zw.z; go += zw.w;

                float ig = 1.f / (1.f + expf(-gi));
                float fg = 1.f / (1.f + expf(-gf));
                float gt = tanhf(gg);
                float og = 1.f / (1.f + expf(-go));

                float cn = fg * creg[mi][ni] + ig * gt;
                creg[mi][ni] = cn;
                hh[(size_t)row * H_DIM + (col >> 2)] = h_of(og * tanhf(cn));
            }
        }

        // ---- Grid barrier between steps ----
        if (t < T_DIM - 1) {
            __syncthreads();
            if (tid == 0) {
                __threadfence();
                atomicAdd(&g_bar_ctr, 1u);
                unsigned target = (unsigned)(t + 1) * GRID_P;
                while (atomicAdd(&g_bar_ctr, 0u) < target) { }
            }
            __syncthreads();
        }
    }

    // Deterministic counter reset for graph replay
    __syncthreads();
    if (tid == 0) {
        unsigned d = atomicAdd(&g_done_ctr, 1u);
        if (d == GRID_P - 1) {
            g_bar_ctr = 0;
            g_done_ctr = 0;
            __threadfence();
        }
    }
}

// ---------------------------------------------------------------------------
// f32x2 SGEMM (label MLP), 64x64 tiles. OUT: 0 fp32, 1 single fp16.
// ---------------------------------------------------------------------------
__device__ __forceinline__ void ffma2(unsigned long long& d,
                                      unsigned long long a,
                                      unsigned long long b) {
    asm("fma.rn.f32x2 %0, %1, %2, %0;" : "+l"(d) : "l"(a), "l"(b));
}
__device__ __forceinline__ unsigned long long pack2(float lo, float hi) {
    unsigned long long r;
    asm("mov.b64 %0, {%1, %2};" : "=l"(r) : "f"(lo), "f"(hi));
    return r;
}
__device__ __forceinline__ float2 unpack2(unsigned long long u) {
    float2 f;
    asm("mov.b64 {%0, %1}, %2;" : "=f"(f.x), "=f"(f.y) : "l"(u));
    return f;
}

template<int BM, int BN, int BK, int TM, int TN, int ACT, int OUT>
__global__ void gemm2_kernel(const float* __restrict__ A,
                             const float* __restrict__ W,
                             const float* __restrict__ bias,
                             float* __restrict__ C,
                             unsigned short* __restrict__ uh,
                             int M, int N, int K)
{
    constexpr int AS_STRIDE = BM + 4;
    constexpr int WS_STRIDE = BN + 4;
    __shared__ float As[BK][AS_STRIDE];
    __shared__ float Ws[BK][WS_STRIDE];

    constexpr int NTH = (BM / TM) * (BN / TN);
    const int tid = threadIdx.x;
    const int tx = tid % (BN / TN);
    const int ty = tid / (BN / TN);
    const int m0 = blockIdx.y * BM;
    const int n0 = blockIdx.x * BN;

    unsigned long long acc2[TM / 2][TN];
#pragma unroll
    for (int p = 0; p < TM / 2; p++)
#pragma unroll
        for (int j = 0; j < TN; j++) acc2[p][j] = 0ULL;

    for (int k0 = 0; k0 < K; k0 += BK) {
#pragma unroll
        for (int i = tid * 4; i < BM * BK; i += NTH * 4) {
            int m = i / BK, k = i % BK;
            float4 v = *(const float4*)(A + (long)(m0 + m) * K + (k0 + k));
            As[k + 0][m] = v.x; As[k + 1][m] = v.y;
            As[k + 2][m] = v.z; As[k + 3][m] = v.w;
        }
#pragma unroll
        for (int i = tid * 4; i < BN * BK; i += NTH * 4) {
            int n = i / BK, k = i % BK;
            float4 v = *(const float4*)(W + (long)(n0 + n) * K + (k0 + k));
            Ws[k + 0][n] = v.x; Ws[k + 1][n] = v.y;
            Ws[k + 2][n] = v.z; Ws[k + 3][n] = v.w;
        }
        __syncthreads();

#pragma unroll
        for (int k = 0; k < BK; k++) {
            unsigned long long am2[TM / 2];
            const ulonglong2* ap = reinterpret_cast<const ulonglong2*>(&As[k][ty * TM]);
#pragma unroll
            for (int q = 0; q < TM / 4; q++) {
                ulonglong2 tt = ap[q];
                am2[2 * q + 0] = tt.x;
                am2[2 * q + 1] = tt.y;
            }
            float4 w4 = *reinterpret_cast<const float4*>(&Ws[k][tx * TN]);
            unsigned long long wd[TN];
            wd[0] = pack2(w4.x, w4.x); wd[1] = pack2(w4.y, w4.y);
            wd[2] = pack2(w4.z, w4.z); wd[3] = pack2(w4.w, w4.w);
#pragma unroll
            for (int p = 0; p < TM / 2; p++)
#pragma unroll
                for (int j = 0; j < TN; j++) ffma2(acc2[p][j], am2[p], wd[j]);
        }
        __syncthreads();
    }

    float4 bv = make_float4(0.f, 0.f, 0.f, 0.f);
    if (bias) bv = *reinterpret_cast<const float4*>(bias + n0 + tx * TN);

#pragma unroll
    for (int p = 0; p < TM / 2; p++) {
        float2 v0 = unpack2(acc2[p][0]);
        float2 v1 = unpack2(acc2[p][1]);
        float2 v2 = unpack2(acc2[p][2]);
        float2 v3 = unpack2(acc2[p][3]);
        float4 rowA = make_float4(v0.x + bv.x, v1.x + bv.y, v2.x + bv.z, v3.x + bv.w);
        float4 rowB = make_float4(v0.y + bv.x, v1.y + bv.y, v2.y + bv.z, v3.y + bv.w);
        if (ACT == 1) {
            rowA.x = fmaxf(rowA.x, 0.f); rowA.y = fmaxf(rowA.y, 0.f);
            rowA.z = fmaxf(rowA.z, 0.f); rowA.w = fmaxf(rowA.w, 0.f);
            rowB.x = fmaxf(rowB.x, 0.f); rowB.y = fmaxf(rowB.y, 0.f);
            rowB.z = fmaxf(rowB.z, 0.f); rowB.w = fmaxf(rowB.w, 0.f);
        }
        int mA = m0 + ty * TM + 2 * p;
        int n  = n0 + tx * TN;
        if (OUT == 0) {
            *reinterpret_cast<float4*>(C + (long)mA * N + n) = rowA;
            *reinterpret_cast<float4*>(C + (long)(mA + 1) * N + n) = rowB;
        } else {
            *(ushort4*)(uh + (size_t)mA * N + n) =
                make_ushort4(h_of(rowA.x), h_of(rowA.y), h_of(rowA.z), h_of(rowA.w));
            *(ushort4*)(uh + (size_t)(mA + 1) * N + n) =
                make_ushort4(h_of(rowB.x), h_of(rowB.y), h_of(rowB.z), h_of(rowB.w));
        }
    }
}

// ---------------------------------------------------------------------------
// Prep kernels
// ---------------------------------------------------------------------------
__device__ __forceinline__ void split4w(const float4* src, int i,
                                        ushort4* hi, ushort4* lo) {
    float4 v = src[i];
    ushort4 h, l;
    hsplit(v.x, h.x, l.x); hsplit(v.y, h.y, l.y);
    hsplit(v.z, h.z, l.z); hsplit(v.w, h.w, l.w);
    hi[i] = h; lo[i] = l;
}

__device__ __forceinline__ void permsplit4w(const float* src, int i,
                                            ushort4* hi, ushort4* lo) {
    int r = i / (H_DIM / 4);
    int c = i % (H_DIM / 4);
    int j = r >> 2, gg = r & 3;
    float4 v = ((const float4*)src)[(size_t)(gg * H_DIM + j) * (H_DIM / 4) + c];
    ushort4 h, l;
    hsplit(v.x, h.x, l.x); hsplit(v.y, h.y, l.y);
    hsplit(v.z, h.z, l.z); hsplit(v.w, h.w, l.w);
    size_t o = (size_t)r * (H_DIM / 4) + c;
    hi[o] = h; lo[o] = l;
}

__global__ void prep_weights(const float* __restrict__ P1, const float* __restrict__ P2,
                             const float* __restrict__ P3,
                             const float* __restrict__ Wih, const float* __restrict__ Whh,
                             const float* __restrict__ bih, const float* __restrict__ bhh,
                             ushort4* P1h, ushort4* P1l, ushort4* P2h, ushort4* P2l,
                             ushort4* P3h, ushort4* P3l,
                             ushort4* Wihh, ushort4* Wihl, ushort4* Whhh, ushort4* Whhl,
                             float* bp)
{
    const int S0 = H_DIM * H_DIM / 4;
    const int S1 = S0 + H_DIM * H_DIM / 4;
    const int S2 = S1 + D_DIM * H_DIM / 4;
    const int S3 = S2 + G_DIM * H_DIM / 4;
    const int S4 = S3 + G_DIM * H_DIM / 4;
    int i = blockIdx.x * blockDim.x + threadIdx.x;
    if      (i < S0) split4w((const float4*)P1, i, P1h, P1l);
    else if (i < S1) split4w((const float4*)P2, i - S0, P2h, P2l);
    else if (i < S2) split4w((const float4*)P3, i - S1, P3h, P3l);
    else if (i < S3) permsplit4w(Wih, i - S2, Wihh, Wihl);
    else if (i < S4) permsplit4w(Whh, i - S3, Whhh, Whhl);
    else if (i < S4 + G_DIM) {
        int k = i - S4;
        int j = k >> 2, gg = k & 3;
        bp[k] = bih[gg * H_DIM + j] + bhh[gg * H_DIM + j];
    }
}

// z -> single fp16
__global__ void cvt_half_kernel(const float4* __restrict__ src,
                                ushort4* __restrict__ dst, int n4)
{
    int i = blockIdx.x * blockDim.x + threadIdx.x;
    if (i >= n4) return;
    float4 v = src[i];
    dst[i] = make_ushort4(h_of(v.x), h_of(v.y), h_of(v.z), h_of(v.w));
}

// ---------------------------------------------------------------------------
// Launch
// ---------------------------------------------------------------------------
extern "C" void kernel_launch(void* const* d_in, const int* in_sizes, int n_in,
                              void* d_out, int out_size)
{
    const float* labels = (const float*)d_in[0];
    const float* z      = (const float*)d_in[1];
    const float* W1     = (const float*)d_in[2];
    const float* b1     = (const float*)d_in[3];
    const float* W2     = (const float*)d_in[4];
    const float* b2     = (const float*)d_in[5];
    const float* W3     = (const float*)d_in[6];
    const float* Wih    = (const float*)d_in[7];
    const float* Whh    = (const float*)d_in[8];
    const float* bih    = (const float*)d_in[9];
    const float* bhh    = (const float*)d_in[10];
    const float* P1     = (const float*)d_in[11];
    const float* pb1    = (const float*)d_in[12];
    const float* P2     = (const float*)d_in[13];
    const float* pb2    = (const float*)d_in[14];
    const float* P3     = (const float*)d_in[15];
    const float* pb3    = (const float*)d_in[16];
    float* out = (float*)d_out;

    float *x1, *x2, *bperm, *CWB, *ZW;
    unsigned short *conds_h, *Wih_h, *Wih_l, *Whh_h, *Whh_l;
    unsigned short *P1_h, *P1_l, *P2_h, *P2_l, *P3_h, *P3_l;
    unsigned short *z_h, *H_h, *y1_h, *y2_h;
    cudaGetSymbolAddress((void**)&x1,     g_x1);
    cudaGetSymbolAddress((void**)&x2,     g_x2);
    cudaGetSymbolAddress((void**)&bperm,  g_bperm);
    cudaGetSymbolAddress((void**)&conds_h, g_conds_h);
    cudaGetSymbolAddress((void**)&Wih_h,  g_Wih_h);
    cudaGetSymbolAddress((void**)&Wih_l,  g_Wih_l);
    cudaGetSymbolAddress((void**)&Whh_h,  g_Whh_h);
    cudaGetSymbolAddress((void**)&Whh_l,  g_Whh_l);
    cudaGetSymbolAddress((void**)&P1_h,   g_P1_h);
    cudaGetSymbolAddress((void**)&P1_l,   g_P1_l);
    cudaGetSymbolAddress((void**)&P2_h,   g_P2_h);
    cudaGetSymbolAddress((void**)&P2_l,   g_P2_l);
    cudaGetSymbolAddress((void**)&P3_h,   g_P3_h);
    cudaGetSymbolAddress((void**)&P3_l,   g_P3_l);
    cudaGetSymbolAddress((void**)&CWB,    g_CWB);
    cudaGetSymbolAddress((void**)&z_h,    g_z_h);
    cudaGetSymbolAddress((void**)&ZW,     g_ZW);
    cudaGetSymbolAddress((void**)&H_h,    g_H_h);
    cudaGetSymbolAddress((void**)&y1_h,   g_y1_h);
    cudaGetSymbolAddress((void**)&y2_h,   g_y2_h);

    const int TB = TB_DIM;

    // Dynamic smem (BK=32, STR=40): 2 stages x (A + TERMS*B tiles)
    constexpr int SM128_T2 = 2 * (128 * 40 + 2 * 128 * 40) * 2;  // 61440 B
    constexpr int SM128_T1 = 2 * (128 * 40 + 1 * 128 * 40) * 2;  // 40960 B
    constexpr int SM64B    = 2 * (128 * 40 + 2 * 64 * 40) * 2;   // 40960 B (BN=64)
    constexpr int SMP      = 2 * (64 * 40 + 2 * 128 * 40) * 2;   // 51200 B (persistent)
    cudaFuncSetAttribute((const void*)hgemm<128,128,64,32,0,0,2>,
                         cudaFuncAttributeMaxDynamicSharedMemorySize, SM128_T2);
    cudaFuncSetAttribute((const void*)hgemm<128,128,64,32,1,0,1>,
                         cudaFuncAttributeMaxDynamicSharedMemorySize, SM128_T1);
    cudaFuncSetAttribute((const void*)hgemm<128,128,64,32,2,1,2>,
                         cudaFuncAttributeMaxDynamicSharedMemorySize, SM128_T2);
    cudaFuncSetAttribute((const void*)hgemm<128,64,64,16,3,0,2>,
                         cudaFuncAttributeMaxDynamicSharedMemorySize, SM64B);
    cudaFuncSetAttribute((const void*)lstm_persistent,
                         cudaFuncAttributeMaxDynamicSharedMemorySize, SMP);

    // [0] fused weight prep
    {
        const int total = 2 * (H_DIM * H_DIM / 4) + D_DIM * H_DIM / 4
                        + 2 * (G_DIM * H_DIM / 4) + G_DIM;
        prep_weights<<<(total + 255) / 256, 256>>>(
            P1, P2, P3, Wih, Whh, bih, bhh,
            (ushort4*)P1_h, (ushort4*)P1_l, (ushort4*)P2_h, (ushort4*)P2_l,
            (ushort4*)P3_h, (ushort4*)P3_l,
            (ushort4*)Wih_h, (ushort4*)Wih_l, (ushort4*)Whh_h, (ushort4*)Whh_l,
            bperm);
    }
    // [1] z -> fp16
    cvt_half_kernel<<<(int)(((size_t)TB * H_DIM / 4) / 256), 256>>>(
        (const float4*)z, (ushort4*)z_h, TB * (H_DIM / 4));

    // [2..4] Label MLP (f32x2, 64x64 tiles); last layer writes conds fp16
    gemm2_kernel<64,64,16,4,4,1,0><<<dim3(H_DIM/64, B_DIM/64), 256>>>(
        labels, W1, b1, x1, nullptr, B_DIM, H_DIM, L_DIM);
    gemm2_kernel<64,64,16,4,4,1,0><<<dim3(H_DIM/64, B_DIM/64), 256>>>(
        x1, W2, b2, x2, nullptr, B_DIM, H_DIM, H_DIM);
    gemm2_kernel<64,64,16,4,4,0,1><<<dim3(H_DIM/64, B_DIM/64), 256>>>(
        x2, W3, nullptr, nullptr, conds_h, B_DIM, H_DIM, H_DIM);

    // [5] CWB = conds @ Wih_perm^T + (bih+bhh)_perm   (2-term, exact-ish)
    hgemm<128,128,64,32,0,0,2><<<dim3(G_DIM/128, B_DIM/128), 256, SM128_T2>>>(
        conds_h, Wih_h, Wih_l, bperm, nullptr,
        CWB, nullptr, B_DIM, G_DIM, H_DIM);
    // [6] ZW = z @ Wih_perm^T + CWB[row % B]   (1-term: biggest GEMM, -50% MMAs)
    hgemm<128,128,64,32,1,0,1><<<dim3(G_DIM/128, TB/128), 256, SM128_T1>>>(
        z_h, Wih_h, nullptr, nullptr, CWB,
        ZW, nullptr, TB, G_DIM, H_DIM);

    // [7] Persistent recurrence (one launch, 256 CTAs @ 2/SM, 2-term)
    lstm_persistent<<<GRID_P, 256, SMP>>>(Whh_h, Whh_l, ZW, H_h);

    // [8..10] Projection MLP over all T*B rows (2-term)
    hgemm<128,128,64,32,2,1,2><<<dim3(H_DIM/128, TB/128), 256, SM128_T2>>>(
        H_h, P1_h, P1_l, pb1, nullptr,
        nullptr, y1_h, TB, H_DIM, H_DIM);
    hgemm<128,128,64,32,2,1,2><<<dim3(H_DIM/128, TB/128), 256, SM128_T2>>>(
        y1_h, P2_h, P2_l, pb2, nullptr,
        nullptr, y2_h, TB, H_DIM, H_DIM);
    hgemm<128,64,64,16,3,0,2><<<dim3(D_DIM/64, TB/128), 256, SM64B>>>(
        y2_h, P3_h, P3_l, pb3, nullptr,
        out, nullptr, TB, D_DIM, H_DIM);
}

// round 12
// speedup vs baseline: 5.5735x; 1.2667x over previous
#include <cuda_runtime.h>
#include <cuda_fp16.h>
#include <math.h>
#include <stdint.h>

// Problem dims (fixed by the dataset)
#define B_DIM 1024
#define T_DIM 128
#define L_DIM 16
#define H_DIM 512
#define D_DIM 64
#define G_DIM 2048          // 4*H
#define TB_DIM (T_DIM * B_DIM)
#define GRID_P 256          // persistent recurrence grid (2 CTAs/SM)

// ---------------------------------------------------------------------------
// Scratch. Activations: single fp16 (ushort). Weights: fp16 hi/lo pairs.
// ---------------------------------------------------------------------------
__device__ float    g_x1[B_DIM * H_DIM];
__device__ float    g_x2[B_DIM * H_DIM];
__device__ float    g_bperm[G_DIM];
__device__ unsigned short g_conds_h[B_DIM * H_DIM];
__device__ unsigned short g_Wih_h[G_DIM * H_DIM];
__device__ unsigned short g_Wih_l[G_DIM * H_DIM];
__device__ unsigned short g_Whh_h[G_DIM * H_DIM];
__device__ unsigned short g_P1_h[H_DIM * H_DIM];
__device__ unsigned short g_P1_l[H_DIM * H_DIM];
__device__ unsigned short g_P2_h[H_DIM * H_DIM];
__device__ unsigned short g_P2_l[H_DIM * H_DIM];
__device__ unsigned short g_P3_h[D_DIM * H_DIM];
__device__ unsigned short g_P3_l[D_DIM * H_DIM];
__device__ float    g_CWB[B_DIM * G_DIM];
__device__ unsigned short g_z_h[(size_t)TB_DIM * H_DIM];   // 128 MB
__device__ float    g_ZW[(size_t)TB_DIM * G_DIM];          // 1 GB
__device__ unsigned short g_H_h[(size_t)TB_DIM * H_DIM];
__device__ unsigned short g_y1_h[(size_t)TB_DIM * H_DIM];
__device__ unsigned short g_y2_h[(size_t)TB_DIM * H_DIM];

// Persistent-kernel grid barrier (monotonic; self-reset at kernel end)
__device__ unsigned g_bar_ctr  = 0;
__device__ unsigned g_done_ctr = 0;

// ---------------------------------------------------------------------------
// Helpers
// ---------------------------------------------------------------------------
__device__ __forceinline__ unsigned short h_of(float x) {
    return __half_as_ushort(__float2half_rn(x));
}
__device__ __forceinline__ void hsplit(float x, unsigned short& hi, unsigned short& lo) {
    __half h = __float2half_rn(x);
    float r = x - __half2float(h);
    __half l = __float2half_rn(r);
    hi = __half_as_ushort(h);
    lo = __half_as_ushort(l);
}

// mma m16n8k16 row.col fp16 -> f32
__device__ __forceinline__ void mma16816(float& c0, float& c1, float& c2, float& c3,
                                         unsigned a0, unsigned a1, unsigned a2, unsigned a3,
                                         unsigned b0, unsigned b1) {
    asm volatile(
        "mma.sync.aligned.m16n8k16.row.col.f32.f16.f16.f32 "
        "{%0,%1,%2,%3}, {%4,%5,%6,%7}, {%8,%9}, {%0,%1,%2,%3};\n"
        : "+f"(c0), "+f"(c1), "+f"(c2), "+f"(c3)
        : "r"(a0), "r"(a1), "r"(a2), "r"(a3), "r"(b0), "r"(b1));
}

__device__ __forceinline__ void ldsm4(unsigned& r0, unsigned& r1,
                                      unsigned& r2, unsigned& r3, uint32_t a) {
    asm volatile("ldmatrix.sync.aligned.m8n8.x4.shared.b16 {%0,%1,%2,%3}, [%4];"
                 : "=r"(r0), "=r"(r1), "=r"(r2), "=r"(r3) : "r"(a));
}

__device__ __forceinline__ void cp_async16(void* sptr, const void* gptr) {
    unsigned sa = (unsigned)__cvta_generic_to_shared(sptr);
    asm volatile("cp.async.cg.shared.global [%0], [%1], 16;\n" :: "r"(sa), "l"(gptr));
}
__device__ __forceinline__ void cp_commit() {
    asm volatile("cp.async.commit_group;\n");
}
template<int N>
__device__ __forceinline__ void cp_wait() {
    asm volatile("cp.async.wait_group %0;\n" :: "n"(N));
}

// ---------------------------------------------------------------------------
// fp16 GEMM: D[M,N] = A@B^T, A single fp16, B = Bh (+ Bl if TERMS==2).
// BK=32 2-stage cp.async, ldmatrix fragments, STR=40 ushorts (conflict-free).
// EPI: 0 = fp32 + bias (CWB)
//      1 = fp32 + addvec[row % B] (ZW build, CWB fold)
//      2 = fp16 out + bias (+relu if ACT)    (P1, P2)
//      3 = fp32 + bias, [T,B]->[B,T] perm    (P3)
// ---------------------------------------------------------------------------
template<int BM, int BN, int WM, int WN, int EPI, int ACT, int TERMS>
__global__ void __launch_bounds__((BM / WM) * (BN / WN) * 32, 2)
hgemm(const unsigned short* __restrict__ A,
      const unsigned short* __restrict__ Bh, const unsigned short* __restrict__ Bl,
      const float* __restrict__ bias,
      const float* __restrict__ addvec,
      float* __restrict__ outf,
      unsigned short* __restrict__ outh,
      int M, int N, int K)
{
    constexpr int BK = 32;
    constexpr int STR = BK + 8;              // 40 ushorts
    constexpr int ATI = BM * STR;
    constexpr int BTI = BN * STR;
    constexpr int STAGE = ATI + TERMS * BTI;
    constexpr int WARPS_N = BN / WN;
    constexpr int NTH = (BM / WM) * (BN / WN) * 32;
    constexpr int MI = WM / 16, NI = WN / 8;

    extern __shared__ unsigned short sm[];

    const int tid  = threadIdx.x;
    const int warp = tid >> 5, lane = tid & 31;
    const int g = lane >> 2, t = lane & 3;
    const int wm0 = (warp / WARPS_N) * WM;
    const int wn0 = (warp % WARPS_N) * WN;
    const int m0 = blockIdx.y * BM;
    const int n0 = blockIdx.x * BN;

    const uint32_t smb = (uint32_t)__cvta_generic_to_shared(sm);
    const int aRow = (lane & 7) + ((lane >> 3) & 1) * 8;
    const int aKh  = (lane >> 4) * 16;
    const int bRow = (lane & 7) + (lane >> 4) * 8;
    const int bKh  = ((lane >> 3) & 1) * 16;
    const uint32_t aBase = smb + (uint32_t)(wm0 + aRow) * STR * 2 + aKh;
    const uint32_t bBase = smb + (uint32_t)(ATI + (wn0 + bRow) * STR) * 2 + bKh;

    float acc[MI][NI][4];
#pragma unroll
    for (int mi = 0; mi < MI; mi++)
#pragma unroll
        for (int ni = 0; ni < NI; ni++)
#pragma unroll
            for (int q = 0; q < 4; q++) acc[mi][ni][q] = 0.f;

    auto load_stage = [&](int k0, int s) {
        unsigned short* st = sm + s * STAGE;
#pragma unroll
        for (int i = tid; i < BM * 4; i += NTH) {
            int r = i >> 2, c = i & 3;
            cp_async16(st + r * STR + c * 8, A + (size_t)(m0 + r) * K + k0 + c * 8);
        }
#pragma unroll
        for (int i = tid; i < BN * 4; i += NTH) {
            int r = i >> 2, c = i & 3;
            const size_t gs = (size_t)(n0 + r) * K + k0 + c * 8;
            cp_async16(st + ATI + r * STR + c * 8, Bh + gs);
            if (TERMS == 2)
                cp_async16(st + ATI + BTI + r * STR + c * 8, Bl + gs);
        }
        cp_commit();
    };

    const int KT = K / BK;
    load_stage(0, 0);

    for (int kt = 0; kt < KT; kt++) {
        const int s = kt & 1;
        if (kt + 1 < KT) { load_stage((kt + 1) * BK, s ^ 1); cp_wait<1>(); }
        else             { cp_wait<0>(); }
        __syncthreads();

        const uint32_t stOff = (uint32_t)(s * STAGE) * 2;
        const uint32_t aA = aBase + stOff;
        const uint32_t bH = bBase + stOff;
        const uint32_t bL = bH + (uint32_t)BTI * 2;

#pragma unroll
        for (int kk = 0; kk < BK; kk += 16) {
            unsigned ah[MI][4], bh[NI][2], bl[NI][2];
#pragma unroll
            for (int mi = 0; mi < MI; mi++)
                ldsm4(ah[mi][0], ah[mi][1], ah[mi][2], ah[mi][3],
                      aA + (uint32_t)(mi * 16 * STR + kk) * 2);
#pragma unroll
            for (int p = 0; p < NI / 2; p++) {
                ldsm4(bh[2*p][0], bh[2*p][1], bh[2*p+1][0], bh[2*p+1][1],
                      bH + (uint32_t)(p * 16 * STR + kk) * 2);
                if (TERMS == 2)
                    ldsm4(bl[2*p][0], bl[2*p][1], bl[2*p+1][0], bl[2*p+1][1],
                          bL + (uint32_t)(p * 16 * STR + kk) * 2);
            }
#pragma unroll
            for (int mi = 0; mi < MI; mi++)
#pragma unroll
                for (int ni = 0; ni < NI; ni++) {
                    mma16816(acc[mi][ni][0], acc[mi][ni][1], acc[mi][ni][2], acc[mi][ni][3],
                             ah[mi][0], ah[mi][1], ah[mi][2], ah[mi][3], bh[ni][0], bh[ni][1]);
                    if (TERMS == 2)
                        mma16816(acc[mi][ni][0], acc[mi][ni][1], acc[mi][ni][2], acc[mi][ni][3],
                                 ah[mi][0], ah[mi][1], ah[mi][2], ah[mi][3], bl[ni][0], bl[ni][1]);
                }
        }
        __syncthreads();
    }

    // ---- Epilogues ----
    if (EPI == 0 || EPI == 2 || EPI == 3) {
        float2 bv[NI];
#pragma unroll
        for (int ni = 0; ni < NI; ni++)
            bv[ni] = *(const float2*)(bias + n0 + wn0 + ni * 8 + 2 * t);

#pragma unroll
        for (int mi = 0; mi < MI; mi++) {
            int row0 = m0 + wm0 + mi * 16 + g;
#pragma unroll
            for (int ni = 0; ni < NI; ni++) {
                int col = n0 + wn0 + ni * 8 + 2 * t;
                float v0 = acc[mi][ni][0] + bv[ni].x;
                float v1 = acc[mi][ni][1] + bv[ni].y;
                float v2 = acc[mi][ni][2] + bv[ni].x;
                float v3 = acc[mi][ni][3] + bv[ni].y;
                if (ACT == 1) {
                    v0 = fmaxf(v0, 0.f); v1 = fmaxf(v1, 0.f);
                    v2 = fmaxf(v2, 0.f); v3 = fmaxf(v3, 0.f);
                }
                if (EPI == 0) {
                    *(float2*)(outf + (size_t)row0 * N + col)       = make_float2(v0, v1);
                    *(float2*)(outf + (size_t)(row0 + 8) * N + col) = make_float2(v2, v3);
                } else if (EPI == 2) {
                    *(ushort2*)(outh + (size_t)row0 * N + col) =
                        make_ushort2(h_of(v0), h_of(v1));
                    *(ushort2*)(outh + (size_t)(row0 + 8) * N + col) =
                        make_ushort2(h_of(v2), h_of(v3));
                } else {
                    int tt0 = row0 / B_DIM, bb0 = row0 % B_DIM;
                    int r1 = row0 + 8;
                    int tt1 = r1 / B_DIM, bb1 = r1 % B_DIM;
                    *(float2*)(outf + ((size_t)bb0 * T_DIM + tt0) * D_DIM + col) = make_float2(v0, v1);
                    *(float2*)(outf + ((size_t)bb1 * T_DIM + tt1) * D_DIM + col) = make_float2(v2, v3);
                }
            }
        }
    } else {
        // EPI == 1
#pragma unroll
        for (int mi = 0; mi < MI; mi++) {
            int row0 = m0 + wm0 + mi * 16 + g;
#pragma unroll
            for (int ni = 0; ni < NI; ni++) {
                int col = n0 + wn0 + ni * 8 + 2 * t;
                float2 a0 = *(const float2*)(addvec + (size_t)(row0 & (B_DIM - 1)) * N + col);
                float2 a1 = *(const float2*)(addvec + (size_t)((row0 + 8) & (B_DIM - 1)) * N + col);
                *(float2*)(outf + (size_t)row0 * N + col) =
                    make_float2(acc[mi][ni][0] + a0.x, acc[mi][ni][1] + a0.y);
                *(float2*)(outf + (size_t)(row0 + 8) * N + col) =
                    make_float2(acc[mi][ni][2] + a1.x, acc[mi][ni][3] + a1.y);
            }
        }
    }
}

// ---------------------------------------------------------------------------
// Persistent LSTM recurrence: 256 CTAs (2/SM), tile 64x128, BK=32,
// fp16 1-term (Whh hi only). c-state in registers; grid barrier between steps.
// ---------------------------------------------------------------------------
__global__ void __launch_bounds__(256, 2)
lstm_persistent(const unsigned short* __restrict__ Whh_h,
                const float* __restrict__ ZW,        // [T][B][G] (perm cols)
                unsigned short* __restrict__ H_h)
{
    constexpr int BM = 64, BN = 128, BK = 32, WM = 32, WN = 32;
    constexpr int STR = BK + 8;
    constexpr int ATI = BM * STR, BTI = BN * STR;
    constexpr int STAGE = ATI + BTI;
    constexpr int WARPS_N = BN / WN;
    constexpr int NTH = 256;
    constexpr int MI = WM / 16, NI = WN / 8;   // 2, 4
    constexpr int K = H_DIM, N = G_DIM;
    constexpr int KT = K / BK;

    extern __shared__ unsigned short sm[];

    const int tid  = threadIdx.x;
    const int warp = tid >> 5, lane = tid & 31;
    const int g = lane >> 2, t4 = lane & 3;
    const int wm0 = (warp / WARPS_N) * WM;
    const int wn0 = (warp % WARPS_N) * WN;
    const int bid = blockIdx.x;
    const int m0 = (bid >> 4) * BM;
    const int n0 = (bid & 15) * BN;

    const uint32_t smb = (uint32_t)__cvta_generic_to_shared(sm);
    const int aRow = (lane & 7) + ((lane >> 3) & 1) * 8;
    const int aKh  = (lane >> 4) * 16;
    const int bRow = (lane & 7) + (lane >> 4) * 8;
    const int bKh  = ((lane >> 3) & 1) * 16;
    const uint32_t aBase = smb + (uint32_t)(wm0 + aRow) * STR * 2 + aKh;
    const uint32_t bBase = smb + (uint32_t)(ATI + (wn0 + bRow) * STR) * 2 + bKh;

    const bool hi_half = (t4 & 1);

    float creg[MI][NI];
#pragma unroll
    for (int mi = 0; mi < MI; mi++)
#pragma unroll
        for (int ni = 0; ni < NI; ni++) creg[mi][ni] = 0.f;

    for (int t = 0; t < T_DIM; t++) {
        float acc[MI][NI][4];
#pragma unroll
        for (int mi = 0; mi < MI; mi++)
#pragma unroll
            for (int ni = 0; ni < NI; ni++)
#pragma unroll
                for (int q = 0; q < 4; q++) acc[mi][ni][q] = 0.f;

        if (t > 0) {
            const unsigned short* Ah = H_h + (size_t)(t - 1) * B_DIM * H_DIM;

            auto load_stage = [&](int k0, int s) {
                unsigned short* st = sm + s * STAGE;
#pragma unroll
                for (int i = tid; i < BM * 4; i += NTH) {
                    int r = i >> 2, c = i & 3;
                    cp_async16(st + r * STR + c * 8, Ah + (size_t)(m0 + r) * K + k0 + c * 8);
                }
#pragma unroll
                for (int i = tid; i < BN * 4; i += NTH) {
                    int r = i >> 2, c = i & 3;
                    cp_async16(st + ATI + r * STR + c * 8,
                               Whh_h + (size_t)(n0 + r) * K + k0 + c * 8);
                }
                cp_commit();
            };

            load_stage(0, 0);
            for (int kt = 0; kt < KT; kt++) {
                const int s = kt & 1;
                if (kt + 1 < KT) { load_stage((kt + 1) * BK, s ^ 1); cp_wait<1>(); }
                else             { cp_wait<0>(); }
                __syncthreads();

                const uint32_t stOff = (uint32_t)(s * STAGE) * 2;
                const uint32_t aA = aBase + stOff;
                const uint32_t bH = bBase + stOff;

#pragma unroll
                for (int kk = 0; kk < BK; kk += 16) {
                    unsigned ah[MI][4], bh[NI][2];
#pragma unroll
                    for (int mi = 0; mi < MI; mi++)
                        ldsm4(ah[mi][0], ah[mi][1], ah[mi][2], ah[mi][3],
                              aA + (uint32_t)(mi * 16 * STR + kk) * 2);
#pragma unroll
                    for (int p = 0; p < NI / 2; p++)
                        ldsm4(bh[2*p][0], bh[2*p][1], bh[2*p+1][0], bh[2*p+1][1],
                              bH + (uint32_t)(p * 16 * STR + kk) * 2);
#pragma unroll
                    for (int mi = 0; mi < MI; mi++)
#pragma unroll
                        for (int ni = 0; ni < NI; ni++)
                            mma16816(acc[mi][ni][0], acc[mi][ni][1], acc[mi][ni][2], acc[mi][ni][3],
                                     ah[mi][0], ah[mi][1], ah[mi][2], ah[mi][3], bh[ni][0], bh[ni][1]);
                }
                __syncthreads();
            }
        }

        // ---- Cell epilogue (c in registers) ----
        const float* zwb = ZW + (size_t)t * B_DIM * G_DIM;
        unsigned short* hh = H_h + (size_t)t * B_DIM * H_DIM;
#pragma unroll
        for (int mi = 0; mi < MI; mi++) {
            int row0 = m0 + wm0 + mi * 16 + g;
#pragma unroll
            for (int ni = 0; ni < NI; ni++) {
                int col = n0 + wn0 + ni * 8 + 2 * t4;
                float c0 = acc[mi][ni][0], c1 = acc[mi][ni][1];
                float c2 = acc[mi][ni][2], c3 = acc[mi][ni][3];
                float sx = __shfl_xor_sync(0xffffffffu, hi_half ? c0 : c2, 1);
                float sy = __shfl_xor_sync(0xffffffffu, hi_half ? c1 : c3, 1);
                int row = hi_half ? row0 + 8 : row0;
                float gi, gf, gg, go;
                if (!hi_half) { gi = c0; gf = c1; gg = sx; go = sy; }
                else          { gi = sx; gf = sy; gg = c2; go = c3; }

                int base = col & ~3;
                float4 zw = *(const float4*)(zwb + (size_t)row * G_DIM + base);
                gi += zw.x; gf += zw.y; gg += zw.z; go += zw.w;

                float ig = 1.f / (1.f + expf(-gi));
                float fg = 1.f / (1.f + expf(-gf));
                float gt = tanhf(gg);
                float og = 1.f / (1.f + expf(-go));

                float cn = fg * creg[mi][ni] + ig * gt;
                creg[mi][ni] = cn;
                hh[(size_t)row * H_DIM + (col >> 2)] = h_of(og * tanhf(cn));
            }
        }

        // ---- Grid barrier between steps ----
        if (t < T_DIM - 1) {
            __syncthreads();
            if (tid == 0) {
                __threadfence();
                atomicAdd(&g_bar_ctr, 1u);
                unsigned target = (unsigned)(t + 1) * GRID_P;
                while (atomicAdd(&g_bar_ctr, 0u) < target) { }
            }
            __syncthreads();
        }
    }

    // Deterministic counter reset for graph replay
    __syncthreads();
    if (tid == 0) {
        unsigned d = atomicAdd(&g_done_ctr, 1u);
        if (d == GRID_P - 1) {
            g_bar_ctr = 0;
            g_done_ctr = 0;
            __threadfence();
        }
    }
}

// ---------------------------------------------------------------------------
// f32x2 SGEMM (label MLP), 64x64 tiles. OUT: 0 fp32, 1 single fp16.
// ---------------------------------------------------------------------------
__device__ __forceinline__ void ffma2(unsigned long long& d,
                                      unsigned long long a,
                                      unsigned long long b) {
    asm("fma.rn.f32x2 %0, %1, %2, %0;" : "+l"(d) : "l"(a), "l"(b));
}
__device__ __forceinline__ unsigned long long pack2(float lo, float hi) {
    unsigned long long r;
    asm("mov.b64 %0, {%1, %2};" : "=l"(r) : "f"(lo), "f"(hi));
    return r;
}
__device__ __forceinline__ float2 unpack2(unsigned long long u) {
    float2 f;
    asm("mov.b64 {%0, %1}, %2;" : "=f"(f.x), "=f"(f.y) : "l"(u));
    return f;
}

template<int BM, int BN, int BK, int TM, int TN, int ACT, int OUT>
__global__ void gemm2_kernel(const float* __restrict__ A,
                             const float* __restrict__ W,
                             const float* __restrict__ bias,
                             float* __restrict__ C,
                             unsigned short* __restrict__ uh,
                             int M, int N, int K)
{
    constexpr int AS_STRIDE = BM + 4;
    constexpr int WS_STRIDE = BN + 4;
    __shared__ float As[BK][AS_STRIDE];
    __shared__ float Ws[BK][WS_STRIDE];

    constexpr int NTH = (BM / TM) * (BN / TN);
    const int tid = threadIdx.x;
    const int tx = tid % (BN / TN);
    const int ty = tid / (BN / TN);
    const int m0 = blockIdx.y * BM;
    const int n0 = blockIdx.x * BN;

    unsigned long long acc2[TM / 2][TN];
#pragma unroll
    for (int p = 0; p < TM / 2; p++)
#pragma unroll
        for (int j = 0; j < TN; j++) acc2[p][j] = 0ULL;

    for (int k0 = 0; k0 < K; k0 += BK) {
#pragma unroll
        for (int i = tid * 4; i < BM * BK; i += NTH * 4) {
            int m = i / BK, k = i % BK;
            float4 v = *(const float4*)(A + (long)(m0 + m) * K + (k0 + k));
            As[k + 0][m] = v.x; As[k + 1][m] = v.y;
            As[k + 2][m] = v.z; As[k + 3][m] = v.w;
        }
#pragma unroll
        for (int i = tid * 4; i < BN * BK; i += NTH * 4) {
            int n = i / BK, k = i % BK;
            float4 v = *(const float4*)(W + (long)(n0 + n) * K + (k0 + k));
            Ws[k + 0][n] = v.x; Ws[k + 1][n] = v.y;
            Ws[k + 2][n] = v.z; Ws[k + 3][n] = v.w;
        }
        __syncthreads();

#pragma unroll
        for (int k = 0; k < BK; k++) {
            unsigned long long am2[TM / 2];
            const ulonglong2* ap = reinterpret_cast<const ulonglong2*>(&As[k][ty * TM]);
#pragma unroll
            for (int q = 0; q < TM / 4; q++) {
                ulonglong2 tt = ap[q];
                am2[2 * q + 0] = tt.x;
                am2[2 * q + 1] = tt.y;
            }
            float4 w4 = *reinterpret_cast<const float4*>(&Ws[k][tx * TN]);
            unsigned long long wd[TN];
            wd[0] = pack2(w4.x, w4.x); wd[1] = pack2(w4.y, w4.y);
            wd[2] = pack2(w4.z, w4.z); wd[3] = pack2(w4.w, w4.w);
#pragma unroll
            for (int p = 0; p < TM / 2; p++)
#pragma unroll
                for (int j = 0; j < TN; j++) ffma2(acc2[p][j], am2[p], wd[j]);
        }
        __syncthreads();
    }

    float4 bv = make_float4(0.f, 0.f, 0.f, 0.f);
    if (bias) bv = *reinterpret_cast<const float4*>(bias + n0 + tx * TN);

#pragma unroll
    for (int p = 0; p < TM / 2; p++) {
        float2 v0 = unpack2(acc2[p][0]);
        float2 v1 = unpack2(acc2[p][1]);
        float2 v2 = unpack2(acc2[p][2]);
        float2 v3 = unpack2(acc2[p][3]);
        float4 rowA = make_float4(v0.x + bv.x, v1.x + bv.y, v2.x + bv.z, v3.x + bv.w);
        float4 rowB = make_float4(v0.y + bv.x, v1.y + bv.y, v2.y + bv.z, v3.y + bv.w);
        if (ACT == 1) {
            rowA.x = fmaxf(rowA.x, 0.f); rowA.y = fmaxf(rowA.y, 0.f);
            rowA.z = fmaxf(rowA.z, 0.f); rowA.w = fmaxf(rowA.w, 0.f);
            rowB.x = fmaxf(rowB.x, 0.f); rowB.y = fmaxf(rowB.y, 0.f);
            rowB.z = fmaxf(rowB.z, 0.f); rowB.w = fmaxf(rowB.w, 0.f);
        }
        int mA = m0 + ty * TM + 2 * p;
        int n  = n0 + tx * TN;
        if (OUT == 0) {
            *reinterpret_cast<float4*>(C + (long)mA * N + n) = rowA;
            *reinterpret_cast<float4*>(C + (long)(mA + 1) * N + n) = rowB;
        } else {
            *(ushort4*)(uh + (size_t)mA * N + n) =
                make_ushort4(h_of(rowA.x), h_of(rowA.y), h_of(rowA.z), h_of(rowA.w));
            *(ushort4*)(uh + (size_t)(mA + 1) * N + n) =
                make_ushort4(h_of(rowB.x), h_of(rowB.y), h_of(rowB.z), h_of(rowB.w));
        }
    }
}

// ---------------------------------------------------------------------------
// Prep kernels
// ---------------------------------------------------------------------------
__device__ __forceinline__ void split4w(const float4* src, int i,
                                        ushort4* hi, ushort4* lo) {
    float4 v = src[i];
    ushort4 h, l;
    hsplit(v.x, h.x, l.x); hsplit(v.y, h.y, l.y);
    hsplit(v.z, h.z, l.z); hsplit(v.w, h.w, l.w);
    hi[i] = h; lo[i] = l;
}

__device__ __forceinline__ void permsplit4w(const float* src, int i,
                                            ushort4* hi, ushort4* lo) {
    int r = i / (H_DIM / 4);
    int c = i % (H_DIM / 4);
    int j = r >> 2, gg = r & 3;
    float4 v = ((const float4*)src)[(size_t)(gg * H_DIM + j) * (H_DIM / 4) + c];
    ushort4 h, l;
    hsplit(v.x, h.x, l.x); hsplit(v.y, h.y, l.y);
    hsplit(v.z, h.z, l.z); hsplit(v.w, h.w, l.w);
    size_t o = (size_t)r * (H_DIM / 4) + c;
    hi[o] = h;
    if (lo) lo[o] = l;
}

__global__ void prep_weights(const float* __restrict__ P1, const float* __restrict__ P2,
                             const float* __restrict__ P3,
                             const float* __restrict__ Wih, const float* __restrict__ Whh,
                             const float* __restrict__ bih, const float* __restrict__ bhh,
                             ushort4* P1h, ushort4* P1l, ushort4* P2h, ushort4* P2l,
                             ushort4* P3h, ushort4* P3l,
                             ushort4* Wihh, ushort4* Wihl, ushort4* Whhh,
                             float* bp)
{
    const int S0 = H_DIM * H_DIM / 4;
    const int S1 = S0 + H_DIM * H_DIM / 4;
    const int S2 = S1 + D_DIM * H_DIM / 4;
    const int S3 = S2 + G_DIM * H_DIM / 4;
    const int S4 = S3 + G_DIM * H_DIM / 4;
    int i = blockIdx.x * blockDim.x + threadIdx.x;
    if      (i < S0) split4w((const float4*)P1, i, P1h, P1l);
    else if (i < S1) split4w((const float4*)P2, i - S0, P2h, P2l);
    else if (i < S2) split4w((const float4*)P3, i - S1, P3h, P3l);
    else if (i < S3) permsplit4w(Wih, i - S2, Wihh, Wihl);
    else if (i < S4) permsplit4w(Whh, i - S3, Whhh, nullptr);
    else if (i < S4 + G_DIM) {
        int k = i - S4;
        int j = k >> 2, gg = k & 3;
        bp[k] = bih[gg * H_DIM + j] + bhh[gg * H_DIM + j];
    }
}

// z -> single fp16
__global__ void cvt_half_kernel(const float4* __restrict__ src,
                                ushort4* __restrict__ dst, int n4)
{
    int i = blockIdx.x * blockDim.x + threadIdx.x;
    if (i >= n4) return;
    float4 v = src[i];
    dst[i] = make_ushort4(h_of(v.x), h_of(v.y), h_of(v.z), h_of(v.w));
}

// ---------------------------------------------------------------------------
// Launch
// ---------------------------------------------------------------------------
extern "C" void kernel_launch(void* const* d_in, const int* in_sizes, int n_in,
                              void* d_out, int out_size)
{
    const float* labels = (const float*)d_in[0];
    const float* z      = (const float*)d_in[1];
    const float* W1     = (const float*)d_in[2];
    const float* b1     = (const float*)d_in[3];
    const float* W2     = (const float*)d_in[4];
    const float* b2     = (const float*)d_in[5];
    const float* W3     = (const float*)d_in[6];
    const float* Wih    = (const float*)d_in[7];
    const float* Whh    = (const float*)d_in[8];
    const float* bih    = (const float*)d_in[9];
    const float* bhh    = (const float*)d_in[10];
    const float* P1     = (const float*)d_in[11];
    const float* pb1    = (const float*)d_in[12];
    const float* P2     = (const float*)d_in[13];
    const float* pb2    = (const float*)d_in[14];
    const float* P3     = (const float*)d_in[15];
    const float* pb3    = (const float*)d_in[16];
    float* out = (float*)d_out;

    float *x1, *x2, *bperm, *CWB, *ZW;
    unsigned short *conds_h, *Wih_h, *Wih_l, *Whh_h;
    unsigned short *P1_h, *P1_l, *P2_h, *P2_l, *P3_h, *P3_l;
    unsigned short *z_h, *H_h, *y1_h, *y2_h;
    cudaGetSymbolAddress((void**)&x1,     g_x1);
    cudaGetSymbolAddress((void**)&x2,     g_x2);
    cudaGetSymbolAddress((void**)&bperm,  g_bperm);
    cudaGetSymbolAddress((void**)&conds_h, g_conds_h);
    cudaGetSymbolAddress((void**)&Wih_h,  g_Wih_h);
    cudaGetSymbolAddress((void**)&Wih_l,  g_Wih_l);
    cudaGetSymbolAddress((void**)&Whh_h,  g_Whh_h);
    cudaGetSymbolAddress((void**)&P1_h,   g_P1_h);
    cudaGetSymbolAddress((void**)&P1_l,   g_P1_l);
    cudaGetSymbolAddress((void**)&P2_h,   g_P2_h);
    cudaGetSymbolAddress((void**)&P2_l,   g_P2_l);
    cudaGetSymbolAddress((void**)&P3_h,   g_P3_h);
    cudaGetSymbolAddress((void**)&P3_l,   g_P3_l);
    cudaGetSymbolAddress((void**)&CWB,    g_CWB);
    cudaGetSymbolAddress((void**)&z_h,    g_z_h);
    cudaGetSymbolAddress((void**)&ZW,     g_ZW);
    cudaGetSymbolAddress((void**)&H_h,    g_H_h);
    cudaGetSymbolAddress((void**)&y1_h,   g_y1_h);
    cudaGetSymbolAddress((void**)&y2_h,   g_y2_h);

    const int TB = TB_DIM;

    // Dynamic smem (BK=32, STR=40): 2 stages x (A + TERMS*B tiles)
    constexpr int SM128_T2 = 2 * (128 * 40 + 2 * 128 * 40) * 2;  // 61440 B
    constexpr int SM128_T1 = 2 * (128 * 40 + 1 * 128 * 40) * 2;  // 40960 B
    constexpr int SM64B    = 2 * (128 * 40 + 2 * 64 * 40) * 2;   // 40960 B (BN=64)
    constexpr int SMP      = 2 * (64 * 40 + 1 * 128 * 40) * 2;   // 30720 B (persistent)
    cudaFuncSetAttribute((const void*)hgemm<128,128,64,32,0,0,2>,
                         cudaFuncAttributeMaxDynamicSharedMemorySize, SM128_T2);
    cudaFuncSetAttribute((const void*)hgemm<128,128,64,32,1,0,1>,
                         cudaFuncAttributeMaxDynamicSharedMemorySize, SM128_T1);
    cudaFuncSetAttribute((const void*)hgemm<128,128,64,32,2,1,2>,
                         cudaFuncAttributeMaxDynamicSharedMemorySize, SM128_T2);
    cudaFuncSetAttribute((const void*)hgemm<128,64,64,16,3,0,2>,
                         cudaFuncAttributeMaxDynamicSharedMemorySize, SM64B);
    cudaFuncSetAttribute((const void*)lstm_persistent,
                         cudaFuncAttributeMaxDynamicSharedMemorySize, SMP);

    // [0] fused weight prep
    {
        const int total = 2 * (H_DIM * H_DIM / 4) + D_DIM * H_DIM / 4
                        + 2 * (G_DIM * H_DIM / 4) + G_DIM;
        prep_weights<<<(total + 255) / 256, 256>>>(
            P1, P2, P3, Wih, Whh, bih, bhh,
            (ushort4*)P1_h, (ushort4*)P1_l, (ushort4*)P2_h, (ushort4*)P2_l,
            (ushort4*)P3_h, (ushort4*)P3_l,
            (ushort4*)Wih_h, (ushort4*)Wih_l, (ushort4*)Whh_h,
            bperm);
    }
    // [1] z -> fp16
    cvt_half_kernel<<<(int)(((size_t)TB * H_DIM / 4) / 256), 256>>>(
        (const float4*)z, (ushort4*)z_h, TB * (H_DIM / 4));

    // [2..4] Label MLP (f32x2, 64x64 tiles); last layer writes conds fp16
    gemm2_kernel<64,64,16,4,4,1,0><<<dim3(H_DIM/64, B_DIM/64), 256>>>(
        labels, W1, b1, x1, nullptr, B_DIM, H_DIM, L_DIM);
    gemm2_kernel<64,64,16,4,4,1,0><<<dim3(H_DIM/64, B_DIM/64), 256>>>(
        x1, W2, b2, x2, nullptr, B_DIM, H_DIM, H_DIM);
    gemm2_kernel<64,64,16,4,4,0,1><<<dim3(H_DIM/64, B_DIM/64), 256>>>(
        x2, W3, nullptr, nullptr, conds_h, B_DIM, H_DIM, H_DIM);

    // [5] CWB = conds @ Wih_perm^T + (bih+bhh)_perm   (2-term)
    hgemm<128,128,64,32,0,0,2><<<dim3(G_DIM/128, B_DIM/128), 256, SM128_T2>>>(
        conds_h, Wih_h, Wih_l, bperm, nullptr,
        CWB, nullptr, B_DIM, G_DIM, H_DIM);
    // [6] ZW = z @ Wih_perm^T + CWB[row % B]   (1-term)
    hgemm<128,128,64,32,1,0,1><<<dim3(G_DIM/128, TB/128), 256, SM128_T1>>>(
        z_h, Wih_h, nullptr, nullptr, CWB,
        ZW, nullptr, TB, G_DIM, H_DIM);

    // [7] Persistent recurrence (one launch, 256 CTAs @ 2/SM, Whh 1-term)
    lstm_persistent<<<GRID_P, 256, SMP>>>(Whh_h, ZW, H_h);

    // [8..10] Projection MLP over all T*B rows (2-term)
    hgemm<128,128,64,32,2,1,2><<<dim3(H_DIM/128, TB/128), 256, SM128_T2>>>(
        H_h, P1_h, P1_l, pb1, nullptr,
        nullptr, y1_h, TB, H_DIM, H_DIM);
    hgemm<128,128,64,32,2,1,2><<<dim3(H_DIM/128, TB/128), 256, SM128_T2>>>(
        y1_h, P2_h, P2_l, pb2, nullptr,
        nullptr, y2_h, TB, H_DIM, H_DIM);
    hgemm<128,64,64,16,3,0,2><<<dim3(D_DIM/64, TB/128), 256, SM64B>>>(
        y2_h, P3_h, P3_l, pb3, nullptr,
        out, nullptr, TB, D_DIM, H_DIM);
}

// round 13
// speedup vs baseline: 6.0360x; 1.0830x over previous
#include <cuda_runtime.h>
#include <cuda_fp16.h>
#include <math.h>
#include <stdint.h>

// Problem dims (fixed by the dataset)
#define B_DIM 1024
#define T_DIM 128
#define L_DIM 16
#define H_DIM 512
#define D_DIM 64
#define G_DIM 2048          // 4*H
#define TB_DIM (T_DIM * B_DIM)
#define GRID_P 256          // persistent recurrence grid (2 CTAs/SM)

// ---------------------------------------------------------------------------
// Scratch. Activations single fp16; Wih 2-term, Whh/P1/P2 1-term, P3 2-term.
// ZW stored fp16 (gate pre-activations, O(1) scale).
// ---------------------------------------------------------------------------
__device__ float    g_x1[B_DIM * H_DIM];
__device__ float    g_x2[B_DIM * H_DIM];
__device__ float    g_bperm[G_DIM];
__device__ unsigned short g_conds_h[B_DIM * H_DIM];
__device__ unsigned short g_Wih_h[G_DIM * H_DIM];
__device__ unsigned short g_Wih_l[G_DIM * H_DIM];
__device__ unsigned short g_Whh_h[G_DIM * H_DIM];
__device__ unsigned short g_P1_h[H_DIM * H_DIM];
__device__ unsigned short g_P2_h[H_DIM * H_DIM];
__device__ unsigned short g_P3_h[D_DIM * H_DIM];
__device__ unsigned short g_P3_l[D_DIM * H_DIM];
__device__ float    g_CWB[B_DIM * G_DIM];
__device__ unsigned short g_z_h[(size_t)TB_DIM * H_DIM];   // 128 MB
__device__ unsigned short g_ZW[(size_t)TB_DIM * G_DIM];    // 512 MB (fp16)
__device__ unsigned short g_H_h[(size_t)TB_DIM * H_DIM];
__device__ unsigned short g_y1_h[(size_t)TB_DIM * H_DIM];
__device__ unsigned short g_y2_h[(size_t)TB_DIM * H_DIM];

// Persistent-kernel grid barrier (monotonic; self-reset at kernel end)
__device__ unsigned g_bar_ctr  = 0;
__device__ unsigned g_done_ctr = 0;

// ---------------------------------------------------------------------------
// Helpers
// ---------------------------------------------------------------------------
__device__ __forceinline__ unsigned short h_of(float x) {
    return __half_as_ushort(__float2half_rn(x));
}
__device__ __forceinline__ float f_of(unsigned short u) {
    return __half2float(__ushort_as_half(u));
}
__device__ __forceinline__ void hsplit(float x, unsigned short& hi, unsigned short& lo) {
    __half h = __float2half_rn(x);
    float r = x - __half2float(h);
    __half l = __float2half_rn(r);
    hi = __half_as_ushort(h);
    lo = __half_as_ushort(l);
}

// mma m16n8k16 row.col fp16 -> f32
__device__ __forceinline__ void mma16816(float& c0, float& c1, float& c2, float& c3,
                                         unsigned a0, unsigned a1, unsigned a2, unsigned a3,
                                         unsigned b0, unsigned b1) {
    asm volatile(
        "mma.sync.aligned.m16n8k16.row.col.f32.f16.f16.f32 "
        "{%0,%1,%2,%3}, {%4,%5,%6,%7}, {%8,%9}, {%0,%1,%2,%3};\n"
        : "+f"(c0), "+f"(c1), "+f"(c2), "+f"(c3)
        : "r"(a0), "r"(a1), "r"(a2), "r"(a3), "r"(b0), "r"(b1));
}

__device__ __forceinline__ void ldsm4(unsigned& r0, unsigned& r1,
                                      unsigned& r2, unsigned& r3, uint32_t a) {
    asm volatile("ldmatrix.sync.aligned.m8n8.x4.shared.b16 {%0,%1,%2,%3}, [%4];"
                 : "=r"(r0), "=r"(r1), "=r"(r2), "=r"(r3) : "r"(a));
}

__device__ __forceinline__ void cp_async16(void* sptr, const void* gptr) {
    unsigned sa = (unsigned)__cvta_generic_to_shared(sptr);
    asm volatile("cp.async.cg.shared.global [%0], [%1], 16;\n" :: "r"(sa), "l"(gptr));
}
__device__ __forceinline__ void cp_commit() {
    asm volatile("cp.async.commit_group;\n");
}
template<int N>
__device__ __forceinline__ void cp_wait() {
    asm volatile("cp.async.wait_group %0;\n" :: "n"(N));
}

// ---------------------------------------------------------------------------
// fp16 GEMM: D[M,N] = A@B^T, A single fp16, B = Bh (+ Bl if TERMS==2).
// BK=32 2-stage cp.async, ldmatrix fragments, STR=40 ushorts (conflict-free).
// EPI: 0 = fp32 + bias (CWB)
//      1 = fp16 out: acc + addvec[row % B][col]  (ZW build, CWB fold)
//      2 = fp16 out + bias (+relu if ACT)    (P1, P2)
//      3 = fp32 + bias, [T,B]->[B,T] perm    (P3)
// ---------------------------------------------------------------------------
template<int BM, int BN, int WM, int WN, int EPI, int ACT, int TERMS>
__global__ void __launch_bounds__((BM / WM) * (BN / WN) * 32, 2)
hgemm(const unsigned short* __restrict__ A,
      const unsigned short* __restrict__ Bh, const unsigned short* __restrict__ Bl,
      const float* __restrict__ bias,
      const float* __restrict__ addvec,
      float* __restrict__ outf,
      unsigned short* __restrict__ outh,
      int M, int N, int K)
{
    constexpr int BK = 32;
    constexpr int STR = BK + 8;              // 40 ushorts
    constexpr int ATI = BM * STR;
    constexpr int BTI = BN * STR;
    constexpr int STAGE = ATI + TERMS * BTI;
    constexpr int WARPS_N = BN / WN;
    constexpr int NTH = (BM / WM) * (BN / WN) * 32;
    constexpr int MI = WM / 16, NI = WN / 8;

    extern __shared__ unsigned short sm[];

    const int tid  = threadIdx.x;
    const int warp = tid >> 5, lane = tid & 31;
    const int g = lane >> 2, t = lane & 3;
    const int wm0 = (warp / WARPS_N) * WM;
    const int wn0 = (warp % WARPS_N) * WN;
    const int m0 = blockIdx.y * BM;
    const int n0 = blockIdx.x * BN;

    const uint32_t smb = (uint32_t)__cvta_generic_to_shared(sm);
    const int aRow = (lane & 7) + ((lane >> 3) & 1) * 8;
    const int aKh  = (lane >> 4) * 16;
    const int bRow = (lane & 7) + (lane >> 4) * 8;
    const int bKh  = ((lane >> 3) & 1) * 16;
    const uint32_t aBase = smb + (uint32_t)(wm0 + aRow) * STR * 2 + aKh;
    const uint32_t bBase = smb + (uint32_t)(ATI + (wn0 + bRow) * STR) * 2 + bKh;

    float acc[MI][NI][4];
#pragma unroll
    for (int mi = 0; mi < MI; mi++)
#pragma unroll
        for (int ni = 0; ni < NI; ni++)
#pragma unroll
            for (int q = 0; q < 4; q++) acc[mi][ni][q] = 0.f;

    auto load_stage = [&](int k0, int s) {
        unsigned short* st = sm + s * STAGE;
#pragma unroll
        for (int i = tid; i < BM * 4; i += NTH) {
            int r = i >> 2, c = i & 3;
            cp_async16(st + r * STR + c * 8, A + (size_t)(m0 + r) * K + k0 + c * 8);
        }
#pragma unroll
        for (int i = tid; i < BN * 4; i += NTH) {
            int r = i >> 2, c = i & 3;
            const size_t gs = (size_t)(n0 + r) * K + k0 + c * 8;
            cp_async16(st + ATI + r * STR + c * 8, Bh + gs);
            if (TERMS == 2)
                cp_async16(st + ATI + BTI + r * STR + c * 8, Bl + gs);
        }
        cp_commit();
    };

    const int KT = K / BK;
    load_stage(0, 0);

    for (int kt = 0; kt < KT; kt++) {
        const int s = kt & 1;
        if (kt + 1 < KT) { load_stage((kt + 1) * BK, s ^ 1); cp_wait<1>(); }
        else             { cp_wait<0>(); }
        __syncthreads();

        const uint32_t stOff = (uint32_t)(s * STAGE) * 2;
        const uint32_t aA = aBase + stOff;
        const uint32_t bH = bBase + stOff;
        const uint32_t bL = bH + (uint32_t)BTI * 2;

#pragma unroll
        for (int kk = 0; kk < BK; kk += 16) {
            unsigned ah[MI][4], bh[NI][2], bl[NI][2];
#pragma unroll
            for (int mi = 0; mi < MI; mi++)
                ldsm4(ah[mi][0], ah[mi][1], ah[mi][2], ah[mi][3],
                      aA + (uint32_t)(mi * 16 * STR + kk) * 2);
#pragma unroll
            for (int p = 0; p < NI / 2; p++) {
                ldsm4(bh[2*p][0], bh[2*p][1], bh[2*p+1][0], bh[2*p+1][1],
                      bH + (uint32_t)(p * 16 * STR + kk) * 2);
                if (TERMS == 2)
                    ldsm4(bl[2*p][0], bl[2*p][1], bl[2*p+1][0], bl[2*p+1][1],
                          bL + (uint32_t)(p * 16 * STR + kk) * 2);
            }
#pragma unroll
            for (int mi = 0; mi < MI; mi++)
#pragma unroll
                for (int ni = 0; ni < NI; ni++) {
                    mma16816(acc[mi][ni][0], acc[mi][ni][1], acc[mi][ni][2], acc[mi][ni][3],
                             ah[mi][0], ah[mi][1], ah[mi][2], ah[mi][3], bh[ni][0], bh[ni][1]);
                    if (TERMS == 2)
                        mma16816(acc[mi][ni][0], acc[mi][ni][1], acc[mi][ni][2], acc[mi][ni][3],
                                 ah[mi][0], ah[mi][1], ah[mi][2], ah[mi][3], bl[ni][0], bl[ni][1]);
                }
        }
        __syncthreads();
    }

    // ---- Epilogues ----
    if (EPI == 0 || EPI == 2 || EPI == 3) {
        float2 bv[NI];
#pragma unroll
        for (int ni = 0; ni < NI; ni++)
            bv[ni] = *(const float2*)(bias + n0 + wn0 + ni * 8 + 2 * t);

#pragma unroll
        for (int mi = 0; mi < MI; mi++) {
            int row0 = m0 + wm0 + mi * 16 + g;
#pragma unroll
            for (int ni = 0; ni < NI; ni++) {
                int col = n0 + wn0 + ni * 8 + 2 * t;
                float v0 = acc[mi][ni][0] + bv[ni].x;
                float v1 = acc[mi][ni][1] + bv[ni].y;
                float v2 = acc[mi][ni][2] + bv[ni].x;
                float v3 = acc[mi][ni][3] + bv[ni].y;
                if (ACT == 1) {
                    v0 = fmaxf(v0, 0.f); v1 = fmaxf(v1, 0.f);
                    v2 = fmaxf(v2, 0.f); v3 = fmaxf(v3, 0.f);
                }
                if (EPI == 0) {
                    *(float2*)(outf + (size_t)row0 * N + col)       = make_float2(v0, v1);
                    *(float2*)(outf + (size_t)(row0 + 8) * N + col) = make_float2(v2, v3);
                } else if (EPI == 2) {
                    *(ushort2*)(outh + (size_t)row0 * N + col) =
                        make_ushort2(h_of(v0), h_of(v1));
                    *(ushort2*)(outh + (size_t)(row0 + 8) * N + col) =
                        make_ushort2(h_of(v2), h_of(v3));
                } else {
                    int tt0 = row0 / B_DIM, bb0 = row0 % B_DIM;
                    int r1 = row0 + 8;
                    int tt1 = r1 / B_DIM, bb1 = r1 % B_DIM;
                    *(float2*)(outf + ((size_t)bb0 * T_DIM + tt0) * D_DIM + col) = make_float2(v0, v1);
                    *(float2*)(outf + ((size_t)bb1 * T_DIM + tt1) * D_DIM + col) = make_float2(v2, v3);
                }
            }
        }
    } else {
        // EPI == 1: fp16 out, + addvec (CWB incl. biases)
#pragma unroll
        for (int mi = 0; mi < MI; mi++) {
            int row0 = m0 + wm0 + mi * 16 + g;
#pragma unroll
            for (int ni = 0; ni < NI; ni++) {
                int col = n0 + wn0 + ni * 8 + 2 * t;
                float2 a0 = *(const float2*)(addvec + (size_t)(row0 & (B_DIM - 1)) * N + col);
                float2 a1 = *(const float2*)(addvec + (size_t)((row0 + 8) & (B_DIM - 1)) * N + col);
                *(ushort2*)(outh + (size_t)row0 * N + col) =
                    make_ushort2(h_of(acc[mi][ni][0] + a0.x), h_of(acc[mi][ni][1] + a0.y));
                *(ushort2*)(outh + (size_t)(row0 + 8) * N + col) =
                    make_ushort2(h_of(acc[mi][ni][2] + a1.x), h_of(acc[mi][ni][3] + a1.y));
            }
        }
    }
}

// ---------------------------------------------------------------------------
// Persistent LSTM recurrence: 256 CTAs (2/SM), tile 64x128, BK=32,
// Whh 1-term. ZW read as fp16. c-state in registers; grid barrier.
// ---------------------------------------------------------------------------
__global__ void __launch_bounds__(256, 2)
lstm_persistent(const unsigned short* __restrict__ Whh_h,
                const unsigned short* __restrict__ ZW,   // fp16 [T][B][G] (perm)
                unsigned short* __restrict__ H_h)
{
    constexpr int BM = 64, BN = 128, BK = 32, WM = 32, WN = 32;
    constexpr int STR = BK + 8;
    constexpr int ATI = BM * STR, BTI = BN * STR;
    constexpr int STAGE = ATI + BTI;
    constexpr int WARPS_N = BN / WN;
    constexpr int NTH = 256;
    constexpr int MI = WM / 16, NI = WN / 8;   // 2, 4
    constexpr int K = H_DIM, N = G_DIM;
    constexpr int KT = K / BK;

    extern __shared__ unsigned short sm[];

    const int tid  = threadIdx.x;
    const int warp = tid >> 5, lane = tid & 31;
    const int g = lane >> 2, t4 = lane & 3;
    const int wm0 = (warp / WARPS_N) * WM;
    const int wn0 = (warp % WARPS_N) * WN;
    const int bid = blockIdx.x;
    const int m0 = (bid >> 4) * BM;
    const int n0 = (bid & 15) * BN;

    const uint32_t smb = (uint32_t)__cvta_generic_to_shared(sm);
    const int aRow = (lane & 7) + ((lane >> 3) & 1) * 8;
    const int aKh  = (lane >> 4) * 16;
    const int bRow = (lane & 7) + (lane >> 4) * 8;
    const int bKh  = ((lane >> 3) & 1) * 16;
    const uint32_t aBase = smb + (uint32_t)(wm0 + aRow) * STR * 2 + aKh;
    const uint32_t bBase = smb + (uint32_t)(ATI + (wn0 + bRow) * STR) * 2 + bKh;

    const bool hi_half = (t4 & 1);

    float creg[MI][NI];
#pragma unroll
    for (int mi = 0; mi < MI; mi++)
#pragma unroll
        for (int ni = 0; ni < NI; ni++) creg[mi][ni] = 0.f;

    for (int t = 0; t < T_DIM; t++) {
        float acc[MI][NI][4];
#pragma unroll
        for (int mi = 0; mi < MI; mi++)
#pragma unroll
            for (int ni = 0; ni < NI; ni++)
#pragma unroll
                for (int q = 0; q < 4; q++) acc[mi][ni][q] = 0.f;

        if (t > 0) {
            const unsigned short* Ah = H_h + (size_t)(t - 1) * B_DIM * H_DIM;

            auto load_stage = [&](int k0, int s) {
                unsigned short* st = sm + s * STAGE;
#pragma unroll
                for (int i = tid; i < BM * 4; i += NTH) {
                    int r = i >> 2, c = i & 3;
                    cp_async16(st + r * STR + c * 8, Ah + (size_t)(m0 + r) * K + k0 + c * 8);
                }
#pragma unroll
                for (int i = tid; i < BN * 4; i += NTH) {
                    int r = i >> 2, c = i & 3;
                    cp_async16(st + ATI + r * STR + c * 8,
                               Whh_h + (size_t)(n0 + r) * K + k0 + c * 8);
                }
                cp_commit();
            };

            load_stage(0, 0);
            for (int kt = 0; kt < KT; kt++) {
                const int s = kt & 1;
                if (kt + 1 < KT) { load_stage((kt + 1) * BK, s ^ 1); cp_wait<1>(); }
                else             { cp_wait<0>(); }
                __syncthreads();

                const uint32_t stOff = (uint32_t)(s * STAGE) * 2;
                const uint32_t aA = aBase + stOff;
                const uint32_t bH = bBase + stOff;

#pragma unroll
                for (int kk = 0; kk < BK; kk += 16) {
                    unsigned ah[MI][4], bh[NI][2];
#pragma unroll
                    for (int mi = 0; mi < MI; mi++)
                        ldsm4(ah[mi][0], ah[mi][1], ah[mi][2], ah[mi][3],
                              aA + (uint32_t)(mi * 16 * STR + kk) * 2);
#pragma unroll
                    for (int p = 0; p < NI / 2; p++)
                        ldsm4(bh[2*p][0], bh[2*p][1], bh[2*p+1][0], bh[2*p+1][1],
                              bH + (uint32_t)(p * 16 * STR + kk) * 2);
#pragma unroll
                    for (int mi = 0; mi < MI; mi++)
#pragma unroll
                        for (int ni = 0; ni < NI; ni++)
                            mma16816(acc[mi][ni][0], acc[mi][ni][1], acc[mi][ni][2], acc[mi][ni][3],
                                     ah[mi][0], ah[mi][1], ah[mi][2], ah[mi][3], bh[ni][0], bh[ni][1]);
                }
                __syncthreads();
            }
        }

        // ---- Cell epilogue (c in registers; ZW fp16) ----
        const unsigned short* zwb = ZW + (size_t)t * B_DIM * G_DIM;
        unsigned short* hh = H_h + (size_t)t * B_DIM * H_DIM;
#pragma unroll
        for (int mi = 0; mi < MI; mi++) {
            int row0 = m0 + wm0 + mi * 16 + g;
#pragma unroll
            for (int ni = 0; ni < NI; ni++) {
                int col = n0 + wn0 + ni * 8 + 2 * t4;
                float c0 = acc[mi][ni][0], c1 = acc[mi][ni][1];
                float c2 = acc[mi][ni][2], c3 = acc[mi][ni][3];
                float sx = __shfl_xor_sync(0xffffffffu, hi_half ? c0 : c2, 1);
                float sy = __shfl_xor_sync(0xffffffffu, hi_half ? c1 : c3, 1);
                int row = hi_half ? row0 + 8 : row0;
                float gi, gf, gg, go;
                if (!hi_half) { gi = c0; gf = c1; gg = sx; go = sy; }
                else          { gi = sx; gf = sy; gg = c2; go = c3; }

                int base = col & ~3;
                ushort4 zr = *(const ushort4*)(zwb + (size_t)row * G_DIM + base);
                gi += f_of(zr.x); gf += f_of(zr.y);
                gg += f_of(zr.z); go += f_of(zr.w);

                float ig = 1.f / (1.f + expf(-gi));
                float fg = 1.f / (1.f + expf(-gf));
                float gt = tanhf(gg);
                float og = 1.f / (1.f + expf(-go));

                float cn = fg * creg[mi][ni] + ig * gt;
                creg[mi][ni] = cn;
                hh[(size_t)row * H_DIM + (col >> 2)] = h_of(og * tanhf(cn));
            }
        }

        // ---- Grid barrier between steps ----
        if (t < T_DIM - 1) {
            __syncthreads();
            if (tid == 0) {
                __threadfence();
                atomicAdd(&g_bar_ctr, 1u);
                unsigned target = (unsigned)(t + 1) * GRID_P;
                while (atomicAdd(&g_bar_ctr, 0u) < target) { }
            }
            __syncthreads();
        }
    }

    // Deterministic counter reset for graph replay
    __syncthreads();
    if (tid == 0) {
        unsigned d = atomicAdd(&g_done_ctr, 1u);
        if (d == GRID_P - 1) {
            g_bar_ctr = 0;
            g_done_ctr = 0;
            __threadfence();
        }
    }
}

// ---------------------------------------------------------------------------
// f32x2 SGEMM (label MLP), 64x64 tiles. OUT: 0 fp32, 1 single fp16.
// ---------------------------------------------------------------------------
__device__ __forceinline__ void ffma2(unsigned long long& d,
                                      unsigned long long a,
                                      unsigned long long b) {
    asm("fma.rn.f32x2 %0, %1, %2, %0;" : "+l"(d) : "l"(a), "l"(b));
}
__device__ __forceinline__ unsigned long long pack2(float lo, float hi) {
    unsigned long long r;
    asm("mov.b64 %0, {%1, %2};" : "=l"(r) : "f"(lo), "f"(hi));
    return r;
}
__device__ __forceinline__ float2 unpack2(unsigned long long u) {
    float2 f;
    asm("mov.b64 {%0, %1}, %2;" : "=f"(f.x), "=f"(f.y) : "l"(u));
    return f;
}

template<int BM, int BN, int BK, int TM, int TN, int ACT, int OUT>
__global__ void gemm2_kernel(const float* __restrict__ A,
                             const float* __restrict__ W,
                             const float* __restrict__ bias,
                             float* __restrict__ C,
                             unsigned short* __restrict__ uh,
                             int M, int N, int K)
{
    constexpr int AS_STRIDE = BM + 4;
    constexpr int WS_STRIDE = BN + 4;
    __shared__ float As[BK][AS_STRIDE];
    __shared__ float Ws[BK][WS_STRIDE];

    constexpr int NTH = (BM / TM) * (BN / TN);
    const int tid = threadIdx.x;
    const int tx = tid % (BN / TN);
    const int ty = tid / (BN / TN);
    const int m0 = blockIdx.y * BM;
    const int n0 = blockIdx.x * BN;

    unsigned long long acc2[TM / 2][TN];
#pragma unroll
    for (int p = 0; p < TM / 2; p++)
#pragma unroll
        for (int j = 0; j < TN; j++) acc2[p][j] = 0ULL;

    for (int k0 = 0; k0 < K; k0 += BK) {
#pragma unroll
        for (int i = tid * 4; i < BM * BK; i += NTH * 4) {
            int m = i / BK, k = i % BK;
            float4 v = *(const float4*)(A + (long)(m0 + m) * K + (k0 + k));
            As[k + 0][m] = v.x; As[k + 1][m] = v.y;
            As[k + 2][m] = v.z; As[k + 3][m] = v.w;
        }
#pragma unroll
        for (int i = tid * 4; i < BN * BK; i += NTH * 4) {
            int n = i / BK, k = i % BK;
            float4 v = *(const float4*)(W + (long)(n0 + n) * K + (k0 + k));
            Ws[k + 0][n] = v.x; Ws[k + 1][n] = v.y;
            Ws[k + 2][n] = v.z; Ws[k + 3][n] = v.w;
        }
        __syncthreads();

#pragma unroll
        for (int k = 0; k < BK; k++) {
            unsigned long long am2[TM / 2];
            const ulonglong2* ap = reinterpret_cast<const ulonglong2*>(&As[k][ty * TM]);
#pragma unroll
            for (int q = 0; q < TM / 4; q++) {
                ulonglong2 tt = ap[q];
                am2[2 * q + 0] = tt.x;
                am2[2 * q + 1] = tt.y;
            }
            float4 w4 = *reinterpret_cast<const float4*>(&Ws[k][tx * TN]);
            unsigned long long wd[TN];
            wd[0] = pack2(w4.x, w4.x); wd[1] = pack2(w4.y, w4.y);
            wd[2] = pack2(w4.z, w4.z); wd[3] = pack2(w4.w, w4.w);
#pragma unroll
            for (int p = 0; p < TM / 2; p++)
#pragma unroll
                for (int j = 0; j < TN; j++) ffma2(acc2[p][j], am2[p], wd[j]);
        }
        __syncthreads();
    }

    float4 bv = make_float4(0.f, 0.f, 0.f, 0.f);
    if (bias) bv = *reinterpret_cast<const float4*>(bias + n0 + tx * TN);

#pragma unroll
    for (int p = 0; p < TM / 2; p++) {
        float2 v0 = unpack2(acc2[p][0]);
        float2 v1 = unpack2(acc2[p][1]);
        float2 v2 = unpack2(acc2[p][2]);
        float2 v3 = unpack2(acc2[p][3]);
        float4 rowA = make_float4(v0.x + bv.x, v1.x + bv.y, v2.x + bv.z, v3.x + bv.w);
        float4 rowB = make_float4(v0.y + bv.x, v1.y + bv.y, v2.y + bv.z, v3.y + bv.w);
        if (ACT == 1) {
            rowA.x = fmaxf(rowA.x, 0.f); rowA.y = fmaxf(rowA.y, 0.f);
            rowA.z = fmaxf(rowA.z, 0.f); rowA.w = fmaxf(rowA.w, 0.f);
            rowB.x = fmaxf(rowB.x, 0.f); rowB.y = fmaxf(rowB.y, 0.f);
            rowB.z = fmaxf(rowB.z, 0.f); rowB.w = fmaxf(rowB.w, 0.f);
        }
        int mA = m0 + ty * TM + 2 * p;
        int n  = n0 + tx * TN;
        if (OUT == 0) {
            *reinterpret_cast<float4*>(C + (long)mA * N + n) = rowA;
            *reinterpret_cast<float4*>(C + (long)(mA + 1) * N + n) = rowB;
        } else {
            *(ushort4*)(uh + (size_t)mA * N + n) =
                make_ushort4(h_of(rowA.x), h_of(rowA.y), h_of(rowA.z), h_of(rowA.w));
            *(ushort4*)(uh + (size_t)(mA + 1) * N + n) =
                make_ushort4(h_of(rowB.x), h_of(rowB.y), h_of(rowB.z), h_of(rowB.w));
        }
    }
}

// ---------------------------------------------------------------------------
// Prep kernels
// ---------------------------------------------------------------------------
__device__ __forceinline__ void split4w(const float4* src, int i,
                                        ushort4* hi, ushort4* lo) {
    float4 v = src[i];
    ushort4 h, l;
    hsplit(v.x, h.x, l.x); hsplit(v.y, h.y, l.y);
    hsplit(v.z, h.z, l.z); hsplit(v.w, h.w, l.w);
    hi[i] = h;
    if (lo) lo[i] = l;
}

__device__ __forceinline__ void permsplit4w(const float* src, int i,
                                            ushort4* hi, ushort4* lo) {
    int r = i / (H_DIM / 4);
    int c = i % (H_DIM / 4);
    int j = r >> 2, gg = r & 3;
    float4 v = ((const float4*)src)[(size_t)(gg * H_DIM + j) * (H_DIM / 4) + c];
    ushort4 h, l;
    hsplit(v.x, h.x, l.x); hsplit(v.y, h.y, l.y);
    hsplit(v.z, h.z, l.z); hsplit(v.w, h.w, l.w);
    size_t o = (size_t)r * (H_DIM / 4) + c;
    hi[o] = h;
    if (lo) lo[o] = l;
}

__global__ void prep_weights(const float* __restrict__ P1, const float* __restrict__ P2,
                             const float* __restrict__ P3,
                             const float* __restrict__ Wih, const float* __restrict__ Whh,
                             const float* __restrict__ bih, const float* __restrict__ bhh,
                             ushort4* P1h, ushort4* P2h,
                             ushort4* P3h, ushort4* P3l,
                             ushort4* Wihh, ushort4* Wihl, ushort4* Whhh,
                             float* bp)
{
    const int S0 = H_DIM * H_DIM / 4;
    const int S1 = S0 + H_DIM * H_DIM / 4;
    const int S2 = S1 + D_DIM * H_DIM / 4;
    const int S3 = S2 + G_DIM * H_DIM / 4;
    const int S4 = S3 + G_DIM * H_DIM / 4;
    int i = blockIdx.x * blockDim.x + threadIdx.x;
    if      (i < S0) split4w((const float4*)P1, i, P1h, nullptr);
    else if (i < S1) split4w((const float4*)P2, i - S0, P2h, nullptr);
    else if (i < S2) split4w((const float4*)P3, i - S1, P3h, P3l);
    else if (i < S3) permsplit4w(Wih, i - S2, Wihh, Wihl);
    else if (i < S4) permsplit4w(Whh, i - S3, Whhh, nullptr);
    else if (i < S4 + G_DIM) {
        int k = i - S4;
        int j = k >> 2, gg = k & 3;
        bp[k] = bih[gg * H_DIM + j] + bhh[gg * H_DIM + j];
    }
}

// z -> single fp16
__global__ void cvt_half_kernel(const float4* __restrict__ src,
                                ushort4* __restrict__ dst, int n4)
{
    int i = blockIdx.x * blockDim.x + threadIdx.x;
    if (i >= n4) return;
    float4 v = src[i];
    dst[i] = make_ushort4(h_of(v.x), h_of(v.y), h_of(v.z), h_of(v.w));
}

// ---------------------------------------------------------------------------
// Launch
// ---------------------------------------------------------------------------
extern "C" void kernel_launch(void* const* d_in, const int* in_sizes, int n_in,
                              void* d_out, int out_size)
{
    const float* labels = (const float*)d_in[0];
    const float* z      = (const float*)d_in[1];
    const float* W1     = (const float*)d_in[2];
    const float* b1     = (const float*)d_in[3];
    const float* W2     = (const float*)d_in[4];
    const float* b2     = (const float*)d_in[5];
    const float* W3     = (const float*)d_in[6];
    const float* Wih    = (const float*)d_in[7];
    const float* Whh    = (const float*)d_in[8];
    const float* bih    = (const float*)d_in[9];
    const float* bhh    = (const float*)d_in[10];
    const float* P1     = (const float*)d_in[11];
    const float* pb1    = (const float*)d_in[12];
    const float* P2     = (const float*)d_in[13];
    const float* pb2    = (const float*)d_in[14];
    const float* P3     = (const float*)d_in[15];
    const float* pb3    = (const float*)d_in[16];
    float* out = (float*)d_out;

    float *x1, *x2, *bperm, *CWB;
    unsigned short *conds_h, *Wih_h, *Wih_l, *Whh_h;
    unsigned short *P1_h, *P2_h, *P3_h, *P3_l;
    unsigned short *z_h, *ZW, *H_h, *y1_h, *y2_h;
    cudaGetSymbolAddress((void**)&x1,     g_x1);
    cudaGetSymbolAddress((void**)&x2,     g_x2);
    cudaGetSymbolAddress((void**)&bperm,  g_bperm);
    cudaGetSymbolAddress((void**)&conds_h, g_conds_h);
    cudaGetSymbolAddress((void**)&Wih_h,  g_Wih_h);
    cudaGetSymbolAddress((void**)&Wih_l,  g_Wih_l);
    cudaGetSymbolAddress((void**)&Whh_h,  g_Whh_h);
    cudaGetSymbolAddress((void**)&P1_h,   g_P1_h);
    cudaGetSymbolAddress((void**)&P2_h,   g_P2_h);
    cudaGetSymbolAddress((void**)&P3_h,   g_P3_h);
    cudaGetSymbolAddress((void**)&P3_l,   g_P3_l);
    cudaGetSymbolAddress((void**)&CWB,    g_CWB);
    cudaGetSymbolAddress((void**)&z_h,    g_z_h);
    cudaGetSymbolAddress((void**)&ZW,     g_ZW);
    cudaGetSymbolAddress((void**)&H_h,    g_H_h);
    cudaGetSymbolAddress((void**)&y1_h,   g_y1_h);
    cudaGetSymbolAddress((void**)&y2_h,   g_y2_h);

    const int TB = TB_DIM;

    // Dynamic smem (BK=32, STR=40): 2 stages x (A + TERMS*B tiles)
    constexpr int SM128_T2 = 2 * (128 * 40 + 2 * 128 * 40) * 2;  // 61440 B
    constexpr int SM128_T1 = 2 * (128 * 40 + 1 * 128 * 40) * 2;  // 40960 B
    constexpr int SM64B    = 2 * (128 * 40 + 2 * 64 * 40) * 2;   // 40960 B (BN=64)
    constexpr int SMP      = 2 * (64 * 40 + 1 * 128 * 40) * 2;   // 30720 B (persistent)
    cudaFuncSetAttribute((const void*)hgemm<128,128,64,32,0,0,2>,
                         cudaFuncAttributeMaxDynamicSharedMemorySize, SM128_T2);
    cudaFuncSetAttribute((const void*)hgemm<128,128,64,32,1,0,1>,
                         cudaFuncAttributeMaxDynamicSharedMemorySize, SM128_T1);
    cudaFuncSetAttribute((const void*)hgemm<128,128,64,32,2,1,1>,
                         cudaFuncAttributeMaxDynamicSharedMemorySize, SM128_T1);
    cudaFuncSetAttribute((const void*)hgemm<128,64,64,16,3,0,2>,
                         cudaFuncAttributeMaxDynamicSharedMemorySize, SM64B);
    cudaFuncSetAttribute((const void*)lstm_persistent,
                         cudaFuncAttributeMaxDynamicSharedMemorySize, SMP);

    // [0] fused weight prep
    {
        const int total = 2 * (H_DIM * H_DIM / 4) + D_DIM * H_DIM / 4
                        + 2 * (G_DIM * H_DIM / 4) + G_DIM;
        prep_weights<<<(total + 255) / 256, 256>>>(
            P1, P2, P3, Wih, Whh, bih, bhh,
            (ushort4*)P1_h, (ushort4*)P2_h,
            (ushort4*)P3_h, (ushort4*)P3_l,
            (ushort4*)Wih_h, (ushort4*)Wih_l, (ushort4*)Whh_h,
            bperm);
    }
    // [1] z -> fp16
    cvt_half_kernel<<<(int)(((size_t)TB * H_DIM / 4) / 256), 256>>>(
        (const float4*)z, (ushort4*)z_h, TB * (H_DIM / 4));

    // [2..4] Label MLP (f32x2, 64x64 tiles); last layer writes conds fp16
    gemm2_kernel<64,64,16,4,4,1,0><<<dim3(H_DIM/64, B_DIM/64), 256>>>(
        labels, W1, b1, x1, nullptr, B_DIM, H_DIM, L_DIM);
    gemm2_kernel<64,64,16,4,4,1,0><<<dim3(H_DIM/64, B_DIM/64), 256>>>(
        x1, W2, b2, x2, nullptr, B_DIM, H_DIM, H_DIM);
    gemm2_kernel<64,64,16,4,4,0,1><<<dim3(H_DIM/64, B_DIM/64), 256>>>(
        x2, W3, nullptr, nullptr, conds_h, B_DIM, H_DIM, H_DIM);

    // [5] CWB = conds @ Wih_perm^T + (bih+bhh)_perm   (2-term, fp32 out)
    hgemm<128,128,64,32,0,0,2><<<dim3(G_DIM/128, B_DIM/128), 256, SM128_T2>>>(
        conds_h, Wih_h, Wih_l, bperm, nullptr,
        CWB, nullptr, B_DIM, G_DIM, H_DIM);
    // [6] ZW = z @ Wih_perm^T + CWB[row % B]   (1-term, fp16 out)
    hgemm<128,128,64,32,1,0,1><<<dim3(G_DIM/128, TB/128), 256, SM128_T1>>>(
        z_h, Wih_h, nullptr, nullptr, CWB,
        nullptr, ZW, TB, G_DIM, H_DIM);

    // [7] Persistent recurrence (one launch, 256 CTAs @ 2/SM, Whh 1-term)
    lstm_persistent<<<GRID_P, 256, SMP>>>(Whh_h, ZW, H_h);

    // [8..10] Projection MLP over all T*B rows (P1/P2 1-term, P3 2-term)
    hgemm<128,128,64,32,2,1,1><<<dim3(H_DIM/128, TB/128), 256, SM128_T1>>>(
        H_h, P1_h, nullptr, pb1, nullptr,
        nullptr, y1_h, TB, H_DIM, H_DIM);
    hgemm<128,128,64,32,2,1,1><<<dim3(H_DIM/128, TB/128), 256, SM128_T1>>>(
        y1_h, P2_h, nullptr, pb2, nullptr,
        nullptr, y2_h, TB, H_DIM, H_DIM);
    hgemm<128,64,64,16,3,0,2><<<dim3(D_DIM/64, TB/128), 256, SM64B>>>(
        y2_h, P3_h, P3_l, pb3, nullptr,
        out, nullptr, TB, D_DIM, H_DIM);
}

// round 14
// speedup vs baseline: 6.4487x; 1.0684x over previous
#include <cuda_runtime.h>
#include <cuda_fp16.h>
#include <math.h>
#include <stdint.h>

// Problem dims (fixed by the dataset)
#define B_DIM 1024
#define T_DIM 128
#define L_DIM 16
#define H_DIM 512
#define D_DIM 64
#define G_DIM 2048          // 4*H
#define TB_DIM (T_DIM * B_DIM)
#define GRID_P 256          // persistent recurrence grid (2 CTAs/SM)

// ---------------------------------------------------------------------------
// Scratch. Activations single fp16; Wih 2-term, Whh/P1/P2 1-term, P3 2-term.
// ZW stored fp16 (gate pre-activations, O(1) scale).
// ---------------------------------------------------------------------------
__device__ float    g_x1[B_DIM * H_DIM];
__device__ float    g_x2[B_DIM * H_DIM];
__device__ float    g_bperm[G_DIM];
__device__ unsigned short g_conds_h[B_DIM * H_DIM];
__device__ unsigned short g_Wih_h[G_DIM * H_DIM];
__device__ unsigned short g_Wih_l[G_DIM * H_DIM];
__device__ unsigned short g_Whh_h[G_DIM * H_DIM];
__device__ unsigned short g_P1_h[H_DIM * H_DIM];
__device__ unsigned short g_P2_h[H_DIM * H_DIM];
__device__ unsigned short g_P3_h[D_DIM * H_DIM];
__device__ unsigned short g_P3_l[D_DIM * H_DIM];
__device__ float    g_CWB[B_DIM * G_DIM];
__device__ unsigned short g_z_h[(size_t)TB_DIM * H_DIM];   // 128 MB
__device__ unsigned short g_ZW[(size_t)TB_DIM * G_DIM];    // 512 MB (fp16)
__device__ unsigned short g_H_h[(size_t)TB_DIM * H_DIM];
__device__ unsigned short g_y1_h[(size_t)TB_DIM * H_DIM];
__device__ unsigned short g_y2_h[(size_t)TB_DIM * H_DIM];

// Persistent-kernel grid barrier (monotonic; self-reset at kernel end)
__device__ unsigned g_bar_ctr  = 0;
__device__ unsigned g_done_ctr = 0;

// ---------------------------------------------------------------------------
// Helpers
// ---------------------------------------------------------------------------
__device__ __forceinline__ unsigned short h_of(float x) {
    return __half_as_ushort(__float2half_rn(x));
}
__device__ __forceinline__ float f_of(unsigned short u) {
    return __half2float(__ushort_as_half(u));
}
__device__ __forceinline__ void hsplit(float x, unsigned short& hi, unsigned short& lo) {
    __half h = __float2half_rn(x);
    float r = x - __half2float(h);
    __half l = __float2half_rn(r);
    hi = __half_as_ushort(h);
    lo = __half_as_ushort(l);
}

// mma m16n8k16 row.col fp16 -> f32
__device__ __forceinline__ void mma16816(float& c0, float& c1, float& c2, float& c3,
                                         unsigned a0, unsigned a1, unsigned a2, unsigned a3,
                                         unsigned b0, unsigned b1) {
    asm volatile(
        "mma.sync.aligned.m16n8k16.row.col.f32.f16.f16.f32 "
        "{%0,%1,%2,%3}, {%4,%5,%6,%7}, {%8,%9}, {%0,%1,%2,%3};\n"
        : "+f"(c0), "+f"(c1), "+f"(c2), "+f"(c3)
        : "r"(a0), "r"(a1), "r"(a2), "r"(a3), "r"(b0), "r"(b1));
}

__device__ __forceinline__ void ldsm4(unsigned& r0, unsigned& r1,
                                      unsigned& r2, unsigned& r3, uint32_t a) {
    asm volatile("ldmatrix.sync.aligned.m8n8.x4.shared.b16 {%0,%1,%2,%3}, [%4];"
                 : "=r"(r0), "=r"(r1), "=r"(r2), "=r"(r3) : "r"(a));
}

__device__ __forceinline__ void cp_async16(void* sptr, const void* gptr) {
    unsigned sa = (unsigned)__cvta_generic_to_shared(sptr);
    asm volatile("cp.async.cg.shared.global [%0], [%1], 16;\n" :: "r"(sa), "l"(gptr));
}
__device__ __forceinline__ void cp_commit() {
    asm volatile("cp.async.commit_group;\n");
}
template<int N>
__device__ __forceinline__ void cp_wait() {
    asm volatile("cp.async.wait_group %0;\n" :: "n"(N));
}

// ---------------------------------------------------------------------------
// fp16 GEMM: D[M,N] = A@B^T, A single fp16, B = Bh (+ Bl if TERMS==2).
// BK=32 2-stage cp.async, ldmatrix fragments, STR=40 ushorts (conflict-free).
// EPI: 0 = fp32 + bias (CWB)
//      1 = fp16 out: acc + addvec[row % B][col]  (ZW build, CWB fold)
//      2 = fp16 out + bias (+relu if ACT)    (P1, P2)
//      3 = fp32 + bias, [T,B]->[B,T] perm    (P3)
// ---------------------------------------------------------------------------
template<int BM, int BN, int WM, int WN, int EPI, int ACT, int TERMS>
__global__ void __launch_bounds__((BM / WM) * (BN / WN) * 32, 2)
hgemm(const unsigned short* __restrict__ A,
      const unsigned short* __restrict__ Bh, const unsigned short* __restrict__ Bl,
      const float* __restrict__ bias,
      const float* __restrict__ addvec,
      float* __restrict__ outf,
      unsigned short* __restrict__ outh,
      int M, int N, int K)
{
    constexpr int BK = 32;
    constexpr int STR = BK + 8;              // 40 ushorts
    constexpr int ATI = BM * STR;
    constexpr int BTI = BN * STR;
    constexpr int STAGE = ATI + TERMS * BTI;
    constexpr int WARPS_N = BN / WN;
    constexpr int NTH = (BM / WM) * (BN / WN) * 32;
    constexpr int MI = WM / 16, NI = WN / 8;

    extern __shared__ unsigned short sm[];

    const int tid  = threadIdx.x;
    const int warp = tid >> 5, lane = tid & 31;
    const int g = lane >> 2, t = lane & 3;
    const int wm0 = (warp / WARPS_N) * WM;
    const int wn0 = (warp % WARPS_N) * WN;
    const int m0 = blockIdx.y * BM;
    const int n0 = blockIdx.x * BN;

    const uint32_t smb = (uint32_t)__cvta_generic_to_shared(sm);
    const int aRow = (lane & 7) + ((lane >> 3) & 1) * 8;
    const int aKh  = (lane >> 4) * 16;
    const int bRow = (lane & 7) + (lane >> 4) * 8;
    const int bKh  = ((lane >> 3) & 1) * 16;
    const uint32_t aBase = smb + (uint32_t)(wm0 + aRow) * STR * 2 + aKh;
    const uint32_t bBase = smb + (uint32_t)(ATI + (wn0 + bRow) * STR) * 2 + bKh;

    float acc[MI][NI][4];
#pragma unroll
    for (int mi = 0; mi < MI; mi++)
#pragma unroll
        for (int ni = 0; ni < NI; ni++)
#pragma unroll
            for (int q = 0; q < 4; q++) acc[mi][ni][q] = 0.f;

    auto load_stage = [&](int k0, int s) {
        unsigned short* st = sm + s * STAGE;
#pragma unroll
        for (int i = tid; i < BM * 4; i += NTH) {
            int r = i >> 2, c = i & 3;
            cp_async16(st + r * STR + c * 8, A + (size_t)(m0 + r) * K + k0 + c * 8);
        }
#pragma unroll
        for (int i = tid; i < BN * 4; i += NTH) {
            int r = i >> 2, c = i & 3;
            const size_t gs = (size_t)(n0 + r) * K + k0 + c * 8;
            cp_async16(st + ATI + r * STR + c * 8, Bh + gs);
            if (TERMS == 2)
                cp_async16(st + ATI + BTI + r * STR + c * 8, Bl + gs);
        }
        cp_commit();
    };

    const int KT = K / BK;
    load_stage(0, 0);

    for (int kt = 0; kt < KT; kt++) {
        const int s = kt & 1;
        if (kt + 1 < KT) { load_stage((kt + 1) * BK, s ^ 1); cp_wait<1>(); }
        else             { cp_wait<0>(); }
        __syncthreads();

        const uint32_t stOff = (uint32_t)(s * STAGE) * 2;
        const uint32_t aA = aBase + stOff;
        const uint32_t bH = bBase + stOff;
        const uint32_t bL = bH + (uint32_t)BTI * 2;

#pragma unroll
        for (int kk = 0; kk < BK; kk += 16) {
            unsigned ah[MI][4], bh[NI][2], bl[NI][2];
#pragma unroll
            for (int mi = 0; mi < MI; mi++)
                ldsm4(ah[mi][0], ah[mi][1], ah[mi][2], ah[mi][3],
                      aA + (uint32_t)(mi * 16 * STR + kk) * 2);
#pragma unroll
            for (int p = 0; p < NI / 2; p++) {
                ldsm4(bh[2*p][0], bh[2*p][1], bh[2*p+1][0], bh[2*p+1][1],
                      bH + (uint32_t)(p * 16 * STR + kk) * 2);
                if (TERMS == 2)
                    ldsm4(bl[2*p][0], bl[2*p][1], bl[2*p+1][0], bl[2*p+1][1],
                          bL + (uint32_t)(p * 16 * STR + kk) * 2);
            }
#pragma unroll
            for (int mi = 0; mi < MI; mi++)
#pragma unroll
                for (int ni = 0; ni < NI; ni++) {
                    mma16816(acc[mi][ni][0], acc[mi][ni][1], acc[mi][ni][2], acc[mi][ni][3],
                             ah[mi][0], ah[mi][1], ah[mi][2], ah[mi][3], bh[ni][0], bh[ni][1]);
                    if (TERMS == 2)
                        mma16816(acc[mi][ni][0], acc[mi][ni][1], acc[mi][ni][2], acc[mi][ni][3],
                                 ah[mi][0], ah[mi][1], ah[mi][2], ah[mi][3], bl[ni][0], bl[ni][1]);
                }
        }
        __syncthreads();
    }

    // ---- Epilogues ----
    if (EPI == 0 || EPI == 2 || EPI == 3) {
        float2 bv[NI];
#pragma unroll
        for (int ni = 0; ni < NI; ni++)
            bv[ni] = *(const float2*)(bias + n0 + wn0 + ni * 8 + 2 * t);

#pragma unroll
        for (int mi = 0; mi < MI; mi++) {
            int row0 = m0 + wm0 + mi * 16 + g;
#pragma unroll
            for (int ni = 0; ni < NI; ni++) {
                int col = n0 + wn0 + ni * 8 + 2 * t;
                float v0 = acc[mi][ni][0] + bv[ni].x;
                float v1 = acc[mi][ni][1] + bv[ni].y;
                float v2 = acc[mi][ni][2] + bv[ni].x;
                float v3 = acc[mi][ni][3] + bv[ni].y;
                if (ACT == 1) {
                    v0 = fmaxf(v0, 0.f); v1 = fmaxf(v1, 0.f);
                    v2 = fmaxf(v2, 0.f); v3 = fmaxf(v3, 0.f);
                }
                if (EPI == 0) {
                    *(float2*)(outf + (size_t)row0 * N + col)       = make_float2(v0, v1);
                    *(float2*)(outf + (size_t)(row0 + 8) * N + col) = make_float2(v2, v3);
                } else if (EPI == 2) {
                    *(ushort2*)(outh + (size_t)row0 * N + col) =
                        make_ushort2(h_of(v0), h_of(v1));
                    *(ushort2*)(outh + (size_t)(row0 + 8) * N + col) =
                        make_ushort2(h_of(v2), h_of(v3));
                } else {
                    int tt0 = row0 / B_DIM, bb0 = row0 % B_DIM;
                    int r1 = row0 + 8;
                    int tt1 = r1 / B_DIM, bb1 = r1 % B_DIM;
                    *(float2*)(outf + ((size_t)bb0 * T_DIM + tt0) * D_DIM + col) = make_float2(v0, v1);
                    *(float2*)(outf + ((size_t)bb1 * T_DIM + tt1) * D_DIM + col) = make_float2(v2, v3);
                }
            }
        }
    } else {
        // EPI == 1: fp16 out, + addvec (CWB incl. biases)
#pragma unroll
        for (int mi = 0; mi < MI; mi++) {
            int row0 = m0 + wm0 + mi * 16 + g;
#pragma unroll
            for (int ni = 0; ni < NI; ni++) {
                int col = n0 + wn0 + ni * 8 + 2 * t;
                float2 a0 = *(const float2*)(addvec + (size_t)(row0 & (B_DIM - 1)) * N + col);
                float2 a1 = *(const float2*)(addvec + (size_t)((row0 + 8) & (B_DIM - 1)) * N + col);
                *(ushort2*)(outh + (size_t)row0 * N + col) =
                    make_ushort2(h_of(acc[mi][ni][0] + a0.x), h_of(acc[mi][ni][1] + a0.y));
                *(ushort2*)(outh + (size_t)(row0 + 8) * N + col) =
                    make_ushort2(h_of(acc[mi][ni][2] + a1.x), h_of(acc[mi][ni][3] + a1.y));
            }
        }
    }
}

// ---------------------------------------------------------------------------
// Persistent LSTM recurrence: 256 CTAs (2/SM), tile 64x128, BK=64 (8 k-iters),
// Whh 1-term. ZW read fp16. c in registers. Grid barrier: atomic arrivals +
// volatile-load polling (no RMW contention on the counter line).
// ---------------------------------------------------------------------------
__global__ void __launch_bounds__(256, 2)
lstm_persistent(const unsigned short* __restrict__ Whh_h,
                const unsigned short* __restrict__ ZW,   // fp16 [T][B][G] (perm)
                unsigned short* __restrict__ H_h)
{
    constexpr int BM = 64, BN = 128, BK = 64, WM = 32, WN = 32;
    constexpr int STR = BK + 8;                // 72 ushorts (144 B rows)
    constexpr int ATI = BM * STR, BTI = BN * STR;
    constexpr int STAGE = ATI + BTI;           // 13824 ushorts
    constexpr int WARPS_N = BN / WN;
    constexpr int NTH = 256;
    constexpr int MI = WM / 16, NI = WN / 8;   // 2, 4
    constexpr int K = H_DIM, N = G_DIM;
    constexpr int KT = K / BK;                 // 8

    extern __shared__ unsigned short sm[];

    const int tid  = threadIdx.x;
    const int warp = tid >> 5, lane = tid & 31;
    const int g = lane >> 2, t4 = lane & 3;
    const int wm0 = (warp / WARPS_N) * WM;
    const int wn0 = (warp % WARPS_N) * WN;
    const int bid = blockIdx.x;
    const int m0 = (bid >> 4) * BM;
    const int n0 = (bid & 15) * BN;

    const uint32_t smb = (uint32_t)__cvta_generic_to_shared(sm);
    const int aRow = (lane & 7) + ((lane >> 3) & 1) * 8;
    const int aKh  = (lane >> 4) * 16;
    const int bRow = (lane & 7) + (lane >> 4) * 8;
    const int bKh  = ((lane >> 3) & 1) * 16;
    const uint32_t aBase = smb + (uint32_t)(wm0 + aRow) * STR * 2 + aKh;
    const uint32_t bBase = smb + (uint32_t)(ATI + (wn0 + bRow) * STR) * 2 + bKh;

    const bool hi_half = (t4 & 1);

    float creg[MI][NI];
#pragma unroll
    for (int mi = 0; mi < MI; mi++)
#pragma unroll
        for (int ni = 0; ni < NI; ni++) creg[mi][ni] = 0.f;

    for (int t = 0; t < T_DIM; t++) {
        float acc[MI][NI][4];
#pragma unroll
        for (int mi = 0; mi < MI; mi++)
#pragma unroll
            for (int ni = 0; ni < NI; ni++)
#pragma unroll
                for (int q = 0; q < 4; q++) acc[mi][ni][q] = 0.f;

        if (t > 0) {
            const unsigned short* Ah = H_h + (size_t)(t - 1) * B_DIM * H_DIM;

            auto load_stage = [&](int k0, int s) {
                unsigned short* st = sm + s * STAGE;
#pragma unroll
                for (int i = tid; i < BM * 8; i += NTH) {
                    int r = i >> 3, c = i & 7;
                    cp_async16(st + r * STR + c * 8, Ah + (size_t)(m0 + r) * K + k0 + c * 8);
                }
#pragma unroll
                for (int i = tid; i < BN * 8; i += NTH) {
                    int r = i >> 3, c = i & 7;
                    cp_async16(st + ATI + r * STR + c * 8,
                               Whh_h + (size_t)(n0 + r) * K + k0 + c * 8);
                }
                cp_commit();
            };

            load_stage(0, 0);
            for (int kt = 0; kt < KT; kt++) {
                const int s = kt & 1;
                if (kt + 1 < KT) { load_stage((kt + 1) * BK, s ^ 1); cp_wait<1>(); }
                else             { cp_wait<0>(); }
                __syncthreads();

                const uint32_t stOff = (uint32_t)(s * STAGE) * 2;
                const uint32_t aA = aBase + stOff;
                const uint32_t bH = bBase + stOff;

#pragma unroll
                for (int kk = 0; kk < BK; kk += 16) {
                    unsigned ah[MI][4], bh[NI][2];
#pragma unroll
                    for (int mi = 0; mi < MI; mi++)
                        ldsm4(ah[mi][0], ah[mi][1], ah[mi][2], ah[mi][3],
                              aA + (uint32_t)(mi * 16 * STR + kk) * 2);
#pragma unroll
                    for (int p = 0; p < NI / 2; p++)
                        ldsm4(bh[2*p][0], bh[2*p][1], bh[2*p+1][0], bh[2*p+1][1],
                              bH + (uint32_t)(p * 16 * STR + kk) * 2);
#pragma unroll
                    for (int mi = 0; mi < MI; mi++)
#pragma unroll
                        for (int ni = 0; ni < NI; ni++)
                            mma16816(acc[mi][ni][0], acc[mi][ni][1], acc[mi][ni][2], acc[mi][ni][3],
                                     ah[mi][0], ah[mi][1], ah[mi][2], ah[mi][3], bh[ni][0], bh[ni][1]);
                }
                __syncthreads();
            }
        }

        // ---- Cell epilogue (c in registers; ZW fp16) ----
        const unsigned short* zwb = ZW + (size_t)t * B_DIM * G_DIM;
        unsigned short* hh = H_h + (size_t)t * B_DIM * H_DIM;
#pragma unroll
        for (int mi = 0; mi < MI; mi++) {
            int row0 = m0 + wm0 + mi * 16 + g;
#pragma unroll
            for (int ni = 0; ni < NI; ni++) {
                int col = n0 + wn0 + ni * 8 + 2 * t4;
                float c0 = acc[mi][ni][0], c1 = acc[mi][ni][1];
                float c2 = acc[mi][ni][2], c3 = acc[mi][ni][3];
                float sx = __shfl_xor_sync(0xffffffffu, hi_half ? c0 : c2, 1);
                float sy = __shfl_xor_sync(0xffffffffu, hi_half ? c1 : c3, 1);
                int row = hi_half ? row0 + 8 : row0;
                float gi, gf, gg, go;
                if (!hi_half) { gi = c0; gf = c1; gg = sx; go = sy; }
                else          { gi = sx; gf = sy; gg = c2; go = c3; }

                int base = col & ~3;
                ushort4 zr = *(const ushort4*)(zwb + (size_t)row * G_DIM + base);
                gi += f_of(zr.x); gf += f_of(zr.y);
                gg += f_of(zr.z); go += f_of(zr.w);

                float ig = 1.f / (1.f + expf(-gi));
                float fg = 1.f / (1.f + expf(-gf));
                float gt = tanhf(gg);
                float og = 1.f / (1.f + expf(-go));

                float cn = fg * creg[mi][ni] + ig * gt;
                creg[mi][ni] = cn;
                hh[(size_t)row * H_DIM + (col >> 2)] = h_of(og * tanhf(cn));
            }
        }

        // ---- Grid barrier: atomic arrival, volatile-load poll ----
        if (t < T_DIM - 1) {
            __syncthreads();
            if (tid == 0) {
                __threadfence();
                atomicAdd(&g_bar_ctr, 1u);
                unsigned target = (unsigned)(t + 1) * GRID_P;
                volatile unsigned* ctr = &g_bar_ctr;
                while (*ctr < target) { }
                __threadfence();   // acquire: order subsequent H reads
            }
            __syncthreads();
        }
    }

    // Deterministic counter reset for graph replay
    __syncthreads();
    if (tid == 0) {
        unsigned d = atomicAdd(&g_done_ctr, 1u);
        if (d == GRID_P - 1) {
            g_bar_ctr = 0;
            g_done_ctr = 0;
            __threadfence();
        }
    }
}

// ---------------------------------------------------------------------------
// f32x2 SGEMM (label MLP), 64x64 tiles. OUT: 0 fp32, 1 single fp16.
// ---------------------------------------------------------------------------
__device__ __forceinline__ void ffma2(unsigned long long& d,
                                      unsigned long long a,
                                      unsigned long long b) {
    asm("fma.rn.f32x2 %0, %1, %2, %0;" : "+l"(d) : "l"(a), "l"(b));
}
__device__ __forceinline__ unsigned long long pack2(float lo, float hi) {
    unsigned long long r;
    asm("mov.b64 %0, {%1, %2};" : "=l"(r) : "f"(lo), "f"(hi));
    return r;
}
__device__ __forceinline__ float2 unpack2(unsigned long long u) {
    float2 f;
    asm("mov.b64 {%0, %1}, %2;" : "=f"(f.x), "=f"(f.y) : "l"(u));
    return f;
}

template<int BM, int BN, int BK, int TM, int TN, int ACT, int OUT>
__global__ void gemm2_kernel(const float* __restrict__ A,
                             const float* __restrict__ W,
                             const float* __restrict__ bias,
                             float* __restrict__ C,
                             unsigned short* __restrict__ uh,
                             int M, int N, int K)
{
    constexpr int AS_STRIDE = BM + 4;
    constexpr int WS_STRIDE = BN + 4;
    __shared__ float As[BK][AS_STRIDE];
    __shared__ float Ws[BK][WS_STRIDE];

    constexpr int NTH = (BM / TM) * (BN / TN);
    const int tid = threadIdx.x;
    const int tx = tid % (BN / TN);
    const int ty = tid / (BN / TN);
    const int m0 = blockIdx.y * BM;
    const int n0 = blockIdx.x * BN;

    unsigned long long acc2[TM / 2][TN];
#pragma unroll
    for (int p = 0; p < TM / 2; p++)
#pragma unroll
        for (int j = 0; j < TN; j++) acc2[p][j] = 0ULL;

    for (int k0 = 0; k0 < K; k0 += BK) {
#pragma unroll
        for (int i = tid * 4; i < BM * BK; i += NTH * 4) {
            int m = i / BK, k = i % BK;
            float4 v = *(const float4*)(A + (long)(m0 + m) * K + (k0 + k));
            As[k + 0][m] = v.x; As[k + 1][m] = v.y;
            As[k + 2][m] = v.z; As[k + 3][m] = v.w;
        }
#pragma unroll
        for (int i = tid * 4; i < BN * BK; i += NTH * 4) {
            int n = i / BK, k = i % BK;
            float4 v = *(const float4*)(W + (long)(n0 + n) * K + (k0 + k));
            Ws[k + 0][n] = v.x; Ws[k + 1][n] = v.y;
            Ws[k + 2][n] = v.z; Ws[k + 3][n] = v.w;
        }
        __syncthreads();

#pragma unroll
        for (int k = 0; k < BK; k++) {
            unsigned long long am2[TM / 2];
            const ulonglong2* ap = reinterpret_cast<const ulonglong2*>(&As[k][ty * TM]);
#pragma unroll
            for (int q = 0; q < TM / 4; q++) {
                ulonglong2 tt = ap[q];
                am2[2 * q + 0] = tt.x;
                am2[2 * q + 1] = tt.y;
            }
            float4 w4 = *reinterpret_cast<const float4*>(&Ws[k][tx * TN]);
            unsigned long long wd[TN];
            wd[0] = pack2(w4.x, w4.x); wd[1] = pack2(w4.y, w4.y);
            wd[2] = pack2(w4.z, w4.z); wd[3] = pack2(w4.w, w4.w);
#pragma unroll
            for (int p = 0; p < TM / 2; p++)
#pragma unroll
                for (int j = 0; j < TN; j++) ffma2(acc2[p][j], am2[p], wd[j]);
        }
        __syncthreads();
    }

    float4 bv = make_float4(0.f, 0.f, 0.f, 0.f);
    if (bias) bv = *reinterpret_cast<const float4*>(bias + n0 + tx * TN);

#pragma unroll
    for (int p = 0; p < TM / 2; p++) {
        float2 v0 = unpack2(acc2[p][0]);
        float2 v1 = unpack2(acc2[p][1]);
        float2 v2 = unpack2(acc2[p][2]);
        float2 v3 = unpack2(acc2[p][3]);
        float4 rowA = make_float4(v0.x + bv.x, v1.x + bv.y, v2.x + bv.z, v3.x + bv.w);
        float4 rowB = make_float4(v0.y + bv.x, v1.y + bv.y, v2.y + bv.z, v3.y + bv.w);
        if (ACT == 1) {
            rowA.x = fmaxf(rowA.x, 0.f); rowA.y = fmaxf(rowA.y, 0.f);
            rowA.z = fmaxf(rowA.z, 0.f); rowA.w = fmaxf(rowA.w, 0.f);
            rowB.x = fmaxf(rowB.x, 0.f); rowB.y = fmaxf(rowB.y, 0.f);
            rowB.z = fmaxf(rowB.z, 0.f); rowB.w = fmaxf(rowB.w, 0.f);
        }
        int mA = m0 + ty * TM + 2 * p;
        int n  = n0 + tx * TN;
        if (OUT == 0) {
            *reinterpret_cast<float4*>(C + (long)mA * N + n) = rowA;
            *reinterpret_cast<float4*>(C + (long)(mA + 1) * N + n) = rowB;
        } else {
            *(ushort4*)(uh + (size_t)mA * N + n) =
                make_ushort4(h_of(rowA.x), h_of(rowA.y), h_of(rowA.z), h_of(rowA.w));
            *(ushort4*)(uh + (size_t)(mA + 1) * N + n) =
                make_ushort4(h_of(rowB.x), h_of(rowB.y), h_of(rowB.z), h_of(rowB.w));
        }
    }
}

// ---------------------------------------------------------------------------
// Prep kernels
// ---------------------------------------------------------------------------
__device__ __forceinline__ void split4w(const float4* src, int i,
                                        ushort4* hi, ushort4* lo) {
    float4 v = src[i];
    ushort4 h, l;
    hsplit(v.x, h.x, l.x); hsplit(v.y, h.y, l.y);
    hsplit(v.z, h.z, l.z); hsplit(v.w, h.w, l.w);
    hi[i] = h;
    if (lo) lo[i] = l;
}

__device__ __forceinline__ void permsplit4w(const float* src, int i,
                                            ushort4* hi, ushort4* lo) {
    int r = i / (H_DIM / 4);
    int c = i % (H_DIM / 4);
    int j = r >> 2, gg = r & 3;
    float4 v = ((const float4*)src)[(size_t)(gg * H_DIM + j) * (H_DIM / 4) + c];
    ushort4 h, l;
    hsplit(v.x, h.x, l.x); hsplit(v.y, h.y, l.y);
    hsplit(v.z, h.z, l.z); hsplit(v.w, h.w, l.w);
    size_t o = (size_t)r * (H_DIM / 4) + c;
    hi[o] = h;
    if (lo) lo[o] = l;
}

__global__ void prep_weights(const float* __restrict__ P1, const float* __restrict__ P2,
                             const float* __restrict__ P3,
                             const float* __restrict__ Wih, const float* __restrict__ Whh,
                             const float* __restrict__ bih, const float* __restrict__ bhh,
                             ushort4* P1h, ushort4* P2h,
                             ushort4* P3h, ushort4* P3l,
                             ushort4* Wihh, ushort4* Wihl, ushort4* Whhh,
                             float* bp)
{
    const int S0 = H_DIM * H_DIM / 4;
    const int S1 = S0 + H_DIM * H_DIM / 4;
    const int S2 = S1 + D_DIM * H_DIM / 4;
    const int S3 = S2 + G_DIM * H_DIM / 4;
    const int S4 = S3 + G_DIM * H_DIM / 4;
    int i = blockIdx.x * blockDim.x + threadIdx.x;
    if      (i < S0) split4w((const float4*)P1, i, P1h, nullptr);
    else if (i < S1) split4w((const float4*)P2, i - S0, P2h, nullptr);
    else if (i < S2) split4w((const float4*)P3, i - S1, P3h, P3l);
    else if (i < S3) permsplit4w(Wih, i - S2, Wihh, Wihl);
    else if (i < S4) permsplit4w(Whh, i - S3, Whhh, nullptr);
    else if (i < S4 + G_DIM) {
        int k = i - S4;
        int j = k >> 2, gg = k & 3;
        bp[k] = bih[gg * H_DIM + j] + bhh[gg * H_DIM + j];
    }
}

// z -> single fp16
__global__ void cvt_half_kernel(const float4* __restrict__ src,
                                ushort4* __restrict__ dst, int n4)
{
    int i = blockIdx.x * blockDim.x + threadIdx.x;
    if (i >= n4) return;
    float4 v = src[i];
    dst[i] = make_ushort4(h_of(v.x), h_of(v.y), h_of(v.z), h_of(v.w));
}

// ---------------------------------------------------------------------------
// Launch
// ---------------------------------------------------------------------------
extern "C" void kernel_launch(void* const* d_in, const int* in_sizes, int n_in,
                              void* d_out, int out_size)
{
    const float* labels = (const float*)d_in[0];
    const float* z      = (const float*)d_in[1];
    const float* W1     = (const float*)d_in[2];
    const float* b1     = (const float*)d_in[3];
    const float* W2     = (const float*)d_in[4];
    const float* b2     = (const float*)d_in[5];
    const float* W3     = (const float*)d_in[6];
    const float* Wih    = (const float*)d_in[7];
    const float* Whh    = (const float*)d_in[8];
    const float* bih    = (const float*)d_in[9];
    const float* bhh    = (const float*)d_in[10];
    const float* P1     = (const float*)d_in[11];
    const float* pb1    = (const float*)d_in[12];
    const float* P2     = (const float*)d_in[13];
    const float* pb2    = (const float*)d_in[14];
    const float* P3     = (const float*)d_in[15];
    const float* pb3    = (const float*)d_in[16];
    float* out = (float*)d_out;

    float *x1, *x2, *bperm, *CWB;
    unsigned short *conds_h, *Wih_h, *Wih_l, *Whh_h;
    unsigned short *P1_h, *P2_h, *P3_h, *P3_l;
    unsigned short *z_h, *ZW, *H_h, *y1_h, *y2_h;
    cudaGetSymbolAddress((void**)&x1,     g_x1);
    cudaGetSymbolAddress((void**)&x2,     g_x2);
    cudaGetSymbolAddress((void**)&bperm,  g_bperm);
    cudaGetSymbolAddress((void**)&conds_h, g_conds_h);
    cudaGetSymbolAddress((void**)&Wih_h,  g_Wih_h);
    cudaGetSymbolAddress((void**)&Wih_l,  g_Wih_l);
    cudaGetSymbolAddress((void**)&Whh_h,  g_Whh_h);
    cudaGetSymbolAddress((void**)&P1_h,   g_P1_h);
    cudaGetSymbolAddress((void**)&P2_h,   g_P2_h);
    cudaGetSymbolAddress((void**)&P3_h,   g_P3_h);
    cudaGetSymbolAddress((void**)&P3_l,   g_P3_l);
    cudaGetSymbolAddress((void**)&CWB,    g_CWB);
    cudaGetSymbolAddress((void**)&z_h,    g_z_h);
    cudaGetSymbolAddress((void**)&ZW,     g_ZW);
    cudaGetSymbolAddress((void**)&H_h,    g_H_h);
    cudaGetSymbolAddress((void**)&y1_h,   g_y1_h);
    cudaGetSymbolAddress((void**)&y2_h,   g_y2_h);

    const int TB = TB_DIM;

    // Dynamic smem: hgemm BK=32 (STR=40); persistent BK=64 (STR=72)
    constexpr int SM128_T2 = 2 * (128 * 40 + 2 * 128 * 40) * 2;  // 61440 B
    constexpr int SM128_T1 = 2 * (128 * 40 + 1 * 128 * 40) * 2;  // 40960 B
    constexpr int SM64B    = 2 * (128 * 40 + 2 * 64 * 40) * 2;   // 40960 B (BN=64)
    constexpr int SMP      = 2 * (64 * 72 + 128 * 72) * 2;       // 55296 B (persistent)
    cudaFuncSetAttribute((const void*)hgemm<128,128,64,32,0,0,2>,
                         cudaFuncAttributeMaxDynamicSharedMemorySize, SM128_T2);
    cudaFuncSetAttribute((const void*)hgemm<128,128,64,32,1,0,1>,
                         cudaFuncAttributeMaxDynamicSharedMemorySize, SM128_T1);
    cudaFuncSetAttribute((const void*)hgemm<128,128,64,32,2,1,1>,
                         cudaFuncAttributeMaxDynamicSharedMemorySize, SM128_T1);
    cudaFuncSetAttribute((const void*)hgemm<128,64,64,16,3,0,2>,
                         cudaFuncAttributeMaxDynamicSharedMemorySize, SM64B);
    cudaFuncSetAttribute((const void*)lstm_persistent,
                         cudaFuncAttributeMaxDynamicSharedMemorySize, SMP);

    // [0] fused weight prep
    {
        const int total = 2 * (H_DIM * H_DIM / 4) + D_DIM * H_DIM / 4
                        + 2 * (G_DIM * H_DIM / 4) + G_DIM;
        prep_weights<<<(total + 255) / 256, 256>>>(
            P1, P2, P3, Wih, Whh, bih, bhh,
            (ushort4*)P1_h, (ushort4*)P2_h,
            (ushort4*)P3_h, (ushort4*)P3_l,
            (ushort4*)Wih_h, (ushort4*)Wih_l, (ushort4*)Whh_h,
            bperm);
    }
    // [1] z -> fp16
    cvt_half_kernel<<<(int)(((size_t)TB * H_DIM / 4) / 256), 256>>>(
        (const float4*)z, (ushort4*)z_h, TB * (H_DIM / 4));

    // [2..4] Label MLP (f32x2, 64x64 tiles); last layer writes conds fp16
    gemm2_kernel<64,64,16,4,4,1,0><<<dim3(H_DIM/64, B_DIM/64), 256>>>(
        labels, W1, b1, x1, nullptr, B_DIM, H_DIM, L_DIM);
    gemm2_kernel<64,64,16,4,4,1,0><<<dim3(H_DIM/64, B_DIM/64), 256>>>(
        x1, W2, b2, x2, nullptr, B_DIM, H_DIM, H_DIM);
    gemm2_kernel<64,64,16,4,4,0,1><<<dim3(H_DIM/64, B_DIM/64), 256>>>(
        x2, W3, nullptr, nullptr, conds_h, B_DIM, H_DIM, H_DIM);

    // [5] CWB = conds @ Wih_perm^T + (bih+bhh)_perm   (2-term, fp32 out)
    hgemm<128,128,64,32,0,0,2><<<dim3(G_DIM/128, B_DIM/128), 256, SM128_T2>>>(
        conds_h, Wih_h, Wih_l, bperm, nullptr,
        CWB, nullptr, B_DIM, G_DIM, H_DIM);
    // [6] ZW = z @ Wih_perm^T + CWB[row % B]   (1-term, fp16 out)
    hgemm<128,128,64,32,1,0,1><<<dim3(G_DIM/128, TB/128), 256, SM128_T1>>>(
        z_h, Wih_h, nullptr, nullptr, CWB,
        nullptr, ZW, TB, G_DIM, H_DIM);

    // [7] Persistent recurrence (one launch, 256 CTAs @ 2/SM, Whh 1-term, BK=64)
    lstm_persistent<<<GRID_P, 256, SMP>>>(Whh_h, ZW, H_h);

    // [8..10] Projection MLP over all T*B rows (P1/P2 1-term, P3 2-term)
    hgemm<128,128,64,32,2,1,1><<<dim3(H_DIM/128, TB/128), 256, SM128_T1>>>(
        H_h, P1_h, nullptr, pb1, nullptr,
        nullptr, y1_h, TB, H_DIM, H_DIM);
    hgemm<128,128,64,32,2,1,1><<<dim3(H_DIM/128, TB/128), 256, SM128_T1>>>(
        y1_h, P2_h, nullptr, pb2, nullptr,
        nullptr, y2_h, TB, H_DIM, H_DIM);
    hgemm<128,64,64,16,3,0,2><<<dim3(D_DIM/64, TB/128), 256, SM64B>>>(
        y2_h, P3_h, P3_l, pb3, nullptr,
        out, nullptr, TB, D_DIM, H_DIM);
}

// round 15
// speedup vs baseline: 6.6031x; 1.0239x over previous
#include <cuda_runtime.h>
#include <cuda_fp16.h>
#include <math.h>
#include <stdint.h>

// Problem dims (fixed by the dataset)
#define B_DIM 1024
#define T_DIM 128
#define L_DIM 16
#define H_DIM 512
#define D_DIM 64
#define G_DIM 2048          // 4*H
#define TB_DIM (T_DIM * B_DIM)
#define GRID_P 256          // persistent recurrence grid (2 CTAs/SM)

// ---------------------------------------------------------------------------
// Scratch. Activations single fp16; Wih/W2/W3/P3 2-term, Whh/P1/P2 1-term.
// ZW stored fp16 (gate pre-activations, O(1) scale).
// ---------------------------------------------------------------------------
__device__ float    g_bperm[G_DIM];
__device__ float    g_zbias[H_DIM];
__device__ unsigned short g_x1h[B_DIM * H_DIM];
__device__ unsigned short g_x2h[B_DIM * H_DIM];
__device__ unsigned short g_conds_h[B_DIM * H_DIM];
__device__ unsigned short g_W2_h[H_DIM * H_DIM];
__device__ unsigned short g_W2_l[H_DIM * H_DIM];
__device__ unsigned short g_W3_h[H_DIM * H_DIM];
__device__ unsigned short g_W3_l[H_DIM * H_DIM];
__device__ unsigned short g_Wih_h[G_DIM * H_DIM];
__device__ unsigned short g_Wih_l[G_DIM * H_DIM];
__device__ unsigned short g_Whh_h[G_DIM * H_DIM];
__device__ unsigned short g_P1_h[H_DIM * H_DIM];
__device__ unsigned short g_P2_h[H_DIM * H_DIM];
__device__ unsigned short g_P3_h[D_DIM * H_DIM];
__device__ unsigned short g_P3_l[D_DIM * H_DIM];
__device__ float    g_CWB[B_DIM * G_DIM];
__device__ unsigned short g_z_h[(size_t)TB_DIM * H_DIM];   // 128 MB
__device__ unsigned short g_ZW[(size_t)TB_DIM * G_DIM];    // 512 MB (fp16)
__device__ unsigned short g_H_h[(size_t)TB_DIM * H_DIM];
__device__ unsigned short g_y1_h[(size_t)TB_DIM * H_DIM];
__device__ unsigned short g_y2_h[(size_t)TB_DIM * H_DIM];

// Persistent-kernel grid barrier (monotonic; self-reset at kernel end)
__device__ unsigned g_bar_ctr  = 0;
__device__ unsigned g_done_ctr = 0;

// ---------------------------------------------------------------------------
// Helpers
// ---------------------------------------------------------------------------
__device__ __forceinline__ unsigned short h_of(float x) {
    return __half_as_ushort(__float2half_rn(x));
}
__device__ __forceinline__ float f_of(unsigned short u) {
    return __half2float(__ushort_as_half(u));
}
__device__ __forceinline__ void hsplit(float x, unsigned short& hi, unsigned short& lo) {
    __half h = __float2half_rn(x);
    float r = x - __half2float(h);
    __half l = __float2half_rn(r);
    hi = __half_as_ushort(h);
    lo = __half_as_ushort(l);
}

// mma m16n8k16 row.col fp16 -> f32
__device__ __forceinline__ void mma16816(float& c0, float& c1, float& c2, float& c3,
                                         unsigned a0, unsigned a1, unsigned a2, unsigned a3,
                                         unsigned b0, unsigned b1) {
    asm volatile(
        "mma.sync.aligned.m16n8k16.row.col.f32.f16.f16.f32 "
        "{%0,%1,%2,%3}, {%4,%5,%6,%7}, {%8,%9}, {%0,%1,%2,%3};\n"
        : "+f"(c0), "+f"(c1), "+f"(c2), "+f"(c3)
        : "r"(a0), "r"(a1), "r"(a2), "r"(a3), "r"(b0), "r"(b1));
}

__device__ __forceinline__ void ldsm4(unsigned& r0, unsigned& r1,
                                      unsigned& r2, unsigned& r3, uint32_t a) {
    asm volatile("ldmatrix.sync.aligned.m8n8.x4.shared.b16 {%0,%1,%2,%3}, [%4];"
                 : "=r"(r0), "=r"(r1), "=r"(r2), "=r"(r3) : "r"(a));
}

__device__ __forceinline__ void cp_async16(void* sptr, const void* gptr) {
    unsigned sa = (unsigned)__cvta_generic_to_shared(sptr);
    asm volatile("cp.async.cg.shared.global [%0], [%1], 16;\n" :: "r"(sa), "l"(gptr));
}
__device__ __forceinline__ void cp_commit() {
    asm volatile("cp.async.commit_group;\n");
}
template<int N>
__device__ __forceinline__ void cp_wait() {
    asm volatile("cp.async.wait_group %0;\n" :: "n"(N));
}

// ---------------------------------------------------------------------------
// fp16 GEMM: D[M,N] = A@B^T, A single fp16, B = Bh (+ Bl if TERMS==2).
// BK=32 2-stage cp.async, ldmatrix fragments, STR=40 ushorts (conflict-free).
// EPI: 0 = fp32 + bias (CWB)
//      1 = fp16 out: acc + addvec[row % B][col]  (ZW build, CWB fold)
//      2 = fp16 out + bias (+relu if ACT)    (label MLP L2/L3, P1, P2)
//      3 = fp32 + bias, [T,B]->[B,T] perm    (P3)
// ---------------------------------------------------------------------------
template<int BM, int BN, int WM, int WN, int EPI, int ACT, int TERMS>
__global__ void __launch_bounds__((BM / WM) * (BN / WN) * 32, 2)
hgemm(const unsigned short* __restrict__ A,
      const unsigned short* __restrict__ Bh, const unsigned short* __restrict__ Bl,
      const float* __restrict__ bias,
      const float* __restrict__ addvec,
      float* __restrict__ outf,
      unsigned short* __restrict__ outh,
      int M, int N, int K)
{
    constexpr int BK = 32;
    constexpr int STR = BK + 8;              // 40 ushorts
    constexpr int ATI = BM * STR;
    constexpr int BTI = BN * STR;
    constexpr int STAGE = ATI + TERMS * BTI;
    constexpr int WARPS_N = BN / WN;
    constexpr int NTH = (BM / WM) * (BN / WN) * 32;
    constexpr int MI = WM / 16, NI = WN / 8;

    extern __shared__ unsigned short sm[];

    const int tid  = threadIdx.x;
    const int warp = tid >> 5, lane = tid & 31;
    const int g = lane >> 2, t = lane & 3;
    const int wm0 = (warp / WARPS_N) * WM;
    const int wn0 = (warp % WARPS_N) * WN;
    const int m0 = blockIdx.y * BM;
    const int n0 = blockIdx.x * BN;

    const uint32_t smb = (uint32_t)__cvta_generic_to_shared(sm);
    const int aRow = (lane & 7) + ((lane >> 3) & 1) * 8;
    const int aKh  = (lane >> 4) * 16;
    const int bRow = (lane & 7) + (lane >> 4) * 8;
    const int bKh  = ((lane >> 3) & 1) * 16;
    const uint32_t aBase = smb + (uint32_t)(wm0 + aRow) * STR * 2 + aKh;
    const uint32_t bBase = smb + (uint32_t)(ATI + (wn0 + bRow) * STR) * 2 + bKh;

    float acc[MI][NI][4];
#pragma unroll
    for (int mi = 0; mi < MI; mi++)
#pragma unroll
        for (int ni = 0; ni < NI; ni++)
#pragma unroll
            for (int q = 0; q < 4; q++) acc[mi][ni][q] = 0.f;

    auto load_stage = [&](int k0, int s) {
        unsigned short* st = sm + s * STAGE;
#pragma unroll
        for (int i = tid; i < BM * 4; i += NTH) {
            int r = i >> 2, c = i & 3;
            cp_async16(st + r * STR + c * 8, A + (size_t)(m0 + r) * K + k0 + c * 8);
        }
#pragma unroll
        for (int i = tid; i < BN * 4; i += NTH) {
            int r = i >> 2, c = i & 3;
            const size_t gs = (size_t)(n0 + r) * K + k0 + c * 8;
            cp_async16(st + ATI + r * STR + c * 8, Bh + gs);
            if (TERMS == 2)
                cp_async16(st + ATI + BTI + r * STR + c * 8, Bl + gs);
        }
        cp_commit();
    };

    const int KT = K / BK;
    load_stage(0, 0);

    for (int kt = 0; kt < KT; kt++) {
        const int s = kt & 1;
        if (kt + 1 < KT) { load_stage((kt + 1) * BK, s ^ 1); cp_wait<1>(); }
        else             { cp_wait<0>(); }
        __syncthreads();

        const uint32_t stOff = (uint32_t)(s * STAGE) * 2;
        const uint32_t aA = aBase + stOff;
        const uint32_t bH = bBase + stOff;
        const uint32_t bL = bH + (uint32_t)BTI * 2;

#pragma unroll
        for (int kk = 0; kk < BK; kk += 16) {
            unsigned ah[MI][4], bh[NI][2], bl[NI][2];
#pragma unroll
            for (int mi = 0; mi < MI; mi++)
                ldsm4(ah[mi][0], ah[mi][1], ah[mi][2], ah[mi][3],
                      aA + (uint32_t)(mi * 16 * STR + kk) * 2);
#pragma unroll
            for (int p = 0; p < NI / 2; p++) {
                ldsm4(bh[2*p][0], bh[2*p][1], bh[2*p+1][0], bh[2*p+1][1],
                      bH + (uint32_t)(p * 16 * STR + kk) * 2);
                if (TERMS == 2)
                    ldsm4(bl[2*p][0], bl[2*p][1], bl[2*p+1][0], bl[2*p+1][1],
                          bL + (uint32_t)(p * 16 * STR + kk) * 2);
            }
#pragma unroll
            for (int mi = 0; mi < MI; mi++)
#pragma unroll
                for (int ni = 0; ni < NI; ni++) {
                    mma16816(acc[mi][ni][0], acc[mi][ni][1], acc[mi][ni][2], acc[mi][ni][3],
                             ah[mi][0], ah[mi][1], ah[mi][2], ah[mi][3], bh[ni][0], bh[ni][1]);
                    if (TERMS == 2)
                        mma16816(acc[mi][ni][0], acc[mi][ni][1], acc[mi][ni][2], acc[mi][ni][3],
                                 ah[mi][0], ah[mi][1], ah[mi][2], ah[mi][3], bl[ni][0], bl[ni][1]);
                }
        }
        __syncthreads();
    }

    // ---- Epilogues ----
    if (EPI == 0 || EPI == 2 || EPI == 3) {
        float2 bv[NI];
#pragma unroll
        for (int ni = 0; ni < NI; ni++)
            bv[ni] = *(const float2*)(bias + n0 + wn0 + ni * 8 + 2 * t);

#pragma unroll
        for (int mi = 0; mi < MI; mi++) {
            int row0 = m0 + wm0 + mi * 16 + g;
#pragma unroll
            for (int ni = 0; ni < NI; ni++) {
                int col = n0 + wn0 + ni * 8 + 2 * t;
                float v0 = acc[mi][ni][0] + bv[ni].x;
                float v1 = acc[mi][ni][1] + bv[ni].y;
                float v2 = acc[mi][ni][2] + bv[ni].x;
                float v3 = acc[mi][ni][3] + bv[ni].y;
                if (ACT == 1) {
                    v0 = fmaxf(v0, 0.f); v1 = fmaxf(v1, 0.f);
                    v2 = fmaxf(v2, 0.f); v3 = fmaxf(v3, 0.f);
                }
                if (EPI == 0) {
                    *(float2*)(outf + (size_t)row0 * N + col)       = make_float2(v0, v1);
                    *(float2*)(outf + (size_t)(row0 + 8) * N + col) = make_float2(v2, v3);
                } else if (EPI == 2) {
                    *(ushort2*)(outh + (size_t)row0 * N + col) =
                        make_ushort2(h_of(v0), h_of(v1));
                    *(ushort2*)(outh + (size_t)(row0 + 8) * N + col) =
                        make_ushort2(h_of(v2), h_of(v3));
                } else {
                    int tt0 = row0 / B_DIM, bb0 = row0 % B_DIM;
                    int r1 = row0 + 8;
                    int tt1 = r1 / B_DIM, bb1 = r1 % B_DIM;
                    *(float2*)(outf + ((size_t)bb0 * T_DIM + tt0) * D_DIM + col) = make_float2(v0, v1);
                    *(float2*)(outf + ((size_t)bb1 * T_DIM + tt1) * D_DIM + col) = make_float2(v2, v3);
                }
            }
        }
    } else {
        // EPI == 1: fp16 out, + addvec (CWB incl. biases)
#pragma unroll
        for (int mi = 0; mi < MI; mi++) {
            int row0 = m0 + wm0 + mi * 16 + g;
#pragma unroll
            for (int ni = 0; ni < NI; ni++) {
                int col = n0 + wn0 + ni * 8 + 2 * t;
                float2 a0 = *(const float2*)(addvec + (size_t)(row0 & (B_DIM - 1)) * N + col);
                float2 a1 = *(const float2*)(addvec + (size_t)((row0 + 8) & (B_DIM - 1)) * N + col);
                *(ushort2*)(outh + (size_t)row0 * N + col) =
                    make_ushort2(h_of(acc[mi][ni][0] + a0.x), h_of(acc[mi][ni][1] + a0.y));
                *(ushort2*)(outh + (size_t)(row0 + 8) * N + col) =
                    make_ushort2(h_of(acc[mi][ni][2] + a1.x), h_of(acc[mi][ni][3] + a1.y));
            }
        }
    }
}

// ---------------------------------------------------------------------------
// Persistent LSTM recurrence: 256 CTAs (2/SM), tile 64x128, BK=64 (8 k-iters),
// Whh 1-term. ZW[t] prefetched into registers BEFORE the step's MMA pipeline
// (rides out DRAM latency under the MMAs). Grid barrier: atomic arrival +
// volatile-load poll.
// ---------------------------------------------------------------------------
__global__ void __launch_bounds__(256, 2)
lstm_persistent(const unsigned short* __restrict__ Whh_h,
                const unsigned short* __restrict__ ZW,   // fp16 [T][B][G] (perm)
                unsigned short* __restrict__ H_h)
{
    constexpr int BM = 64, BN = 128, BK = 64, WM = 32, WN = 32;
    constexpr int STR = BK + 8;                // 72 ushorts
    constexpr int ATI = BM * STR, BTI = BN * STR;
    constexpr int STAGE = ATI + BTI;
    constexpr int WARPS_N = BN / WN;
    constexpr int NTH = 256;
    constexpr int MI = WM / 16, NI = WN / 8;   // 2, 4
    constexpr int K = H_DIM, N = G_DIM;
    constexpr int KT = K / BK;                 // 8

    extern __shared__ unsigned short sm[];

    const int tid  = threadIdx.x;
    const int warp = tid >> 5, lane = tid & 31;
    const int g = lane >> 2, t4 = lane & 3;
    const int wm0 = (warp / WARPS_N) * WM;
    const int wn0 = (warp % WARPS_N) * WN;
    const int bid = blockIdx.x;
    const int m0 = (bid >> 4) * BM;
    const int n0 = (bid & 15) * BN;

    const uint32_t smb = (uint32_t)__cvta_generic_to_shared(sm);
    const int aRow = (lane & 7) + ((lane >> 3) & 1) * 8;
    const int aKh  = (lane >> 4) * 16;
    const int bRow = (lane & 7) + (lane >> 4) * 8;
    const int bKh  = ((lane >> 3) & 1) * 16;
    const uint32_t aBase = smb + (uint32_t)(wm0 + aRow) * STR * 2 + aKh;
    const uint32_t bBase = smb + (uint32_t)(ATI + (wn0 + bRow) * STR) * 2 + bKh;

    const bool hi_half = (t4 & 1);

    // Per-thread (row, zw-offset) for the cell lanes (fixed across steps)
    int rowIdx[MI];
    size_t zwOff[MI][NI];
#pragma unroll
    for (int mi = 0; mi < MI; mi++) {
        int row0 = m0 + wm0 + mi * 16 + g;
        int row = hi_half ? row0 + 8 : row0;
        rowIdx[mi] = row;
#pragma unroll
        for (int ni = 0; ni < NI; ni++) {
            int col = n0 + wn0 + ni * 8 + 2 * t4;
            zwOff[mi][ni] = (size_t)row * G_DIM + (col & ~3);
        }
    }

    float creg[MI][NI];
#pragma unroll
    for (int mi = 0; mi < MI; mi++)
#pragma unroll
        for (int ni = 0; ni < NI; ni++) creg[mi][ni] = 0.f;

    for (int t = 0; t < T_DIM; t++) {
        // ---- Prefetch ZW[t] into registers (overlaps with MMA below) ----
        const unsigned short* zwb = ZW + (size_t)t * B_DIM * G_DIM;
        ushort4 zpre[MI][NI];
#pragma unroll
        for (int mi = 0; mi < MI; mi++)
#pragma unroll
            for (int ni = 0; ni < NI; ni++)
                zpre[mi][ni] = *(const ushort4*)(zwb + zwOff[mi][ni]);

        float acc[MI][NI][4];
#pragma unroll
        for (int mi = 0; mi < MI; mi++)
#pragma unroll
            for (int ni = 0; ni < NI; ni++)
#pragma unroll
                for (int q = 0; q < 4; q++) acc[mi][ni][q] = 0.f;

        if (t > 0) {
            const unsigned short* Ah = H_h + (size_t)(t - 1) * B_DIM * H_DIM;

            auto load_stage = [&](int k0, int s) {
                unsigned short* st = sm + s * STAGE;
#pragma unroll
                for (int i = tid; i < BM * 8; i += NTH) {
                    int r = i >> 3, c = i & 7;
                    cp_async16(st + r * STR + c * 8, Ah + (size_t)(m0 + r) * K + k0 + c * 8);
                }
#pragma unroll
                for (int i = tid; i < BN * 8; i += NTH) {
                    int r = i >> 3, c = i & 7;
                    cp_async16(st + ATI + r * STR + c * 8,
                               Whh_h + (size_t)(n0 + r) * K + k0 + c * 8);
                }
                cp_commit();
            };

            load_stage(0, 0);
            for (int kt = 0; kt < KT; kt++) {
                const int s = kt & 1;
                if (kt + 1 < KT) { load_stage((kt + 1) * BK, s ^ 1); cp_wait<1>(); }
                else             { cp_wait<0>(); }
                __syncthreads();

                const uint32_t stOff = (uint32_t)(s * STAGE) * 2;
                const uint32_t aA = aBase + stOff;
                const uint32_t bH = bBase + stOff;

#pragma unroll
                for (int kk = 0; kk < BK; kk += 16) {
                    unsigned ah[MI][4], bh[NI][2];
#pragma unroll
                    for (int mi = 0; mi < MI; mi++)
                        ldsm4(ah[mi][0], ah[mi][1], ah[mi][2], ah[mi][3],
                              aA + (uint32_t)(mi * 16 * STR + kk) * 2);
#pragma unroll
                    for (int p = 0; p < NI / 2; p++)
                        ldsm4(bh[2*p][0], bh[2*p][1], bh[2*p+1][0], bh[2*p+1][1],
                              bH + (uint32_t)(p * 16 * STR + kk) * 2);
#pragma unroll
                    for (int mi = 0; mi < MI; mi++)
#pragma unroll
                        for (int ni = 0; ni < NI; ni++)
                            mma16816(acc[mi][ni][0], acc[mi][ni][1], acc[mi][ni][2], acc[mi][ni][3],
                                     ah[mi][0], ah[mi][1], ah[mi][2], ah[mi][3], bh[ni][0], bh[ni][1]);
                }
                __syncthreads();
            }
        }

        // ---- Cell epilogue (c in registers; ZW prefetched) ----
        unsigned short* hh = H_h + (size_t)t * B_DIM * H_DIM;
#pragma unroll
        for (int mi = 0; mi < MI; mi++) {
            int row = rowIdx[mi];
#pragma unroll
            for (int ni = 0; ni < NI; ni++) {
                int col = n0 + wn0 + ni * 8 + 2 * t4;
                float c0 = acc[mi][ni][0], c1 = acc[mi][ni][1];
                float c2 = acc[mi][ni][2], c3 = acc[mi][ni][3];
                float sx = __shfl_xor_sync(0xffffffffu, hi_half ? c0 : c2, 1);
                float sy = __shfl_xor_sync(0xffffffffu, hi_half ? c1 : c3, 1);
                float gi, gf, gg, go;
                if (!hi_half) { gi = c0; gf = c1; gg = sx; go = sy; }
                else          { gi = sx; gf = sy; gg = c2; go = c3; }

                ushort4 zr = zpre[mi][ni];
                gi += f_of(zr.x); gf += f_of(zr.y);
                gg += f_of(zr.z); go += f_of(zr.w);

                float ig = 1.f / (1.f + expf(-gi));
                float fg = 1.f / (1.f + expf(-gf));
                float gt = tanhf(gg);
                float og = 1.f / (1.f + expf(-go));

                float cn = fg * creg[mi][ni] + ig * gt;
                creg[mi][ni] = cn;
                hh[(size_t)row * H_DIM + (col >> 2)] = h_of(og * tanhf(cn));
            }
        }

        // ---- Grid barrier: atomic arrival, volatile-load poll ----
        if (t < T_DIM - 1) {
            __syncthreads();
            if (tid == 0) {
                __threadfence();
                atomicAdd(&g_bar_ctr, 1u);
                unsigned target = (unsigned)(t + 1) * GRID_P;
                volatile unsigned* ctr = &g_bar_ctr;
                while (*ctr < target) { }
                __threadfence();
            }
            __syncthreads();
        }
    }

    // Deterministic counter reset for graph replay
    __syncthreads();
    if (tid == 0) {
        unsigned d = atomicAdd(&g_done_ctr, 1u);
        if (d == GRID_P - 1) {
            g_bar_ctr = 0;
            g_done_ctr = 0;
            __threadfence();
        }
    }
}

// ---------------------------------------------------------------------------
// f32x2 SGEMM (label MLP layer 1, K=16). OUT: 0 fp32, 1 single fp16.
// ---------------------------------------------------------------------------
__device__ __forceinline__ void ffma2(unsigned long long& d,
                                      unsigned long long a,
                                      unsigned long long b) {
    asm("fma.rn.f32x2 %0, %1, %2, %0;" : "+l"(d) : "l"(a), "l"(b));
}
__device__ __forceinline__ unsigned long long pack2(float lo, float hi) {
    unsigned long long r;
    asm("mov.b64 %0, {%1, %2};" : "=l"(r) : "f"(lo), "f"(hi));
    return r;
}
__device__ __forceinline__ float2 unpack2(unsigned long long u) {
    float2 f;
    asm("mov.b64 {%0, %1}, %2;" : "=f"(f.x), "=f"(f.y) : "l"(u));
    return f;
}

template<int BM, int BN, int BK, int TM, int TN, int ACT, int OUT>
__global__ void gemm2_kernel(const float* __restrict__ A,
                             const float* __restrict__ W,
                             const float* __restrict__ bias,
                             float* __restrict__ C,
                             unsigned short* __restrict__ uh,
                             int M, int N, int K)
{
    constexpr int AS_STRIDE = BM + 4;
    constexpr int WS_STRIDE = BN + 4;
    __shared__ float As[BK][AS_STRIDE];
    __shared__ float Ws[BK][WS_STRIDE];

    constexpr int NTH = (BM / TM) * (BN / TN);
    const int tid = threadIdx.x;
    const int tx = tid % (BN / TN);
    const int ty = tid / (BN / TN);
    const int m0 = blockIdx.y * BM;
    const int n0 = blockIdx.x * BN;

    unsigned long long acc2[TM / 2][TN];
#pragma unroll
    for (int p = 0; p < TM / 2; p++)
#pragma unroll
        for (int j = 0; j < TN; j++) acc2[p][j] = 0ULL;

    for (int k0 = 0; k0 < K; k0 += BK) {
#pragma unroll
        for (int i = tid * 4; i < BM * BK; i += NTH * 4) {
            int m = i / BK, k = i % BK;
            float4 v = *(const float4*)(A + (long)(m0 + m) * K + (k0 + k));
            As[k + 0][m] = v.x; As[k + 1][m] = v.y;
            As[k + 2][m] = v.z; As[k + 3][m] = v.w;
        }
#pragma unroll
        for (int i = tid * 4; i < BN * BK; i += NTH * 4) {
            int n = i / BK, k = i % BK;
            float4 v = *(const float4*)(W + (long)(n0 + n) * K + (k0 + k));
            Ws[k + 0][n] = v.x; Ws[k + 1][n] = v.y;
            Ws[k + 2][n] = v.z; Ws[k + 3][n] = v.w;
        }
        __syncthreads();

#pragma unroll
        for (int k = 0; k < BK; k++) {
            unsigned long long am2[TM / 2];
            const ulonglong2* ap = reinterpret_cast<const ulonglong2*>(&As[k][ty * TM]);
#pragma unroll
            for (int q = 0; q < TM / 4; q++) {
                ulonglong2 tt = ap[q];
                am2[2 * q + 0] = tt.x;
                am2[2 * q + 1] = tt.y;
            }
            float4 w4 = *reinterpret_cast<const float4*>(&Ws[k][tx * TN]);
            unsigned long long wd[TN];
            wd[0] = pack2(w4.x, w4.x); wd[1] = pack2(w4.y, w4.y);
            wd[2] = pack2(w4.z, w4.z); wd[3] = pack2(w4.w, w4.w);
#pragma unroll
            for (int p = 0; p < TM / 2; p++)
#pragma unroll
                for (int j = 0; j < TN; j++) ffma2(acc2[p][j], am2[p], wd[j]);
        }
        __syncthreads();
    }

    float4 bv = make_float4(0.f, 0.f, 0.f, 0.f);
    if (bias) bv = *reinterpret_cast<const float4*>(bias + n0 + tx * TN);

#pragma unroll
    for (int p = 0; p < TM / 2; p++) {
        float2 v0 = unpack2(acc2[p][0]);
        float2 v1 = unpack2(acc2[p][1]);
        float2 v2 = unpack2(acc2[p][2]);
        float2 v3 = unpack2(acc2[p][3]);
        float4 rowA = make_float4(v0.x + bv.x, v1.x + bv.y, v2.x + bv.z, v3.x + bv.w);
        float4 rowB = make_float4(v0.y + bv.x, v1.y + bv.y, v2.y + bv.z, v3.y + bv.w);
        if (ACT == 1) {
            rowA.x = fmaxf(rowA.x, 0.f); rowA.y = fmaxf(rowA.y, 0.f);
            rowA.z = fmaxf(rowA.z, 0.f); rowA.w = fmaxf(rowA.w, 0.f);
            rowB.x = fmaxf(rowB.x, 0.f); rowB.y = fmaxf(rowB.y, 0.f);
            rowB.z = fmaxf(rowB.z, 0.f); rowB.w = fmaxf(rowB.w, 0.f);
        }
        int mA = m0 + ty * TM + 2 * p;
        int n  = n0 + tx * TN;
        if (OUT == 0) {
            *reinterpret_cast<float4*>(C + (long)mA * N + n) = rowA;
            *reinterpret_cast<float4*>(C + (long)(mA + 1) * N + n) = rowB;
        } else {
            *(ushort4*)(uh + (size_t)mA * N + n) =
                make_ushort4(h_of(rowA.x), h_of(rowA.y), h_of(rowA.z), h_of(rowA.w));
            *(ushort4*)(uh + (size_t)(mA + 1) * N + n) =
                make_ushort4(h_of(rowB.x), h_of(rowB.y), h_of(rowB.z), h_of(rowB.w));
        }
    }
}

// ---------------------------------------------------------------------------
// Prep kernels
// ---------------------------------------------------------------------------
__device__ __forceinline__ void split4w(const float4* src, int i,
                                        ushort4* hi, ushort4* lo) {
    float4 v = src[i];
    ushort4 h, l;
    hsplit(v.x, h.x, l.x); hsplit(v.y, h.y, l.y);
    hsplit(v.z, h.z, l.z); hsplit(v.w, h.w, l.w);
    hi[i] = h;
    if (lo) lo[i] = l;
}

__device__ __forceinline__ void permsplit4w(const float* src, int i,
                                            ushort4* hi, ushort4* lo) {
    int r = i / (H_DIM / 4);
    int c = i % (H_DIM / 4);
    int j = r >> 2, gg = r & 3;
    float4 v = ((const float4*)src)[(size_t)(gg * H_DIM + j) * (H_DIM / 4) + c];
    ushort4 h, l;
    hsplit(v.x, h.x, l.x); hsplit(v.y, h.y, l.y);
    hsplit(v.z, h.z, l.z); hsplit(v.w, h.w, l.w);
    size_t o = (size_t)r * (H_DIM / 4) + c;
    hi[o] = h;
    if (lo) lo[o] = l;
}

__global__ void prep_weights(const float* __restrict__ P1, const float* __restrict__ P2,
                             const float* __restrict__ P3,
                             const float* __restrict__ Wih, const float* __restrict__ Whh,
                             const float* __restrict__ W2, const float* __restrict__ W3,
                             const float* __restrict__ bih, const float* __restrict__ bhh,
                             ushort4* P1h, ushort4* P2h,
                             ushort4* P3h, ushort4* P3l,
                             ushort4* Wihh, ushort4* Wihl, ushort4* Whhh,
                             ushort4* W2h, ushort4* W2l, ushort4* W3h, ushort4* W3l,
                             float* bp, float* zb)
{
    const int S0 = H_DIM * H_DIM / 4;              // P1
    const int S1 = S0 + H_DIM * H_DIM / 4;         // P2
    const int S2 = S1 + D_DIM * H_DIM / 4;         // P3
    const int S3 = S2 + G_DIM * H_DIM / 4;         // Wih
    const int S4 = S3 + G_DIM * H_DIM / 4;         // Whh
    const int S5 = S4 + H_DIM * H_DIM / 4;         // W2
    const int S6 = S5 + H_DIM * H_DIM / 4;         // W3
    int i = blockIdx.x * blockDim.x + threadIdx.x;
    if      (i < S0) split4w((const float4*)P1, i, P1h, nullptr);
    else if (i < S1) split4w((const float4*)P2, i - S0, P2h, nullptr);
    else if (i < S2) split4w((const float4*)P3, i - S1, P3h, P3l);
    else if (i < S3) permsplit4w(Wih, i - S2, Wihh, Wihl);
    else if (i < S4) permsplit4w(Whh, i - S3, Whhh, nullptr);
    else if (i < S5) split4w((const float4*)W2, i - S4, W2h, W2l);
    else if (i < S6) split4w((const float4*)W3, i - S5, W3h, W3l);
    else if (i < S6 + G_DIM) {
        int k = i - S6;
        int j = k >> 2, gg = k & 3;
        bp[k] = bih[gg * H_DIM + j] + bhh[gg * H_DIM + j];
    }
    else if (i < S6 + G_DIM + H_DIM) {
        zb[i - S6 - G_DIM] = 0.f;
    }
}

// z -> single fp16
__global__ void cvt_half_kernel(const float4* __restrict__ src,
                                ushort4* __restrict__ dst, int n4)
{
    int i = blockIdx.x * blockDim.x + threadIdx.x;
    if (i >= n4) return;
    float4 v = src[i];
    dst[i] = make_ushort4(h_of(v.x), h_of(v.y), h_of(v.z), h_of(v.w));
}

// ---------------------------------------------------------------------------
// Launch
// ---------------------------------------------------------------------------
extern "C" void kernel_launch(void* const* d_in, const int* in_sizes, int n_in,
                              void* d_out, int out_size)
{
    const float* labels = (const float*)d_in[0];
    const float* z      = (const float*)d_in[1];
    const float* W1     = (const float*)d_in[2];
    const float* b1     = (const float*)d_in[3];
    const float* W2     = (const float*)d_in[4];
    const float* b2     = (const float*)d_in[5];
    const float* W3     = (const float*)d_in[6];
    const float* Wih    = (const float*)d_in[7];
    const float* Whh    = (const float*)d_in[8];
    const float* bih    = (const float*)d_in[9];
    const float* bhh    = (const float*)d_in[10];
    const float* P1     = (const float*)d_in[11];
    const float* pb1    = (const float*)d_in[12];
    const float* P2     = (const float*)d_in[13];
    const float* pb2    = (const float*)d_in[14];
    const float* P3     = (const float*)d_in[15];
    const float* pb3    = (const float*)d_in[16];
    float* out = (float*)d_out;

    float *bperm, *zbias, *CWB;
    unsigned short *x1h, *x2h, *conds_h;
    unsigned short *W2_h, *W2_l, *W3_h, *W3_l;
    unsigned short *Wih_h, *Wih_l, *Whh_h;
    unsigned short *P1_h, *P2_h, *P3_h, *P3_l;
    unsigned short *z_h, *ZW, *H_h, *y1_h, *y2_h;
    cudaGetSymbolAddress((void**)&bperm,  g_bperm);
    cudaGetSymbolAddress((void**)&zbias,  g_zbias);
    cudaGetSymbolAddress((void**)&x1h,    g_x1h);
    cudaGetSymbolAddress((void**)&x2h,    g_x2h);
    cudaGetSymbolAddress((void**)&conds_h, g_conds_h);
    cudaGetSymbolAddress((void**)&W2_h,   g_W2_h);
    cudaGetSymbolAddress((void**)&W2_l,   g_W2_l);
    cudaGetSymbolAddress((void**)&W3_h,   g_W3_h);
    cudaGetSymbolAddress((void**)&W3_l,   g_W3_l);
    cudaGetSymbolAddress((void**)&Wih_h,  g_Wih_h);
    cudaGetSymbolAddress((void**)&Wih_l,  g_Wih_l);
    cudaGetSymbolAddress((void**)&Whh_h,  g_Whh_h);
    cudaGetSymbolAddress((void**)&P1_h,   g_P1_h);
    cudaGetSymbolAddress((void**)&P2_h,   g_P2_h);
    cudaGetSymbolAddress((void**)&P3_h,   g_P3_h);
    cudaGetSymbolAddress((void**)&P3_l,   g_P3_l);
    cudaGetSymbolAddress((void**)&CWB,    g_CWB);
    cudaGetSymbolAddress((void**)&z_h,    g_z_h);
    cudaGetSymbolAddress((void**)&ZW,     g_ZW);
    cudaGetSymbolAddress((void**)&H_h,    g_H_h);
    cudaGetSymbolAddress((void**)&y1_h,   g_y1_h);
    cudaGetSymbolAddress((void**)&y2_h,   g_y2_h);

    const int TB = TB_DIM;

    // Dynamic smem: hgemm BK=32 (STR=40); persistent BK=64 (STR=72)
    constexpr int SM128_T2 = 2 * (128 * 40 + 2 * 128 * 40) * 2;  // 61440 B
    constexpr int SM128_T1 = 2 * (128 * 40 + 1 * 128 * 40) * 2;  // 40960 B
    constexpr int SM64B    = 2 * (128 * 40 + 2 * 64 * 40) * 2;   // 40960 B (BN=64)
    constexpr int SMP      = 2 * (64 * 72 + 128 * 72) * 2;       // 55296 B
    cudaFuncSetAttribute((const void*)hgemm<128,128,64,32,0,0,2>,
                         cudaFuncAttributeMaxDynamicSharedMemorySize, SM128_T2);
    cudaFuncSetAttribute((const void*)hgemm<128,128,64,32,1,0,1>,
                         cudaFuncAttributeMaxDynamicSharedMemorySize, SM128_T1);
    cudaFuncSetAttribute((const void*)hgemm<128,128,64,32,2,1,1>,
                         cudaFuncAttributeMaxDynamicSharedMemorySize, SM128_T1);
    cudaFuncSetAttribute((const void*)hgemm<128,128,64,32,2,1,2>,
                         cudaFuncAttributeMaxDynamicSharedMemorySize, SM128_T2);
    cudaFuncSetAttribute((const void*)hgemm<128,128,64,32,2,0,2>,
                         cudaFuncAttributeMaxDynamicSharedMemorySize, SM128_T2);
    cudaFuncSetAttribute((const void*)hgemm<128,64,64,16,3,0,2>,
                         cudaFuncAttributeMaxDynamicSharedMemorySize, SM64B);
    cudaFuncSetAttribute((const void*)lstm_persistent,
                         cudaFuncAttributeMaxDynamicSharedMemorySize, SMP);

    // [0] fused weight prep
    {
        const int total = 4 * (H_DIM * H_DIM / 4) + D_DIM * H_DIM / 4
                        + 2 * (G_DIM * H_DIM / 4) + G_DIM + H_DIM;
        prep_weights<<<(total + 255) / 256, 256>>>(
            P1, P2, P3, Wih, Whh, W2, W3, bih, bhh,
            (ushort4*)P1_h, (ushort4*)P2_h,
            (ushort4*)P3_h, (ushort4*)P3_l,
            (ushort4*)Wih_h, (ushort4*)Wih_l, (ushort4*)Whh_h,
            (ushort4*)W2_h, (ushort4*)W2_l, (ushort4*)W3_h, (ushort4*)W3_l,
            bperm, zbias);
    }
    // [1] z -> fp16
    cvt_half_kernel<<<(int)(((size_t)TB * H_DIM / 4) / 256), 256>>>(
        (const float4*)z, (ushort4*)z_h, TB * (H_DIM / 4));

    // [2] Label MLP layer 1 (K=16, f32x2) -> fp16
    gemm2_kernel<64,64,16,4,4,1,1><<<dim3(H_DIM/64, B_DIM/64), 256>>>(
        labels, W1, b1, nullptr, x1h, B_DIM, H_DIM, L_DIM);
    // [3,4] Label MLP layers 2-3 on tensor cores (2-term weights)
    hgemm<128,128,64,32,2,1,2><<<dim3(H_DIM/128, B_DIM/128), 256, SM128_T2>>>(
        x1h, W2_h, W2_l, b2, nullptr, nullptr, x2h, B_DIM, H_DIM, H_DIM);
    hgemm<128,128,64,32,2,0,2><<<dim3(H_DIM/128, B_DIM/128), 256, SM128_T2>>>(
        x2h, W3_h, W3_l, zbias, nullptr, nullptr, conds_h, B_DIM, H_DIM, H_DIM);

    // [5] CWB = conds @ Wih_perm^T + (bih+bhh)_perm   (2-term, fp32 out)
    hgemm<128,128,64,32,0,0,2><<<dim3(G_DIM/128, B_DIM/128), 256, SM128_T2>>>(
        conds_h, Wih_h, Wih_l, bperm, nullptr,
        CWB, nullptr, B_DIM, G_DIM, H_DIM);
    // [6] ZW = z @ Wih_perm^T + CWB[row % B]   (1-term, fp16 out)
    hgemm<128,128,64,32,1,0,1><<<dim3(G_DIM/128, TB/128), 256, SM128_T1>>>(
        z_h, Wih_h, nullptr, nullptr, CWB,
        nullptr, ZW, TB, G_DIM, H_DIM);

    // [7] Persistent recurrence (256 CTAs @ 2/SM, Whh 1-term, BK=64, ZW prefetch)
    lstm_persistent<<<GRID_P, 256, SMP>>>(Whh_h, ZW, H_h);

    // [8..10] Projection MLP over all T*B rows (P1/P2 1-term, P3 2-term)
    hgemm<128,128,64,32,2,1,1><<<dim3(H_DIM/128, TB/128), 256, SM128_T1>>>(
        H_h, P1_h, nullptr, pb1, nullptr,
        nullptr, y1_h, TB, H_DIM, H_DIM);
    hgemm<128,128,64,32,2,1,1><<<dim3(H_DIM/128, TB/128), 256, SM128_T1>>>(
        y1_h, P2_h, nullptr, pb2, nullptr,
        nullptr, y2_h, TB, H_DIM, H_DIM);
    hgemm<128,64,64,16,3,0,2><<<dim3(D_DIM/64, TB/128), 256, SM64B>>>(
        y2_h, P3_h, P3_l, pb3, nullptr,
        out, nullptr, TB, D_DIM, H_DIM);
}